// round 2
// baseline (speedup 1.0000x reference)
#include <cuda_runtime.h>
#include <math.h>

// B=1024, S=32, D=1024, D2=2048
// inputs: x[B,S,D], pe[S,D], Wq[D2,D2], bq[D2], Wk, bk, Wv, bv, Wfc[1,S*D2], bfc[1]
// out: [B,1] fp32

// ----- static scratch (no allocation) -----
__device__ float g_Y[33554432];   // Y = X@M + Bm  [32768,1024]
__device__ float g_M[1048576];    // M = Wq1^T Wk1 [1024,1024]
__device__ float g_Cq[65536];     // [32,2048]
__device__ float g_Ck[65536];
__device__ float g_Cv[65536];
__device__ float g_A [32768];     // A  = Ck@Wq1 [32,1024]
__device__ float g_Bm[32768];     // Bm = Cq@Wk1
__device__ float g_G [32768];     // G  = Wf@Wv1
__device__ float g_part[786432];  // [3][8][32][1024] K-split partials
__device__ float g_c[1024];       // c = Cq@Ck^T [32,32]
__device__ float g_P[1024];       // P = Wf@Cv^T [32,32]

__device__ __forceinline__ float wredsum(float v) {
#pragma unroll
    for (int o = 16; o; o >>= 1) v += __shfl_xor_sync(0xffffffffu, v, o);
    return v;
}
__device__ __forceinline__ float wredmax(float v) {
#pragma unroll
    for (int o = 16; o; o >>= 1) v = fmaxf(v, __shfl_xor_sync(0xffffffffu, v, o));
    return v;
}

// ----- kernel 1: Cq/Ck/Cv = pe @ W2^T + b  -----
// grid(256,1,3) block 256. warp handles column d2 = bx*8+warp.
__global__ void k_precompC(const float* __restrict__ pe,
                           const float* __restrict__ Wq, const float* __restrict__ bq,
                           const float* __restrict__ Wk, const float* __restrict__ bk,
                           const float* __restrict__ Wv, const float* __restrict__ bv) {
    const float* W; const float* bias; float* out;
    if (blockIdx.z == 0)      { W = Wq; bias = bq; out = g_Cq; }
    else if (blockIdx.z == 1) { W = Wk; bias = bk; out = g_Ck; }
    else                      { W = Wv; bias = bv; out = g_Cv; }
    __shared__ float pes[32][33];
    int tid = threadIdx.x;
    int warp = tid >> 5, lane = tid & 31;
    int d2 = blockIdx.x * 8 + warp;
    float acc[32];
#pragma unroll
    for (int i = 0; i < 32; i++) acc[i] = 0.f;
    for (int e0 = 0; e0 < 1024; e0 += 32) {
        __syncthreads();
#pragma unroll
        for (int p = 0; p < 4; p++) {
            int idx = p * 256 + tid;
            pes[idx >> 5][idx & 31] = pe[(idx >> 5) * 1024 + e0 + (idx & 31)];
        }
        __syncthreads();
        float wv = W[(size_t)d2 * 2048 + 1024 + e0 + lane];
#pragma unroll
        for (int i = 0; i < 32; i++) acc[i] += pes[i][lane] * wv;
    }
    float res = 0.f;
#pragma unroll
    for (int i = 0; i < 32; i++) {
        float r = wredsum(acc[i]);
        if (lane == i) res = r;
    }
    out[lane * 2048 + d2] = res + bias[d2];
}

// ----- kernel 2: M = Wq1^T @ Wk1 (K=2048) ----- grid(16,16) block 256
__global__ __launch_bounds__(256) void k_gemmM(const float* __restrict__ Wq,
                                               const float* __restrict__ Wk) {
    __shared__ __align__(16) float As[16][64];
    __shared__ __align__(16) float Bs[16][64];
    int tid = threadIdx.x;
    int m0 = blockIdx.y * 64, n0 = blockIdx.x * 64;
    int lr = tid >> 4, lc = (tid & 15) * 4;
    int ty = tid >> 4, tx = tid & 15;
    float acc[4][4] = {};
    for (int k0 = 0; k0 < 2048; k0 += 16) {
        float4 av = *(const float4*)(Wq + (size_t)(k0 + lr) * 2048 + m0 + lc);
        float4 bv = *(const float4*)(Wk + (size_t)(k0 + lr) * 2048 + n0 + lc);
        __syncthreads();
        *(float4*)&As[lr][lc] = av;
        *(float4*)&Bs[lr][lc] = bv;
        __syncthreads();
#pragma unroll
        for (int kk = 0; kk < 16; kk++) {
            float4 a = *(const float4*)&As[kk][ty * 4];
            float4 b = *(const float4*)&Bs[kk][tx * 4];
            float aa[4] = {a.x, a.y, a.z, a.w};
            float bb[4] = {b.x, b.y, b.z, b.w};
#pragma unroll
            for (int i = 0; i < 4; i++)
#pragma unroll
                for (int j = 0; j < 4; j++) acc[i][j] += aa[i] * bb[j];
        }
    }
#pragma unroll
    for (int i = 0; i < 4; i++) {
        float4 r = make_float4(acc[i][0], acc[i][1], acc[i][2], acc[i][3]);
        *(float4*)(g_M + (size_t)(m0 + ty * 4 + i) * 1024 + n0 + tx * 4) = r;
    }
}

// ----- kernel 3: skinny gemms (K-split) ----- grid(8,8,3) block 128
__global__ void k_skinny(const float* __restrict__ Wq, const float* __restrict__ Wk,
                         const float* __restrict__ Wv, const float* __restrict__ Wfc) {
    const float* L; const float* R;
    int z = blockIdx.z;
    if (z == 0)      { L = g_Ck; R = Wq; }   // A  = Ck@Wq1
    else if (z == 1) { L = g_Cq; R = Wk; }   // Bm = Cq@Wk1
    else             { L = Wfc;  R = Wv; }   // G  = Wf@Wv1
    __shared__ float Lsh[32][64];
    int tid = threadIdx.x;
    int e  = blockIdx.x * 128 + tid;
    int d0 = blockIdx.y * 256;
    float acc[32];
#pragma unroll
    for (int j = 0; j < 32; j++) acc[j] = 0.f;
    for (int c0 = 0; c0 < 256; c0 += 64) {
        __syncthreads();
#pragma unroll
        for (int p = 0; p < 16; p++) {
            int idx = p * 128 + tid;
            Lsh[idx >> 6][idx & 63] = L[(idx >> 6) * 2048 + d0 + c0 + (idx & 63)];
        }
        __syncthreads();
#pragma unroll 4
        for (int dd = 0; dd < 64; dd++) {
            float w = R[(size_t)(d0 + c0 + dd) * 2048 + e];
#pragma unroll
            for (int j = 0; j < 32; j++) acc[j] += Lsh[j][dd] * w;
        }
    }
    int base = ((z * 8 + blockIdx.y) * 32) * 1024 + e;
#pragma unroll
    for (int j = 0; j < 32; j++) g_part[base + j * 1024] = acc[j];
}

__global__ void k_skred() {
    int idx = blockIdx.x * 256 + threadIdx.x;  // 98304 total
    int z = idx >> 15;
    int r = idx & 32767;
    float s = 0.f;
#pragma unroll
    for (int kc = 0; kc < 8; kc++) s += g_part[(z * 8 + kc) * 32768 + r];
    float* out = (z == 0) ? g_A : (z == 1) ? g_Bm : g_G;
    out[r] = s;
}

// ----- kernel 4: c = Cq@Ck^T, P = Wf@Cv^T ----- grid(32,2) block 256
__global__ void k_small(const float* __restrict__ Wfc) {
    int i = blockIdx.x;
    const float* L; const float* R; float* out;
    if (blockIdx.y == 0) { L = g_Cq; R = g_Ck; out = g_c; }
    else                 { L = Wfc;  R = g_Cv; out = g_P; }
    int tid = threadIdx.x, warp = tid >> 5, lane = tid & 31;
    float acc[4] = {0.f, 0.f, 0.f, 0.f};
    for (int d = lane; d < 2048; d += 32) {
        float lv = L[i * 2048 + d];
#pragma unroll
        for (int q = 0; q < 4; q++) acc[q] += lv * R[(warp * 4 + q) * 2048 + d];
    }
#pragma unroll
    for (int q = 0; q < 4; q++) {
        float r = wredsum(acc[q]);
        if (lane == 0) out[i * 32 + warp * 4 + q] = r;
    }
}

// ----- kernel 5: Y = X @ M + Bm[row%32] ----- grid(8,256) block 256, 128x128x16
__global__ __launch_bounds__(256) void k_ygemm(const float* __restrict__ X) {
    __shared__ __align__(16) float As[16][132];
    __shared__ __align__(16) float Bs[16][128];
    int tid = threadIdx.x;
    int bn = blockIdx.x, bm = blockIdx.y;
    int tx = tid & 15, ty = tid >> 4;
    const float* Xg = X + (size_t)bm * 128 * 1024;
    const float* Mg = g_M + bn * 128;
    float acc[8][8] = {};
    int ar0 = tid >> 2, ac = (tid & 3) * 4;
    int br0 = tid >> 5, bc = (tid & 31) * 4;
    for (int k0 = 0; k0 < 1024; k0 += 16) {
        float4 a0 = *(const float4*)(Xg + (size_t)ar0 * 1024 + k0 + ac);
        float4 a1 = *(const float4*)(Xg + (size_t)(ar0 + 64) * 1024 + k0 + ac);
        float4 b0 = *(const float4*)(Mg + (size_t)(k0 + br0) * 1024 + bc);
        float4 b1 = *(const float4*)(Mg + (size_t)(k0 + br0 + 8) * 1024 + bc);
        __syncthreads();
        As[ac + 0][ar0] = a0.x; As[ac + 1][ar0] = a0.y;
        As[ac + 2][ar0] = a0.z; As[ac + 3][ar0] = a0.w;
        As[ac + 0][ar0 + 64] = a1.x; As[ac + 1][ar0 + 64] = a1.y;
        As[ac + 2][ar0 + 64] = a1.z; As[ac + 3][ar0 + 64] = a1.w;
        *(float4*)&Bs[br0][bc]     = b0;
        *(float4*)&Bs[br0 + 8][bc] = b1;
        __syncthreads();
#pragma unroll
        for (int kk = 0; kk < 16; kk++) {
            float a[8], b[8];
            *(float4*)&a[0] = *(const float4*)&As[kk][ty * 4];
            *(float4*)&a[4] = *(const float4*)&As[kk][64 + ty * 4];
            *(float4*)&b[0] = *(const float4*)&Bs[kk][tx * 4];
            *(float4*)&b[4] = *(const float4*)&Bs[kk][64 + tx * 4];
#pragma unroll
            for (int i = 0; i < 8; i++)
#pragma unroll
                for (int j = 0; j < 8; j++) acc[i][j] += a[i] * b[j];
        }
    }
#pragma unroll
    for (int gi = 0; gi < 2; gi++) {
#pragma unroll
        for (int i = 0; i < 4; i++) {
            int grow = bm * 128 + gi * 64 + ty * 4 + i;
            int pei  = grow & 31;
#pragma unroll
            for (int gj = 0; gj < 2; gj++) {
                int gcol = bn * 128 + gj * 64 + tx * 4;
                float4 bb = *(const float4*)(g_Bm + pei * 1024 + gcol);
                float4 r;
                r.x = acc[gi * 4 + i][gj * 4 + 0] + bb.x;
                r.y = acc[gi * 4 + i][gj * 4 + 1] + bb.y;
                r.z = acc[gi * 4 + i][gj * 4 + 2] + bb.z;
                r.w = acc[gi * 4 + i][gj * 4 + 3] + bb.w;
                *(float4*)(g_Y + (size_t)grow * 1024 + gcol) = r;
            }
        }
    }
}

// ----- kernel 6: per-batch R=[Y_b;A;G]@X_b^T, logits, softmax(dim=1), reduce -----
// grid(1024) block 256
__global__ __launch_bounds__(256) void k_attn(const float* __restrict__ X,
                                              const float* __restrict__ bfc,
                                              float* __restrict__ out) {
    __shared__ __align__(16) float Ws[96 * 64];
    __shared__ __align__(16) float Xs[64 * 36];
    __shared__ float wpart[8];
    int tid = threadIdx.x;
    int b = blockIdx.x;
    const float* Xb = X + (size_t)b * 32768;
    const float* Yb = g_Y + (size_t)b * 32768;
    int rgrp = tid >> 3, cgrp = tid & 7;     // rows rgrp*3..+2, cols cgrp*4..+3
    float acc[3][4] = {};
    for (int k0 = 0; k0 < 1024; k0 += 64) {
        __syncthreads();
#pragma unroll
        for (int p = 0; p < 8; p++) {
            int idx = p * 256 + tid;
            int j = idx >> 6, kk = idx & 63;
            Xs[kk * 36 + j] = Xb[j * 1024 + k0 + kk];
        }
#pragma unroll
        for (int p = 0; p < 24; p++) {
            int idx = p * 256 + tid;
            int row = idx >> 6, kk = idx & 63;
            const float* src = (row < 32) ? (Yb + row * 1024)
                              : (row < 64) ? (g_A + (row - 32) * 1024)
                                           : (g_G + (row - 64) * 1024);
            Ws[row * 64 + kk] = src[k0 + kk];
        }
        __syncthreads();
#pragma unroll 8
        for (int kk = 0; kk < 64; kk++) {
            float4 xv = *(const float4*)&Xs[kk * 36 + cgrp * 4];
            float xa[4] = {xv.x, xv.y, xv.z, xv.w};
#pragma unroll
            for (int ri = 0; ri < 3; ri++) {
                float wv = Ws[(rgrp * 3 + ri) * 64 + kk];
#pragma unroll
                for (int ci = 0; ci < 4; ci++) acc[ri][ci] += wv * xa[ci];
            }
        }
    }
    __syncthreads();
    float* Rs = Ws;  // reuse: [96][33]
#pragma unroll
    for (int ri = 0; ri < 3; ri++)
#pragma unroll
        for (int ci = 0; ci < 4; ci++)
            Rs[(rgrp * 3 + ri) * 33 + cgrp * 4 + ci] = acc[ri][ci];
    __syncthreads();

    int w = tid >> 5, lane = tid & 31;
    const float rscale = 0.022097086912079608f;  // 1/sqrt(2048)
    float local = 0.f;
#pragma unroll
    for (int q = 0; q < 4; q++) {
        int j = w * 4 + q;
        // logit[i=lane][j] = Y'_b[i].x_j + A[j].x_i + c[i,j]
        float lg = (Rs[lane * 33 + j] + Rs[(32 + j) * 33 + lane] + g_c[lane * 32 + j]) * rscale;
        float mx = wredmax(lg);
        float ex = __expf(lg - mx);
        float sm = wredsum(ex);
        float contrib = (ex / sm) * (Rs[(64 + lane) * 33 + j] + g_P[lane * 32 + j]);
        local += wredsum(contrib);
    }
    if (lane == 0) wpart[w] = local;
    __syncthreads();
    if (tid == 0) {
        float t = 0.f;
#pragma unroll
        for (int i = 0; i < 8; i++) t += wpart[i];
        out[b] = t + bfc[0];
    }
}

extern "C" void kernel_launch(void* const* d_in, const int* in_sizes, int n_in,
                              void* d_out, int out_size) {
    const float* x   = (const float*)d_in[0];
    const float* pe  = (const float*)d_in[1];
    const float* Wq  = (const float*)d_in[2];
    const float* bq  = (const float*)d_in[3];
    const float* Wk  = (const float*)d_in[4];
    const float* bk  = (const float*)d_in[5];
    const float* Wv  = (const float*)d_in[6];
    const float* bv  = (const float*)d_in[7];
    const float* Wfc = (const float*)d_in[8];
    const float* bfc = (const float*)d_in[9];
    float* out = (float*)d_out;

    k_precompC<<<dim3(256, 1, 3), 256>>>(pe, Wq, bq, Wk, bk, Wv, bv);
    k_gemmM<<<dim3(16, 16), 256>>>(Wq, Wk);
    k_skinny<<<dim3(8, 8, 3), 128>>>(Wq, Wk, Wv, Wfc);
    k_skred<<<384, 256>>>();
    k_small<<<dim3(32, 2), 256>>>(Wfc);
    k_ygemm<<<dim3(8, 256), 256>>>(x);
    k_attn<<<1024, 256>>>(x, bfc, out);
}

// round 4
// speedup vs baseline: 1.4772x; 1.4772x over previous
#include <cuda_runtime.h>
#include <cuda_bf16.h>
#include <math.h>
#include <stdint.h>

// B=1024, S=32, D=1024, D2=2048
// out[b] via: Cq/Ck/Cv = pe@W2^T+b ; M=Wq1^T Wk1 ; A=Ck@Wq1 ; Bm=Cq@Wk1 ; G=Wf@Wv1
//            c=Cq@Ck^T ; P=Wf@Cv^T ; Y=X@M+Bm ; per-batch attn+reduce.
// Y-GEMM on mma.sync bf16 (2-way split, 3 products hh+hl+lh, fp32 reg accum).

// ----- static scratch -----
__device__ float g_Y[33554432];   // [32768,1024]
__device__ float g_M[1048576];    // [1024,1024]
__device__ float g_Cq[65536], g_Ck[65536], g_Cv[65536];
__device__ float g_A[32768], g_Bm[32768], g_G[32768];
__device__ float g_part[786432];
__device__ float g_c[1024], g_P[1024];
__device__ __align__(16) __nv_bfloat16 g_Xhi[33554432];  // [32768,1024]
__device__ __align__(16) __nv_bfloat16 g_Xlo[33554432];
__device__ __align__(16) __nv_bfloat16 g_MhiT[1048576];  // [n=1024,k=1024] = M^T split
__device__ __align__(16) __nv_bfloat16 g_MloT[1048576];

__device__ __forceinline__ float wredsum(float v) {
#pragma unroll
    for (int o = 16; o; o >>= 1) v += __shfl_xor_sync(0xffffffffu, v, o);
    return v;
}
__device__ __forceinline__ float wredmax(float v) {
#pragma unroll
    for (int o = 16; o; o >>= 1) v = fmaxf(v, __shfl_xor_sync(0xffffffffu, v, o));
    return v;
}
__device__ __forceinline__ uint32_t smem_u32(const void* p) {
    uint32_t a;
    asm("{ .reg .u64 t; cvta.to.shared.u64 t, %1; cvt.u32.u64 %0, t; }" : "=r"(a) : "l"(p));
    return a;
}

// ----- kernel 1: Cq/Ck/Cv = pe @ W2^T + b -----
__global__ void k_precompC(const float* __restrict__ pe,
                           const float* __restrict__ Wq, const float* __restrict__ bq,
                           const float* __restrict__ Wk, const float* __restrict__ bk,
                           const float* __restrict__ Wv, const float* __restrict__ bv) {
    const float* W; const float* bias; float* out;
    if (blockIdx.z == 0)      { W = Wq; bias = bq; out = g_Cq; }
    else if (blockIdx.z == 1) { W = Wk; bias = bk; out = g_Ck; }
    else                      { W = Wv; bias = bv; out = g_Cv; }
    __shared__ float pes[32][33];
    int tid = threadIdx.x;
    int warp = tid >> 5, lane = tid & 31;
    int d2 = blockIdx.x * 8 + warp;
    float acc[32];
#pragma unroll
    for (int i = 0; i < 32; i++) acc[i] = 0.f;
    for (int e0 = 0; e0 < 1024; e0 += 32) {
        __syncthreads();
#pragma unroll
        for (int p = 0; p < 4; p++) {
            int idx = p * 256 + tid;
            pes[idx >> 5][idx & 31] = pe[(idx >> 5) * 1024 + e0 + (idx & 31)];
        }
        __syncthreads();
        float wv = W[(size_t)d2 * 2048 + 1024 + e0 + lane];
#pragma unroll
        for (int i = 0; i < 32; i++) acc[i] += pes[i][lane] * wv;
    }
    float res = 0.f;
#pragma unroll
    for (int i = 0; i < 32; i++) {
        float r = wredsum(acc[i]);
        if (lane == i) res = r;
    }
    out[lane * 2048 + d2] = res + bias[d2];
}

// ----- kernel 2: M = Wq1^T @ Wk1 -----
__global__ __launch_bounds__(256) void k_gemmM(const float* __restrict__ Wq,
                                               const float* __restrict__ Wk) {
    __shared__ __align__(16) float As[16][64];
    __shared__ __align__(16) float Bs[16][64];
    int tid = threadIdx.x;
    int m0 = blockIdx.y * 64, n0 = blockIdx.x * 64;
    int lr = tid >> 4, lc = (tid & 15) * 4;
    int ty = tid >> 4, tx = tid & 15;
    float acc[4][4] = {};
    for (int k0 = 0; k0 < 2048; k0 += 16) {
        float4 av = *(const float4*)(Wq + (size_t)(k0 + lr) * 2048 + m0 + lc);
        float4 bv = *(const float4*)(Wk + (size_t)(k0 + lr) * 2048 + n0 + lc);
        __syncthreads();
        *(float4*)&As[lr][lc] = av;
        *(float4*)&Bs[lr][lc] = bv;
        __syncthreads();
#pragma unroll
        for (int kk = 0; kk < 16; kk++) {
            float4 a = *(const float4*)&As[kk][ty * 4];
            float4 b = *(const float4*)&Bs[kk][tx * 4];
            float aa[4] = {a.x, a.y, a.z, a.w};
            float bb[4] = {b.x, b.y, b.z, b.w};
#pragma unroll
            for (int i = 0; i < 4; i++)
#pragma unroll
                for (int j = 0; j < 4; j++) acc[i][j] += aa[i] * bb[j];
        }
    }
#pragma unroll
    for (int i = 0; i < 4; i++) {
        float4 r = make_float4(acc[i][0], acc[i][1], acc[i][2], acc[i][3]);
        *(float4*)(g_M + (size_t)(m0 + ty * 4 + i) * 1024 + n0 + tx * 4) = r;
    }
}

// ----- split M (transpose + bf16 hi/lo): MhiT/MloT[n][k] = split(M[k][n]) -----
__global__ void k_splitM() {
    __shared__ float t[32][33];
    int bx = blockIdx.x, by = blockIdx.y;
    int x = threadIdx.x, y = threadIdx.y;  // 32x8
#pragma unroll
    for (int i = 0; i < 32; i += 8)
        t[y + i][x] = g_M[(size_t)(by * 32 + y + i) * 1024 + bx * 32 + x];
    __syncthreads();
#pragma unroll
    for (int i = 0; i < 32; i += 8) {
        float v = t[x][y + i];
        __nv_bfloat16 h = __float2bfloat16(v);
        __nv_bfloat16 l = __float2bfloat16(v - __bfloat162float(h));
        size_t o = (size_t)(bx * 32 + y + i) * 1024 + by * 32 + x;
        g_MhiT[o] = h;
        g_MloT[o] = l;
    }
}

// ----- split X: Xhi/Xlo bf16 -----
__global__ void k_splitX(const float* __restrict__ x) {
    size_t i = ((size_t)blockIdx.x * 256 + threadIdx.x) * 4;  // grid 32768
    float4 v = *(const float4*)(x + i);
    __nv_bfloat16 h0 = __float2bfloat16(v.x), h1 = __float2bfloat16(v.y);
    __nv_bfloat16 h2 = __float2bfloat16(v.z), h3 = __float2bfloat16(v.w);
    __nv_bfloat162 hi0(h0, h1), hi1(h2, h3);
    __nv_bfloat162 lo0(__float2bfloat16(v.x - __bfloat162float(h0)),
                       __float2bfloat16(v.y - __bfloat162float(h1)));
    __nv_bfloat162 lo1(__float2bfloat16(v.z - __bfloat162float(h2)),
                       __float2bfloat16(v.w - __bfloat162float(h3)));
    *(__nv_bfloat162*)(g_Xhi + i) = hi0;
    *(__nv_bfloat162*)(g_Xhi + i + 2) = hi1;
    *(__nv_bfloat162*)(g_Xlo + i) = lo0;
    *(__nv_bfloat162*)(g_Xlo + i + 2) = lo1;
}

// ----- kernel 3: skinny gemms -----
__global__ void k_skinny(const float* __restrict__ Wq, const float* __restrict__ Wk,
                         const float* __restrict__ Wv, const float* __restrict__ Wfc) {
    const float* L; const float* R;
    int z = blockIdx.z;
    if (z == 0)      { L = g_Ck; R = Wq; }
    else if (z == 1) { L = g_Cq; R = Wk; }
    else             { L = Wfc;  R = Wv; }
    __shared__ float Lsh[32][64];
    int tid = threadIdx.x;
    int e  = blockIdx.x * 128 + tid;
    int d0 = blockIdx.y * 256;
    float acc[32];
#pragma unroll
    for (int j = 0; j < 32; j++) acc[j] = 0.f;
    for (int c0 = 0; c0 < 256; c0 += 64) {
        __syncthreads();
#pragma unroll
        for (int p = 0; p < 16; p++) {
            int idx = p * 128 + tid;
            Lsh[idx >> 6][idx & 63] = L[(idx >> 6) * 2048 + d0 + c0 + (idx & 63)];
        }
        __syncthreads();
#pragma unroll 4
        for (int dd = 0; dd < 64; dd++) {
            float w = R[(size_t)(d0 + c0 + dd) * 2048 + e];
#pragma unroll
            for (int j = 0; j < 32; j++) acc[j] += Lsh[j][dd] * w;
        }
    }
    int base = ((z * 8 + blockIdx.y) * 32) * 1024 + e;
#pragma unroll
    for (int j = 0; j < 32; j++) g_part[base + j * 1024] = acc[j];
}

__global__ void k_skred() {
    int idx = blockIdx.x * 256 + threadIdx.x;
    int z = idx >> 15;
    int r = idx & 32767;
    float s = 0.f;
#pragma unroll
    for (int kc = 0; kc < 8; kc++) s += g_part[(z * 8 + kc) * 32768 + r];
    float* out = (z == 0) ? g_A : (z == 1) ? g_Bm : g_G;
    out[r] = s;
}

// ----- kernel 4: c = Cq@Ck^T, P = Wf@Cv^T -----
__global__ void k_small(const float* __restrict__ Wfc) {
    int i = blockIdx.x;
    const float* L; const float* R; float* out;
    if (blockIdx.y == 0) { L = g_Cq; R = g_Ck; out = g_c; }
    else                 { L = Wfc;  R = g_Cv; out = g_P; }
    int tid = threadIdx.x, warp = tid >> 5, lane = tid & 31;
    float acc[4] = {0.f, 0.f, 0.f, 0.f};
    for (int d = lane; d < 2048; d += 32) {
        float lv = L[i * 2048 + d];
#pragma unroll
        for (int q = 0; q < 4; q++) acc[q] += lv * R[(warp * 4 + q) * 2048 + d];
    }
#pragma unroll
    for (int q = 0; q < 4; q++) {
        float r = wredsum(acc[q]);
        if (lane == 0) out[i * 32 + warp * 4 + q] = r;
    }
}

// ================= kernel 5: Y = X@M + Bm via mma.sync bf16 =================
// CTA 128x128, BK=64, 8 warps (2x4), warp tile 64x32, fp32 reg accum.
// 3 products: Xhi*MhiT + Xhi*MloT + Xlo*MhiT (48 flattened k-chunk iterations).
#define YPAD 72                       // halves per smem row (144 B)
#define YA_BYTES (128 * YPAD * 2)     // 18432
#define YSTAGE  (2 * YA_BYTES)        // A + B = 36864
#define YSMEM   (2 * YSTAGE)          // double buffer = 73728

__device__ __forceinline__ void ldsm4(uint32_t* r, uint32_t addr) {
    asm volatile("ldmatrix.sync.aligned.m8n8.x4.shared.b16 {%0,%1,%2,%3}, [%4];"
                 : "=r"(r[0]), "=r"(r[1]), "=r"(r[2]), "=r"(r[3]) : "r"(addr));
}
__device__ __forceinline__ void mma16816(float* d, const uint32_t* a,
                                         uint32_t b0, uint32_t b1) {
    asm volatile(
        "mma.sync.aligned.m16n8k16.row.col.f32.bf16.bf16.f32 "
        "{%0,%1,%2,%3}, {%4,%5,%6,%7}, {%8,%9}, {%0,%1,%2,%3};"
        : "+f"(d[0]), "+f"(d[1]), "+f"(d[2]), "+f"(d[3])
        : "r"(a[0]), "r"(a[1]), "r"(a[2]), "r"(a[3]), "r"(b0), "r"(b1));
}
__device__ __forceinline__ void cpasync16(uint32_t saddr, const void* gaddr) {
    asm volatile("cp.async.cg.shared.global [%0], [%1], 16;" :: "r"(saddr), "l"(gaddr));
}

__device__ __forceinline__ void ytc_stage(uint32_t sb, int s,
                                          const __nv_bfloat16* __restrict__ Asrc,
                                          const __nv_bfloat16* __restrict__ Bsrc,
                                          int m0, int n0, int k0, int tid) {
    uint32_t sa = sb + s * YSTAGE;
    uint32_t sbB = sa + YA_BYTES;
#pragma unroll
    for (int p = 0; p < 4; p++) {
        int idx = p * 256 + tid;          // 0..1023
        int row = idx >> 3, c = idx & 7;  // 128 rows x 8 16B-chunks
        uint32_t so = (uint32_t)(row * YPAD + c * 8) * 2;
        cpasync16(sa + so, Asrc + (size_t)(m0 + row) * 1024 + k0 + c * 8);
        cpasync16(sbB + so, Bsrc + (size_t)(n0 + row) * 1024 + k0 + c * 8);
    }
}

__global__ __launch_bounds__(256, 2) void k_ygemm_mma() {
    extern __shared__ __align__(16) char ysmem[];
    const uint32_t sb = smem_u32(ysmem);
    const int tid = threadIdx.x, lane = tid & 31, wid = tid >> 5;
    const int wm = wid >> 2, wn = wid & 3;
    const int m0 = blockIdx.y * 128, n0 = blockIdx.x * 128;

    const __nv_bfloat16* APs[3] = {g_Xhi, g_Xhi, g_Xlo};
    const __nv_bfloat16* BPs[3] = {g_MhiT, g_MloT, g_MhiT};

    ytc_stage(sb, 0, APs[0], BPs[0], m0, n0, 0, tid);
    asm volatile("cp.async.commit_group;" ::: "memory");

    float d[4][4][4] = {};
    // ldmatrix source rows (within CTA tile), fixed per thread
    const int aRow = wm * 64 + (lane & 15);
    const int aCol = (lane >> 4) * 8;
    const int bRow = wn * 32 + (lane & 7) + (lane >> 4) * 8;
    const int bCol = ((lane >> 3) & 1) * 8;

    for (int it = 0; it < 48; it++) {
        int nit = it + 1;
        if (nit < 48) {
            ytc_stage(sb, nit & 1, APs[nit >> 4], BPs[nit >> 4], m0, n0,
                      (nit & 15) * 64, tid);
            asm volatile("cp.async.commit_group;" ::: "memory");
            asm volatile("cp.async.wait_group 1;" ::: "memory");
        } else {
            asm volatile("cp.async.wait_group 0;" ::: "memory");
        }
        __syncthreads();
        uint32_t abase = sb + (it & 1) * YSTAGE;
        uint32_t bbase = abase + YA_BYTES;
#pragma unroll
        for (int ks = 0; ks < 4; ks++) {
            int kc = ks * 16;
            uint32_t ar[4][4];
#pragma unroll
            for (int i = 0; i < 4; i++)
                ldsm4(ar[i], abase + (uint32_t)((aRow + i * 16) * YPAD + kc + aCol) * 2);
            uint32_t br[2][4];
#pragma unroll
            for (int j = 0; j < 2; j++)
                ldsm4(br[j], bbase + (uint32_t)((bRow + j * 16) * YPAD + kc + bCol) * 2);
#pragma unroll
            for (int i = 0; i < 4; i++)
#pragma unroll
                for (int j = 0; j < 4; j++)
                    mma16816(d[i][j], ar[i], br[j >> 1][(j & 1) * 2],
                             br[j >> 1][(j & 1) * 2 + 1]);
        }
        __syncthreads();
    }

    // epilogue: add Bm[row&31] and store to g_Y
    const int grp = lane >> 2, tig = lane & 3;
    const int mb = m0 + wm * 64, nb = n0 + wn * 32;
#pragma unroll
    for (int i = 0; i < 4; i++) {
        int r0 = mb + i * 16 + grp, r1 = r0 + 8;
#pragma unroll
        for (int j = 0; j < 4; j++) {
            int cc = nb + j * 8 + tig * 2;
            float2 bm0 = *(const float2*)(g_Bm + (r0 & 31) * 1024 + cc);
            float2 bm1 = *(const float2*)(g_Bm + (r1 & 31) * 1024 + cc);
            float2 o0 = make_float2(d[i][j][0] + bm0.x, d[i][j][1] + bm0.y);
            float2 o1 = make_float2(d[i][j][2] + bm1.x, d[i][j][3] + bm1.y);
            *(float2*)(g_Y + (size_t)r0 * 1024 + cc) = o0;
            *(float2*)(g_Y + (size_t)r1 * 1024 + cc) = o1;
        }
    }
}

// ----- kernel 6: per-batch attention + epilogue -----
__global__ __launch_bounds__(256) void k_attn(const float* __restrict__ X,
                                              const float* __restrict__ bfc,
                                              float* __restrict__ out) {
    __shared__ __align__(16) float Ws[96 * 64];
    __shared__ __align__(16) float Xs[64 * 36];
    __shared__ float wpart[8];
    int tid = threadIdx.x;
    int b = blockIdx.x;
    const float* Xb = X + (size_t)b * 32768;
    const float* Yb = g_Y + (size_t)b * 32768;
    int rgrp = tid >> 3, cgrp = tid & 7;
    float acc[3][4] = {};
    for (int k0 = 0; k0 < 1024; k0 += 64) {
        __syncthreads();
#pragma unroll
        for (int p = 0; p < 8; p++) {
            int idx = p * 256 + tid;
            int j = idx >> 6, kk = idx & 63;
            Xs[kk * 36 + j] = Xb[j * 1024 + k0 + kk];
        }
#pragma unroll
        for (int p = 0; p < 24; p++) {
            int idx = p * 256 + tid;
            int row = idx >> 6, kk = idx & 63;
            const float* src = (row < 32) ? (Yb + row * 1024)
                              : (row < 64) ? (g_A + (row - 32) * 1024)
                                           : (g_G + (row - 64) * 1024);
            Ws[row * 64 + kk] = src[k0 + kk];
        }
        __syncthreads();
#pragma unroll 8
        for (int kk = 0; kk < 64; kk++) {
            float4 xv = *(const float4*)&Xs[kk * 36 + cgrp * 4];
            float xa[4] = {xv.x, xv.y, xv.z, xv.w};
#pragma unroll
            for (int ri = 0; ri < 3; ri++) {
                float wv = Ws[(rgrp * 3 + ri) * 64 + kk];
#pragma unroll
                for (int ci = 0; ci < 4; ci++) acc[ri][ci] += wv * xa[ci];
            }
        }
    }
    __syncthreads();
    float* Rs = Ws;
#pragma unroll
    for (int ri = 0; ri < 3; ri++)
#pragma unroll
        for (int ci = 0; ci < 4; ci++)
            Rs[(rgrp * 3 + ri) * 33 + cgrp * 4 + ci] = acc[ri][ci];
    __syncthreads();

    int w = tid >> 5, lane = tid & 31;
    const float rscale = 0.022097086912079608f;  // 1/sqrt(2048)
    float local = 0.f;
#pragma unroll
    for (int q = 0; q < 4; q++) {
        int j = w * 4 + q;
        float lg = (Rs[lane * 33 + j] + Rs[(32 + j) * 33 + lane] + g_c[lane * 32 + j]) * rscale;
        float mx = wredmax(lg);
        float ex = __expf(lg - mx);
        float sm = wredsum(ex);
        float contrib = (ex / sm) * (Rs[(64 + lane) * 33 + j] + g_P[lane * 32 + j]);
        local += wredsum(contrib);
    }
    if (lane == 0) wpart[w] = local;
    __syncthreads();
    if (tid == 0) {
        float t = 0.f;
#pragma unroll
        for (int i = 0; i < 8; i++) t += wpart[i];
        out[b] = t + bfc[0];
    }
}

extern "C" void kernel_launch(void* const* d_in, const int* in_sizes, int n_in,
                              void* d_out, int out_size) {
    const float* x   = (const float*)d_in[0];
    const float* pe  = (const float*)d_in[1];
    const float* Wq  = (const float*)d_in[2];
    const float* bq  = (const float*)d_in[3];
    const float* Wk  = (const float*)d_in[4];
    const float* bk  = (const float*)d_in[5];
    const float* Wv  = (const float*)d_in[6];
    const float* bv  = (const float*)d_in[7];
    const float* Wfc = (const float*)d_in[8];
    const float* bfc = (const float*)d_in[9];
    float* out = (float*)d_out;

    cudaFuncSetAttribute(k_ygemm_mma, cudaFuncAttributeMaxDynamicSharedMemorySize, YSMEM);

    k_precompC<<<dim3(256, 1, 3), 256>>>(pe, Wq, bq, Wk, bk, Wv, bv);
    k_gemmM<<<dim3(16, 16), 256>>>(Wq, Wk);
    k_splitM<<<dim3(32, 32), dim3(32, 8)>>>();
    k_splitX<<<32768, 256>>>(x);
    k_skinny<<<dim3(8, 8, 3), 128>>>(Wq, Wk, Wv, Wfc);
    k_skred<<<384, 256>>>();
    k_small<<<dim3(32, 2), 256>>>(Wfc);
    k_ygemm_mma<<<dim3(8, 256), 256, YSMEM>>>();
    k_attn<<<1024, 256>>>(x, bfc, out);
}

// round 5
// speedup vs baseline: 2.2427x; 1.5182x over previous
#include <cuda_runtime.h>
#include <cuda_bf16.h>
#include <cuda_fp16.h>
#include <math.h>
#include <stdint.h>

// B=1024, S=32, D=1024, D2=2048
// out[b] via: Cq/Ck/Cv = pe@W2^T+b ; M=Wq1^T Wk1 (bf16 3-split mma) ;
// A=Ck@Wq1 ; Bm=Cq@Wk1 ; G=Wf@Wv1 ; c=Cq@Ck^T ; P=Wf@Cv^T ;
// Y=X@M+Bm (fp16 single-product mma) ; per-batch attn+reduce (fp32).

// ----- static scratch -----
__device__ float g_Y[33554432];   // [32768,1024]
__device__ float g_M[1048576];    // [1024,1024]
__device__ float g_Cq[65536], g_Ck[65536], g_Cv[65536];
__device__ float g_A[32768], g_Bm[32768], g_G[32768];
__device__ float g_part[786432];
__device__ float g_c[1024], g_P[1024];
__device__ __align__(16) __half g_Xh[33554432];          // fp16 X [32768,1024]
__device__ __align__(16) __half g_MhT[1048576];          // fp16 M^T [n=f][k=e]
__device__ __align__(16) __nv_bfloat16 g_WqTh[2097152];  // [e=1024][d2=2048]
__device__ __align__(16) __nv_bfloat16 g_WqTl[2097152];
__device__ __align__(16) __nv_bfloat16 g_WkTh[2097152];
__device__ __align__(16) __nv_bfloat16 g_WkTl[2097152];

__device__ __forceinline__ float wredsum(float v) {
#pragma unroll
    for (int o = 16; o; o >>= 1) v += __shfl_xor_sync(0xffffffffu, v, o);
    return v;
}
__device__ __forceinline__ float wredmax(float v) {
#pragma unroll
    for (int o = 16; o; o >>= 1) v = fmaxf(v, __shfl_xor_sync(0xffffffffu, v, o));
    return v;
}
__device__ __forceinline__ uint32_t smem_u32(const void* p) {
    uint32_t a;
    asm("{ .reg .u64 t; cvta.to.shared.u64 t, %1; cvt.u32.u64 %0, t; }" : "=r"(a) : "l"(p));
    return a;
}
__device__ __forceinline__ void ldsm4(uint32_t* r, uint32_t addr) {
    asm volatile("ldmatrix.sync.aligned.m8n8.x4.shared.b16 {%0,%1,%2,%3}, [%4];"
                 : "=r"(r[0]), "=r"(r[1]), "=r"(r[2]), "=r"(r[3]) : "r"(addr));
}
__device__ __forceinline__ void mma_bf16(float* d, const uint32_t* a,
                                         uint32_t b0, uint32_t b1) {
    asm volatile(
        "mma.sync.aligned.m16n8k16.row.col.f32.bf16.bf16.f32 "
        "{%0,%1,%2,%3}, {%4,%5,%6,%7}, {%8,%9}, {%0,%1,%2,%3};"
        : "+f"(d[0]), "+f"(d[1]), "+f"(d[2]), "+f"(d[3])
        : "r"(a[0]), "r"(a[1]), "r"(a[2]), "r"(a[3]), "r"(b0), "r"(b1));
}
__device__ __forceinline__ void mma_f16(float* d, const uint32_t* a,
                                        uint32_t b0, uint32_t b1) {
    asm volatile(
        "mma.sync.aligned.m16n8k16.row.col.f32.f16.f16.f32 "
        "{%0,%1,%2,%3}, {%4,%5,%6,%7}, {%8,%9}, {%0,%1,%2,%3};"
        : "+f"(d[0]), "+f"(d[1]), "+f"(d[2]), "+f"(d[3])
        : "r"(a[0]), "r"(a[1]), "r"(a[2]), "r"(a[3]), "r"(b0), "r"(b1));
}
__device__ __forceinline__ void cpasync16(uint32_t saddr, const void* gaddr) {
    asm volatile("cp.async.cg.shared.global [%0], [%1], 16;" :: "r"(saddr), "l"(gaddr));
}

// ----- kernel 1: Cq/Ck/Cv = pe @ W2^T + b -----
__global__ void k_precompC(const float* __restrict__ pe,
                           const float* __restrict__ Wq, const float* __restrict__ bq,
                           const float* __restrict__ Wk, const float* __restrict__ bk,
                           const float* __restrict__ Wv, const float* __restrict__ bv) {
    const float* W; const float* bias; float* out;
    if (blockIdx.z == 0)      { W = Wq; bias = bq; out = g_Cq; }
    else if (blockIdx.z == 1) { W = Wk; bias = bk; out = g_Ck; }
    else                      { W = Wv; bias = bv; out = g_Cv; }
    __shared__ float pes[32][33];
    int tid = threadIdx.x;
    int warp = tid >> 5, lane = tid & 31;
    int d2 = blockIdx.x * 8 + warp;
    float acc[32];
#pragma unroll
    for (int i = 0; i < 32; i++) acc[i] = 0.f;
    for (int e0 = 0; e0 < 1024; e0 += 32) {
        __syncthreads();
#pragma unroll
        for (int p = 0; p < 4; p++) {
            int idx = p * 256 + tid;
            pes[idx >> 5][idx & 31] = pe[(idx >> 5) * 1024 + e0 + (idx & 31)];
        }
        __syncthreads();
        float wv = W[(size_t)d2 * 2048 + 1024 + e0 + lane];
#pragma unroll
        for (int i = 0; i < 32; i++) acc[i] += pes[i][lane] * wv;
    }
    float res = 0.f;
#pragma unroll
    for (int i = 0; i < 32; i++) {
        float r = wredsum(acc[i]);
        if (lane == i) res = r;
    }
    out[lane * 2048 + d2] = res + bias[d2];
}

// ----- transpose+split Wq1/Wk1: WT[e][d2] = hi/lo bf16 of W[d2][e] -----
__global__ void k_splitWT(const float* __restrict__ Wq, const float* __restrict__ Wk) {
    __shared__ float t[32][33];
    const float* W = blockIdx.z ? Wk : Wq;
    __nv_bfloat16* oh = blockIdx.z ? g_WkTh : g_WqTh;
    __nv_bfloat16* ol = blockIdx.z ? g_WkTl : g_WqTl;
    int bx = blockIdx.x, by = blockIdx.y;   // bx: e-tile (32), by: d2-tile (64)
    int x = threadIdx.x, y = threadIdx.y;   // 32x8
#pragma unroll
    for (int i = 0; i < 32; i += 8)
        t[y + i][x] = W[(size_t)(by * 32 + y + i) * 2048 + bx * 32 + x];
    __syncthreads();
#pragma unroll
    for (int i = 0; i < 32; i += 8) {
        float v = t[x][y + i];
        __nv_bfloat16 h = __float2bfloat16(v);
        __nv_bfloat16 l = __float2bfloat16(v - __bfloat162float(h));
        size_t o = (size_t)(bx * 32 + y + i) * 2048 + by * 32 + x;
        oh[o] = h;
        ol[o] = l;
    }
}

// ----- kernel 2: M = Wq1^T @ Wk1 via bf16 3-product mma -----
// m=e(1024), n=f(1024), k=d2(2048). CTA 128x128, BK=64, 8 warps (2x4).
#define GPAD 72
#define GBUF (128 * GPAD * 2)    // 18432
#define GSTAGE (4 * GBUF)        // Ah,Al,Bh,Bl = 73728
#define GSMEM (2 * GSTAGE)       // 147456

__device__ __forceinline__ void g_stage(uint32_t sb, int s, int m0, int n0,
                                        int k0, int tid) {
    uint32_t sa = sb + s * GSTAGE;
#pragma unroll
    for (int p = 0; p < 16; p++) {
        int idx = p * 256 + tid;
        int buf = idx >> 10;               // 0..3
        int t = idx & 1023;
        int row = t >> 3, c = t & 7;
        const __nv_bfloat16* src =
            (buf == 0) ? g_WqTh : (buf == 1) ? g_WqTl : (buf == 2) ? g_WkTh : g_WkTl;
        int r0 = (buf < 2) ? m0 : n0;
        cpasync16(sa + buf * GBUF + (uint32_t)(row * GPAD + c * 8) * 2,
                  src + (size_t)(r0 + row) * 2048 + k0 + c * 8);
    }
}

__global__ __launch_bounds__(256, 1) void k_gemmM_mma() {
    extern __shared__ __align__(16) char gsmem[];
    const uint32_t sb = smem_u32(gsmem);
    const int tid = threadIdx.x, lane = tid & 31, wid = tid >> 5;
    const int wm = wid >> 2, wn = wid & 3;
    const int m0 = blockIdx.y * 128, n0 = blockIdx.x * 128;

    g_stage(sb, 0, m0, n0, 0, tid);
    asm volatile("cp.async.commit_group;" ::: "memory");

    float d[4][4][4] = {};
    const int aRow = wm * 64 + (lane & 15);
    const int aCol = (lane >> 4) * 8;
    const int bRow = wn * 32 + (lane & 7) + (lane >> 4) * 8;
    const int bCol = ((lane >> 3) & 1) * 8;

    for (int it = 0; it < 32; it++) {
        int nit = it + 1;
        if (nit < 32) {
            g_stage(sb, nit & 1, m0, n0, nit * 64, tid);
            asm volatile("cp.async.commit_group;" ::: "memory");
            asm volatile("cp.async.wait_group 1;" ::: "memory");
        } else {
            asm volatile("cp.async.wait_group 0;" ::: "memory");
        }
        __syncthreads();
        uint32_t st = sb + (it & 1) * GSTAGE;
#pragma unroll
        for (int ks = 0; ks < 4; ks++) {
            int kc = ks * 16;
            uint32_t arh[4][4], arl[4][4];
#pragma unroll
            for (int i = 0; i < 4; i++) {
                uint32_t ao = (uint32_t)((aRow + i * 16) * GPAD + kc + aCol) * 2;
                ldsm4(arh[i], st + ao);
                ldsm4(arl[i], st + GBUF + ao);
            }
            uint32_t brh[2][4], brl[2][4];
#pragma unroll
            for (int j = 0; j < 2; j++) {
                uint32_t bo = (uint32_t)((bRow + j * 16) * GPAD + kc + bCol) * 2;
                ldsm4(brh[j], st + 2 * GBUF + bo);
                ldsm4(brl[j], st + 3 * GBUF + bo);
            }
#pragma unroll
            for (int i = 0; i < 4; i++)
#pragma unroll
                for (int j = 0; j < 4; j++) {
                    uint32_t h0 = brh[j >> 1][(j & 1) * 2], h1 = brh[j >> 1][(j & 1) * 2 + 1];
                    uint32_t l0 = brl[j >> 1][(j & 1) * 2], l1 = brl[j >> 1][(j & 1) * 2 + 1];
                    mma_bf16(d[i][j], arh[i], h0, h1);
                    mma_bf16(d[i][j], arh[i], l0, l1);
                    mma_bf16(d[i][j], arl[i], h0, h1);
                }
        }
        __syncthreads();
    }
    const int grp = lane >> 2, tig = lane & 3;
    const int mb = m0 + wm * 64, nb = n0 + wn * 32;
#pragma unroll
    for (int i = 0; i < 4; i++) {
        int r0 = mb + i * 16 + grp, r1 = r0 + 8;
#pragma unroll
        for (int j = 0; j < 4; j++) {
            int cc = nb + j * 8 + tig * 2;
            *(float2*)(g_M + (size_t)r0 * 1024 + cc) = make_float2(d[i][j][0], d[i][j][1]);
            *(float2*)(g_M + (size_t)r1 * 1024 + cc) = make_float2(d[i][j][2], d[i][j][3]);
        }
    }
}

// ----- split M (transpose, fp16): MhT[f][e] = M[e][f] -----
__global__ void k_splitM() {
    __shared__ float t[32][33];
    int bx = blockIdx.x, by = blockIdx.y;
    int x = threadIdx.x, y = threadIdx.y;  // 32x8
#pragma unroll
    for (int i = 0; i < 32; i += 8)
        t[y + i][x] = g_M[(size_t)(by * 32 + y + i) * 1024 + bx * 32 + x];
    __syncthreads();
#pragma unroll
    for (int i = 0; i < 32; i += 8)
        g_MhT[(size_t)(bx * 32 + y + i) * 1024 + by * 32 + x] = __float2half_rn(t[x][y + i]);
}

// ----- convert X to fp16 -----
__global__ void k_splitX(const float* __restrict__ x) {
    size_t i = ((size_t)blockIdx.x * 256 + threadIdx.x) * 4;  // grid 32768
    float4 v = *(const float4*)(x + i);
    __half2 a(__float2half_rn(v.x), __float2half_rn(v.y));
    __half2 b(__float2half_rn(v.z), __float2half_rn(v.w));
    *(__half2*)(g_Xh + i) = a;
    *(__half2*)(g_Xh + i + 2) = b;
}

// ----- kernel 3: skinny gemms -----
__global__ void k_skinny(const float* __restrict__ Wq, const float* __restrict__ Wk,
                         const float* __restrict__ Wv, const float* __restrict__ Wfc) {
    const float* L; const float* R;
    int z = blockIdx.z;
    if (z == 0)      { L = g_Ck; R = Wq; }
    else if (z == 1) { L = g_Cq; R = Wk; }
    else             { L = Wfc;  R = Wv; }
    __shared__ float Lsh[32][64];
    int tid = threadIdx.x;
    int e  = blockIdx.x * 128 + tid;
    int d0 = blockIdx.y * 256;
    float acc[32];
#pragma unroll
    for (int j = 0; j < 32; j++) acc[j] = 0.f;
    for (int c0 = 0; c0 < 256; c0 += 64) {
        __syncthreads();
#pragma unroll
        for (int p = 0; p < 16; p++) {
            int idx = p * 128 + tid;
            Lsh[idx >> 6][idx & 63] = L[(idx >> 6) * 2048 + d0 + c0 + (idx & 63)];
        }
        __syncthreads();
#pragma unroll 4
        for (int dd = 0; dd < 64; dd++) {
            float w = R[(size_t)(d0 + c0 + dd) * 2048 + e];
#pragma unroll
            for (int j = 0; j < 32; j++) acc[j] += Lsh[j][dd] * w;
        }
    }
    int base = ((z * 8 + blockIdx.y) * 32) * 1024 + e;
#pragma unroll
    for (int j = 0; j < 32; j++) g_part[base + j * 1024] = acc[j];
}

__global__ void k_skred() {
    int idx = blockIdx.x * 256 + threadIdx.x;
    int z = idx >> 15;
    int r = idx & 32767;
    float s = 0.f;
#pragma unroll
    for (int kc = 0; kc < 8; kc++) s += g_part[(z * 8 + kc) * 32768 + r];
    float* out = (z == 0) ? g_A : (z == 1) ? g_Bm : g_G;
    out[r] = s;
}

// ----- kernel 4: c = Cq@Ck^T, P = Wf@Cv^T -----
__global__ void k_small(const float* __restrict__ Wfc) {
    int i = blockIdx.x;
    const float* L; const float* R; float* out;
    if (blockIdx.y == 0) { L = g_Cq; R = g_Ck; out = g_c; }
    else                 { L = Wfc;  R = g_Cv; out = g_P; }
    int tid = threadIdx.x, warp = tid >> 5, lane = tid & 31;
    float acc[4] = {0.f, 0.f, 0.f, 0.f};
    for (int d = lane; d < 2048; d += 32) {
        float lv = L[i * 2048 + d];
#pragma unroll
        for (int q = 0; q < 4; q++) acc[q] += lv * R[(warp * 4 + q) * 2048 + d];
    }
#pragma unroll
    for (int q = 0; q < 4; q++) {
        float r = wredsum(acc[q]);
        if (lane == 0) out[i * 32 + warp * 4 + q] = r;
    }
}

// ====== kernel 5: Y = X@M + Bm, fp16 single-product mma ======
// CTA 256x128, BK=64, 512 threads (16 warps 4x4), warp tile 64x32.
#define YPAD 72
#define YA_BYTES (256 * YPAD * 2)          // 36864
#define YB_BYTES (128 * YPAD * 2)          // 18432
#define YSTAGE (YA_BYTES + YB_BYTES)       // 55296
#define YSMEM (2 * YSTAGE)                 // 110592

__device__ __forceinline__ void y_stage(uint32_t sb, int s, int m0, int n0,
                                        int k0, int tid) {
    uint32_t sa = sb + s * YSTAGE;
#pragma unroll
    for (int p = 0; p < 6; p++) {
        int idx = p * 512 + tid;
        if (idx < 2048) {               // A: 256 rows x 8 chunks
            int row = idx >> 3, c = idx & 7;
            cpasync16(sa + (uint32_t)(row * YPAD + c * 8) * 2,
                      g_Xh + (size_t)(m0 + row) * 1024 + k0 + c * 8);
        } else {                        // B: 128 rows x 8 chunks
            int t = idx - 2048;
            int row = t >> 3, c = t & 7;
            cpasync16(sa + YA_BYTES + (uint32_t)(row * YPAD + c * 8) * 2,
                      g_MhT + (size_t)(n0 + row) * 1024 + k0 + c * 8);
        }
    }
}

__global__ __launch_bounds__(512, 1) void k_ygemm_mma() {
    extern __shared__ __align__(16) char ysmem[];
    const uint32_t sb = smem_u32(ysmem);
    const int tid = threadIdx.x, lane = tid & 31, wid = tid >> 5;
    const int wm = wid >> 2, wn = wid & 3;
    const int m0 = blockIdx.y * 256, n0 = blockIdx.x * 128;

    y_stage(sb, 0, m0, n0, 0, tid);
    asm volatile("cp.async.commit_group;" ::: "memory");

    float d[4][4][4] = {};
    const int aRow = wm * 64 + (lane & 15);
    const int aCol = (lane >> 4) * 8;
    const int bRow = wn * 32 + (lane & 7) + (lane >> 4) * 8;
    const int bCol = ((lane >> 3) & 1) * 8;

    for (int it = 0; it < 16; it++) {
        int nit = it + 1;
        if (nit < 16) {
            y_stage(sb, nit & 1, m0, n0, nit * 64, tid);
            asm volatile("cp.async.commit_group;" ::: "memory");
            asm volatile("cp.async.wait_group 1;" ::: "memory");
        } else {
            asm volatile("cp.async.wait_group 0;" ::: "memory");
        }
        __syncthreads();
        uint32_t abase = sb + (it & 1) * YSTAGE;
        uint32_t bbase = abase + YA_BYTES;
#pragma unroll
        for (int ks = 0; ks < 4; ks++) {
            int kc = ks * 16;
            uint32_t ar[4][4];
#pragma unroll
            for (int i = 0; i < 4; i++)
                ldsm4(ar[i], abase + (uint32_t)((aRow + i * 16) * YPAD + kc + aCol) * 2);
            uint32_t br[2][4];
#pragma unroll
            for (int j = 0; j < 2; j++)
                ldsm4(br[j], bbase + (uint32_t)((bRow + j * 16) * YPAD + kc + bCol) * 2);
#pragma unroll
            for (int i = 0; i < 4; i++)
#pragma unroll
                for (int j = 0; j < 4; j++)
                    mma_f16(d[i][j], ar[i], br[j >> 1][(j & 1) * 2],
                            br[j >> 1][(j & 1) * 2 + 1]);
        }
        __syncthreads();
    }

    const int grp = lane >> 2, tig = lane & 3;
    const int mb = m0 + wm * 64, nb = n0 + wn * 32;
#pragma unroll
    for (int i = 0; i < 4; i++) {
        int r0 = mb + i * 16 + grp, r1 = r0 + 8;
#pragma unroll
        for (int j = 0; j < 4; j++) {
            int cc = nb + j * 8 + tig * 2;
            float2 bm0 = *(const float2*)(g_Bm + (r0 & 31) * 1024 + cc);
            float2 bm1 = *(const float2*)(g_Bm + (r1 & 31) * 1024 + cc);
            *(float2*)(g_Y + (size_t)r0 * 1024 + cc) =
                make_float2(d[i][j][0] + bm0.x, d[i][j][1] + bm0.y);
            *(float2*)(g_Y + (size_t)r1 * 1024 + cc) =
                make_float2(d[i][j][2] + bm1.x, d[i][j][3] + bm1.y);
        }
    }
}

// ----- kernel 6: per-batch attention + epilogue (fp32) -----
__global__ __launch_bounds__(256) void k_attn(const float* __restrict__ X,
                                              const float* __restrict__ bfc,
                                              float* __restrict__ out) {
    __shared__ __align__(16) float Ws[96 * 64];
    __shared__ __align__(16) float Xs[64 * 36];
    __shared__ float wpart[8];
    int tid = threadIdx.x;
    int b = blockIdx.x;
    const float* Xb = X + (size_t)b * 32768;
    const float* Yb = g_Y + (size_t)b * 32768;
    int rgrp = tid >> 3, cgrp = tid & 7;
    float acc[3][4] = {};
    for (int k0 = 0; k0 < 1024; k0 += 64) {
        __syncthreads();
#pragma unroll
        for (int p = 0; p < 8; p++) {
            int idx = p * 256 + tid;
            int j = idx >> 6, kk = idx & 63;
            Xs[kk * 36 + j] = Xb[j * 1024 + k0 + kk];
        }
#pragma unroll
        for (int p = 0; p < 24; p++) {
            int idx = p * 256 + tid;
            int row = idx >> 6, kk = idx & 63;
            const float* src = (row < 32) ? (Yb + row * 1024)
                              : (row < 64) ? (g_A + (row - 32) * 1024)
                                           : (g_G + (row - 64) * 1024);
            Ws[row * 64 + kk] = src[k0 + kk];
        }
        __syncthreads();
#pragma unroll 8
        for (int kk = 0; kk < 64; kk++) {
            float4 xv = *(const float4*)&Xs[kk * 36 + cgrp * 4];
            float xa[4] = {xv.x, xv.y, xv.z, xv.w};
#pragma unroll
            for (int ri = 0; ri < 3; ri++) {
                float wv = Ws[(rgrp * 3 + ri) * 64 + kk];
#pragma unroll
                for (int ci = 0; ci < 4; ci++) acc[ri][ci] += wv * xa[ci];
            }
        }
    }
    __syncthreads();
    float* Rs = Ws;
#pragma unroll
    for (int ri = 0; ri < 3; ri++)
#pragma unroll
        for (int ci = 0; ci < 4; ci++)
            Rs[(rgrp * 3 + ri) * 33 + cgrp * 4 + ci] = acc[ri][ci];
    __syncthreads();

    int w = tid >> 5, lane = tid & 31;
    const float rscale = 0.022097086912079608f;  // 1/sqrt(2048)
    float local = 0.f;
#pragma unroll
    for (int q = 0; q < 4; q++) {
        int j = w * 4 + q;
        float lg = (Rs[lane * 33 + j] + Rs[(32 + j) * 33 + lane] + g_c[lane * 32 + j]) * rscale;
        float mx = wredmax(lg);
        float ex = __expf(lg - mx);
        float sm = wredsum(ex);
        float contrib = (ex / sm) * (Rs[(64 + lane) * 33 + j] + g_P[lane * 32 + j]);
        local += wredsum(contrib);
    }
    if (lane == 0) wpart[w] = local;
    __syncthreads();
    if (tid == 0) {
        float t = 0.f;
#pragma unroll
        for (int i = 0; i < 8; i++) t += wpart[i];
        out[b] = t + bfc[0];
    }
}

extern "C" void kernel_launch(void* const* d_in, const int* in_sizes, int n_in,
                              void* d_out, int out_size) {
    const float* x   = (const float*)d_in[0];
    const float* pe  = (const float*)d_in[1];
    const float* Wq  = (const float*)d_in[2];
    const float* bq  = (const float*)d_in[3];
    const float* Wk  = (const float*)d_in[4];
    const float* bk  = (const float*)d_in[5];
    const float* Wv  = (const float*)d_in[6];
    const float* bv  = (const float*)d_in[7];
    const float* Wfc = (const float*)d_in[8];
    const float* bfc = (const float*)d_in[9];
    float* out = (float*)d_out;

    cudaFuncSetAttribute(k_gemmM_mma, cudaFuncAttributeMaxDynamicSharedMemorySize, GSMEM);
    cudaFuncSetAttribute(k_ygemm_mma, cudaFuncAttributeMaxDynamicSharedMemorySize, YSMEM);

    k_precompC<<<dim3(256, 1, 3), 256>>>(pe, Wq, bq, Wk, bk, Wv, bv);
    k_splitWT<<<dim3(32, 64, 2), dim3(32, 8)>>>(Wq, Wk);
    k_gemmM_mma<<<dim3(8, 8), 256, GSMEM>>>();
    k_splitM<<<dim3(32, 32), dim3(32, 8)>>>();
    k_splitX<<<32768, 256>>>(x);
    k_skinny<<<dim3(8, 8, 3), 128>>>(Wq, Wk, Wv, Wfc);
    k_skred<<<384, 256>>>();
    k_small<<<dim3(32, 2), 256>>>(Wfc);
    k_ygemm_mma<<<dim3(8, 128), 512, YSMEM>>>();
    k_attn<<<1024, 256>>>(x, bfc, out);
}

// round 6
// speedup vs baseline: 3.2907x; 1.4673x over previous
#include <cuda_runtime.h>
#include <cuda_bf16.h>
#include <cuda_fp16.h>
#include <math.h>
#include <stdint.h>

// B=1024, S=32, D=1024, D2=2048
// out[b]: Cq/Ck/Cv = pe@W2^T+b ; M=Wq1^T Wk1 (bf16 3-split mma) ;
// A=Ck@Wq1 ; Bm=Cq@Wk1 ; G=Wf@Wv1 ; c=Cq@Ck^T ; P=Wf@Cv^T ;
// k_yz: Y=X@M+Bm (fp16 mma) fused with Z_b = Y'_b @ X_b^T partials (3-product mma);
// k_rag: [A;G]@Xall^T (3-product mma) ; k_attn2: reduce+softmax(dim=1)+dot.

// ----- static scratch -----
__device__ float g_M[1048576];    // [1024,1024]
__device__ float g_Cq[65536], g_Ck[65536], g_Cv[65536];
__device__ float g_A[32768], g_Bm[32768], g_G[32768];
__device__ float g_part[786432];
__device__ float g_c[1024], g_P[1024];
__device__ float g_Zpart[8388608];   // [8 nblk][1024 b][32][32]
__device__ float g_RAG[2097152];     // [64][32768]
__device__ __align__(16) __half g_Xh[33554432];   // fp16 X [32768,1024]
__device__ __align__(16) __half g_Xl[33554432];   // fp16 residual
__device__ __align__(16) __half g_MhT[1048576];   // fp16 M^T [f][e]
__device__ __align__(16) __half g_AGh[65536];     // [64][1024] = [A;G] hi
__device__ __align__(16) __half g_AGl[65536];
__device__ __align__(16) __nv_bfloat16 g_WqTh[2097152];  // [e][d2]
__device__ __align__(16) __nv_bfloat16 g_WqTl[2097152];
__device__ __align__(16) __nv_bfloat16 g_WkTh[2097152];
__device__ __align__(16) __nv_bfloat16 g_WkTl[2097152];

__device__ __forceinline__ float wredsum(float v) {
#pragma unroll
    for (int o = 16; o; o >>= 1) v += __shfl_xor_sync(0xffffffffu, v, o);
    return v;
}
__device__ __forceinline__ float wredmax(float v) {
#pragma unroll
    for (int o = 16; o; o >>= 1) v = fmaxf(v, __shfl_xor_sync(0xffffffffu, v, o));
    return v;
}
__device__ __forceinline__ uint32_t smem_u32(const void* p) {
    uint32_t a;
    asm("{ .reg .u64 t; cvta.to.shared.u64 t, %1; cvt.u32.u64 %0, t; }" : "=r"(a) : "l"(p));
    return a;
}
__device__ __forceinline__ void ldsm4(uint32_t* r, uint32_t addr) {
    asm volatile("ldmatrix.sync.aligned.m8n8.x4.shared.b16 {%0,%1,%2,%3}, [%4];"
                 : "=r"(r[0]), "=r"(r[1]), "=r"(r[2]), "=r"(r[3]) : "r"(addr));
}
__device__ __forceinline__ void mma_bf16(float* d, const uint32_t* a,
                                         uint32_t b0, uint32_t b1) {
    asm volatile(
        "mma.sync.aligned.m16n8k16.row.col.f32.bf16.bf16.f32 "
        "{%0,%1,%2,%3}, {%4,%5,%6,%7}, {%8,%9}, {%0,%1,%2,%3};"
        : "+f"(d[0]), "+f"(d[1]), "+f"(d[2]), "+f"(d[3])
        : "r"(a[0]), "r"(a[1]), "r"(a[2]), "r"(a[3]), "r"(b0), "r"(b1));
}
__device__ __forceinline__ void mma_f16(float* d, const uint32_t* a,
                                        uint32_t b0, uint32_t b1) {
    asm volatile(
        "mma.sync.aligned.m16n8k16.row.col.f32.f16.f16.f32 "
        "{%0,%1,%2,%3}, {%4,%5,%6,%7}, {%8,%9}, {%0,%1,%2,%3};"
        : "+f"(d[0]), "+f"(d[1]), "+f"(d[2]), "+f"(d[3])
        : "r"(a[0]), "r"(a[1]), "r"(a[2]), "r"(a[3]), "r"(b0), "r"(b1));
}
__device__ __forceinline__ void cpasync16(uint32_t saddr, const void* gaddr) {
    asm volatile("cp.async.cg.shared.global [%0], [%1], 16;" :: "r"(saddr), "l"(gaddr));
}

// ----- kernel 1: Cq/Ck/Cv = pe @ W2^T + b -----
__global__ void k_precompC(const float* __restrict__ pe,
                           const float* __restrict__ Wq, const float* __restrict__ bq,
                           const float* __restrict__ Wk, const float* __restrict__ bk,
                           const float* __restrict__ Wv, const float* __restrict__ bv) {
    const float* W; const float* bias; float* out;
    if (blockIdx.z == 0)      { W = Wq; bias = bq; out = g_Cq; }
    else if (blockIdx.z == 1) { W = Wk; bias = bk; out = g_Ck; }
    else                      { W = Wv; bias = bv; out = g_Cv; }
    __shared__ float pes[32][33];
    int tid = threadIdx.x;
    int warp = tid >> 5, lane = tid & 31;
    int d2 = blockIdx.x * 8 + warp;
    float acc[32];
#pragma unroll
    for (int i = 0; i < 32; i++) acc[i] = 0.f;
    for (int e0 = 0; e0 < 1024; e0 += 32) {
        __syncthreads();
#pragma unroll
        for (int p = 0; p < 4; p++) {
            int idx = p * 256 + tid;
            pes[idx >> 5][idx & 31] = pe[(idx >> 5) * 1024 + e0 + (idx & 31)];
        }
        __syncthreads();
        float wv = W[(size_t)d2 * 2048 + 1024 + e0 + lane];
#pragma unroll
        for (int i = 0; i < 32; i++) acc[i] += pes[i][lane] * wv;
    }
    float res = 0.f;
#pragma unroll
    for (int i = 0; i < 32; i++) {
        float r = wredsum(acc[i]);
        if (lane == i) res = r;
    }
    out[lane * 2048 + d2] = res + bias[d2];
}

// ----- transpose+split Wq1/Wk1 -----
__global__ void k_splitWT(const float* __restrict__ Wq, const float* __restrict__ Wk) {
    __shared__ float t[32][33];
    const float* W = blockIdx.z ? Wk : Wq;
    __nv_bfloat16* oh = blockIdx.z ? g_WkTh : g_WqTh;
    __nv_bfloat16* ol = blockIdx.z ? g_WkTl : g_WqTl;
    int bx = blockIdx.x, by = blockIdx.y;
    int x = threadIdx.x, y = threadIdx.y;  // 32x8
#pragma unroll
    for (int i = 0; i < 32; i += 8)
        t[y + i][x] = W[(size_t)(by * 32 + y + i) * 2048 + bx * 32 + x];
    __syncthreads();
#pragma unroll
    for (int i = 0; i < 32; i += 8) {
        float v = t[x][y + i];
        __nv_bfloat16 h = __float2bfloat16(v);
        __nv_bfloat16 l = __float2bfloat16(v - __bfloat162float(h));
        size_t o = (size_t)(bx * 32 + y + i) * 2048 + by * 32 + x;
        oh[o] = h;
        ol[o] = l;
    }
}

// ----- kernel 2: M = Wq1^T @ Wk1, bf16 3-product mma -----
#define GPAD 72
#define GBUF (128 * GPAD * 2)
#define GSTAGE (4 * GBUF)
#define GSMEM (2 * GSTAGE)

__device__ __forceinline__ void g_stage(uint32_t sb, int s, int m0, int n0,
                                        int k0, int tid) {
    uint32_t sa = sb + s * GSTAGE;
#pragma unroll
    for (int p = 0; p < 16; p++) {
        int idx = p * 256 + tid;
        int buf = idx >> 10;
        int t = idx & 1023;
        int row = t >> 3, c = t & 7;
        const __nv_bfloat16* src =
            (buf == 0) ? g_WqTh : (buf == 1) ? g_WqTl : (buf == 2) ? g_WkTh : g_WkTl;
        int r0 = (buf < 2) ? m0 : n0;
        cpasync16(sa + buf * GBUF + (uint32_t)(row * GPAD + c * 8) * 2,
                  src + (size_t)(r0 + row) * 2048 + k0 + c * 8);
    }
}

__global__ __launch_bounds__(256, 1) void k_gemmM_mma() {
    extern __shared__ __align__(16) char gsmem[];
    const uint32_t sb = smem_u32(gsmem);
    const int tid = threadIdx.x, lane = tid & 31, wid = tid >> 5;
    const int wm = wid >> 2, wn = wid & 3;
    const int m0 = blockIdx.y * 128, n0 = blockIdx.x * 128;

    g_stage(sb, 0, m0, n0, 0, tid);
    asm volatile("cp.async.commit_group;" ::: "memory");

    float d[4][4][4] = {};
    const int aRow = wm * 64 + (lane & 15);
    const int aCol = (lane >> 4) * 8;
    const int bRow = wn * 32 + (lane & 7) + (lane >> 4) * 8;
    const int bCol = ((lane >> 3) & 1) * 8;

    for (int it = 0; it < 32; it++) {
        int nit = it + 1;
        if (nit < 32) {
            g_stage(sb, nit & 1, m0, n0, nit * 64, tid);
            asm volatile("cp.async.commit_group;" ::: "memory");
            asm volatile("cp.async.wait_group 1;" ::: "memory");
        } else {
            asm volatile("cp.async.wait_group 0;" ::: "memory");
        }
        __syncthreads();
        uint32_t st = sb + (it & 1) * GSTAGE;
#pragma unroll
        for (int ks = 0; ks < 4; ks++) {
            int kc = ks * 16;
            uint32_t arh[4][4], arl[4][4];
#pragma unroll
            for (int i = 0; i < 4; i++) {
                uint32_t ao = (uint32_t)((aRow + i * 16) * GPAD + kc + aCol) * 2;
                ldsm4(arh[i], st + ao);
                ldsm4(arl[i], st + GBUF + ao);
            }
            uint32_t brh[2][4], brl[2][4];
#pragma unroll
            for (int j = 0; j < 2; j++) {
                uint32_t bo = (uint32_t)((bRow + j * 16) * GPAD + kc + bCol) * 2;
                ldsm4(brh[j], st + 2 * GBUF + bo);
                ldsm4(brl[j], st + 3 * GBUF + bo);
            }
#pragma unroll
            for (int i = 0; i < 4; i++)
#pragma unroll
                for (int j = 0; j < 4; j++) {
                    uint32_t h0 = brh[j >> 1][(j & 1) * 2], h1 = brh[j >> 1][(j & 1) * 2 + 1];
                    uint32_t l0 = brl[j >> 1][(j & 1) * 2], l1 = brl[j >> 1][(j & 1) * 2 + 1];
                    mma_bf16(d[i][j], arh[i], h0, h1);
                    mma_bf16(d[i][j], arh[i], l0, l1);
                    mma_bf16(d[i][j], arl[i], h0, h1);
                }
        }
        __syncthreads();
    }
    const int grp = lane >> 2, tig = lane & 3;
    const int mb = m0 + wm * 64, nb = n0 + wn * 32;
#pragma unroll
    for (int i = 0; i < 4; i++) {
        int r0 = mb + i * 16 + grp, r1 = r0 + 8;
#pragma unroll
        for (int j = 0; j < 4; j++) {
            int cc = nb + j * 8 + tig * 2;
            *(float2*)(g_M + (size_t)r0 * 1024 + cc) = make_float2(d[i][j][0], d[i][j][1]);
            *(float2*)(g_M + (size_t)r1 * 1024 + cc) = make_float2(d[i][j][2], d[i][j][3]);
        }
    }
}

// ----- split M (transpose, fp16) -----
__global__ void k_splitM() {
    __shared__ float t[32][33];
    int bx = blockIdx.x, by = blockIdx.y;
    int x = threadIdx.x, y = threadIdx.y;
#pragma unroll
    for (int i = 0; i < 32; i += 8)
        t[y + i][x] = g_M[(size_t)(by * 32 + y + i) * 1024 + bx * 32 + x];
    __syncthreads();
#pragma unroll
    for (int i = 0; i < 32; i += 8)
        g_MhT[(size_t)(bx * 32 + y + i) * 1024 + by * 32 + x] = __float2half_rn(t[x][y + i]);
}

// ----- X -> fp16 hi + lo -----
__global__ void k_splitX(const float* __restrict__ x) {
    size_t i = ((size_t)blockIdx.x * 256 + threadIdx.x) * 4;
    float4 v = *(const float4*)(x + i);
    __half h0 = __float2half_rn(v.x), h1 = __float2half_rn(v.y);
    __half h2 = __float2half_rn(v.z), h3 = __float2half_rn(v.w);
    *(__half2*)(g_Xh + i)     = __halves2half2(h0, h1);
    *(__half2*)(g_Xh + i + 2) = __halves2half2(h2, h3);
    *(__half2*)(g_Xl + i)     = __halves2half2(__float2half_rn(v.x - __half2float(h0)),
                                               __float2half_rn(v.y - __half2float(h1)));
    *(__half2*)(g_Xl + i + 2) = __halves2half2(__float2half_rn(v.z - __half2float(h2)),
                                               __float2half_rn(v.w - __half2float(h3)));
}

// ----- kernel 3: skinny gemms -----
__global__ void k_skinny(const float* __restrict__ Wq, const float* __restrict__ Wk,
                         const float* __restrict__ Wv, const float* __restrict__ Wfc) {
    const float* L; const float* R;
    int z = blockIdx.z;
    if (z == 0)      { L = g_Ck; R = Wq; }
    else if (z == 1) { L = g_Cq; R = Wk; }
    else             { L = Wfc;  R = Wv; }
    __shared__ float Lsh[32][64];
    int tid = threadIdx.x;
    int e  = blockIdx.x * 128 + tid;
    int d0 = blockIdx.y * 256;
    float acc[32];
#pragma unroll
    for (int j = 0; j < 32; j++) acc[j] = 0.f;
    for (int c0 = 0; c0 < 256; c0 += 64) {
        __syncthreads();
#pragma unroll
        for (int p = 0; p < 16; p++) {
            int idx = p * 128 + tid;
            Lsh[idx >> 6][idx & 63] = L[(idx >> 6) * 2048 + d0 + c0 + (idx & 63)];
        }
        __syncthreads();
#pragma unroll 4
        for (int dd = 0; dd < 64; dd++) {
            float w = R[(size_t)(d0 + c0 + dd) * 2048 + e];
#pragma unroll
            for (int j = 0; j < 32; j++) acc[j] += Lsh[j][dd] * w;
        }
    }
    int base = ((z * 8 + blockIdx.y) * 32) * 1024 + e;
#pragma unroll
    for (int j = 0; j < 32; j++) g_part[base + j * 1024] = acc[j];
}

__global__ void k_skred() {
    int idx = blockIdx.x * 256 + threadIdx.x;
    int z = idx >> 15;
    int r = idx & 32767;
    float s = 0.f;
#pragma unroll
    for (int kc = 0; kc < 8; kc++) s += g_part[(z * 8 + kc) * 32768 + r];
    float* out = (z == 0) ? g_A : (z == 1) ? g_Bm : g_G;
    out[r] = s;
}

// ----- split [A;G] to fp16 hi/lo [64][1024] -----
__global__ void k_splitAG() {
    int row = blockIdx.x;
    const float* src = (row < 32) ? (g_A + row * 1024) : (g_G + (row - 32) * 1024);
    for (int col = threadIdx.x; col < 1024; col += 256) {
        float v = src[col];
        __half h = __float2half_rn(v);
        g_AGh[row * 1024 + col] = h;
        g_AGl[row * 1024 + col] = __float2half_rn(v - __half2float(h));
    }
}

// ----- kernel 4: c = Cq@Ck^T, P = Wf@Cv^T -----
__global__ void k_small(const float* __restrict__ Wfc) {
    int i = blockIdx.x;
    const float* L; const float* R; float* out;
    if (blockIdx.y == 0) { L = g_Cq; R = g_Ck; out = g_c; }
    else                 { L = Wfc;  R = g_Cv; out = g_P; }
    int tid = threadIdx.x, warp = tid >> 5, lane = tid & 31;
    float acc[4] = {0.f, 0.f, 0.f, 0.f};
    for (int d = lane; d < 2048; d += 32) {
        float lv = L[i * 2048 + d];
#pragma unroll
        for (int q = 0; q < 4; q++) acc[q] += lv * R[(warp * 4 + q) * 2048 + d];
    }
#pragma unroll
    for (int q = 0; q < 4; q++) {
        float r = wredsum(acc[q]);
        if (lane == 0) out[i * 32 + warp * 4 + q] = r;
    }
}

// ====== kernel 5: fused Y=X@M+Bm  +  Z_b partial = Y'_b @ X_b^T ======
// CTA 256x128, 512 threads (16 warps 4x4), fp16 mma main loop;
// epilogue: Y'->fp16 hi/lo in smem, 3-product Z mma, write g_Zpart.
#define YPAD 72
#define YA_BYTES (256 * YPAD * 2)          // 36864
#define YB_BYTES (128 * YPAD * 2)          // 18432
#define YSTAGE (YA_BYTES + YB_BYTES)       // 55296
#define ZBUF (256 * 72 * 2)                // 36864 per epilogue buffer
#define YSMEM (4 * ZBUF)                   // 147456 (>= 2*YSTAGE main usage)

__device__ __forceinline__ void y_stage(uint32_t sb, int s, int m0, int n0,
                                        int k0, int tid) {
    uint32_t sa = sb + s * YSTAGE;
#pragma unroll
    for (int p = 0; p < 6; p++) {
        int idx = p * 512 + tid;
        if (idx < 2048) {
            int row = idx >> 3, c = idx & 7;
            cpasync16(sa + (uint32_t)(row * YPAD + c * 8) * 2,
                      g_Xh + (size_t)(m0 + row) * 1024 + k0 + c * 8);
        } else {
            int t = idx - 2048;
            int row = t >> 3, c = t & 7;
            cpasync16(sa + YA_BYTES + (uint32_t)(row * YPAD + c * 8) * 2,
                      g_MhT + (size_t)(n0 + row) * 1024 + k0 + c * 8);
        }
    }
}

__global__ __launch_bounds__(512, 1) void k_yz() {
    extern __shared__ __align__(16) char ysmem[];
    const uint32_t sb = smem_u32(ysmem);
    const int tid = threadIdx.x, lane = tid & 31, wid = tid >> 5;
    const int wm = wid >> 2, wn = wid & 3;
    const int m0 = blockIdx.y * 256, n0 = blockIdx.x * 128;

    y_stage(sb, 0, m0, n0, 0, tid);
    asm volatile("cp.async.commit_group;" ::: "memory");

    float d[4][4][4] = {};
    const int aRow = wm * 64 + (lane & 15);
    const int aCol = (lane >> 4) * 8;
    const int bRow = wn * 32 + (lane & 7) + (lane >> 4) * 8;
    const int bCol = ((lane >> 3) & 1) * 8;

    for (int it = 0; it < 16; it++) {
        int nit = it + 1;
        if (nit < 16) {
            y_stage(sb, nit & 1, m0, n0, nit * 64, tid);
            asm volatile("cp.async.commit_group;" ::: "memory");
            asm volatile("cp.async.wait_group 1;" ::: "memory");
        } else {
            asm volatile("cp.async.wait_group 0;" ::: "memory");
        }
        __syncthreads();
        uint32_t abase = sb + (it & 1) * YSTAGE;
        uint32_t bbase = abase + YA_BYTES;
#pragma unroll
        for (int ks = 0; ks < 4; ks++) {
            int kc = ks * 16;
            uint32_t ar[4][4];
#pragma unroll
            for (int i = 0; i < 4; i++)
                ldsm4(ar[i], abase + (uint32_t)((aRow + i * 16) * YPAD + kc + aCol) * 2);
            uint32_t br[2][4];
#pragma unroll
            for (int j = 0; j < 2; j++)
                ldsm4(br[j], bbase + (uint32_t)((bRow + j * 16) * YPAD + kc + bCol) * 2);
#pragma unroll
            for (int i = 0; i < 4; i++)
#pragma unroll
                for (int j = 0; j < 4; j++)
                    mma_f16(d[i][j], ar[i], br[j >> 1][(j & 1) * 2],
                            br[j >> 1][(j & 1) * 2 + 1]);
        }
        __syncthreads();
    }

    // ---- epilogue: add Bm, then fused Z partials ----
    const int grp = lane >> 2, tig = lane & 3;
    const int nbl = wn * 32;
#pragma unroll
    for (int i = 0; i < 4; i++) {
        int r0 = wm * 64 + i * 16 + grp;
        int p0 = r0 & 31, p1 = (r0 + 8) & 31;
#pragma unroll
        for (int j = 0; j < 4; j++) {
            int cc = n0 + nbl + j * 8 + tig * 2;
            float2 b0 = *(const float2*)(g_Bm + p0 * 1024 + cc);
            float2 b1 = *(const float2*)(g_Bm + p1 * 1024 + cc);
            d[i][j][0] += b0.x; d[i][j][1] += b0.y;
            d[i][j][2] += b1.x; d[i][j][3] += b1.y;
        }
    }

    const int bb = wid >> 1;   // local batch 0..7
    const int nh = wid & 1;    // n-half of Z columns
    const uint32_t ZYH = sb, ZYL = sb + ZBUF, ZXH = sb + 2 * ZBUF, ZXL = sb + 3 * ZBUF;
    float z[2][2][4] = {};

#pragma unroll 1
    for (int h = 0; h < 2; h++) {
        __syncthreads();
        // load X hi/lo tiles [256 x 64] for f-cols n0+h*64..
#pragma unroll
        for (int p = 0; p < 8; p++) {
            int idx = p * 512 + tid;       // 0..4095
            int bufl = idx >> 11;
            int t = idx & 2047;
            int row = t >> 3, ch = t & 7;
            const __half* src = bufl ? g_Xl : g_Xh;
            uint32_t dst = (bufl ? ZXL : ZXH) + (uint32_t)(row * 72 + ch * 8) * 2;
            cpasync16(dst, src + (size_t)(m0 + row) * 1024 + n0 + h * 64 + ch * 8);
        }
        asm volatile("cp.async.commit_group;" ::: "memory");
        // write Y' hi/lo for this f-half
        if ((wn >> 1) == h) {
#pragma unroll
            for (int i = 0; i < 4; i++) {
                int r0 = wm * 64 + i * 16 + grp;
#pragma unroll
                for (int j = 0; j < 4; j++) {
                    int cl = (nbl - h * 64) + j * 8 + tig * 2;
                    float v0 = d[i][j][0], v1 = d[i][j][1];
                    float v2 = d[i][j][2], v3 = d[i][j][3];
                    __half h0 = __float2half_rn(v0), h1 = __float2half_rn(v1);
                    __half h2 = __float2half_rn(v2), h3 = __float2half_rn(v3);
                    *(__half2*)(ysmem + ((r0) * 72 + cl) * 2) = __halves2half2(h0, h1);
                    *(__half2*)(ysmem + ((r0 + 8) * 72 + cl) * 2) = __halves2half2(h2, h3);
                    *(__half2*)(ysmem + ZBUF + ((r0) * 72 + cl) * 2) =
                        __halves2half2(__float2half_rn(v0 - __half2float(h0)),
                                       __float2half_rn(v1 - __half2float(h1)));
                    *(__half2*)(ysmem + ZBUF + ((r0 + 8) * 72 + cl) * 2) =
                        __halves2half2(__float2half_rn(v2 - __half2float(h2)),
                                       __float2half_rn(v3 - __half2float(h3)));
                }
            }
        }
        asm volatile("cp.async.wait_group 0;" ::: "memory");
        __syncthreads();
        // Z mma: batch bb, n-cols nh*16..+15, k=64
#pragma unroll
        for (int ks = 0; ks < 4; ks++) {
            int kc = ks * 16;
            uint32_t ayh[2][4], ayl[2][4];
#pragma unroll
            for (int mi = 0; mi < 2; mi++) {
                uint32_t ao = (uint32_t)((bb * 32 + mi * 16 + (lane & 15)) * 72 +
                                         kc + (lane >> 4) * 8) * 2;
                ldsm4(ayh[mi], ZYH + ao);
                ldsm4(ayl[mi], ZYL + ao);
            }
            uint32_t bxh[4], bxl[4];
            uint32_t bo = (uint32_t)((bb * 32 + nh * 16 + (lane & 7) + (lane >> 4) * 8) * 72 +
                                     kc + ((lane >> 3) & 1) * 8) * 2;
            ldsm4(bxh, ZXH + bo);
            ldsm4(bxl, ZXL + bo);
#pragma unroll
            for (int mi = 0; mi < 2; mi++)
#pragma unroll
                for (int nj = 0; nj < 2; nj++) {
                    mma_f16(z[mi][nj], ayh[mi], bxh[nj * 2], bxh[nj * 2 + 1]);
                    mma_f16(z[mi][nj], ayh[mi], bxl[nj * 2], bxl[nj * 2 + 1]);
                    mma_f16(z[mi][nj], ayl[mi], bxh[nj * 2], bxh[nj * 2 + 1]);
                }
        }
    }
    // store Z partials
    {
        int b = blockIdx.y * 8 + bb;
        size_t base = ((size_t)blockIdx.x * 1024 + b) * 1024;
#pragma unroll
        for (int mi = 0; mi < 2; mi++) {
            int i0 = mi * 16 + grp;
#pragma unroll
            for (int nj = 0; nj < 2; nj++) {
                int j0 = nh * 16 + nj * 8 + tig * 2;
                *(float2*)(g_Zpart + base + i0 * 32 + j0) =
                    make_float2(z[mi][nj][0], z[mi][nj][1]);
                *(float2*)(g_Zpart + base + (i0 + 8) * 32 + j0) =
                    make_float2(z[mi][nj][2], z[mi][nj][3]);
            }
        }
    }
}

// ====== kernel 6: RAG = [A;G] @ Xall^T  (M=64, N=32768, K=1024) ======
#define RPAD 72
#define R_A_BYTES (64 * RPAD * 2)                 // 9216
#define R_B_BYTES (256 * RPAD * 2)                // 36864
#define RSTAGE (2 * R_A_BYTES + 2 * R_B_BYTES)    // 92160
#define RSMEM (2 * RSTAGE)                        // 184320

__device__ __forceinline__ void r_stage(uint32_t sb, int s, int n0, int k0, int tid) {
    uint32_t sa = sb + s * RSTAGE;
#pragma unroll
    for (int p = 0; p < 4; p++) {
        int idx = p * 256 + tid;   // 0..1023
        int bufl = idx >> 9;
        int t = idx & 511;
        int row = t >> 3, ch = t & 7;
        const __half* src = bufl ? g_AGl : g_AGh;
        cpasync16(sa + bufl * R_A_BYTES + (uint32_t)(row * RPAD + ch * 8) * 2,
                  src + (size_t)row * 1024 + k0 + ch * 8);
    }
#pragma unroll
    for (int p = 0; p < 16; p++) {
        int idx = p * 256 + tid;   // 0..4095
        int bufl = idx >> 11;
        int t = idx & 2047;
        int row = t >> 3, ch = t & 7;
        const __half* src = bufl ? g_Xl : g_Xh;
        cpasync16(sa + 2 * R_A_BYTES + bufl * R_B_BYTES + (uint32_t)(row * RPAD + ch * 8) * 2,
                  src + (size_t)(n0 + row) * 1024 + k0 + ch * 8);
    }
}

__global__ __launch_bounds__(256, 1) void k_rag() {
    extern __shared__ __align__(16) char rsmem[];
    const uint32_t sb = smem_u32(rsmem);
    const int tid = threadIdx.x, lane = tid & 31, wid = tid >> 5;
    const int wm = wid >> 2, wn = wid & 3;   // wm 0..1, wn 0..3
    const int n0 = blockIdx.x * 256;

    r_stage(sb, 0, n0, 0, tid);
    asm volatile("cp.async.commit_group;" ::: "memory");

    float d[2][4][2][4] = {};
    const int aRowB = wm * 32 + (lane & 15);
    const int aCol = (lane >> 4) * 8;
    const int bRowB = wn * 64 + (lane & 7) + (lane >> 4) * 8;
    const int bCol = ((lane >> 3) & 1) * 8;

    for (int it = 0; it < 16; it++) {
        int nit = it + 1;
        if (nit < 16) {
            r_stage(sb, nit & 1, n0, nit * 64, tid);
            asm volatile("cp.async.commit_group;" ::: "memory");
            asm volatile("cp.async.wait_group 1;" ::: "memory");
        } else {
            asm volatile("cp.async.wait_group 0;" ::: "memory");
        }
        __syncthreads();
        uint32_t st = sb + (it & 1) * RSTAGE;
        uint32_t sB = st + 2 * R_A_BYTES;
#pragma unroll
        for (int ks = 0; ks < 4; ks++) {
            int kc = ks * 16;
            uint32_t ah[2][4], al[2][4];
#pragma unroll
            for (int mi = 0; mi < 2; mi++) {
                uint32_t ao = (uint32_t)((aRowB + mi * 16) * RPAD + kc + aCol) * 2;
                ldsm4(ah[mi], st + ao);
                ldsm4(al[mi], st + R_A_BYTES + ao);
            }
            uint32_t bh[4][4], bl[4][4];
#pragma unroll
            for (int nj = 0; nj < 4; nj++) {
                uint32_t bo = (uint32_t)((bRowB + nj * 16) * RPAD + kc + bCol) * 2;
                ldsm4(bh[nj], sB + bo);
                ldsm4(bl[nj], sB + R_B_BYTES + bo);
            }
#pragma unroll
            for (int mi = 0; mi < 2; mi++)
#pragma unroll
                for (int nj = 0; nj < 4; nj++)
#pragma unroll
                    for (int s = 0; s < 2; s++) {
                        mma_f16(d[mi][nj][s], ah[mi], bh[nj][s * 2], bh[nj][s * 2 + 1]);
                        mma_f16(d[mi][nj][s], ah[mi], bl[nj][s * 2], bl[nj][s * 2 + 1]);
                        mma_f16(d[mi][nj][s], al[mi], bh[nj][s * 2], bh[nj][s * 2 + 1]);
                    }
        }
        __syncthreads();
    }
    const int grp = lane >> 2, tig = lane & 3;
#pragma unroll
    for (int mi = 0; mi < 2; mi++) {
        int r0 = wm * 32 + mi * 16 + grp, r1 = r0 + 8;
#pragma unroll
        for (int nj = 0; nj < 4; nj++)
#pragma unroll
            for (int s = 0; s < 2; s++) {
                int col = n0 + wn * 64 + nj * 16 + s * 8 + tig * 2;
                *(float2*)(g_RAG + (size_t)r0 * 32768 + col) =
                    make_float2(d[mi][nj][s][0], d[mi][nj][s][1]);
                *(float2*)(g_RAG + (size_t)r1 * 32768 + col) =
                    make_float2(d[mi][nj][s][2], d[mi][nj][s][3]);
            }
    }
}

// ----- kernel 7: reduce Z partials + softmax(dim=1) + final dot -----
__global__ __launch_bounds__(256) void k_attn2(const float* __restrict__ bfc,
                                               float* __restrict__ out) {
    __shared__ float Zs[32 * 33];
    __shared__ float As[32 * 33];
    __shared__ float Vs[32 * 33];
    __shared__ float wpart[8];
    int tid = threadIdx.x, b = blockIdx.x;
#pragma unroll
    for (int p = 0; p < 4; p++) {
        int idx = p * 256 + tid;
        int i = idx >> 5, j = idx & 31;
        float s = 0.f;
#pragma unroll
        for (int nb = 0; nb < 8; nb++)
            s += g_Zpart[((size_t)nb * 1024 + b) * 1024 + idx];
        Zs[i * 33 + j] = s;
        As[i * 33 + j] = g_RAG[(size_t)j * 32768 + b * 32 + i];          // A[j].x_i
        Vs[i * 33 + j] = g_RAG[(size_t)(32 + i) * 32768 + b * 32 + j];   // G[i].x_j
    }
    __syncthreads();
    int w = tid >> 5, lane = tid & 31;
    const float rscale = 0.022097086912079608f;  // 1/sqrt(2048)
    float local = 0.f;
#pragma unroll
    for (int q = 0; q < 4; q++) {
        int j = w * 4 + q;
        float lg = (Zs[lane * 33 + j] + As[lane * 33 + j] + g_c[lane * 32 + j]) * rscale;
        float mx = wredmax(lg);
        float ex = __expf(lg - mx);
        float sm = wredsum(ex);
        float contrib = (ex / sm) * (Vs[lane * 33 + j] + g_P[lane * 32 + j]);
        local += wredsum(contrib);
    }
    if (lane == 0) wpart[w] = local;
    __syncthreads();
    if (tid == 0) {
        float t = 0.f;
#pragma unroll
        for (int i = 0; i < 8; i++) t += wpart[i];
        out[b] = t + bfc[0];
    }
}

extern "C" void kernel_launch(void* const* d_in, const int* in_sizes, int n_in,
                              void* d_out, int out_size) {
    const float* x   = (const float*)d_in[0];
    const float* pe  = (const float*)d_in[1];
    const float* Wq  = (const float*)d_in[2];
    const float* bq  = (const float*)d_in[3];
    const float* Wk  = (const float*)d_in[4];
    const float* bk  = (const float*)d_in[5];
    const float* Wv  = (const float*)d_in[6];
    const float* bv  = (const float*)d_in[7];
    const float* Wfc = (const float*)d_in[8];
    const float* bfc = (const float*)d_in[9];
    float* out = (float*)d_out;

    cudaFuncSetAttribute(k_gemmM_mma, cudaFuncAttributeMaxDynamicSharedMemorySize, GSMEM);
    cudaFuncSetAttribute(k_yz, cudaFuncAttributeMaxDynamicSharedMemorySize, YSMEM);
    cudaFuncSetAttribute(k_rag, cudaFuncAttributeMaxDynamicSharedMemorySize, RSMEM);

    k_precompC<<<dim3(256, 1, 3), 256>>>(pe, Wq, bq, Wk, bk, Wv, bv);
    k_splitWT<<<dim3(32, 64, 2), dim3(32, 8)>>>(Wq, Wk);
    k_gemmM_mma<<<dim3(8, 8), 256, GSMEM>>>();
    k_splitM<<<dim3(32, 32), dim3(32, 8)>>>();
    k_splitX<<<32768, 256>>>(x);
    k_skinny<<<dim3(8, 8, 3), 128>>>(Wq, Wk, Wv, Wfc);
    k_skred<<<384, 256>>>();
    k_splitAG<<<64, 256>>>();
    k_small<<<dim3(32, 2), 256>>>(Wfc);
    k_yz<<<dim3(8, 128), 512, YSMEM>>>();
    k_rag<<<128, 256, RSMEM>>>();
    k_attn2<<<1024, 256>>>(bfc, out);
}

// round 7
// speedup vs baseline: 3.4080x; 1.0357x over previous
#include <cuda_runtime.h>
#include <cuda_bf16.h>
#include <cuda_fp16.h>
#include <math.h>
#include <stdint.h>

// B=1024, S=32, D=1024, D2=2048
// out[b]: Cq/Ck/Cv = pe@W2^T+b ; MhT=(Wq1^T Wk1)^T (bf16 3-split mma, split-K) ;
// A=Ck@Wq1 ; Bm=Cq@Wk1 ; G=Wf@Wv1 ; c=Cq@Ck^T ; P=Wf@Cv^T ;
// k_yz: Y=X@M+Bm (fp16 mma) fused with Z_b = Y'_b @ X_b^T partials (3-product mma);
// k_rag: [A;G]@Xall^T (3-product mma) ; k_attn2: reduce+softmax(dim=1)+dot.

// ----- static scratch -----
__device__ float g_Cq[65536], g_Ck[65536], g_Cv[65536];
__device__ float g_A[32768], g_Bm[32768], g_G[32768];
__device__ float g_part[786432];
__device__ float g_c[1024], g_P[1024];
__device__ float g_Zpart[8388608];   // gemmM split-K partials, then [8 nblk][1024 b][32][32]
__device__ float g_RAG[2097152];     // [64][32768]
__device__ __align__(16) __half g_Xh[33554432];   // fp16 X [32768,1024]
__device__ __align__(16) __half g_Xl[33554432];   // fp16 residual
__device__ __align__(16) __half g_MhT[1048576];   // fp16 M^T [f][e]
__device__ __align__(16) __half g_AGh[65536];     // [64][1024] = [A;G] hi
__device__ __align__(16) __half g_AGl[65536];
__device__ __align__(16) __nv_bfloat16 g_WqTh[2097152];  // [e][d2]
__device__ __align__(16) __nv_bfloat16 g_WqTl[2097152];
__device__ __align__(16) __nv_bfloat16 g_WkTh[2097152];
__device__ __align__(16) __nv_bfloat16 g_WkTl[2097152];

__device__ __forceinline__ float wredsum(float v) {
#pragma unroll
    for (int o = 16; o; o >>= 1) v += __shfl_xor_sync(0xffffffffu, v, o);
    return v;
}
__device__ __forceinline__ float wredmax(float v) {
#pragma unroll
    for (int o = 16; o; o >>= 1) v = fmaxf(v, __shfl_xor_sync(0xffffffffu, v, o));
    return v;
}
__device__ __forceinline__ uint32_t smem_u32(const void* p) {
    uint32_t a;
    asm("{ .reg .u64 t; cvta.to.shared.u64 t, %1; cvt.u32.u64 %0, t; }" : "=r"(a) : "l"(p));
    return a;
}
__device__ __forceinline__ void ldsm4(uint32_t* r, uint32_t addr) {
    asm volatile("ldmatrix.sync.aligned.m8n8.x4.shared.b16 {%0,%1,%2,%3}, [%4];"
                 : "=r"(r[0]), "=r"(r[1]), "=r"(r[2]), "=r"(r[3]) : "r"(addr));
}
__device__ __forceinline__ void mma_bf16(float* d, const uint32_t* a,
                                         uint32_t b0, uint32_t b1) {
    asm volatile(
        "mma.sync.aligned.m16n8k16.row.col.f32.bf16.bf16.f32 "
        "{%0,%1,%2,%3}, {%4,%5,%6,%7}, {%8,%9}, {%0,%1,%2,%3};"
        : "+f"(d[0]), "+f"(d[1]), "+f"(d[2]), "+f"(d[3])
        : "r"(a[0]), "r"(a[1]), "r"(a[2]), "r"(a[3]), "r"(b0), "r"(b1));
}
__device__ __forceinline__ void mma_f16(float* d, const uint32_t* a,
                                        uint32_t b0, uint32_t b1) {
    asm volatile(
        "mma.sync.aligned.m16n8k16.row.col.f32.f16.f16.f32 "
        "{%0,%1,%2,%3}, {%4,%5,%6,%7}, {%8,%9}, {%0,%1,%2,%3};"
        : "+f"(d[0]), "+f"(d[1]), "+f"(d[2]), "+f"(d[3])
        : "r"(a[0]), "r"(a[1]), "r"(a[2]), "r"(a[3]), "r"(b0), "r"(b1));
}
__device__ __forceinline__ void cpasync16(uint32_t saddr, const void* gaddr) {
    asm volatile("cp.async.cg.shared.global [%0], [%1], 16;" :: "r"(saddr), "l"(gaddr));
}
#define CP_COMMIT() asm volatile("cp.async.commit_group;" ::: "memory")
#define CP_WAIT(n)  asm volatile("cp.async.wait_group %0;" :: "n"(n) : "memory")

// ===== merged prep: precompC (768 blk) | splitWT (4096 blk) | splitX (32768 blk) =====
__global__ __launch_bounds__(256) void k_prep(const float* __restrict__ x,
                                              const float* __restrict__ pe,
                                              const float* __restrict__ Wq, const float* __restrict__ bq,
                                              const float* __restrict__ Wk, const float* __restrict__ bk,
                                              const float* __restrict__ Wv, const float* __restrict__ bv) {
    __shared__ float sh[32 * 33];
    int blk = blockIdx.x;
    int tid = threadIdx.x;
    if (blk < 768) {
        // ---- Cq/Ck/Cv = pe @ W2^T + b ----
        int bz = blk >> 8, bx = blk & 255;
        const float* W; const float* bias; float* out;
        if (bz == 0)      { W = Wq; bias = bq; out = g_Cq; }
        else if (bz == 1) { W = Wk; bias = bk; out = g_Ck; }
        else              { W = Wv; bias = bv; out = g_Cv; }
        int warp = tid >> 5, lane = tid & 31;
        int d2 = bx * 8 + warp;
        float acc[32];
#pragma unroll
        for (int i = 0; i < 32; i++) acc[i] = 0.f;
        for (int e0 = 0; e0 < 1024; e0 += 32) {
            __syncthreads();
#pragma unroll
            for (int p = 0; p < 4; p++) {
                int idx = p * 256 + tid;
                sh[(idx >> 5) * 33 + (idx & 31)] = pe[(idx >> 5) * 1024 + e0 + (idx & 31)];
            }
            __syncthreads();
            float wv = W[(size_t)d2 * 2048 + 1024 + e0 + lane];
#pragma unroll
            for (int i = 0; i < 32; i++) acc[i] += sh[i * 33 + lane] * wv;
        }
        float res = 0.f;
#pragma unroll
        for (int i = 0; i < 32; i++) {
            float r = wredsum(acc[i]);
            if (lane == i) res = r;
        }
        out[lane * 2048 + d2] = res + bias[d2];
    } else if (blk < 768 + 4096) {
        // ---- transpose+split Wq1/Wk1: WT[e][d2] hi/lo bf16 ----
        int b2 = blk - 768;
        int bx = b2 & 31, by = (b2 >> 5) & 63, bz = b2 >> 11;
        const float* W = bz ? Wk : Wq;
        __nv_bfloat16* oh = bz ? g_WkTh : g_WqTh;
        __nv_bfloat16* ol = bz ? g_WkTl : g_WqTl;
        int xx = tid & 31, yy = tid >> 5;   // 32 x 8
#pragma unroll
        for (int i = 0; i < 32; i += 8)
            sh[(yy + i) * 33 + xx] = W[(size_t)(by * 32 + yy + i) * 2048 + bx * 32 + xx];
        __syncthreads();
#pragma unroll
        for (int i = 0; i < 32; i += 8) {
            float v = sh[xx * 33 + yy + i];
            __nv_bfloat16 h = __float2bfloat16(v);
            __nv_bfloat16 l = __float2bfloat16(v - __bfloat162float(h));
            size_t o = (size_t)(bx * 32 + yy + i) * 2048 + by * 32 + xx;
            oh[o] = h;
            ol[o] = l;
        }
    } else {
        // ---- X -> fp16 hi + lo ----
        size_t i = ((size_t)(blk - 4864) * 256 + tid) * 4;
        float4 v = *(const float4*)(x + i);
        __half h0 = __float2half_rn(v.x), h1 = __float2half_rn(v.y);
        __half h2 = __float2half_rn(v.z), h3 = __float2half_rn(v.w);
        *(__half2*)(g_Xh + i)     = __halves2half2(h0, h1);
        *(__half2*)(g_Xh + i + 2) = __halves2half2(h2, h3);
        *(__half2*)(g_Xl + i)     = __halves2half2(__float2half_rn(v.x - __half2float(h0)),
                                                   __float2half_rn(v.y - __half2float(h1)));
        *(__half2*)(g_Xl + i + 2) = __halves2half2(__float2half_rn(v.z - __half2float(h2)),
                                                   __float2half_rn(v.w - __half2float(h3)));
    }
}

// ----- kernel 2: M partials = Wq1^T @ Wk1, bf16 3-product mma, split-K=2, 3-stage -----
#define GPAD 72
#define GBUF (128 * GPAD * 2)
#define GSTAGE (4 * GBUF)        // 73728
#define GSMEM (3 * GSTAGE)       // 221184

__device__ __forceinline__ void g_stage(uint32_t sb, int s, int m0, int n0,
                                        int k0, int tid) {
    uint32_t sa = sb + s * GSTAGE;
#pragma unroll
    for (int p = 0; p < 16; p++) {
        int idx = p * 256 + tid;
        int buf = idx >> 10;
        int t = idx & 1023;
        int row = t >> 3, c = t & 7;
        const __nv_bfloat16* src =
            (buf == 0) ? g_WqTh : (buf == 1) ? g_WqTl : (buf == 2) ? g_WkTh : g_WkTl;
        int r0 = (buf < 2) ? m0 : n0;
        cpasync16(sa + buf * GBUF + (uint32_t)(row * GPAD + c * 8) * 2,
                  src + (size_t)(r0 + row) * 2048 + k0 + c * 8);
    }
}

__global__ __launch_bounds__(256, 1) void k_gemmM_mma() {
    extern __shared__ __align__(16) char gsmem[];
    const uint32_t sb = smem_u32(gsmem);
    const int tid = threadIdx.x, lane = tid & 31, wid = tid >> 5;
    const int wm = wid >> 2, wn = wid & 3;
    const int m0 = blockIdx.y * 128, n0 = blockIdx.x * 128;
    const int kbase = blockIdx.z * 1024;

    g_stage(sb, 0, m0, n0, kbase, tid);
    CP_COMMIT();
    g_stage(sb, 1, m0, n0, kbase + 64, tid);
    CP_COMMIT();

    float d[4][4][4] = {};
    const int aRow = wm * 64 + (lane & 15);
    const int aCol = (lane >> 4) * 8;
    const int bRow = wn * 32 + (lane & 7) + (lane >> 4) * 8;
    const int bCol = ((lane >> 3) & 1) * 8;

    for (int it = 0; it < 16; it++) {
        if (it < 15) CP_WAIT(1); else CP_WAIT(0);
        __syncthreads();
        if (it + 2 < 16) {
            int s = (it + 2) % 3;
            g_stage(sb, s, m0, n0, kbase + (it + 2) * 64, tid);
            CP_COMMIT();
        }
        uint32_t st = sb + (it % 3) * GSTAGE;
#pragma unroll
        for (int ks = 0; ks < 4; ks++) {
            int kc = ks * 16;
            uint32_t arh[4][4], arl[4][4];
#pragma unroll
            for (int i = 0; i < 4; i++) {
                uint32_t ao = (uint32_t)((aRow + i * 16) * GPAD + kc + aCol) * 2;
                ldsm4(arh[i], st + ao);
                ldsm4(arl[i], st + GBUF + ao);
            }
            uint32_t brh[2][4], brl[2][4];
#pragma unroll
            for (int j = 0; j < 2; j++) {
                uint32_t bo = (uint32_t)((bRow + j * 16) * GPAD + kc + bCol) * 2;
                ldsm4(brh[j], st + 2 * GBUF + bo);
                ldsm4(brl[j], st + 3 * GBUF + bo);
            }
#pragma unroll
            for (int i = 0; i < 4; i++)
#pragma unroll
                for (int j = 0; j < 4; j++) {
                    uint32_t h0 = brh[j >> 1][(j & 1) * 2], h1 = brh[j >> 1][(j & 1) * 2 + 1];
                    uint32_t l0 = brl[j >> 1][(j & 1) * 2], l1 = brl[j >> 1][(j & 1) * 2 + 1];
                    mma_bf16(d[i][j], arh[i], h0, h1);
                    mma_bf16(d[i][j], arh[i], l0, l1);
                    mma_bf16(d[i][j], arl[i], h0, h1);
                }
        }
    }
    float* outp = g_Zpart + (size_t)blockIdx.z * 1048576;
    const int grp = lane >> 2, tig = lane & 3;
    const int mb = m0 + wm * 64, nb = n0 + wn * 32;
#pragma unroll
    for (int i = 0; i < 4; i++) {
        int r0 = mb + i * 16 + grp, r1 = r0 + 8;
#pragma unroll
        for (int j = 0; j < 4; j++) {
            int cc = nb + j * 8 + tig * 2;
            *(float2*)(outp + (size_t)r0 * 1024 + cc) = make_float2(d[i][j][0], d[i][j][1]);
            *(float2*)(outp + (size_t)r1 * 1024 + cc) = make_float2(d[i][j][2], d[i][j][3]);
        }
    }
}

// ----- k_Mred: sum split-K partials + transpose + fp16 -> g_MhT -----
__global__ void k_Mred() {
    __shared__ float t[32][33];
    int bx = blockIdx.x, by = blockIdx.y;
    int x = threadIdx.x, y = threadIdx.y;   // 32 x 8
#pragma unroll
    for (int i = 0; i < 32; i += 8) {
        size_t o = (size_t)(by * 32 + y + i) * 1024 + bx * 32 + x;
        t[y + i][x] = g_Zpart[o] + g_Zpart[1048576 + o];
    }
    __syncthreads();
#pragma unroll
    for (int i = 0; i < 32; i += 8)
        g_MhT[(size_t)(bx * 32 + y + i) * 1024 + by * 32 + x] = __float2half_rn(t[x][y + i]);
}

// ----- kernel 3: skinny gemms -----
__global__ void k_skinny(const float* __restrict__ Wq, const float* __restrict__ Wk,
                         const float* __restrict__ Wv, const float* __restrict__ Wfc) {
    const float* L; const float* R;
    int z = blockIdx.z;
    if (z == 0)      { L = g_Ck; R = Wq; }
    else if (z == 1) { L = g_Cq; R = Wk; }
    else             { L = Wfc;  R = Wv; }
    __shared__ float Lsh[32][64];
    int tid = threadIdx.x;
    int e  = blockIdx.x * 128 + tid;
    int d0 = blockIdx.y * 256;
    float acc[32];
#pragma unroll
    for (int j = 0; j < 32; j++) acc[j] = 0.f;
    for (int c0 = 0; c0 < 256; c0 += 64) {
        __syncthreads();
#pragma unroll
        for (int p = 0; p < 16; p++) {
            int idx = p * 128 + tid;
            Lsh[idx >> 6][idx & 63] = L[(idx >> 6) * 2048 + d0 + c0 + (idx & 63)];
        }
        __syncthreads();
#pragma unroll 4
        for (int dd = 0; dd < 64; dd++) {
            float w = R[(size_t)(d0 + c0 + dd) * 2048 + e];
#pragma unroll
            for (int j = 0; j < 32; j++) acc[j] += Lsh[j][dd] * w;
        }
    }
    int base = ((z * 8 + blockIdx.y) * 32) * 1024 + e;
#pragma unroll
    for (int j = 0; j < 32; j++) g_part[base + j * 1024] = acc[j];
}

// ----- k_skred: reduce skinny partials; also emit AG fp16 hi/lo -----
__global__ void k_skred() {
    int idx = blockIdx.x * 256 + threadIdx.x;
    int z = idx >> 15;
    int r = idx & 32767;
    float s = 0.f;
#pragma unroll
    for (int kc = 0; kc < 8; kc++) s += g_part[(z * 8 + kc) * 32768 + r];
    float* out = (z == 0) ? g_A : (z == 1) ? g_Bm : g_G;
    out[r] = s;
    if (z != 1) {
        int agrow = (z == 0) ? (r >> 10) : 32 + (r >> 10);
        int col = r & 1023;
        __half h = __float2half_rn(s);
        g_AGh[agrow * 1024 + col] = h;
        g_AGl[agrow * 1024 + col] = __float2half_rn(s - __half2float(h));
    }
}

// ----- kernel 4: c = Cq@Ck^T, P = Wf@Cv^T -----
__global__ void k_small(const float* __restrict__ Wfc) {
    int i = blockIdx.x;
    const float* L; const float* R; float* out;
    if (blockIdx.y == 0) { L = g_Cq; R = g_Ck; out = g_c; }
    else                 { L = Wfc;  R = g_Cv; out = g_P; }
    int tid = threadIdx.x, warp = tid >> 5, lane = tid & 31;
    float acc[4] = {0.f, 0.f, 0.f, 0.f};
    for (int d = lane; d < 2048; d += 32) {
        float lv = L[i * 2048 + d];
#pragma unroll
        for (int q = 0; q < 4; q++) acc[q] += lv * R[(warp * 4 + q) * 2048 + d];
    }
#pragma unroll
    for (int q = 0; q < 4; q++) {
        float r = wredsum(acc[q]);
        if (lane == 0) out[i * 32 + warp * 4 + q] = r;
    }
}

// ====== kernel 5: fused Y=X@M+Bm + Z partials, 3-stage pipeline ======
#define YPAD 72
#define YA_BYTES (256 * YPAD * 2)          // 36864
#define YB_BYTES (128 * YPAD * 2)          // 18432
#define YSTAGE (YA_BYTES + YB_BYTES)       // 55296
#define ZBUF (256 * 72 * 2)                // 36864
#define YSMEM (3 * YSTAGE)                 // 165888 (>= 4*ZBUF epilogue use)

__device__ __forceinline__ void y_stage(uint32_t sb, int s, int m0, int n0,
                                        int k0, int tid) {
    uint32_t sa = sb + s * YSTAGE;
#pragma unroll
    for (int p = 0; p < 6; p++) {
        int idx = p * 512 + tid;
        if (idx < 2048) {
            int row = idx >> 3, c = idx & 7;
            cpasync16(sa + (uint32_t)(row * YPAD + c * 8) * 2,
                      g_Xh + (size_t)(m0 + row) * 1024 + k0 + c * 8);
        } else {
            int t = idx - 2048;
            int row = t >> 3, c = t & 7;
            cpasync16(sa + YA_BYTES + (uint32_t)(row * YPAD + c * 8) * 2,
                      g_MhT + (size_t)(n0 + row) * 1024 + k0 + c * 8);
        }
    }
}

__global__ __launch_bounds__(512, 1) void k_yz() {
    extern __shared__ __align__(16) char ysmem[];
    const uint32_t sb = smem_u32(ysmem);
    const int tid = threadIdx.x, lane = tid & 31, wid = tid >> 5;
    const int wm = wid >> 2, wn = wid & 3;
    const int m0 = blockIdx.y * 256, n0 = blockIdx.x * 128;

    y_stage(sb, 0, m0, n0, 0, tid);
    CP_COMMIT();
    y_stage(sb, 1, m0, n0, 64, tid);
    CP_COMMIT();

    float d[4][4][4] = {};
    const int aRow = wm * 64 + (lane & 15);
    const int aCol = (lane >> 4) * 8;
    const int bRow = wn * 32 + (lane & 7) + (lane >> 4) * 8;
    const int bCol = ((lane >> 3) & 1) * 8;

    for (int it = 0; it < 16; it++) {
        if (it < 15) CP_WAIT(1); else CP_WAIT(0);
        __syncthreads();
        if (it + 2 < 16) {
            y_stage(sb, (it + 2) % 3, m0, n0, (it + 2) * 64, tid);
            CP_COMMIT();
        }
        uint32_t abase = sb + (it % 3) * YSTAGE;
        uint32_t bbase = abase + YA_BYTES;
#pragma unroll
        for (int ks = 0; ks < 4; ks++) {
            int kc = ks * 16;
            uint32_t ar[4][4];
#pragma unroll
            for (int i = 0; i < 4; i++)
                ldsm4(ar[i], abase + (uint32_t)((aRow + i * 16) * YPAD + kc + aCol) * 2);
            uint32_t br[2][4];
#pragma unroll
            for (int j = 0; j < 2; j++)
                ldsm4(br[j], bbase + (uint32_t)((bRow + j * 16) * YPAD + kc + bCol) * 2);
#pragma unroll
            for (int i = 0; i < 4; i++)
#pragma unroll
                for (int j = 0; j < 4; j++)
                    mma_f16(d[i][j], ar[i], br[j >> 1][(j & 1) * 2],
                            br[j >> 1][(j & 1) * 2 + 1]);
        }
    }
    __syncthreads();

    // ---- epilogue: add Bm, then fused Z partials ----
    const int grp = lane >> 2, tig = lane & 3;
    const int nbl = wn * 32;
#pragma unroll
    for (int i = 0; i < 4; i++) {
        int r0 = wm * 64 + i * 16 + grp;
        int p0 = r0 & 31, p1 = (r0 + 8) & 31;
#pragma unroll
        for (int j = 0; j < 4; j++) {
            int cc = n0 + nbl + j * 8 + tig * 2;
            float2 b0 = *(const float2*)(g_Bm + p0 * 1024 + cc);
            float2 b1 = *(const float2*)(g_Bm + p1 * 1024 + cc);
            d[i][j][0] += b0.x; d[i][j][1] += b0.y;
            d[i][j][2] += b1.x; d[i][j][3] += b1.y;
        }
    }

    const int bb = wid >> 1;   // local batch 0..7
    const int nh = wid & 1;    // n-half of Z columns
    const uint32_t ZYH = sb, ZYL = sb + ZBUF, ZXH = sb + 2 * ZBUF, ZXL = sb + 3 * ZBUF;
    float z[2][2][4] = {};

#pragma unroll 1
    for (int h = 0; h < 2; h++) {
        __syncthreads();
#pragma unroll
        for (int p = 0; p < 8; p++) {
            int idx = p * 512 + tid;       // 0..4095
            int bufl = idx >> 11;
            int t = idx & 2047;
            int row = t >> 3, ch = t & 7;
            const __half* src = bufl ? g_Xl : g_Xh;
            uint32_t dst = (bufl ? ZXL : ZXH) + (uint32_t)(row * 72 + ch * 8) * 2;
            cpasync16(dst, src + (size_t)(m0 + row) * 1024 + n0 + h * 64 + ch * 8);
        }
        CP_COMMIT();
        if ((wn >> 1) == h) {
#pragma unroll
            for (int i = 0; i < 4; i++) {
                int r0 = wm * 64 + i * 16 + grp;
#pragma unroll
                for (int j = 0; j < 4; j++) {
                    int cl = (nbl - h * 64) + j * 8 + tig * 2;
                    float v0 = d[i][j][0], v1 = d[i][j][1];
                    float v2 = d[i][j][2], v3 = d[i][j][3];
                    __half h0 = __float2half_rn(v0), h1 = __float2half_rn(v1);
                    __half h2 = __float2half_rn(v2), h3 = __float2half_rn(v3);
                    *(__half2*)(ysmem + ((r0) * 72 + cl) * 2) = __halves2half2(h0, h1);
                    *(__half2*)(ysmem + ((r0 + 8) * 72 + cl) * 2) = __halves2half2(h2, h3);
                    *(__half2*)(ysmem + ZBUF + ((r0) * 72 + cl) * 2) =
                        __halves2half2(__float2half_rn(v0 - __half2float(h0)),
                                       __float2half_rn(v1 - __half2float(h1)));
                    *(__half2*)(ysmem + ZBUF + ((r0 + 8) * 72 + cl) * 2) =
                        __halves2half2(__float2half_rn(v2 - __half2float(h2)),
                                       __float2half_rn(v3 - __half2float(h3)));
                }
            }
        }
        CP_WAIT(0);
        __syncthreads();
#pragma unroll
        for (int ks = 0; ks < 4; ks++) {
            int kc = ks * 16;
            uint32_t ayh[2][4], ayl[2][4];
#pragma unroll
            for (int mi = 0; mi < 2; mi++) {
                uint32_t ao = (uint32_t)((bb * 32 + mi * 16 + (lane & 15)) * 72 +
                                         kc + (lane >> 4) * 8) * 2;
                ldsm4(ayh[mi], ZYH + ao);
                ldsm4(ayl[mi], ZYL + ao);
            }
            uint32_t bxh[4], bxl[4];
            uint32_t bo = (uint32_t)((bb * 32 + nh * 16 + (lane & 7) + (lane >> 4) * 8) * 72 +
                                     kc + ((lane >> 3) & 1) * 8) * 2;
            ldsm4(bxh, ZXH + bo);
            ldsm4(bxl, ZXL + bo);
#pragma unroll
            for (int mi = 0; mi < 2; mi++)
#pragma unroll
                for (int nj = 0; nj < 2; nj++) {
                    mma_f16(z[mi][nj], ayh[mi], bxh[nj * 2], bxh[nj * 2 + 1]);
                    mma_f16(z[mi][nj], ayh[mi], bxl[nj * 2], bxl[nj * 2 + 1]);
                    mma_f16(z[mi][nj], ayl[mi], bxh[nj * 2], bxh[nj * 2 + 1]);
                }
        }
    }
    {
        int b = blockIdx.y * 8 + bb;
        size_t base = ((size_t)blockIdx.x * 1024 + b) * 1024;
#pragma unroll
        for (int mi = 0; mi < 2; mi++) {
            int i0 = mi * 16 + grp;
#pragma unroll
            for (int nj = 0; nj < 2; nj++) {
                int j0 = nh * 16 + nj * 8 + tig * 2;
                *(float2*)(g_Zpart + base + i0 * 32 + j0) =
                    make_float2(z[mi][nj][0], z[mi][nj][1]);
                *(float2*)(g_Zpart + base + (i0 + 8) * 32 + j0) =
                    make_float2(z[mi][nj][2], z[mi][nj][3]);
            }
        }
    }
}

// ====== kernel 6: RAG = [A;G] @ Xall^T ======
#define RPAD 72
#define R_A_BYTES (64 * RPAD * 2)
#define R_B_BYTES (256 * RPAD * 2)
#define RSTAGE (2 * R_A_BYTES + 2 * R_B_BYTES)
#define RSMEM (2 * RSTAGE)

__device__ __forceinline__ void r_stage(uint32_t sb, int s, int n0, int k0, int tid) {
    uint32_t sa = sb + s * RSTAGE;
#pragma unroll
    for (int p = 0; p < 4; p++) {
        int idx = p * 256 + tid;
        int bufl = idx >> 9;
        int t = idx & 511;
        int row = t >> 3, ch = t & 7;
        const __half* src = bufl ? g_AGl : g_AGh;
        cpasync16(sa + bufl * R_A_BYTES + (uint32_t)(row * RPAD + ch * 8) * 2,
                  src + (size_t)row * 1024 + k0 + ch * 8);
    }
#pragma unroll
    for (int p = 0; p < 16; p++) {
        int idx = p * 256 + tid;
        int bufl = idx >> 11;
        int t = idx & 2047;
        int row = t >> 3, ch = t & 7;
        const __half* src = bufl ? g_Xl : g_Xh;
        cpasync16(sa + 2 * R_A_BYTES + bufl * R_B_BYTES + (uint32_t)(row * RPAD + ch * 8) * 2,
                  src + (size_t)(n0 + row) * 1024 + k0 + ch * 8);
    }
}

__global__ __launch_bounds__(256, 1) void k_rag() {
    extern __shared__ __align__(16) char rsmem[];
    const uint32_t sb = smem_u32(rsmem);
    const int tid = threadIdx.x, lane = tid & 31, wid = tid >> 5;
    const int wm = wid >> 2, wn = wid & 3;
    const int n0 = blockIdx.x * 256;

    r_stage(sb, 0, n0, 0, tid);
    CP_COMMIT();

    float d[2][4][2][4] = {};
    const int aRowB = wm * 32 + (lane & 15);
    const int aCol = (lane >> 4) * 8;
    const int bRowB = wn * 64 + (lane & 7) + (lane >> 4) * 8;
    const int bCol = ((lane >> 3) & 1) * 8;

    for (int it = 0; it < 16; it++) {
        int nit = it + 1;
        if (nit < 16) {
            r_stage(sb, nit & 1, n0, nit * 64, tid);
            CP_COMMIT();
            CP_WAIT(1);
        } else {
            CP_WAIT(0);
        }
        __syncthreads();
        uint32_t st = sb + (it & 1) * RSTAGE;
        uint32_t sB = st + 2 * R_A_BYTES;
#pragma unroll
        for (int ks = 0; ks < 4; ks++) {
            int kc = ks * 16;
            uint32_t ah[2][4], al[2][4];
#pragma unroll
            for (int mi = 0; mi < 2; mi++) {
                uint32_t ao = (uint32_t)((aRowB + mi * 16) * RPAD + kc + aCol) * 2;
                ldsm4(ah[mi], st + ao);
                ldsm4(al[mi], st + R_A_BYTES + ao);
            }
            uint32_t bh[4][4], bl[4][4];
#pragma unroll
            for (int nj = 0; nj < 4; nj++) {
                uint32_t bo = (uint32_t)((bRowB + nj * 16) * RPAD + kc + bCol) * 2;
                ldsm4(bh[nj], sB + bo);
                ldsm4(bl[nj], sB + R_B_BYTES + bo);
            }
#pragma unroll
            for (int mi = 0; mi < 2; mi++)
#pragma unroll
                for (int nj = 0; nj < 4; nj++)
#pragma unroll
                    for (int s = 0; s < 2; s++) {
                        mma_f16(d[mi][nj][s], ah[mi], bh[nj][s * 2], bh[nj][s * 2 + 1]);
                        mma_f16(d[mi][nj][s], ah[mi], bl[nj][s * 2], bl[nj][s * 2 + 1]);
                        mma_f16(d[mi][nj][s], al[mi], bh[nj][s * 2], bh[nj][s * 2 + 1]);
                    }
        }
        __syncthreads();
    }
    const int grp = lane >> 2, tig = lane & 3;
#pragma unroll
    for (int mi = 0; mi < 2; mi++) {
        int r0 = wm * 32 + mi * 16 + grp, r1 = r0 + 8;
#pragma unroll
        for (int nj = 0; nj < 4; nj++)
#pragma unroll
            for (int s = 0; s < 2; s++) {
                int col = n0 + wn * 64 + nj * 16 + s * 8 + tig * 2;
                *(float2*)(g_RAG + (size_t)r0 * 32768 + col) =
                    make_float2(d[mi][nj][s][0], d[mi][nj][s][1]);
                *(float2*)(g_RAG + (size_t)r1 * 32768 + col) =
                    make_float2(d[mi][nj][s][2], d[mi][nj][s][3]);
            }
    }
}

// ----- kernel 7: reduce Z partials + softmax(dim=1) + final dot -----
__global__ __launch_bounds__(256) void k_attn2(const float* __restrict__ bfc,
                                               float* __restrict__ out) {
    __shared__ float Zs[32 * 33];
    __shared__ float As[32 * 33];
    __shared__ float Vs[32 * 33];
    __shared__ float wpart[8];
    int tid = threadIdx.x, b = blockIdx.x;
#pragma unroll
    for (int p = 0; p < 4; p++) {
        int idx = p * 256 + tid;
        int i = idx >> 5, j = idx & 31;
        float s = 0.f;
#pragma unroll
        for (int nb = 0; nb < 8; nb++)
            s += g_Zpart[((size_t)nb * 1024 + b) * 1024 + idx];
        Zs[i * 33 + j] = s;
        As[i * 33 + j] = g_RAG[(size_t)j * 32768 + b * 32 + i];
        Vs[i * 33 + j] = g_RAG[(size_t)(32 + i) * 32768 + b * 32 + j];
    }
    __syncthreads();
    int w = tid >> 5, lane = tid & 31;
    const float rscale = 0.022097086912079608f;  // 1/sqrt(2048)
    float local = 0.f;
#pragma unroll
    for (int q = 0; q < 4; q++) {
        int j = w * 4 + q;
        float lg = (Zs[lane * 33 + j] + As[lane * 33 + j] + g_c[lane * 32 + j]) * rscale;
        float mx = wredmax(lg);
        float ex = __expf(lg - mx);
        float sm = wredsum(ex);
        float contrib = (ex / sm) * (Vs[lane * 33 + j] + g_P[lane * 32 + j]);
        local += wredsum(contrib);
    }
    if (lane == 0) wpart[w] = local;
    __syncthreads();
    if (tid == 0) {
        float t = 0.f;
#pragma unroll
        for (int i = 0; i < 8; i++) t += wpart[i];
        out[b] = t + bfc[0];
    }
}

extern "C" void kernel_launch(void* const* d_in, const int* in_sizes, int n_in,
                              void* d_out, int out_size) {
    const float* x   = (const float*)d_in[0];
    const float* pe  = (const float*)d_in[1];
    const float* Wq  = (const float*)d_in[2];
    const float* bq  = (const float*)d_in[3];
    const float* Wk  = (const float*)d_in[4];
    const float* bk  = (const float*)d_in[5];
    const float* Wv  = (const float*)d_in[6];
    const float* bv  = (const float*)d_in[7];
    const float* Wfc = (const float*)d_in[8];
    const float* bfc = (const float*)d_in[9];
    float* out = (float*)d_out;

    cudaFuncSetAttribute(k_gemmM_mma, cudaFuncAttributeMaxDynamicSharedMemorySize, GSMEM);
    cudaFuncSetAttribute(k_yz, cudaFuncAttributeMaxDynamicSharedMemorySize, YSMEM);
    cudaFuncSetAttribute(k_rag, cudaFuncAttributeMaxDynamicSharedMemorySize, RSMEM);

    k_prep<<<37632, 256>>>(x, pe, Wq, bq, Wk, bk, Wv, bv);
    k_gemmM_mma<<<dim3(8, 8, 2), 256, GSMEM>>>();
    k_Mred<<<dim3(32, 32), dim3(32, 8)>>>();
    k_skinny<<<dim3(8, 8, 3), 128>>>(Wq, Wk, Wv, Wfc);
    k_skred<<<384, 256>>>();
    k_small<<<dim3(32, 2), 256>>>(Wfc);
    k_yz<<<dim3(8, 128), 512, YSMEM>>>();
    k_rag<<<128, 256, RSMEM>>>();
    k_attn2<<<1024, 256>>>(bfc, out);
}

// round 8
// speedup vs baseline: 3.5295x; 1.0356x over previous
#include <cuda_runtime.h>
#include <cuda_bf16.h>
#include <cuda_fp16.h>
#include <math.h>
#include <stdint.h>

// B=1024, S=32, D=1024, D2=2048
// out[b]: Cq/Ck/Cv = pe@W2^T+b ; MhT=(Wq1^T Wk1)^T (bf16 3-split mma, split-K=4) ;
// A=Ck@Wq1 ; Bm=Cq@Wk1 ; G=Wf@Wv1 (split-K=32 SIMT) ; c=Cq@Ck^T ; P=Wf@Cv^T ;
// k_yz: Y=X@M+Bm (fp16 mma) fused with Z_b = Y'_b @ X_b^T partials (3-product mma);
// k_rag: [A;G]@Xall^T (3-product mma) ; k_attn2: reduce+softmax(dim=1)+dot.

// ----- static scratch -----
__device__ float g_Cq[65536], g_Ck[65536], g_Cv[65536];
__device__ float g_A[32768], g_Bm[32768], g_G[32768];
__device__ float g_part[3145728];    // [3][32][32][1024] skinny split-K partials
__device__ float g_c[1024], g_P[1024];
__device__ float g_Zpart[8388608];   // gemmM split-K partials (4x1M), then Z partials
__device__ float g_RAG[2097152];     // [64][32768]
__device__ __align__(16) __half g_Xh[33554432];   // fp16 X [32768,1024]
__device__ __align__(16) __half g_Xl[33554432];   // fp16 residual
__device__ __align__(16) __half g_MhT[1048576];   // fp16 M^T [f][e]
__device__ __align__(16) __half g_AGh[65536];     // [64][1024] = [A;G] hi
__device__ __align__(16) __half g_AGl[65536];
__device__ __align__(16) __nv_bfloat16 g_WqTh[2097152];  // [e][d2]
__device__ __align__(16) __nv_bfloat16 g_WqTl[2097152];
__device__ __align__(16) __nv_bfloat16 g_WkTh[2097152];
__device__ __align__(16) __nv_bfloat16 g_WkTl[2097152];

__device__ __forceinline__ float wredsum(float v) {
#pragma unroll
    for (int o = 16; o; o >>= 1) v += __shfl_xor_sync(0xffffffffu, v, o);
    return v;
}
__device__ __forceinline__ float wredmax(float v) {
#pragma unroll
    for (int o = 16; o; o >>= 1) v = fmaxf(v, __shfl_xor_sync(0xffffffffu, v, o));
    return v;
}
__device__ __forceinline__ uint32_t smem_u32(const void* p) {
    uint32_t a;
    asm("{ .reg .u64 t; cvta.to.shared.u64 t, %1; cvt.u32.u64 %0, t; }" : "=r"(a) : "l"(p));
    return a;
}
__device__ __forceinline__ void ldsm4(uint32_t* r, uint32_t addr) {
    asm volatile("ldmatrix.sync.aligned.m8n8.x4.shared.b16 {%0,%1,%2,%3}, [%4];"
                 : "=r"(r[0]), "=r"(r[1]), "=r"(r[2]), "=r"(r[3]) : "r"(addr));
}
__device__ __forceinline__ void mma_bf16(float* d, const uint32_t* a,
                                         uint32_t b0, uint32_t b1) {
    asm volatile(
        "mma.sync.aligned.m16n8k16.row.col.f32.bf16.bf16.f32 "
        "{%0,%1,%2,%3}, {%4,%5,%6,%7}, {%8,%9}, {%0,%1,%2,%3};"
        : "+f"(d[0]), "+f"(d[1]), "+f"(d[2]), "+f"(d[3])
        : "r"(a[0]), "r"(a[1]), "r"(a[2]), "r"(a[3]), "r"(b0), "r"(b1));
}
__device__ __forceinline__ void mma_f16(float* d, const uint32_t* a,
                                        uint32_t b0, uint32_t b1) {
    asm volatile(
        "mma.sync.aligned.m16n8k16.row.col.f32.f16.f16.f32 "
        "{%0,%1,%2,%3}, {%4,%5,%6,%7}, {%8,%9}, {%0,%1,%2,%3};"
        : "+f"(d[0]), "+f"(d[1]), "+f"(d[2]), "+f"(d[3])
        : "r"(a[0]), "r"(a[1]), "r"(a[2]), "r"(a[3]), "r"(b0), "r"(b1));
}
__device__ __forceinline__ void cpasync16(uint32_t saddr, const void* gaddr) {
    asm volatile("cp.async.cg.shared.global [%0], [%1], 16;" :: "r"(saddr), "l"(gaddr));
}
#define CP_COMMIT() asm volatile("cp.async.commit_group;" ::: "memory")
#define CP_WAIT(n)  asm volatile("cp.async.wait_group %0;" :: "n"(n) : "memory")

// ===== merged prep: precompC (768 blk) | splitWT (4096 blk) | splitX (32768 blk) =====
__global__ __launch_bounds__(256) void k_prep(const float* __restrict__ x,
                                              const float* __restrict__ pe,
                                              const float* __restrict__ Wq, const float* __restrict__ bq,
                                              const float* __restrict__ Wk, const float* __restrict__ bk,
                                              const float* __restrict__ Wv, const float* __restrict__ bv) {
    __shared__ float sh[32 * 33];
    int blk = blockIdx.x;
    int tid = threadIdx.x;
    if (blk < 768) {
        int bz = blk >> 8, bx = blk & 255;
        const float* W; const float* bias; float* out;
        if (bz == 0)      { W = Wq; bias = bq; out = g_Cq; }
        else if (bz == 1) { W = Wk; bias = bk; out = g_Ck; }
        else              { W = Wv; bias = bv; out = g_Cv; }
        int warp = tid >> 5, lane = tid & 31;
        int d2 = bx * 8 + warp;
        float acc[32];
#pragma unroll
        for (int i = 0; i < 32; i++) acc[i] = 0.f;
        for (int e0 = 0; e0 < 1024; e0 += 32) {
            __syncthreads();
#pragma unroll
            for (int p = 0; p < 4; p++) {
                int idx = p * 256 + tid;
                sh[(idx >> 5) * 33 + (idx & 31)] = pe[(idx >> 5) * 1024 + e0 + (idx & 31)];
            }
            __syncthreads();
            float wv = W[(size_t)d2 * 2048 + 1024 + e0 + lane];
#pragma unroll
            for (int i = 0; i < 32; i++) acc[i] += sh[i * 33 + lane] * wv;
        }
        float res = 0.f;
#pragma unroll
        for (int i = 0; i < 32; i++) {
            float r = wredsum(acc[i]);
            if (lane == i) res = r;
        }
        out[lane * 2048 + d2] = res + bias[d2];
    } else if (blk < 768 + 4096) {
        int b2 = blk - 768;
        int bx = b2 & 31, by = (b2 >> 5) & 63, bz = b2 >> 11;
        const float* W = bz ? Wk : Wq;
        __nv_bfloat16* oh = bz ? g_WkTh : g_WqTh;
        __nv_bfloat16* ol = bz ? g_WkTl : g_WqTl;
        int xx = tid & 31, yy = tid >> 5;   // 32 x 8
#pragma unroll
        for (int i = 0; i < 32; i += 8)
            sh[(yy + i) * 33 + xx] = W[(size_t)(by * 32 + yy + i) * 2048 + bx * 32 + xx];
        __syncthreads();
#pragma unroll
        for (int i = 0; i < 32; i += 8) {
            float v = sh[xx * 33 + yy + i];
            __nv_bfloat16 h = __float2bfloat16(v);
            __nv_bfloat16 l = __float2bfloat16(v - __bfloat162float(h));
            size_t o = (size_t)(bx * 32 + yy + i) * 2048 + by * 32 + xx;
            oh[o] = h;
            ol[o] = l;
        }
    } else {
        size_t i = ((size_t)(blk - 4864) * 256 + tid) * 4;
        float4 v = *(const float4*)(x + i);
        __half h0 = __float2half_rn(v.x), h1 = __float2half_rn(v.y);
        __half h2 = __float2half_rn(v.z), h3 = __float2half_rn(v.w);
        *(__half2*)(g_Xh + i)     = __halves2half2(h0, h1);
        *(__half2*)(g_Xh + i + 2) = __halves2half2(h2, h3);
        *(__half2*)(g_Xl + i)     = __halves2half2(__float2half_rn(v.x - __half2float(h0)),
                                                   __float2half_rn(v.y - __half2float(h1)));
        *(__half2*)(g_Xl + i + 2) = __halves2half2(__float2half_rn(v.z - __half2float(h2)),
                                                   __float2half_rn(v.w - __half2float(h3)));
    }
}

// ----- kernel 2: M partials = Wq1^T @ Wk1, bf16 3-product mma, split-K=4 -----
#define GPAD 72
#define GBUF (128 * GPAD * 2)
#define GSTAGE (4 * GBUF)        // 73728
#define GSMEM (3 * GSTAGE)       // 221184

__device__ __forceinline__ void g_stage(uint32_t sb, int s, int m0, int n0,
                                        int k0, int tid) {
    uint32_t sa = sb + s * GSTAGE;
#pragma unroll
    for (int p = 0; p < 16; p++) {
        int idx = p * 256 + tid;
        int buf = idx >> 10;
        int t = idx & 1023;
        int row = t >> 3, c = t & 7;
        const __nv_bfloat16* src =
            (buf == 0) ? g_WqTh : (buf == 1) ? g_WqTl : (buf == 2) ? g_WkTh : g_WkTl;
        int r0 = (buf < 2) ? m0 : n0;
        cpasync16(sa + buf * GBUF + (uint32_t)(row * GPAD + c * 8) * 2,
                  src + (size_t)(r0 + row) * 2048 + k0 + c * 8);
    }
}

__global__ __launch_bounds__(256, 1) void k_gemmM_mma() {
    extern __shared__ __align__(16) char gsmem[];
    const uint32_t sb = smem_u32(gsmem);
    const int tid = threadIdx.x, lane = tid & 31, wid = tid >> 5;
    const int wm = wid >> 2, wn = wid & 3;
    const int m0 = blockIdx.y * 128, n0 = blockIdx.x * 128;
    const int kbase = blockIdx.z * 512;

    g_stage(sb, 0, m0, n0, kbase, tid);
    CP_COMMIT();
    g_stage(sb, 1, m0, n0, kbase + 64, tid);
    CP_COMMIT();

    float d[4][4][4] = {};
    const int aRow = wm * 64 + (lane & 15);
    const int aCol = (lane >> 4) * 8;
    const int bRow = wn * 32 + (lane & 7) + (lane >> 4) * 8;
    const int bCol = ((lane >> 3) & 1) * 8;

    for (int it = 0; it < 8; it++) {
        if (it < 7) CP_WAIT(1); else CP_WAIT(0);
        __syncthreads();
        if (it + 2 < 8) {
            g_stage(sb, (it + 2) % 3, m0, n0, kbase + (it + 2) * 64, tid);
            CP_COMMIT();
        }
        uint32_t st = sb + (it % 3) * GSTAGE;
#pragma unroll
        for (int ks = 0; ks < 4; ks++) {
            int kc = ks * 16;
            uint32_t arh[4][4], arl[4][4];
#pragma unroll
            for (int i = 0; i < 4; i++) {
                uint32_t ao = (uint32_t)((aRow + i * 16) * GPAD + kc + aCol) * 2;
                ldsm4(arh[i], st + ao);
                ldsm4(arl[i], st + GBUF + ao);
            }
            uint32_t brh[2][4], brl[2][4];
#pragma unroll
            for (int j = 0; j < 2; j++) {
                uint32_t bo = (uint32_t)((bRow + j * 16) * GPAD + kc + bCol) * 2;
                ldsm4(brh[j], st + 2 * GBUF + bo);
                ldsm4(brl[j], st + 3 * GBUF + bo);
            }
#pragma unroll
            for (int i = 0; i < 4; i++)
#pragma unroll
                for (int j = 0; j < 4; j++) {
                    uint32_t h0 = brh[j >> 1][(j & 1) * 2], h1 = brh[j >> 1][(j & 1) * 2 + 1];
                    uint32_t l0 = brl[j >> 1][(j & 1) * 2], l1 = brl[j >> 1][(j & 1) * 2 + 1];
                    mma_bf16(d[i][j], arh[i], h0, h1);
                    mma_bf16(d[i][j], arh[i], l0, l1);
                    mma_bf16(d[i][j], arl[i], h0, h1);
                }
        }
    }
    float* outp = g_Zpart + (size_t)blockIdx.z * 1048576;
    const int grp = lane >> 2, tig = lane & 3;
    const int mb = m0 + wm * 64, nb = n0 + wn * 32;
#pragma unroll
    for (int i = 0; i < 4; i++) {
        int r0 = mb + i * 16 + grp, r1 = r0 + 8;
#pragma unroll
        for (int j = 0; j < 4; j++) {
            int cc = nb + j * 8 + tig * 2;
            *(float2*)(outp + (size_t)r0 * 1024 + cc) = make_float2(d[i][j][0], d[i][j][1]);
            *(float2*)(outp + (size_t)r1 * 1024 + cc) = make_float2(d[i][j][2], d[i][j][3]);
        }
    }
}

// ----- k_Mred: sum 4 split-K partials + transpose + fp16 -> g_MhT -----
__global__ void k_Mred() {
    __shared__ float t[32][33];
    int bx = blockIdx.x, by = blockIdx.y;
    int x = threadIdx.x, y = threadIdx.y;   // 32 x 8
#pragma unroll
    for (int i = 0; i < 32; i += 8) {
        size_t o = (size_t)(by * 32 + y + i) * 1024 + bx * 32 + x;
        t[y + i][x] = g_Zpart[o] + g_Zpart[1048576 + o] +
                      g_Zpart[2097152 + o] + g_Zpart[3145728 + o];
    }
    __syncthreads();
#pragma unroll
    for (int i = 0; i < 32; i += 8)
        g_MhT[(size_t)(bx * 32 + y + i) * 1024 + by * 32 + x] = __float2half_rn(t[x][y + i]);
}

// ----- kernel 3: skinny gemms, split-K=32 -----
// grid(8 e-tiles, 32 k-chunks, 3), block 128
__global__ __launch_bounds__(128) void k_skinny(const float* __restrict__ Wq,
                                                const float* __restrict__ Wk,
                                                const float* __restrict__ Wv,
                                                const float* __restrict__ Wfc) {
    const float* L; const float* R;
    int z = blockIdx.z;
    if (z == 0)      { L = g_Ck; R = Wq; }
    else if (z == 1) { L = g_Cq; R = Wk; }
    else             { L = Wfc;  R = Wv; }
    __shared__ float Lsh[32][64];
    int tid = threadIdx.x;
    int e  = blockIdx.x * 128 + tid;
    int d0 = blockIdx.y * 64;
    float acc[32];
#pragma unroll
    for (int j = 0; j < 32; j++) acc[j] = 0.f;
#pragma unroll
    for (int p = 0; p < 16; p++) {
        int idx = p * 128 + tid;
        Lsh[idx >> 6][idx & 63] = L[(idx >> 6) * 2048 + d0 + (idx & 63)];
    }
    __syncthreads();
#pragma unroll 4
    for (int dd = 0; dd < 64; dd++) {
        float w = R[(size_t)(d0 + dd) * 2048 + e];
#pragma unroll
        for (int j = 0; j < 32; j++) acc[j] += Lsh[j][dd] * w;
    }
    int base = ((z * 32 + blockIdx.y) * 32) * 1024 + e;
#pragma unroll
    for (int j = 0; j < 32; j++) g_part[base + j * 1024] = acc[j];
}

// ----- k_skred: reduce 32 skinny partials; also emit AG fp16 hi/lo -----
__global__ void k_skred() {
    int idx = blockIdx.x * 256 + threadIdx.x;   // 98304
    int z = idx >> 15;
    int r = idx & 32767;
    float s = 0.f;
#pragma unroll
    for (int kc = 0; kc < 32; kc++) s += g_part[(z * 32 + kc) * 32768 + r];
    float* out = (z == 0) ? g_A : (z == 1) ? g_Bm : g_G;
    out[r] = s;
    if (z != 1) {
        int agrow = (z == 0) ? (r >> 10) : 32 + (r >> 10);
        int col = r & 1023;
        __half h = __float2half_rn(s);
        g_AGh[agrow * 1024 + col] = h;
        g_AGl[agrow * 1024 + col] = __float2half_rn(s - __half2float(h));
    }
}

// ----- kernel 4: c = Cq@Ck^T, P = Wf@Cv^T -----
__global__ void k_small(const float* __restrict__ Wfc) {
    int i = blockIdx.x;
    const float* L; const float* R; float* out;
    if (blockIdx.y == 0) { L = g_Cq; R = g_Ck; out = g_c; }
    else                 { L = Wfc;  R = g_Cv; out = g_P; }
    int tid = threadIdx.x, warp = tid >> 5, lane = tid & 31;
    float acc[4] = {0.f, 0.f, 0.f, 0.f};
    for (int d = lane; d < 2048; d += 32) {
        float lv = L[i * 2048 + d];
#pragma unroll
        for (int q = 0; q < 4; q++) acc[q] += lv * R[(warp * 4 + q) * 2048 + d];
    }
#pragma unroll
    for (int q = 0; q < 4; q++) {
        float r = wredsum(acc[q]);
        if (lane == 0) out[i * 32 + warp * 4 + q] = r;
    }
}

// ====== kernel 5: fused Y=X@M+Bm + Z partials, 3-stage pipeline ======
#define YPAD 72
#define YA_BYTES (256 * YPAD * 2)          // 36864
#define YB_BYTES (128 * YPAD * 2)          // 18432
#define YSTAGE (YA_BYTES + YB_BYTES)       // 55296
#define ZBUF (256 * 72 * 2)                // 36864
#define YSMEM (3 * YSTAGE)                 // 165888 (>= 4*ZBUF epilogue use)

__device__ __forceinline__ void y_stage(uint32_t sb, int s, int m0, int n0,
                                        int k0, int tid) {
    uint32_t sa = sb + s * YSTAGE;
#pragma unroll
    for (int p = 0; p < 6; p++) {
        int idx = p * 512 + tid;
        if (idx < 2048) {
            int row = idx >> 3, c = idx & 7;
            cpasync16(sa + (uint32_t)(row * YPAD + c * 8) * 2,
                      g_Xh + (size_t)(m0 + row) * 1024 + k0 + c * 8);
        } else {
            int t = idx - 2048;
            int row = t >> 3, c = t & 7;
            cpasync16(sa + YA_BYTES + (uint32_t)(row * YPAD + c * 8) * 2,
                      g_MhT + (size_t)(n0 + row) * 1024 + k0 + c * 8);
        }
    }
}

__global__ __launch_bounds__(512, 1) void k_yz() {
    extern __shared__ __align__(16) char ysmem[];
    const uint32_t sb = smem_u32(ysmem);
    const int tid = threadIdx.x, lane = tid & 31, wid = tid >> 5;
    const int wm = wid >> 2, wn = wid & 3;
    const int m0 = blockIdx.y * 256, n0 = blockIdx.x * 128;

    y_stage(sb, 0, m0, n0, 0, tid);
    CP_COMMIT();
    y_stage(sb, 1, m0, n0, 64, tid);
    CP_COMMIT();

    float d[4][4][4] = {};
    const int aRow = wm * 64 + (lane & 15);
    const int aCol = (lane >> 4) * 8;
    const int bRow = wn * 32 + (lane & 7) + (lane >> 4) * 8;
    const int bCol = ((lane >> 3) & 1) * 8;

    for (int it = 0; it < 16; it++) {
        if (it < 15) CP_WAIT(1); else CP_WAIT(0);
        __syncthreads();
        if (it + 2 < 16) {
            y_stage(sb, (it + 2) % 3, m0, n0, (it + 2) * 64, tid);
            CP_COMMIT();
        }
        uint32_t abase = sb + (it % 3) * YSTAGE;
        uint32_t bbase = abase + YA_BYTES;
#pragma unroll
        for (int ks = 0; ks < 4; ks++) {
            int kc = ks * 16;
            uint32_t ar[4][4];
#pragma unroll
            for (int i = 0; i < 4; i++)
                ldsm4(ar[i], abase + (uint32_t)((aRow + i * 16) * YPAD + kc + aCol) * 2);
            uint32_t br[2][4];
#pragma unroll
            for (int j = 0; j < 2; j++)
                ldsm4(br[j], bbase + (uint32_t)((bRow + j * 16) * YPAD + kc + bCol) * 2);
#pragma unroll
            for (int i = 0; i < 4; i++)
#pragma unroll
                for (int j = 0; j < 4; j++)
                    mma_f16(d[i][j], ar[i], br[j >> 1][(j & 1) * 2],
                            br[j >> 1][(j & 1) * 2 + 1]);
        }
    }
    __syncthreads();

    // ---- epilogue: add Bm, then fused Z partials ----
    const int grp = lane >> 2, tig = lane & 3;
    const int nbl = wn * 32;
#pragma unroll
    for (int i = 0; i < 4; i++) {
        int r0 = wm * 64 + i * 16 + grp;
        int p0 = r0 & 31, p1 = (r0 + 8) & 31;
#pragma unroll
        for (int j = 0; j < 4; j++) {
            int cc = n0 + nbl + j * 8 + tig * 2;
            float2 b0 = *(const float2*)(g_Bm + p0 * 1024 + cc);
            float2 b1 = *(const float2*)(g_Bm + p1 * 1024 + cc);
            d[i][j][0] += b0.x; d[i][j][1] += b0.y;
            d[i][j][2] += b1.x; d[i][j][3] += b1.y;
        }
    }

    const int bb = wid >> 1;
    const int nh = wid & 1;
    const uint32_t ZYH = sb, ZYL = sb + ZBUF, ZXH = sb + 2 * ZBUF, ZXL = sb + 3 * ZBUF;
    float z[2][2][4] = {};

#pragma unroll 1
    for (int h = 0; h < 2; h++) {
        __syncthreads();
#pragma unroll
        for (int p = 0; p < 8; p++) {
            int idx = p * 512 + tid;
            int bufl = idx >> 11;
            int t = idx & 2047;
            int row = t >> 3, ch = t & 7;
            const __half* src = bufl ? g_Xl : g_Xh;
            uint32_t dst = (bufl ? ZXL : ZXH) + (uint32_t)(row * 72 + ch * 8) * 2;
            cpasync16(dst, src + (size_t)(m0 + row) * 1024 + n0 + h * 64 + ch * 8);
        }
        CP_COMMIT();
        if ((wn >> 1) == h) {
#pragma unroll
            for (int i = 0; i < 4; i++) {
                int r0 = wm * 64 + i * 16 + grp;
#pragma unroll
                for (int j = 0; j < 4; j++) {
                    int cl = (nbl - h * 64) + j * 8 + tig * 2;
                    float v0 = d[i][j][0], v1 = d[i][j][1];
                    float v2 = d[i][j][2], v3 = d[i][j][3];
                    __half h0 = __float2half_rn(v0), h1 = __float2half_rn(v1);
                    __half h2 = __float2half_rn(v2), h3 = __float2half_rn(v3);
                    *(__half2*)(ysmem + ((r0) * 72 + cl) * 2) = __halves2half2(h0, h1);
                    *(__half2*)(ysmem + ((r0 + 8) * 72 + cl) * 2) = __halves2half2(h2, h3);
                    *(__half2*)(ysmem + ZBUF + ((r0) * 72 + cl) * 2) =
                        __halves2half2(__float2half_rn(v0 - __half2float(h0)),
                                       __float2half_rn(v1 - __half2float(h1)));
                    *(__half2*)(ysmem + ZBUF + ((r0 + 8) * 72 + cl) * 2) =
                        __halves2half2(__float2half_rn(v2 - __half2float(h2)),
                                       __float2half_rn(v3 - __half2float(h3)));
                }
            }
        }
        CP_WAIT(0);
        __syncthreads();
#pragma unroll
        for (int ks = 0; ks < 4; ks++) {
            int kc = ks * 16;
            uint32_t ayh[2][4], ayl[2][4];
#pragma unroll
            for (int mi = 0; mi < 2; mi++) {
                uint32_t ao = (uint32_t)((bb * 32 + mi * 16 + (lane & 15)) * 72 +
                                         kc + (lane >> 4) * 8) * 2;
                ldsm4(ayh[mi], ZYH + ao);
                ldsm4(ayl[mi], ZYL + ao);
            }
            uint32_t bxh[4], bxl[4];
            uint32_t bo = (uint32_t)((bb * 32 + nh * 16 + (lane & 7) + (lane >> 4) * 8) * 72 +
                                     kc + ((lane >> 3) & 1) * 8) * 2;
            ldsm4(bxh, ZXH + bo);
            ldsm4(bxl, ZXL + bo);
#pragma unroll
            for (int mi = 0; mi < 2; mi++)
#pragma unroll
                for (int nj = 0; nj < 2; nj++) {
                    mma_f16(z[mi][nj], ayh[mi], bxh[nj * 2], bxh[nj * 2 + 1]);
                    mma_f16(z[mi][nj], ayh[mi], bxl[nj * 2], bxl[nj * 2 + 1]);
                    mma_f16(z[mi][nj], ayl[mi], bxh[nj * 2], bxh[nj * 2 + 1]);
                }
        }
    }
    {
        int b = blockIdx.y * 8 + bb;
        size_t base = ((size_t)blockIdx.x * 1024 + b) * 1024;
#pragma unroll
        for (int mi = 0; mi < 2; mi++) {
            int i0 = mi * 16 + grp;
#pragma unroll
            for (int nj = 0; nj < 2; nj++) {
                int j0 = nh * 16 + nj * 8 + tig * 2;
                *(float2*)(g_Zpart + base + i0 * 32 + j0) =
                    make_float2(z[mi][nj][0], z[mi][nj][1]);
                *(float2*)(g_Zpart + base + (i0 + 8) * 32 + j0) =
                    make_float2(z[mi][nj][2], z[mi][nj][3]);
            }
        }
    }
}

// ====== kernel 6: RAG = [A;G] @ Xall^T ======
#define RPAD 72
#define R_A_BYTES (64 * RPAD * 2)
#define R_B_BYTES (256 * RPAD * 2)
#define RSTAGE (2 * R_A_BYTES + 2 * R_B_BYTES)
#define RSMEM (2 * RSTAGE)

__device__ __forceinline__ void r_stage(uint32_t sb, int s, int n0, int k0, int tid) {
    uint32_t sa = sb + s * RSTAGE;
#pragma unroll
    for (int p = 0; p < 4; p++) {
        int idx = p * 256 + tid;
        int bufl = idx >> 9;
        int t = idx & 511;
        int row = t >> 3, ch = t & 7;
        const __half* src = bufl ? g_AGl : g_AGh;
        cpasync16(sa + bufl * R_A_BYTES + (uint32_t)(row * RPAD + ch * 8) * 2,
                  src + (size_t)row * 1024 + k0 + ch * 8);
    }
#pragma unroll
    for (int p = 0; p < 16; p++) {
        int idx = p * 256 + tid;
        int bufl = idx >> 11;
        int t = idx & 2047;
        int row = t >> 3, ch = t & 7;
        const __half* src = bufl ? g_Xl : g_Xh;
        cpasync16(sa + 2 * R_A_BYTES + bufl * R_B_BYTES + (uint32_t)(row * RPAD + ch * 8) * 2,
                  src + (size_t)(n0 + row) * 1024 + k0 + ch * 8);
    }
}

__global__ __launch_bounds__(256, 1) void k_rag() {
    extern __shared__ __align__(16) char rsmem[];
    const uint32_t sb = smem_u32(rsmem);
    const int tid = threadIdx.x, lane = tid & 31, wid = tid >> 5;
    const int wm = wid >> 2, wn = wid & 3;
    const int n0 = blockIdx.x * 256;

    r_stage(sb, 0, n0, 0, tid);
    CP_COMMIT();

    float d[2][4][2][4] = {};
    const int aRowB = wm * 32 + (lane & 15);
    const int aCol = (lane >> 4) * 8;
    const int bRowB = wn * 64 + (lane & 7) + (lane >> 4) * 8;
    const int bCol = ((lane >> 3) & 1) * 8;

    for (int it = 0; it < 16; it++) {
        int nit = it + 1;
        if (nit < 16) {
            r_stage(sb, nit & 1, n0, nit * 64, tid);
            CP_COMMIT();
            CP_WAIT(1);
        } else {
            CP_WAIT(0);
        }
        __syncthreads();
        uint32_t st = sb + (it & 1) * RSTAGE;
        uint32_t sB = st + 2 * R_A_BYTES;
#pragma unroll
        for (int ks = 0; ks < 4; ks++) {
            int kc = ks * 16;
            uint32_t ah[2][4], al[2][4];
#pragma unroll
            for (int mi = 0; mi < 2; mi++) {
                uint32_t ao = (uint32_t)((aRowB + mi * 16) * RPAD + kc + aCol) * 2;
                ldsm4(ah[mi], st + ao);
                ldsm4(al[mi], st + R_A_BYTES + ao);
            }
            uint32_t bh[4][4], bl[4][4];
#pragma unroll
            for (int nj = 0; nj < 4; nj++) {
                uint32_t bo = (uint32_t)((bRowB + nj * 16) * RPAD + kc + bCol) * 2;
                ldsm4(bh[nj], sB + bo);
                ldsm4(bl[nj], sB + R_B_BYTES + bo);
            }
#pragma unroll
            for (int mi = 0; mi < 2; mi++)
#pragma unroll
                for (int nj = 0; nj < 4; nj++)
#pragma unroll
                    for (int s = 0; s < 2; s++) {
                        mma_f16(d[mi][nj][s], ah[mi], bh[nj][s * 2], bh[nj][s * 2 + 1]);
                        mma_f16(d[mi][nj][s], ah[mi], bl[nj][s * 2], bl[nj][s * 2 + 1]);
                        mma_f16(d[mi][nj][s], al[mi], bh[nj][s * 2], bh[nj][s * 2 + 1]);
                    }
        }
        __syncthreads();
    }
    const int grp = lane >> 2, tig = lane & 3;
#pragma unroll
    for (int mi = 0; mi < 2; mi++) {
        int r0 = wm * 32 + mi * 16 + grp, r1 = r0 + 8;
#pragma unroll
        for (int nj = 0; nj < 4; nj++)
#pragma unroll
            for (int s = 0; s < 2; s++) {
                int col = n0 + wn * 64 + nj * 16 + s * 8 + tig * 2;
                *(float2*)(g_RAG + (size_t)r0 * 32768 + col) =
                    make_float2(d[mi][nj][s][0], d[mi][nj][s][1]);
                *(float2*)(g_RAG + (size_t)r1 * 32768 + col) =
                    make_float2(d[mi][nj][s][2], d[mi][nj][s][3]);
            }
    }
}

// ----- kernel 7: reduce Z partials + softmax(dim=1) + final dot -----
__global__ __launch_bounds__(256) void k_attn2(const float* __restrict__ bfc,
                                               float* __restrict__ out) {
    __shared__ float Zs[32 * 33];
    __shared__ float As[32 * 33];
    __shared__ float Vs[32 * 33];
    __shared__ float wpart[8];
    int tid = threadIdx.x, b = blockIdx.x;
#pragma unroll
    for (int p = 0; p < 4; p++) {
        int idx = p * 256 + tid;
        int i = idx >> 5, j = idx & 31;
        float s = 0.f;
#pragma unroll
        for (int nb = 0; nb < 8; nb++)
            s += g_Zpart[((size_t)nb * 1024 + b) * 1024 + idx];
        Zs[i * 33 + j] = s;
        As[i * 33 + j] = g_RAG[(size_t)j * 32768 + b * 32 + i];
        Vs[i * 33 + j] = g_RAG[(size_t)(32 + i) * 32768 + b * 32 + j];
    }
    __syncthreads();
    int w = tid >> 5, lane = tid & 31;
    const float rscale = 0.022097086912079608f;  // 1/sqrt(2048)
    float local = 0.f;
#pragma unroll
    for (int q = 0; q < 4; q++) {
        int j = w * 4 + q;
        float lg = (Zs[lane * 33 + j] + As[lane * 33 + j] + g_c[lane * 32 + j]) * rscale;
        float mx = wredmax(lg);
        float ex = __expf(lg - mx);
        float sm = wredsum(ex);
        float contrib = (ex / sm) * (Vs[lane * 33 + j] + g_P[lane * 32 + j]);
        local += wredsum(contrib);
    }
    if (lane == 0) wpart[w] = local;
    __syncthreads();
    if (tid == 0) {
        float t = 0.f;
#pragma unroll
        for (int i = 0; i < 8; i++) t += wpart[i];
        out[b] = t + bfc[0];
    }
}

extern "C" void kernel_launch(void* const* d_in, const int* in_sizes, int n_in,
                              void* d_out, int out_size) {
    const float* x   = (const float*)d_in[0];
    const float* pe  = (const float*)d_in[1];
    const float* Wq  = (const float*)d_in[2];
    const float* bq  = (const float*)d_in[3];
    const float* Wk  = (const float*)d_in[4];
    const float* bk  = (const float*)d_in[5];
    const float* Wv  = (const float*)d_in[6];
    const float* bv  = (const float*)d_in[7];
    const float* Wfc = (const float*)d_in[8];
    const float* bfc = (const float*)d_in[9];
    float* out = (float*)d_out;

    cudaFuncSetAttribute(k_gemmM_mma, cudaFuncAttributeMaxDynamicSharedMemorySize, GSMEM);
    cudaFuncSetAttribute(k_yz, cudaFuncAttributeMaxDynamicSharedMemorySize, YSMEM);
    cudaFuncSetAttribute(k_rag, cudaFuncAttributeMaxDynamicSharedMemorySize, RSMEM);

    k_prep<<<37632, 256>>>(x, pe, Wq, bq, Wk, bk, Wv, bv);
    k_gemmM_mma<<<dim3(8, 8, 4), 256, GSMEM>>>();
    k_Mred<<<dim3(32, 32), dim3(32, 8)>>>();
    k_skinny<<<dim3(8, 32, 3), 128>>>(Wq, Wk, Wv, Wfc);
    k_skred<<<384, 256>>>();
    k_small<<<dim3(32, 2), 256>>>(Wfc);
    k_yz<<<dim3(8, 128), 512, YSMEM>>>();
    k_rag<<<128, 256, RSMEM>>>();
    k_attn2<<<1024, 256>>>(bfc, out);
}

// round 9
// speedup vs baseline: 3.6216x; 1.0261x over previous
#include <cuda_runtime.h>
#include <cuda_bf16.h>
#include <cuda_fp16.h>
#include <math.h>
#include <stdint.h>

// B=1024, S=32, D=1024, D2=2048
// out[b]: Cq/Ck/Cv = pe@W2^T+b ; MhT=(Wq1^T Wk1)^T (bf16 3-split mma, split-K=4) ;
// A=Ck@Wq1 ; Bm=Cq@Wk1 ; G=Wf@Wv1 (bf16 3-split mma, split-K=4) ; c,P small ;
// k_yz: Y=X@M+Bm (fp16 mma) fused with Z_b = Y'_b @ X_b^T partials (3-product);
// k_rag: [A;G]@Xall^T (3-product mma) ; k_attn2: reduce+softmax(dim=1)+dot.

// ----- static scratch -----
__device__ float g_Cq[65536], g_Ck[65536], g_Cv[65536];
__device__ float g_A[32768], g_Bm[32768], g_G[32768];
__device__ float g_part[393216];     // [3][4][32][1024] skinny split-K partials
__device__ float g_c[1024], g_P[1024];
__device__ float g_Zpart[8388608];   // gemmM split-K partials (4x1M), then Z partials
__device__ float g_RAG[2097152];     // [64][32768]
__device__ __align__(16) __half g_Xh[33554432];   // fp16 X [32768,1024]
__device__ __align__(16) __half g_Xl[33554432];   // fp16 residual
__device__ __align__(16) __half g_MhT[1048576];   // fp16 M^T [f][e]
__device__ __align__(16) __half g_AGh[65536];     // [64][1024] = [A;G] hi
__device__ __align__(16) __half g_AGl[65536];
__device__ __align__(16) __nv_bfloat16 g_WqTh[2097152];  // [e][d2]
__device__ __align__(16) __nv_bfloat16 g_WqTl[2097152];
__device__ __align__(16) __nv_bfloat16 g_WkTh[2097152];
__device__ __align__(16) __nv_bfloat16 g_WkTl[2097152];
__device__ __align__(16) __nv_bfloat16 g_WvTh[2097152];
__device__ __align__(16) __nv_bfloat16 g_WvTl[2097152];
__device__ __align__(16) __nv_bfloat16 g_CqH[65536], g_CqL[65536];  // [32,2048]
__device__ __align__(16) __nv_bfloat16 g_CkH[65536], g_CkL[65536];
__device__ __align__(16) __nv_bfloat16 g_WfH[65536], g_WfL[65536];

__device__ __forceinline__ float wredsum(float v) {
#pragma unroll
    for (int o = 16; o; o >>= 1) v += __shfl_xor_sync(0xffffffffu, v, o);
    return v;
}
__device__ __forceinline__ float wredmax(float v) {
#pragma unroll
    for (int o = 16; o; o >>= 1) v = fmaxf(v, __shfl_xor_sync(0xffffffffu, v, o));
    return v;
}
__device__ __forceinline__ uint32_t smem_u32(const void* p) {
    uint32_t a;
    asm("{ .reg .u64 t; cvta.to.shared.u64 t, %1; cvt.u32.u64 %0, t; }" : "=r"(a) : "l"(p));
    return a;
}
__device__ __forceinline__ void ldsm4(uint32_t* r, uint32_t addr) {
    asm volatile("ldmatrix.sync.aligned.m8n8.x4.shared.b16 {%0,%1,%2,%3}, [%4];"
                 : "=r"(r[0]), "=r"(r[1]), "=r"(r[2]), "=r"(r[3]) : "r"(addr));
}
__device__ __forceinline__ void mma_bf16(float* d, const uint32_t* a,
                                         uint32_t b0, uint32_t b1) {
    asm volatile(
        "mma.sync.aligned.m16n8k16.row.col.f32.bf16.bf16.f32 "
        "{%0,%1,%2,%3}, {%4,%5,%6,%7}, {%8,%9}, {%0,%1,%2,%3};"
        : "+f"(d[0]), "+f"(d[1]), "+f"(d[2]), "+f"(d[3])
        : "r"(a[0]), "r"(a[1]), "r"(a[2]), "r"(a[3]), "r"(b0), "r"(b1));
}
__device__ __forceinline__ void mma_f16(float* d, const uint32_t* a,
                                        uint32_t b0, uint32_t b1) {
    asm volatile(
        "mma.sync.aligned.m16n8k16.row.col.f32.f16.f16.f32 "
        "{%0,%1,%2,%3}, {%4,%5,%6,%7}, {%8,%9}, {%0,%1,%2,%3};"
        : "+f"(d[0]), "+f"(d[1]), "+f"(d[2]), "+f"(d[3])
        : "r"(a[0]), "r"(a[1]), "r"(a[2]), "r"(a[3]), "r"(b0), "r"(b1));
}
__device__ __forceinline__ void cpasync16(uint32_t saddr, const void* gaddr) {
    asm volatile("cp.async.cg.shared.global [%0], [%1], 16;" :: "r"(saddr), "l"(gaddr));
}
#define CP_COMMIT() asm volatile("cp.async.commit_group;" ::: "memory")
#define CP_WAIT(n)  asm volatile("cp.async.wait_group %0;" :: "n"(n) : "memory")

// ===== merged prep =====
// blk [0,768): Cq/Ck/Cv (+ bf16 hi/lo for Cq/Ck)
// blk [768, 6912): transpose+split Wq1/Wk1/Wv1 (2048 each)
// blk [6912, 6976): Wfc -> bf16 hi/lo
// blk [6976, 39744): X -> fp16 hi/lo
__global__ __launch_bounds__(256) void k_prep(const float* __restrict__ x,
                                              const float* __restrict__ pe,
                                              const float* __restrict__ Wq, const float* __restrict__ bq,
                                              const float* __restrict__ Wk, const float* __restrict__ bk,
                                              const float* __restrict__ Wv, const float* __restrict__ bv,
                                              const float* __restrict__ Wfc) {
    __shared__ float sh[32 * 33];
    int blk = blockIdx.x;
    int tid = threadIdx.x;
    if (blk < 768) {
        int bz = blk >> 8, bx = blk & 255;
        const float* W; const float* bias; float* out;
        if (bz == 0)      { W = Wq; bias = bq; out = g_Cq; }
        else if (bz == 1) { W = Wk; bias = bk; out = g_Ck; }
        else              { W = Wv; bias = bv; out = g_Cv; }
        int warp = tid >> 5, lane = tid & 31;
        int d2 = bx * 8 + warp;
        float acc[32];
#pragma unroll
        for (int i = 0; i < 32; i++) acc[i] = 0.f;
        for (int e0 = 0; e0 < 1024; e0 += 32) {
            __syncthreads();
#pragma unroll
            for (int p = 0; p < 4; p++) {
                int idx = p * 256 + tid;
                sh[(idx >> 5) * 33 + (idx & 31)] = pe[(idx >> 5) * 1024 + e0 + (idx & 31)];
            }
            __syncthreads();
            float wv = W[(size_t)d2 * 2048 + 1024 + e0 + lane];
#pragma unroll
            for (int i = 0; i < 32; i++) acc[i] += sh[i * 33 + lane] * wv;
        }
        float res = 0.f;
#pragma unroll
        for (int i = 0; i < 32; i++) {
            float r = wredsum(acc[i]);
            if (lane == i) res = r;
        }
        float val = res + bias[d2];
        out[lane * 2048 + d2] = val;
        if (bz < 2) {
            __nv_bfloat16 h = __float2bfloat16(val);
            __nv_bfloat16 l = __float2bfloat16(val - __bfloat162float(h));
            __nv_bfloat16* oh = bz ? g_CkH : g_CqH;
            __nv_bfloat16* ol = bz ? g_CkL : g_CqL;
            oh[lane * 2048 + d2] = h;
            ol[lane * 2048 + d2] = l;
        }
    } else if (blk < 6912) {
        int b2 = blk - 768;
        int bx = b2 & 31, by = (b2 >> 5) & 63, bz = b2 >> 11;
        const float* W = (bz == 0) ? Wq : (bz == 1) ? Wk : Wv;
        __nv_bfloat16* oh = (bz == 0) ? g_WqTh : (bz == 1) ? g_WkTh : g_WvTh;
        __nv_bfloat16* ol = (bz == 0) ? g_WqTl : (bz == 1) ? g_WkTl : g_WvTl;
        int xx = tid & 31, yy = tid >> 5;   // 32 x 8
#pragma unroll
        for (int i = 0; i < 32; i += 8)
            sh[(yy + i) * 33 + xx] = W[(size_t)(by * 32 + yy + i) * 2048 + bx * 32 + xx];
        __syncthreads();
#pragma unroll
        for (int i = 0; i < 32; i += 8) {
            float v = sh[xx * 33 + yy + i];
            __nv_bfloat16 h = __float2bfloat16(v);
            __nv_bfloat16 l = __float2bfloat16(v - __bfloat162float(h));
            size_t o = (size_t)(bx * 32 + yy + i) * 2048 + by * 32 + xx;
            oh[o] = h;
            ol[o] = l;
        }
    } else if (blk < 6976) {
        int idx4 = (blk - 6912) * 256 + tid;  // 0..16383
        float4 v = *(const float4*)(Wfc + (size_t)idx4 * 4);
        float vv[4] = {v.x, v.y, v.z, v.w};
#pragma unroll
        for (int q = 0; q < 4; q++) {
            __nv_bfloat16 h = __float2bfloat16(vv[q]);
            g_WfH[idx4 * 4 + q] = h;
            g_WfL[idx4 * 4 + q] = __float2bfloat16(vv[q] - __bfloat162float(h));
        }
    } else {
        size_t i = ((size_t)(blk - 6976) * 256 + tid) * 4;
        float4 v = *(const float4*)(x + i);
        __half h0 = __float2half_rn(v.x), h1 = __float2half_rn(v.y);
        __half h2 = __float2half_rn(v.z), h3 = __float2half_rn(v.w);
        *(__half2*)(g_Xh + i)     = __halves2half2(h0, h1);
        *(__half2*)(g_Xh + i + 2) = __halves2half2(h2, h3);
        *(__half2*)(g_Xl + i)     = __halves2half2(__float2half_rn(v.x - __half2float(h0)),
                                                   __float2half_rn(v.y - __half2float(h1)));
        *(__half2*)(g_Xl + i + 2) = __halves2half2(__float2half_rn(v.z - __half2float(h2)),
                                                   __float2half_rn(v.w - __half2float(h3)));
    }
}

// ----- kernel 2: M partials = Wq1^T @ Wk1, bf16 3-product mma, split-K=4 -----
#define GPAD 72
#define GBUF (128 * GPAD * 2)
#define GSTAGE (4 * GBUF)        // 73728
#define GSMEM (3 * GSTAGE)       // 221184

__device__ __forceinline__ void g_stage(uint32_t sb, int s, int m0, int n0,
                                        int k0, int tid) {
    uint32_t sa = sb + s * GSTAGE;
#pragma unroll
    for (int p = 0; p < 16; p++) {
        int idx = p * 256 + tid;
        int buf = idx >> 10;
        int t = idx & 1023;
        int row = t >> 3, c = t & 7;
        const __nv_bfloat16* src =
            (buf == 0) ? g_WqTh : (buf == 1) ? g_WqTl : (buf == 2) ? g_WkTh : g_WkTl;
        int r0 = (buf < 2) ? m0 : n0;
        cpasync16(sa + buf * GBUF + (uint32_t)(row * GPAD + c * 8) * 2,
                  src + (size_t)(r0 + row) * 2048 + k0 + c * 8);
    }
}

__global__ __launch_bounds__(256, 1) void k_gemmM_mma() {
    extern __shared__ __align__(16) char gsmem[];
    const uint32_t sb = smem_u32(gsmem);
    const int tid = threadIdx.x, lane = tid & 31, wid = tid >> 5;
    const int wm = wid >> 2, wn = wid & 3;
    const int m0 = blockIdx.y * 128, n0 = blockIdx.x * 128;
    const int kbase = blockIdx.z * 512;

    g_stage(sb, 0, m0, n0, kbase, tid);
    CP_COMMIT();
    g_stage(sb, 1, m0, n0, kbase + 64, tid);
    CP_COMMIT();

    float d[4][4][4] = {};
    const int aRow = wm * 64 + (lane & 15);
    const int aCol = (lane >> 4) * 8;
    const int bRow = wn * 32 + (lane & 7) + (lane >> 4) * 8;
    const int bCol = ((lane >> 3) & 1) * 8;

    for (int it = 0; it < 8; it++) {
        if (it < 7) CP_WAIT(1); else CP_WAIT(0);
        __syncthreads();
        if (it + 2 < 8) {
            g_stage(sb, (it + 2) % 3, m0, n0, kbase + (it + 2) * 64, tid);
            CP_COMMIT();
        }
        uint32_t st = sb + (it % 3) * GSTAGE;
#pragma unroll
        for (int ks = 0; ks < 4; ks++) {
            int kc = ks * 16;
            uint32_t arh[4][4], arl[4][4];
#pragma unroll
            for (int i = 0; i < 4; i++) {
                uint32_t ao = (uint32_t)((aRow + i * 16) * GPAD + kc + aCol) * 2;
                ldsm4(arh[i], st + ao);
                ldsm4(arl[i], st + GBUF + ao);
            }
            uint32_t brh[2][4], brl[2][4];
#pragma unroll
            for (int j = 0; j < 2; j++) {
                uint32_t bo = (uint32_t)((bRow + j * 16) * GPAD + kc + bCol) * 2;
                ldsm4(brh[j], st + 2 * GBUF + bo);
                ldsm4(brl[j], st + 3 * GBUF + bo);
            }
#pragma unroll
            for (int i = 0; i < 4; i++)
#pragma unroll
                for (int j = 0; j < 4; j++) {
                    uint32_t h0 = brh[j >> 1][(j & 1) * 2], h1 = brh[j >> 1][(j & 1) * 2 + 1];
                    uint32_t l0 = brl[j >> 1][(j & 1) * 2], l1 = brl[j >> 1][(j & 1) * 2 + 1];
                    mma_bf16(d[i][j], arh[i], h0, h1);
                    mma_bf16(d[i][j], arh[i], l0, l1);
                    mma_bf16(d[i][j], arl[i], h0, h1);
                }
        }
    }
    float* outp = g_Zpart + (size_t)blockIdx.z * 1048576;
    const int grp = lane >> 2, tig = lane & 3;
    const int mb = m0 + wm * 64, nb = n0 + wn * 32;
#pragma unroll
    for (int i = 0; i < 4; i++) {
        int r0 = mb + i * 16 + grp, r1 = r0 + 8;
#pragma unroll
        for (int j = 0; j < 4; j++) {
            int cc = nb + j * 8 + tig * 2;
            *(float2*)(outp + (size_t)r0 * 1024 + cc) = make_float2(d[i][j][0], d[i][j][1]);
            *(float2*)(outp + (size_t)r1 * 1024 + cc) = make_float2(d[i][j][2], d[i][j][3]);
        }
    }
}

// ----- k_Mred: sum 4 split-K partials + transpose + fp16 -> g_MhT -----
__global__ void k_Mred() {
    __shared__ float t[32][33];
    int bx = blockIdx.x, by = blockIdx.y;
    int x = threadIdx.x, y = threadIdx.y;   // 32 x 8
#pragma unroll
    for (int i = 0; i < 32; i += 8) {
        size_t o = (size_t)(by * 32 + y + i) * 1024 + bx * 32 + x;
        t[y + i][x] = g_Zpart[o] + g_Zpart[1048576 + o] +
                      g_Zpart[2097152 + o] + g_Zpart[3145728 + o];
    }
    __syncthreads();
#pragma unroll
    for (int i = 0; i < 32; i += 8)
        g_MhT[(size_t)(bx * 32 + y + i) * 1024 + by * 32 + x] = __float2half_rn(t[x][y + i]);
}

// ----- kernel 3: skinny gemms via bf16 3-product mma, split-K=4 -----
// M=32, N=1024, K=2048. grid (8 n-tiles x 128, 4 k-split, 3). 128 threads.
#define SK_AB (32 * 72 * 2)                 // 4608 per A buf
#define SK_BB (128 * 72 * 2)                // 18432 per B buf
#define SKSTAGE (2 * SK_AB + 2 * SK_BB)     // 46080
#define SKSMEM (2 * SKSTAGE)                // 92160

__device__ __forceinline__ void sk_stage(uint32_t sb, int s,
                                         const __nv_bfloat16* __restrict__ Ah,
                                         const __nv_bfloat16* __restrict__ Al,
                                         const __nv_bfloat16* __restrict__ Bh,
                                         const __nv_bfloat16* __restrict__ Bl,
                                         int n0, int k0, int tid) {
    uint32_t sa = sb + s * SKSTAGE;
#pragma unroll
    for (int p = 0; p < 4; p++) {
        int idx = p * 128 + tid;           // 0..511
        int bufl = idx >> 8;
        int t = idx & 255;                 // 32 rows x 8 chunks
        int row = t >> 3, ch = t & 7;
        const __nv_bfloat16* src = bufl ? Al : Ah;
        cpasync16(sa + bufl * SK_AB + (uint32_t)(row * 72 + ch * 8) * 2,
                  src + (size_t)row * 2048 + k0 + ch * 8);
    }
#pragma unroll
    for (int p = 0; p < 16; p++) {
        int idx = p * 128 + tid;           // 0..2047
        int bufl = idx >> 10;
        int t = idx & 1023;                // 128 rows x 8 chunks
        int row = t >> 3, ch = t & 7;
        const __nv_bfloat16* src = bufl ? Bl : Bh;
        cpasync16(sa + 2 * SK_AB + bufl * SK_BB + (uint32_t)(row * 72 + ch * 8) * 2,
                  src + (size_t)(n0 + row) * 2048 + k0 + ch * 8);
    }
}

__global__ __launch_bounds__(128, 1) void k_skinny_mma() {
    extern __shared__ __align__(16) char sksmem[];
    const uint32_t sb = smem_u32(sksmem);
    const int tid = threadIdx.x, lane = tid & 31, wn = tid >> 5;  // 4 warps
    const int z = blockIdx.z;
    const int n0 = blockIdx.x * 128;
    const int kbase = blockIdx.y * 512;

    const __nv_bfloat16* Ah = (z == 0) ? g_CkH : (z == 1) ? g_CqH : g_WfH;
    const __nv_bfloat16* Al = (z == 0) ? g_CkL : (z == 1) ? g_CqL : g_WfL;
    const __nv_bfloat16* Bh = (z == 0) ? g_WqTh : (z == 1) ? g_WkTh : g_WvTh;
    const __nv_bfloat16* Bl = (z == 0) ? g_WqTl : (z == 1) ? g_WkTl : g_WvTl;

    sk_stage(sb, 0, Ah, Al, Bh, Bl, n0, kbase, tid);
    CP_COMMIT();

    float d[2][2][2][4] = {};
    const int aRow = lane & 15;
    const int aCol = (lane >> 4) * 8;
    const int bRow = wn * 32 + (lane & 7) + (lane >> 4) * 8;
    const int bCol = ((lane >> 3) & 1) * 8;

    for (int it = 0; it < 8; it++) {
        int nit = it + 1;
        if (nit < 8) {
            sk_stage(sb, nit & 1, Ah, Al, Bh, Bl, n0, kbase + nit * 64, tid);
            CP_COMMIT();
            CP_WAIT(1);
        } else {
            CP_WAIT(0);
        }
        __syncthreads();
        uint32_t st = sb + (it & 1) * SKSTAGE;
        uint32_t sB = st + 2 * SK_AB;
#pragma unroll
        for (int ks = 0; ks < 4; ks++) {
            int kc = ks * 16;
            uint32_t ah[2][4], al[2][4];
#pragma unroll
            for (int mi = 0; mi < 2; mi++) {
                uint32_t ao = (uint32_t)((mi * 16 + aRow) * 72 + kc + aCol) * 2;
                ldsm4(ah[mi], st + ao);
                ldsm4(al[mi], st + SK_AB + ao);
            }
            uint32_t bh[2][4], bl[2][4];
#pragma unroll
            for (int nj = 0; nj < 2; nj++) {
                uint32_t bo = (uint32_t)((bRow + nj * 16) * 72 + kc + bCol) * 2;
                ldsm4(bh[nj], sB + bo);
                ldsm4(bl[nj], sB + SK_BB + bo);
            }
#pragma unroll
            for (int mi = 0; mi < 2; mi++)
#pragma unroll
                for (int nj = 0; nj < 2; nj++)
#pragma unroll
                    for (int s = 0; s < 2; s++) {
                        mma_bf16(d[mi][nj][s], ah[mi], bh[nj][s * 2], bh[nj][s * 2 + 1]);
                        mma_bf16(d[mi][nj][s], ah[mi], bl[nj][s * 2], bl[nj][s * 2 + 1]);
                        mma_bf16(d[mi][nj][s], al[mi], bh[nj][s * 2], bh[nj][s * 2 + 1]);
                    }
        }
        __syncthreads();
    }
    // write partials [3][4][32][1024]
    float* outp = g_part + ((size_t)z * 4 + blockIdx.y) * 32768;
    const int grp = lane >> 2, tig = lane & 3;
#pragma unroll
    for (int mi = 0; mi < 2; mi++) {
        int r0 = mi * 16 + grp, r1 = r0 + 8;
#pragma unroll
        for (int nj = 0; nj < 2; nj++)
#pragma unroll
            for (int s = 0; s < 2; s++) {
                int col = n0 + wn * 32 + nj * 16 + s * 8 + tig * 2;
                *(float2*)(outp + r0 * 1024 + col) = make_float2(d[mi][nj][s][0], d[mi][nj][s][1]);
                *(float2*)(outp + r1 * 1024 + col) = make_float2(d[mi][nj][s][2], d[mi][nj][s][3]);
            }
    }
}

// ----- k_skred: reduce 4 skinny partials; also emit AG fp16 hi/lo -----
__global__ void k_skred() {
    int idx = blockIdx.x * 256 + threadIdx.x;   // 98304
    int z = idx >> 15;
    int r = idx & 32767;
    float s = 0.f;
#pragma unroll
    for (int kc = 0; kc < 4; kc++) s += g_part[((size_t)z * 4 + kc) * 32768 + r];
    float* out = (z == 0) ? g_A : (z == 1) ? g_Bm : g_G;
    out[r] = s;
    if (z != 1) {
        int agrow = (z == 0) ? (r >> 10) : 32 + (r >> 10);
        int col = r & 1023;
        __half h = __float2half_rn(s);
        g_AGh[agrow * 1024 + col] = h;
        g_AGl[agrow * 1024 + col] = __float2half_rn(s - __half2float(h));
    }
}

// ----- kernel 4: c = Cq@Ck^T, P = Wf@Cv^T -----
__global__ void k_small(const float* __restrict__ Wfc) {
    int i = blockIdx.x;
    const float* L; const float* R; float* out;
    if (blockIdx.y == 0) { L = g_Cq; R = g_Ck; out = g_c; }
    else                 { L = Wfc;  R = g_Cv; out = g_P; }
    int tid = threadIdx.x, warp = tid >> 5, lane = tid & 31;
    float acc[4] = {0.f, 0.f, 0.f, 0.f};
    for (int d = lane; d < 2048; d += 32) {
        float lv = L[i * 2048 + d];
#pragma unroll
        for (int q = 0; q < 4; q++) acc[q] += lv * R[(warp * 4 + q) * 2048 + d];
    }
#pragma unroll
    for (int q = 0; q < 4; q++) {
        float r = wredsum(acc[q]);
        if (lane == 0) out[i * 32 + warp * 4 + q] = r;
    }
}

// ====== kernel 5: fused Y=X@M+Bm + Z partials, 3-stage pipeline ======
#define YPAD 72
#define YA_BYTES (256 * YPAD * 2)          // 36864
#define YB_BYTES (128 * YPAD * 2)          // 18432
#define YSTAGE (YA_BYTES + YB_BYTES)       // 55296
#define ZBUF (256 * 72 * 2)                // 36864
#define YSMEM (3 * YSTAGE)                 // 165888 (>= 4*ZBUF epilogue use)

__device__ __forceinline__ void y_stage(uint32_t sb, int s, int m0, int n0,
                                        int k0, int tid) {
    uint32_t sa = sb + s * YSTAGE;
#pragma unroll
    for (int p = 0; p < 6; p++) {
        int idx = p * 512 + tid;
        if (idx < 2048) {
            int row = idx >> 3, c = idx & 7;
            cpasync16(sa + (uint32_t)(row * YPAD + c * 8) * 2,
                      g_Xh + (size_t)(m0 + row) * 1024 + k0 + c * 8);
        } else {
            int t = idx - 2048;
            int row = t >> 3, c = t & 7;
            cpasync16(sa + YA_BYTES + (uint32_t)(row * YPAD + c * 8) * 2,
                      g_MhT + (size_t)(n0 + row) * 1024 + k0 + c * 8);
        }
    }
}

__global__ __launch_bounds__(512, 1) void k_yz() {
    extern __shared__ __align__(16) char ysmem[];
    const uint32_t sb = smem_u32(ysmem);
    const int tid = threadIdx.x, lane = tid & 31, wid = tid >> 5;
    const int wm = wid >> 2, wn = wid & 3;
    const int m0 = blockIdx.y * 256, n0 = blockIdx.x * 128;

    y_stage(sb, 0, m0, n0, 0, tid);
    CP_COMMIT();
    y_stage(sb, 1, m0, n0, 64, tid);
    CP_COMMIT();

    float d[4][4][4] = {};
    const int aRow = wm * 64 + (lane & 15);
    const int aCol = (lane >> 4) * 8;
    const int bRow = wn * 32 + (lane & 7) + (lane >> 4) * 8;
    const int bCol = ((lane >> 3) & 1) * 8;

    for (int it = 0; it < 16; it++) {
        if (it < 15) CP_WAIT(1); else CP_WAIT(0);
        __syncthreads();
        if (it + 2 < 16) {
            y_stage(sb, (it + 2) % 3, m0, n0, (it + 2) * 64, tid);
            CP_COMMIT();
        }
        uint32_t abase = sb + (it % 3) * YSTAGE;
        uint32_t bbase = abase + YA_BYTES;
#pragma unroll
        for (int ks = 0; ks < 4; ks++) {
            int kc = ks * 16;
            uint32_t ar[4][4];
#pragma unroll
            for (int i = 0; i < 4; i++)
                ldsm4(ar[i], abase + (uint32_t)((aRow + i * 16) * YPAD + kc + aCol) * 2);
            uint32_t br[2][4];
#pragma unroll
            for (int j = 0; j < 2; j++)
                ldsm4(br[j], bbase + (uint32_t)((bRow + j * 16) * YPAD + kc + bCol) * 2);
#pragma unroll
            for (int i = 0; i < 4; i++)
#pragma unroll
                for (int j = 0; j < 4; j++)
                    mma_f16(d[i][j], ar[i], br[j >> 1][(j & 1) * 2],
                            br[j >> 1][(j & 1) * 2 + 1]);
        }
    }
    __syncthreads();

    // ---- epilogue: add Bm, then fused Z partials ----
    const int grp = lane >> 2, tig = lane & 3;
    const int nbl = wn * 32;
#pragma unroll
    for (int i = 0; i < 4; i++) {
        int r0 = wm * 64 + i * 16 + grp;
        int p0 = r0 & 31, p1 = (r0 + 8) & 31;
#pragma unroll
        for (int j = 0; j < 4; j++) {
            int cc = n0 + nbl + j * 8 + tig * 2;
            float2 b0 = *(const float2*)(g_Bm + p0 * 1024 + cc);
            float2 b1 = *(const float2*)(g_Bm + p1 * 1024 + cc);
            d[i][j][0] += b0.x; d[i][j][1] += b0.y;
            d[i][j][2] += b1.x; d[i][j][3] += b1.y;
        }
    }

    const int bb = wid >> 1;
    const int nh = wid & 1;
    const uint32_t ZYH = sb, ZYL = sb + ZBUF, ZXH = sb + 2 * ZBUF, ZXL = sb + 3 * ZBUF;
    float z[2][2][4] = {};

#pragma unroll 1
    for (int h = 0; h < 2; h++) {
        __syncthreads();
#pragma unroll
        for (int p = 0; p < 8; p++) {
            int idx = p * 512 + tid;
            int bufl = idx >> 11;
            int t = idx & 2047;
            int row = t >> 3, ch = t & 7;
            const __half* src = bufl ? g_Xl : g_Xh;
            uint32_t dst = (bufl ? ZXL : ZXH) + (uint32_t)(row * 72 + ch * 8) * 2;
            cpasync16(dst, src + (size_t)(m0 + row) * 1024 + n0 + h * 64 + ch * 8);
        }
        CP_COMMIT();
        if ((wn >> 1) == h) {
#pragma unroll
            for (int i = 0; i < 4; i++) {
                int r0 = wm * 64 + i * 16 + grp;
#pragma unroll
                for (int j = 0; j < 4; j++) {
                    int cl = (nbl - h * 64) + j * 8 + tig * 2;
                    float v0 = d[i][j][0], v1 = d[i][j][1];
                    float v2 = d[i][j][2], v3 = d[i][j][3];
                    __half h0 = __float2half_rn(v0), h1 = __float2half_rn(v1);
                    __half h2 = __float2half_rn(v2), h3 = __float2half_rn(v3);
                    *(__half2*)(ysmem + ((r0) * 72 + cl) * 2) = __halves2half2(h0, h1);
                    *(__half2*)(ysmem + ((r0 + 8) * 72 + cl) * 2) = __halves2half2(h2, h3);
                    *(__half2*)(ysmem + ZBUF + ((r0) * 72 + cl) * 2) =
                        __halves2half2(__float2half_rn(v0 - __half2float(h0)),
                                       __float2half_rn(v1 - __half2float(h1)));
                    *(__half2*)(ysmem + ZBUF + ((r0 + 8) * 72 + cl) * 2) =
                        __halves2half2(__float2half_rn(v2 - __half2float(h2)),
                                       __float2half_rn(v3 - __half2float(h3)));
                }
            }
        }
        CP_WAIT(0);
        __syncthreads();
#pragma unroll
        for (int ks = 0; ks < 4; ks++) {
            int kc = ks * 16;
            uint32_t ayh[2][4], ayl[2][4];
#pragma unroll
            for (int mi = 0; mi < 2; mi++) {
                uint32_t ao = (uint32_t)((bb * 32 + mi * 16 + (lane & 15)) * 72 +
                                         kc + (lane >> 4) * 8) * 2;
                ldsm4(ayh[mi], ZYH + ao);
                ldsm4(ayl[mi], ZYL + ao);
            }
            uint32_t bxh[4], bxl[4];
            uint32_t bo = (uint32_t)((bb * 32 + nh * 16 + (lane & 7) + (lane >> 4) * 8) * 72 +
                                     kc + ((lane >> 3) & 1) * 8) * 2;
            ldsm4(bxh, ZXH + bo);
            ldsm4(bxl, ZXL + bo);
#pragma unroll
            for (int mi = 0; mi < 2; mi++)
#pragma unroll
                for (int nj = 0; nj < 2; nj++) {
                    mma_f16(z[mi][nj], ayh[mi], bxh[nj * 2], bxh[nj * 2 + 1]);
                    mma_f16(z[mi][nj], ayh[mi], bxl[nj * 2], bxl[nj * 2 + 1]);
                    mma_f16(z[mi][nj], ayl[mi], bxh[nj * 2], bxh[nj * 2 + 1]);
                }
        }
    }
    {
        int b = blockIdx.y * 8 + bb;
        size_t base = ((size_t)blockIdx.x * 1024 + b) * 1024;
#pragma unroll
        for (int mi = 0; mi < 2; mi++) {
            int i0 = mi * 16 + grp;
#pragma unroll
            for (int nj = 0; nj < 2; nj++) {
                int j0 = nh * 16 + nj * 8 + tig * 2;
                *(float2*)(g_Zpart + base + i0 * 32 + j0) =
                    make_float2(z[mi][nj][0], z[mi][nj][1]);
                *(float2*)(g_Zpart + base + (i0 + 8) * 32 + j0) =
                    make_float2(z[mi][nj][2], z[mi][nj][3]);
            }
        }
    }
}

// ====== kernel 6: RAG = [A;G] @ Xall^T ======
#define RPAD 72
#define R_A_BYTES (64 * RPAD * 2)
#define R_B_BYTES (256 * RPAD * 2)
#define RSTAGE (2 * R_A_BYTES + 2 * R_B_BYTES)
#define RSMEM (2 * RSTAGE)

__device__ __forceinline__ void r_stage(uint32_t sb, int s, int n0, int k0, int tid) {
    uint32_t sa = sb + s * RSTAGE;
#pragma unroll
    for (int p = 0; p < 4; p++) {
        int idx = p * 256 + tid;
        int bufl = idx >> 9;
        int t = idx & 511;
        int row = t >> 3, ch = t & 7;
        const __half* src = bufl ? g_AGl : g_AGh;
        cpasync16(sa + bufl * R_A_BYTES + (uint32_t)(row * RPAD + ch * 8) * 2,
                  src + (size_t)row * 1024 + k0 + ch * 8);
    }
#pragma unroll
    for (int p = 0; p < 16; p++) {
        int idx = p * 256 + tid;
        int bufl = idx >> 11;
        int t = idx & 2047;
        int row = t >> 3, ch = t & 7;
        const __half* src = bufl ? g_Xl : g_Xh;
        cpasync16(sa + 2 * R_A_BYTES + bufl * R_B_BYTES + (uint32_t)(row * RPAD + ch * 8) * 2,
                  src + (size_t)(n0 + row) * 1024 + k0 + ch * 8);
    }
}

__global__ __launch_bounds__(256, 1) void k_rag() {
    extern __shared__ __align__(16) char rsmem[];
    const uint32_t sb = smem_u32(rsmem);
    const int tid = threadIdx.x, lane = tid & 31, wid = tid >> 5;
    const int wm = wid >> 2, wn = wid & 3;
    const int n0 = blockIdx.x * 256;

    r_stage(sb, 0, n0, 0, tid);
    CP_COMMIT();

    float d[2][4][2][4] = {};
    const int aRowB = wm * 32 + (lane & 15);
    const int aCol = (lane >> 4) * 8;
    const int bRowB = wn * 64 + (lane & 7) + (lane >> 4) * 8;
    const int bCol = ((lane >> 3) & 1) * 8;

    for (int it = 0; it < 16; it++) {
        int nit = it + 1;
        if (nit < 16) {
            r_stage(sb, nit & 1, n0, nit * 64, tid);
            CP_COMMIT();
            CP_WAIT(1);
        } else {
            CP_WAIT(0);
        }
        __syncthreads();
        uint32_t st = sb + (it & 1) * RSTAGE;
        uint32_t sB = st + 2 * R_A_BYTES;
#pragma unroll
        for (int ks = 0; ks < 4; ks++) {
            int kc = ks * 16;
            uint32_t ah[2][4], al[2][4];
#pragma unroll
            for (int mi = 0; mi < 2; mi++) {
                uint32_t ao = (uint32_t)((aRowB + mi * 16) * RPAD + kc + aCol) * 2;
                ldsm4(ah[mi], st + ao);
                ldsm4(al[mi], st + R_A_BYTES + ao);
            }
            uint32_t bh[4][4], bl[4][4];
#pragma unroll
            for (int nj = 0; nj < 4; nj++) {
                uint32_t bo = (uint32_t)((bRowB + nj * 16) * RPAD + kc + bCol) * 2;
                ldsm4(bh[nj], sB + bo);
                ldsm4(bl[nj], sB + R_B_BYTES + bo);
            }
#pragma unroll
            for (int mi = 0; mi < 2; mi++)
#pragma unroll
                for (int nj = 0; nj < 4; nj++)
#pragma unroll
                    for (int s = 0; s < 2; s++) {
                        mma_f16(d[mi][nj][s], ah[mi], bh[nj][s * 2], bh[nj][s * 2 + 1]);
                        mma_f16(d[mi][nj][s], ah[mi], bl[nj][s * 2], bl[nj][s * 2 + 1]);
                        mma_f16(d[mi][nj][s], al[mi], bh[nj][s * 2], bh[nj][s * 2 + 1]);
                    }
        }
        __syncthreads();
    }
    const int grp = lane >> 2, tig = lane & 3;
#pragma unroll
    for (int mi = 0; mi < 2; mi++) {
        int r0 = wm * 32 + mi * 16 + grp, r1 = r0 + 8;
#pragma unroll
        for (int nj = 0; nj < 4; nj++)
#pragma unroll
            for (int s = 0; s < 2; s++) {
                int col = n0 + wn * 64 + nj * 16 + s * 8 + tig * 2;
                *(float2*)(g_RAG + (size_t)r0 * 32768 + col) =
                    make_float2(d[mi][nj][s][0], d[mi][nj][s][1]);
                *(float2*)(g_RAG + (size_t)r1 * 32768 + col) =
                    make_float2(d[mi][nj][s][2], d[mi][nj][s][3]);
            }
    }
}

// ----- kernel 7: reduce Z partials + softmax(dim=1) + final dot -----
__global__ __launch_bounds__(256) void k_attn2(const float* __restrict__ bfc,
                                               float* __restrict__ out) {
    __shared__ float Zs[32 * 33];
    __shared__ float As[32 * 33];
    __shared__ float Vs[32 * 33];
    __shared__ float wpart[8];
    int tid = threadIdx.x, b = blockIdx.x;
#pragma unroll
    for (int p = 0; p < 4; p++) {
        int idx = p * 256 + tid;
        int i = idx >> 5, j = idx & 31;
        float s = 0.f;
#pragma unroll
        for (int nb = 0; nb < 8; nb++)
            s += g_Zpart[((size_t)nb * 1024 + b) * 1024 + idx];
        Zs[i * 33 + j] = s;
        As[i * 33 + j] = g_RAG[(size_t)j * 32768 + b * 32 + i];
        Vs[i * 33 + j] = g_RAG[(size_t)(32 + i) * 32768 + b * 32 + j];
    }
    __syncthreads();
    int w = tid >> 5, lane = tid & 31;
    const float rscale = 0.022097086912079608f;  // 1/sqrt(2048)
    float local = 0.f;
#pragma unroll
    for (int q = 0; q < 4; q++) {
        int j = w * 4 + q;
        float lg = (Zs[lane * 33 + j] + As[lane * 33 + j] + g_c[lane * 32 + j]) * rscale;
        float mx = wredmax(lg);
        float ex = __expf(lg - mx);
        float sm = wredsum(ex);
        float contrib = (ex / sm) * (Vs[lane * 33 + j] + g_P[lane * 32 + j]);
        local += wredsum(contrib);
    }
    if (lane == 0) wpart[w] = local;
    __syncthreads();
    if (tid == 0) {
        float t = 0.f;
#pragma unroll
        for (int i = 0; i < 8; i++) t += wpart[i];
        out[b] = t + bfc[0];
    }
}

extern "C" void kernel_launch(void* const* d_in, const int* in_sizes, int n_in,
                              void* d_out, int out_size) {
    const float* x   = (const float*)d_in[0];
    const float* pe  = (const float*)d_in[1];
    const float* Wq  = (const float*)d_in[2];
    const float* bq  = (const float*)d_in[3];
    const float* Wk  = (const float*)d_in[4];
    const float* bk  = (const float*)d_in[5];
    const float* Wv  = (const float*)d_in[6];
    const float* bv  = (const float*)d_in[7];
    const float* Wfc = (const float*)d_in[8];
    const float* bfc = (const float*)d_in[9];
    float* out = (float*)d_out;

    cudaFuncSetAttribute(k_gemmM_mma, cudaFuncAttributeMaxDynamicSharedMemorySize, GSMEM);
    cudaFuncSetAttribute(k_skinny_mma, cudaFuncAttributeMaxDynamicSharedMemorySize, SKSMEM);
    cudaFuncSetAttribute(k_yz, cudaFuncAttributeMaxDynamicSharedMemorySize, YSMEM);
    cudaFuncSetAttribute(k_rag, cudaFuncAttributeMaxDynamicSharedMemorySize, RSMEM);

    k_prep<<<39744, 256>>>(x, pe, Wq, bq, Wk, bk, Wv, bv, Wfc);
    k_gemmM_mma<<<dim3(8, 8, 4), 256, GSMEM>>>();
    k_Mred<<<dim3(32, 32), dim3(32, 8)>>>();
    k_skinny_mma<<<dim3(8, 4, 3), 128, SKSMEM>>>();
    k_skred<<<384, 256>>>();
    k_small<<<dim3(32, 2), 256>>>(Wfc);
    k_yz<<<dim3(8, 128), 512, YSMEM>>>();
    k_rag<<<128, 256, RSMEM>>>();
    k_attn2<<<1024, 256>>>(bfc, out);
}

// round 10
// speedup vs baseline: 3.6625x; 1.0113x over previous
#include <cuda_runtime.h>
#include <cuda_bf16.h>
#include <cuda_fp16.h>
#include <math.h>
#include <stdint.h>

// B=1024, S=32, D=1024, D2=2048
// out[b]: Cq/Ck/Cv = pe@W2^T+b ; MhT=(Wq1^T Wk1)^T (bf16 3-split mma, split-K=4) ;
// A=Ck@Wq1 ; Bm=Cq@Wk1 ; G=Wf@Wv1 (bf16 3-split mma, split-K=4) ; c,P small ;
// k_yz: Y=X@M+Bm (fp16 mma, tile 128x256) fused with Z partials (3-product, k/n-split);
// k_rag: [A;G]@Xall^T (3-product mma) ; k_attn2: reduce+softmax(dim=1)+dot.

// ----- static scratch -----
__device__ float g_Cq[65536], g_Ck[65536], g_Cv[65536];
__device__ float g_A[32768], g_Bm[32768], g_G[32768];
__device__ float g_part[393216];     // [3][4][32][1024] skinny split-K partials
__device__ float g_c[1024], g_P[1024];
__device__ float g_Zpart[8388608];   // gemmM split-K partials (4x1M), then Z partials [8][1024][32][32]
__device__ float g_RAG[2097152];     // [64][32768]
__device__ __align__(16) __half g_Xh[33554432];   // fp16 X [32768,1024]
__device__ __align__(16) __half g_Xl[33554432];   // fp16 residual
__device__ __align__(16) __half g_MhT[1048576];   // fp16 M^T [f][e]
__device__ __align__(16) __half g_AGh[65536];     // [64][1024] = [A;G] hi
__device__ __align__(16) __half g_AGl[65536];
__device__ __align__(16) __nv_bfloat16 g_WqTh[2097152];  // [e][d2]
__device__ __align__(16) __nv_bfloat16 g_WqTl[2097152];
__device__ __align__(16) __nv_bfloat16 g_WkTh[2097152];
__device__ __align__(16) __nv_bfloat16 g_WkTl[2097152];
__device__ __align__(16) __nv_bfloat16 g_WvTh[2097152];
__device__ __align__(16) __nv_bfloat16 g_WvTl[2097152];
__device__ __align__(16) __nv_bfloat16 g_CqH[65536], g_CqL[65536];  // [32,2048]
__device__ __align__(16) __nv_bfloat16 g_CkH[65536], g_CkL[65536];
__device__ __align__(16) __nv_bfloat16 g_WfH[65536], g_WfL[65536];

__device__ __forceinline__ float wredsum(float v) {
#pragma unroll
    for (int o = 16; o; o >>= 1) v += __shfl_xor_sync(0xffffffffu, v, o);
    return v;
}
__device__ __forceinline__ float wredmax(float v) {
#pragma unroll
    for (int o = 16; o; o >>= 1) v = fmaxf(v, __shfl_xor_sync(0xffffffffu, v, o));
    return v;
}
__device__ __forceinline__ uint32_t smem_u32(const void* p) {
    uint32_t a;
    asm("{ .reg .u64 t; cvta.to.shared.u64 t, %1; cvt.u32.u64 %0, t; }" : "=r"(a) : "l"(p));
    return a;
}
__device__ __forceinline__ void ldsm4(uint32_t* r, uint32_t addr) {
    asm volatile("ldmatrix.sync.aligned.m8n8.x4.shared.b16 {%0,%1,%2,%3}, [%4];"
                 : "=r"(r[0]), "=r"(r[1]), "=r"(r[2]), "=r"(r[3]) : "r"(addr));
}
__device__ __forceinline__ void mma_bf16(float* d, const uint32_t* a,
                                         uint32_t b0, uint32_t b1) {
    asm volatile(
        "mma.sync.aligned.m16n8k16.row.col.f32.bf16.bf16.f32 "
        "{%0,%1,%2,%3}, {%4,%5,%6,%7}, {%8,%9}, {%0,%1,%2,%3};"
        : "+f"(d[0]), "+f"(d[1]), "+f"(d[2]), "+f"(d[3])
        : "r"(a[0]), "r"(a[1]), "r"(a[2]), "r"(a[3]), "r"(b0), "r"(b1));
}
__device__ __forceinline__ void mma_f16(float* d, const uint32_t* a,
                                        uint32_t b0, uint32_t b1) {
    asm volatile(
        "mma.sync.aligned.m16n8k16.row.col.f32.f16.f16.f32 "
        "{%0,%1,%2,%3}, {%4,%5,%6,%7}, {%8,%9}, {%0,%1,%2,%3};"
        : "+f"(d[0]), "+f"(d[1]), "+f"(d[2]), "+f"(d[3])
        : "r"(a[0]), "r"(a[1]), "r"(a[2]), "r"(a[3]), "r"(b0), "r"(b1));
}
__device__ __forceinline__ void cpasync16(uint32_t saddr, const void* gaddr) {
    asm volatile("cp.async.cg.shared.global [%0], [%1], 16;" :: "r"(saddr), "l"(gaddr));
}
#define CP_COMMIT() asm volatile("cp.async.commit_group;" ::: "memory")
#define CP_WAIT(n)  asm volatile("cp.async.wait_group %0;" :: "n"(n) : "memory")

// ===== merged prep =====
__global__ __launch_bounds__(256) void k_prep(const float* __restrict__ x,
                                              const float* __restrict__ pe,
                                              const float* __restrict__ Wq, const float* __restrict__ bq,
                                              const float* __restrict__ Wk, const float* __restrict__ bk,
                                              const float* __restrict__ Wv, const float* __restrict__ bv,
                                              const float* __restrict__ Wfc) {
    __shared__ float sh[32 * 33];
    int blk = blockIdx.x;
    int tid = threadIdx.x;
    if (blk < 768) {
        int bz = blk >> 8, bx = blk & 255;
        const float* W; const float* bias; float* out;
        if (bz == 0)      { W = Wq; bias = bq; out = g_Cq; }
        else if (bz == 1) { W = Wk; bias = bk; out = g_Ck; }
        else              { W = Wv; bias = bv; out = g_Cv; }
        int warp = tid >> 5, lane = tid & 31;
        int d2 = bx * 8 + warp;
        float acc[32];
#pragma unroll
        for (int i = 0; i < 32; i++) acc[i] = 0.f;
        for (int e0 = 0; e0 < 1024; e0 += 32) {
            __syncthreads();
#pragma unroll
            for (int p = 0; p < 4; p++) {
                int idx = p * 256 + tid;
                sh[(idx >> 5) * 33 + (idx & 31)] = pe[(idx >> 5) * 1024 + e0 + (idx & 31)];
            }
            __syncthreads();
            float wv = W[(size_t)d2 * 2048 + 1024 + e0 + lane];
#pragma unroll
            for (int i = 0; i < 32; i++) acc[i] += sh[i * 33 + lane] * wv;
        }
        float res = 0.f;
#pragma unroll
        for (int i = 0; i < 32; i++) {
            float r = wredsum(acc[i]);
            if (lane == i) res = r;
        }
        float val = res + bias[d2];
        out[lane * 2048 + d2] = val;
        if (bz < 2) {
            __nv_bfloat16 h = __float2bfloat16(val);
            __nv_bfloat16 l = __float2bfloat16(val - __bfloat162float(h));
            __nv_bfloat16* oh = bz ? g_CkH : g_CqH;
            __nv_bfloat16* ol = bz ? g_CkL : g_CqL;
            oh[lane * 2048 + d2] = h;
            ol[lane * 2048 + d2] = l;
        }
    } else if (blk < 6912) {
        int b2 = blk - 768;
        int bx = b2 & 31, by = (b2 >> 5) & 63, bz = b2 >> 11;
        const float* W = (bz == 0) ? Wq : (bz == 1) ? Wk : Wv;
        __nv_bfloat16* oh = (bz == 0) ? g_WqTh : (bz == 1) ? g_WkTh : g_WvTh;
        __nv_bfloat16* ol = (bz == 0) ? g_WqTl : (bz == 1) ? g_WkTl : g_WvTl;
        int xx = tid & 31, yy = tid >> 5;   // 32 x 8
#pragma unroll
        for (int i = 0; i < 32; i += 8)
            sh[(yy + i) * 33 + xx] = W[(size_t)(by * 32 + yy + i) * 2048 + bx * 32 + xx];
        __syncthreads();
#pragma unroll
        for (int i = 0; i < 32; i += 8) {
            float v = sh[xx * 33 + yy + i];
            __nv_bfloat16 h = __float2bfloat16(v);
            __nv_bfloat16 l = __float2bfloat16(v - __bfloat162float(h));
            size_t o = (size_t)(bx * 32 + yy + i) * 2048 + by * 32 + xx;
            oh[o] = h;
            ol[o] = l;
        }
    } else if (blk < 6976) {
        int idx4 = (blk - 6912) * 256 + tid;
        float4 v = *(const float4*)(Wfc + (size_t)idx4 * 4);
        float vv[4] = {v.x, v.y, v.z, v.w};
#pragma unroll
        for (int q = 0; q < 4; q++) {
            __nv_bfloat16 h = __float2bfloat16(vv[q]);
            g_WfH[idx4 * 4 + q] = h;
            g_WfL[idx4 * 4 + q] = __float2bfloat16(vv[q] - __bfloat162float(h));
        }
    } else {
        size_t i = ((size_t)(blk - 6976) * 256 + tid) * 4;
        float4 v = *(const float4*)(x + i);
        __half h0 = __float2half_rn(v.x), h1 = __float2half_rn(v.y);
        __half h2 = __float2half_rn(v.z), h3 = __float2half_rn(v.w);
        *(__half2*)(g_Xh + i)     = __halves2half2(h0, h1);
        *(__half2*)(g_Xh + i + 2) = __halves2half2(h2, h3);
        *(__half2*)(g_Xl + i)     = __halves2half2(__float2half_rn(v.x - __half2float(h0)),
                                                   __float2half_rn(v.y - __half2float(h1)));
        *(__half2*)(g_Xl + i + 2) = __halves2half2(__float2half_rn(v.z - __half2float(h2)),
                                                   __float2half_rn(v.w - __half2float(h3)));
    }
}

// ----- kernel 2: M partials = Wq1^T @ Wk1, bf16 3-product mma, split-K=4 -----
#define GPAD 72
#define GBUF (128 * GPAD * 2)
#define GSTAGE (4 * GBUF)        // 73728
#define GSMEM (3 * GSTAGE)       // 221184

__device__ __forceinline__ void g_stage(uint32_t sb, int s, int m0, int n0,
                                        int k0, int tid) {
    uint32_t sa = sb + s * GSTAGE;
#pragma unroll
    for (int p = 0; p < 16; p++) {
        int idx = p * 256 + tid;
        int buf = idx >> 10;
        int t = idx & 1023;
        int row = t >> 3, c = t & 7;
        const __nv_bfloat16* src =
            (buf == 0) ? g_WqTh : (buf == 1) ? g_WqTl : (buf == 2) ? g_WkTh : g_WkTl;
        int r0 = (buf < 2) ? m0 : n0;
        cpasync16(sa + buf * GBUF + (uint32_t)(row * GPAD + c * 8) * 2,
                  src + (size_t)(r0 + row) * 2048 + k0 + c * 8);
    }
}

__global__ __launch_bounds__(256, 1) void k_gemmM_mma() {
    extern __shared__ __align__(16) char gsmem[];
    const uint32_t sb = smem_u32(gsmem);
    const int tid = threadIdx.x, lane = tid & 31, wid = tid >> 5;
    const int wm = wid >> 2, wn = wid & 3;
    const int m0 = blockIdx.y * 128, n0 = blockIdx.x * 128;
    const int kbase = blockIdx.z * 512;

    g_stage(sb, 0, m0, n0, kbase, tid);
    CP_COMMIT();
    g_stage(sb, 1, m0, n0, kbase + 64, tid);
    CP_COMMIT();

    float d[4][4][4] = {};
    const int aRow = wm * 64 + (lane & 15);
    const int aCol = (lane >> 4) * 8;
    const int bRow = wn * 32 + (lane & 7) + (lane >> 4) * 8;
    const int bCol = ((lane >> 3) & 1) * 8;

    for (int it = 0; it < 8; it++) {
        if (it < 7) CP_WAIT(1); else CP_WAIT(0);
        __syncthreads();
        if (it + 2 < 8) {
            g_stage(sb, (it + 2) % 3, m0, n0, kbase + (it + 2) * 64, tid);
            CP_COMMIT();
        }
        uint32_t st = sb + (it % 3) * GSTAGE;
#pragma unroll
        for (int ks = 0; ks < 4; ks++) {
            int kc = ks * 16;
            uint32_t arh[4][4], arl[4][4];
#pragma unroll
            for (int i = 0; i < 4; i++) {
                uint32_t ao = (uint32_t)((aRow + i * 16) * GPAD + kc + aCol) * 2;
                ldsm4(arh[i], st + ao);
                ldsm4(arl[i], st + GBUF + ao);
            }
            uint32_t brh[2][4], brl[2][4];
#pragma unroll
            for (int j = 0; j < 2; j++) {
                uint32_t bo = (uint32_t)((bRow + j * 16) * GPAD + kc + bCol) * 2;
                ldsm4(brh[j], st + 2 * GBUF + bo);
                ldsm4(brl[j], st + 3 * GBUF + bo);
            }
#pragma unroll
            for (int i = 0; i < 4; i++)
#pragma unroll
                for (int j = 0; j < 4; j++) {
                    uint32_t h0 = brh[j >> 1][(j & 1) * 2], h1 = brh[j >> 1][(j & 1) * 2 + 1];
                    uint32_t l0 = brl[j >> 1][(j & 1) * 2], l1 = brl[j >> 1][(j & 1) * 2 + 1];
                    mma_bf16(d[i][j], arh[i], h0, h1);
                    mma_bf16(d[i][j], arh[i], l0, l1);
                    mma_bf16(d[i][j], arl[i], h0, h1);
                }
        }
    }
    float* outp = g_Zpart + (size_t)blockIdx.z * 1048576;
    const int grp = lane >> 2, tig = lane & 3;
    const int mb = m0 + wm * 64, nb = n0 + wn * 32;
#pragma unroll
    for (int i = 0; i < 4; i++) {
        int r0 = mb + i * 16 + grp, r1 = r0 + 8;
#pragma unroll
        for (int j = 0; j < 4; j++) {
            int cc = nb + j * 8 + tig * 2;
            *(float2*)(outp + (size_t)r0 * 1024 + cc) = make_float2(d[i][j][0], d[i][j][1]);
            *(float2*)(outp + (size_t)r1 * 1024 + cc) = make_float2(d[i][j][2], d[i][j][3]);
        }
    }
}

// ----- k_Mred -----
__global__ void k_Mred() {
    __shared__ float t[32][33];
    int bx = blockIdx.x, by = blockIdx.y;
    int x = threadIdx.x, y = threadIdx.y;
#pragma unroll
    for (int i = 0; i < 32; i += 8) {
        size_t o = (size_t)(by * 32 + y + i) * 1024 + bx * 32 + x;
        t[y + i][x] = g_Zpart[o] + g_Zpart[1048576 + o] +
                      g_Zpart[2097152 + o] + g_Zpart[3145728 + o];
    }
    __syncthreads();
#pragma unroll
    for (int i = 0; i < 32; i += 8)
        g_MhT[(size_t)(bx * 32 + y + i) * 1024 + by * 32 + x] = __float2half_rn(t[x][y + i]);
}

// ----- kernel 3: skinny gemms via bf16 3-product mma, split-K=4 -----
#define SK_AB (32 * 72 * 2)
#define SK_BB (128 * 72 * 2)
#define SKSTAGE (2 * SK_AB + 2 * SK_BB)
#define SKSMEM (2 * SKSTAGE)

__device__ __forceinline__ void sk_stage(uint32_t sb, int s,
                                         const __nv_bfloat16* __restrict__ Ah,
                                         const __nv_bfloat16* __restrict__ Al,
                                         const __nv_bfloat16* __restrict__ Bh,
                                         const __nv_bfloat16* __restrict__ Bl,
                                         int n0, int k0, int tid) {
    uint32_t sa = sb + s * SKSTAGE;
#pragma unroll
    for (int p = 0; p < 4; p++) {
        int idx = p * 128 + tid;
        int bufl = idx >> 8;
        int t = idx & 255;
        int row = t >> 3, ch = t & 7;
        const __nv_bfloat16* src = bufl ? Al : Ah;
        cpasync16(sa + bufl * SK_AB + (uint32_t)(row * 72 + ch * 8) * 2,
                  src + (size_t)row * 2048 + k0 + ch * 8);
    }
#pragma unroll
    for (int p = 0; p < 16; p++) {
        int idx = p * 128 + tid;
        int bufl = idx >> 10;
        int t = idx & 1023;
        int row = t >> 3, ch = t & 7;
        const __nv_bfloat16* src = bufl ? Bl : Bh;
        cpasync16(sa + 2 * SK_AB + bufl * SK_BB + (uint32_t)(row * 72 + ch * 8) * 2,
                  src + (size_t)(n0 + row) * 2048 + k0 + ch * 8);
    }
}

__global__ __launch_bounds__(128, 1) void k_skinny_mma() {
    extern __shared__ __align__(16) char sksmem[];
    const uint32_t sb = smem_u32(sksmem);
    const int tid = threadIdx.x, lane = tid & 31, wn = tid >> 5;
    const int z = blockIdx.z;
    const int n0 = blockIdx.x * 128;
    const int kbase = blockIdx.y * 512;

    const __nv_bfloat16* Ah = (z == 0) ? g_CkH : (z == 1) ? g_CqH : g_WfH;
    const __nv_bfloat16* Al = (z == 0) ? g_CkL : (z == 1) ? g_CqL : g_WfL;
    const __nv_bfloat16* Bh = (z == 0) ? g_WqTh : (z == 1) ? g_WkTh : g_WvTh;
    const __nv_bfloat16* Bl = (z == 0) ? g_WqTl : (z == 1) ? g_WkTl : g_WvTl;

    sk_stage(sb, 0, Ah, Al, Bh, Bl, n0, kbase, tid);
    CP_COMMIT();

    float d[2][2][2][4] = {};
    const int aRow = lane & 15;
    const int aCol = (lane >> 4) * 8;
    const int bRow = wn * 32 + (lane & 7) + (lane >> 4) * 8;
    const int bCol = ((lane >> 3) & 1) * 8;

    for (int it = 0; it < 8; it++) {
        int nit = it + 1;
        if (nit < 8) {
            sk_stage(sb, nit & 1, Ah, Al, Bh, Bl, n0, kbase + nit * 64, tid);
            CP_COMMIT();
            CP_WAIT(1);
        } else {
            CP_WAIT(0);
        }
        __syncthreads();
        uint32_t st = sb + (it & 1) * SKSTAGE;
        uint32_t sB = st + 2 * SK_AB;
#pragma unroll
        for (int ks = 0; ks < 4; ks++) {
            int kc = ks * 16;
            uint32_t ah[2][4], al[2][4];
#pragma unroll
            for (int mi = 0; mi < 2; mi++) {
                uint32_t ao = (uint32_t)((mi * 16 + aRow) * 72 + kc + aCol) * 2;
                ldsm4(ah[mi], st + ao);
                ldsm4(al[mi], st + SK_AB + ao);
            }
            uint32_t bh[2][4], bl[2][4];
#pragma unroll
            for (int nj = 0; nj < 2; nj++) {
                uint32_t bo = (uint32_t)((bRow + nj * 16) * 72 + kc + bCol) * 2;
                ldsm4(bh[nj], sB + bo);
                ldsm4(bl[nj], sB + SK_BB + bo);
            }
#pragma unroll
            for (int mi = 0; mi < 2; mi++)
#pragma unroll
                for (int nj = 0; nj < 2; nj++)
#pragma unroll
                    for (int s = 0; s < 2; s++) {
                        mma_bf16(d[mi][nj][s], ah[mi], bh[nj][s * 2], bh[nj][s * 2 + 1]);
                        mma_bf16(d[mi][nj][s], ah[mi], bl[nj][s * 2], bl[nj][s * 2 + 1]);
                        mma_bf16(d[mi][nj][s], al[mi], bh[nj][s * 2], bh[nj][s * 2 + 1]);
                    }
        }
        __syncthreads();
    }
    float* outp = g_part + ((size_t)z * 4 + blockIdx.y) * 32768;
    const int grp = lane >> 2, tig = lane & 3;
#pragma unroll
    for (int mi = 0; mi < 2; mi++) {
        int r0 = mi * 16 + grp, r1 = r0 + 8;
#pragma unroll
        for (int nj = 0; nj < 2; nj++)
#pragma unroll
            for (int s = 0; s < 2; s++) {
                int col = n0 + wn * 32 + nj * 16 + s * 8 + tig * 2;
                *(float2*)(outp + r0 * 1024 + col) = make_float2(d[mi][nj][s][0], d[mi][nj][s][1]);
                *(float2*)(outp + r1 * 1024 + col) = make_float2(d[mi][nj][s][2], d[mi][nj][s][3]);
            }
    }
}

// ----- k_skred -----
__global__ void k_skred() {
    int idx = blockIdx.x * 256 + threadIdx.x;
    int z = idx >> 15;
    int r = idx & 32767;
    float s = 0.f;
#pragma unroll
    for (int kc = 0; kc < 4; kc++) s += g_part[((size_t)z * 4 + kc) * 32768 + r];
    float* out = (z == 0) ? g_A : (z == 1) ? g_Bm : g_G;
    out[r] = s;
    if (z != 1) {
        int agrow = (z == 0) ? (r >> 10) : 32 + (r >> 10);
        int col = r & 1023;
        __half h = __float2half_rn(s);
        g_AGh[agrow * 1024 + col] = h;
        g_AGl[agrow * 1024 + col] = __float2half_rn(s - __half2float(h));
    }
}

// ----- kernel 4: c = Cq@Ck^T, P = Wf@Cv^T -----
__global__ void k_small(const float* __restrict__ Wfc) {
    int i = blockIdx.x;
    const float* L; const float* R; float* out;
    if (blockIdx.y == 0) { L = g_Cq; R = g_Ck; out = g_c; }
    else                 { L = Wfc;  R = g_Cv; out = g_P; }
    int tid = threadIdx.x, warp = tid >> 5, lane = tid & 31;
    float acc[4] = {0.f, 0.f, 0.f, 0.f};
    for (int d = lane; d < 2048; d += 32) {
        float lv = L[i * 2048 + d];
#pragma unroll
        for (int q = 0; q < 4; q++) acc[q] += lv * R[(warp * 4 + q) * 2048 + d];
    }
#pragma unroll
    for (int q = 0; q < 4; q++) {
        float r = wredsum(acc[q]);
        if (lane == 0) out[i * 32 + warp * 4 + q] = r;
    }
}

// ====== kernel 5: fused Y=X@M+Bm (tile 128x256) + Z partials ======
#define YPAD 72
#define YA_BYTES (128 * YPAD * 2)          // 18432
#define YB_BYTES (256 * YPAD * 2)          // 36864
#define YSTAGE (YA_BYTES + YB_BYTES)       // 55296
#define ZBUF (128 * 136 * 2)               // 34816
#define YSMEM (3 * YSTAGE)                 // 165888 (>= 4*ZBUF)

__device__ __forceinline__ void y_stage(uint32_t sb, int s, int m0, int n0,
                                        int k0, int tid) {
    uint32_t sa = sb + s * YSTAGE;
#pragma unroll
    for (int p = 0; p < 6; p++) {
        int idx = p * 512 + tid;   // 0..3071
        if (idx < 1024) {          // A: 128 rows x 8 chunks
            int row = idx >> 3, c = idx & 7;
            cpasync16(sa + (uint32_t)(row * YPAD + c * 8) * 2,
                      g_Xh + (size_t)(m0 + row) * 1024 + k0 + c * 8);
        } else {                   // B: 256 rows x 8 chunks
            int t = idx - 1024;
            int row = t >> 3, c = t & 7;
            cpasync16(sa + YA_BYTES + (uint32_t)(row * YPAD + c * 8) * 2,
                      g_MhT + (size_t)(n0 + row) * 1024 + k0 + c * 8);
        }
    }
}

__global__ __launch_bounds__(512, 1) void k_yz() {
    extern __shared__ __align__(16) char ysmem[];
    const uint32_t sb = smem_u32(ysmem);
    const int tid = threadIdx.x, lane = tid & 31, wid = tid >> 5;
    const int wm = wid >> 3, wn = wid & 7;       // 2 x 8 warps
    const int m0 = blockIdx.y * 128, n0 = blockIdx.x * 256;

    y_stage(sb, 0, m0, n0, 0, tid);
    CP_COMMIT();
    y_stage(sb, 1, m0, n0, 64, tid);
    CP_COMMIT();

    float d[4][4][4] = {};
    const int aRow = wm * 64 + (lane & 15);
    const int aCol = (lane >> 4) * 8;
    const int bRow = wn * 32 + (lane & 7) + (lane >> 4) * 8;
    const int bCol = ((lane >> 3) & 1) * 8;

    for (int it = 0; it < 16; it++) {
        if (it < 15) CP_WAIT(1); else CP_WAIT(0);
        __syncthreads();
        if (it + 2 < 16) {
            y_stage(sb, (it + 2) % 3, m0, n0, (it + 2) * 64, tid);
            CP_COMMIT();
        }
        uint32_t abase = sb + (it % 3) * YSTAGE;
        uint32_t bbase = abase + YA_BYTES;
#pragma unroll
        for (int ks = 0; ks < 4; ks++) {
            int kc = ks * 16;
            uint32_t ar[4][4];
#pragma unroll
            for (int i = 0; i < 4; i++)
                ldsm4(ar[i], abase + (uint32_t)((aRow + i * 16) * YPAD + kc + aCol) * 2);
            uint32_t br[2][4];
#pragma unroll
            for (int j = 0; j < 2; j++)
                ldsm4(br[j], bbase + (uint32_t)((bRow + j * 16) * YPAD + kc + bCol) * 2);
#pragma unroll
            for (int i = 0; i < 4; i++)
#pragma unroll
                for (int j = 0; j < 4; j++)
                    mma_f16(d[i][j], ar[i], br[j >> 1][(j & 1) * 2],
                            br[j >> 1][(j & 1) * 2 + 1]);
        }
    }
    __syncthreads();

    // ---- epilogue: add Bm, then fused Z partials ----
    const int grp = lane >> 2, tig = lane & 3;
#pragma unroll
    for (int i = 0; i < 4; i++) {
        int r0 = wm * 64 + i * 16 + grp;         // local row 0..127
        int p0 = r0 & 31, p1 = (r0 + 8) & 31;    // m0 is a multiple of 128
#pragma unroll
        for (int j = 0; j < 4; j++) {
            int cc = n0 + wn * 32 + j * 8 + tig * 2;
            float2 b0 = *(const float2*)(g_Bm + p0 * 1024 + cc);
            float2 b1 = *(const float2*)(g_Bm + p1 * 1024 + cc);
            d[i][j][0] += b0.x; d[i][j][1] += b0.y;
            d[i][j][2] += b1.x; d[i][j][3] += b1.y;
        }
    }

    const int bb = wid >> 2;       // local batch 0..3
    const int kq = (wid >> 1) & 1; // k-half of each f-half
    const int nh = wid & 1;        // n-half of Z columns (16 each)
    const uint32_t ZYH = sb, ZYL = sb + ZBUF, ZXH = sb + 2 * ZBUF, ZXL = sb + 3 * ZBUF;
    float z[2][2][4] = {};

#pragma unroll 1
    for (int h = 0; h < 2; h++) {
        __syncthreads();
        // load X hi/lo tiles [128 x 128] for f-cols n0+h*128..
#pragma unroll
        for (int p = 0; p < 8; p++) {
            int idx = p * 512 + tid;       // 0..4095
            int bufl = idx >> 11;
            int t = idx & 2047;            // 128 rows x 16 chunks
            int row = t >> 4, ch = t & 15;
            const __half* src = bufl ? g_Xl : g_Xh;
            uint32_t dst = (bufl ? ZXL : ZXH) + (uint32_t)(row * 136 + ch * 8) * 2;
            cpasync16(dst, src + (size_t)(m0 + row) * 1024 + n0 + h * 128 + ch * 8);
        }
        CP_COMMIT();
        // write Y' hi/lo for this f-half (warps whose n-range lies in half h)
        if ((wn >> 2) == h) {
#pragma unroll
            for (int i = 0; i < 4; i++) {
                int r0 = wm * 64 + i * 16 + grp;
#pragma unroll
                for (int j = 0; j < 4; j++) {
                    int cl = (wn & 3) * 32 + j * 8 + tig * 2;   // 0..127
                    float v0 = d[i][j][0], v1 = d[i][j][1];
                    float v2 = d[i][j][2], v3 = d[i][j][3];
                    __half h0 = __float2half_rn(v0), h1 = __float2half_rn(v1);
                    __half h2 = __float2half_rn(v2), h3 = __float2half_rn(v3);
                    *(__half2*)(ysmem + ((r0) * 136 + cl) * 2) = __halves2half2(h0, h1);
                    *(__half2*)(ysmem + ((r0 + 8) * 136 + cl) * 2) = __halves2half2(h2, h3);
                    *(__half2*)(ysmem + ZBUF + ((r0) * 136 + cl) * 2) =
                        __halves2half2(__float2half_rn(v0 - __half2float(h0)),
                                       __float2half_rn(v1 - __half2float(h1)));
                    *(__half2*)(ysmem + ZBUF + ((r0 + 8) * 136 + cl) * 2) =
                        __halves2half2(__float2half_rn(v2 - __half2float(h2)),
                                       __float2half_rn(v3 - __half2float(h3)));
                }
            }
        }
        CP_WAIT(0);
        __syncthreads();
        // Z mma: batch bb, n-half nh (16 cols), k-quarter kq (64 of this 128-half)
#pragma unroll
        for (int ksl = 0; ksl < 4; ksl++) {
            int kc = (kq * 4 + ksl) * 16;
            uint32_t ayh[2][4], ayl[2][4];
#pragma unroll
            for (int mi = 0; mi < 2; mi++) {
                uint32_t ao = (uint32_t)((bb * 32 + mi * 16 + (lane & 15)) * 136 +
                                         kc + (lane >> 4) * 8) * 2;
                ldsm4(ayh[mi], ZYH + ao);
                ldsm4(ayl[mi], ZYL + ao);
            }
            uint32_t bxh[4], bxl[4];
            uint32_t bo = (uint32_t)((bb * 32 + nh * 16 + (lane & 7) + (lane >> 4) * 8) * 136 +
                                     kc + ((lane >> 3) & 1) * 8) * 2;
            ldsm4(bxh, ZXH + bo);
            ldsm4(bxl, ZXL + bo);
#pragma unroll
            for (int mi = 0; mi < 2; mi++)
#pragma unroll
                for (int no = 0; no < 2; no++) {
                    mma_f16(z[mi][no], ayh[mi], bxh[no * 2], bxh[no * 2 + 1]);
                    mma_f16(z[mi][no], ayh[mi], bxl[no * 2], bxl[no * 2 + 1]);
                    mma_f16(z[mi][no], ayl[mi], bxh[no * 2], bxh[no * 2 + 1]);
                }
        }
    }
    // store Z partials: slot = blockIdx.x*2 + kq (8 slots total)
    {
        int b = blockIdx.y * 4 + bb;
        size_t base = ((size_t)(blockIdx.x * 2 + kq) * 1024 + b) * 1024;
#pragma unroll
        for (int mi = 0; mi < 2; mi++) {
            int i0 = mi * 16 + grp;
#pragma unroll
            for (int no = 0; no < 2; no++) {
                int j0 = nh * 16 + no * 8 + tig * 2;
                *(float2*)(g_Zpart + base + i0 * 32 + j0) =
                    make_float2(z[mi][no][0], z[mi][no][1]);
                *(float2*)(g_Zpart + base + (i0 + 8) * 32 + j0) =
                    make_float2(z[mi][no][2], z[mi][no][3]);
            }
        }
    }
}

// ====== kernel 6: RAG = [A;G] @ Xall^T ======
#define RPAD 72
#define R_A_BYTES (64 * RPAD * 2)
#define R_B_BYTES (256 * RPAD * 2)
#define RSTAGE (2 * R_A_BYTES + 2 * R_B_BYTES)
#define RSMEM (2 * RSTAGE)

__device__ __forceinline__ void r_stage(uint32_t sb, int s, int n0, int k0, int tid) {
    uint32_t sa = sb + s * RSTAGE;
#pragma unroll
    for (int p = 0; p < 4; p++) {
        int idx = p * 256 + tid;
        int bufl = idx >> 9;
        int t = idx & 511;
        int row = t >> 3, ch = t & 7;
        const __half* src = bufl ? g_AGl : g_AGh;
        cpasync16(sa + bufl * R_A_BYTES + (uint32_t)(row * RPAD + ch * 8) * 2,
                  src + (size_t)row * 1024 + k0 + ch * 8);
    }
#pragma unroll
    for (int p = 0; p < 16; p++) {
        int idx = p * 256 + tid;
        int bufl = idx >> 11;
        int t = idx & 2047;
        int row = t >> 3, ch = t & 7;
        const __half* src = bufl ? g_Xl : g_Xh;
        cpasync16(sa + 2 * R_A_BYTES + bufl * R_B_BYTES + (uint32_t)(row * RPAD + ch * 8) * 2,
                  src + (size_t)(n0 + row) * 1024 + k0 + ch * 8);
    }
}

__global__ __launch_bounds__(256, 1) void k_rag() {
    extern __shared__ __align__(16) char rsmem[];
    const uint32_t sb = smem_u32(rsmem);
    const int tid = threadIdx.x, lane = tid & 31, wid = tid >> 5;
    const int wm = wid >> 2, wn = wid & 3;
    const int n0 = blockIdx.x * 256;

    r_stage(sb, 0, n0, 0, tid);
    CP_COMMIT();

    float d[2][4][2][4] = {};
    const int aRowB = wm * 32 + (lane & 15);
    const int aCol = (lane >> 4) * 8;
    const int bRowB = wn * 64 + (lane & 7) + (lane >> 4) * 8;
    const int bCol = ((lane >> 3) & 1) * 8;

    for (int it = 0; it < 16; it++) {
        int nit = it + 1;
        if (nit < 16) {
            r_stage(sb, nit & 1, n0, nit * 64, tid);
            CP_COMMIT();
            CP_WAIT(1);
        } else {
            CP_WAIT(0);
        }
        __syncthreads();
        uint32_t st = sb + (it & 1) * RSTAGE;
        uint32_t sB = st + 2 * R_A_BYTES;
#pragma unroll
        for (int ks = 0; ks < 4; ks++) {
            int kc = ks * 16;
            uint32_t ah[2][4], al[2][4];
#pragma unroll
            for (int mi = 0; mi < 2; mi++) {
                uint32_t ao = (uint32_t)((aRowB + mi * 16) * RPAD + kc + aCol) * 2;
                ldsm4(ah[mi], st + ao);
                ldsm4(al[mi], st + R_A_BYTES + ao);
            }
            uint32_t bh[4][4], bl[4][4];
#pragma unroll
            for (int nj = 0; nj < 4; nj++) {
                uint32_t bo = (uint32_t)((bRowB + nj * 16) * RPAD + kc + bCol) * 2;
                ldsm4(bh[nj], sB + bo);
                ldsm4(bl[nj], sB + R_B_BYTES + bo);
            }
#pragma unroll
            for (int mi = 0; mi < 2; mi++)
#pragma unroll
                for (int nj = 0; nj < 4; nj++)
#pragma unroll
                    for (int s = 0; s < 2; s++) {
                        mma_f16(d[mi][nj][s], ah[mi], bh[nj][s * 2], bh[nj][s * 2 + 1]);
                        mma_f16(d[mi][nj][s], ah[mi], bl[nj][s * 2], bl[nj][s * 2 + 1]);
                        mma_f16(d[mi][nj][s], al[mi], bh[nj][s * 2], bh[nj][s * 2 + 1]);
                    }
        }
        __syncthreads();
    }
    const int grp = lane >> 2, tig = lane & 3;
#pragma unroll
    for (int mi = 0; mi < 2; mi++) {
        int r0 = wm * 32 + mi * 16 + grp, r1 = r0 + 8;
#pragma unroll
        for (int nj = 0; nj < 4; nj++)
#pragma unroll
            for (int s = 0; s < 2; s++) {
                int col = n0 + wn * 64 + nj * 16 + s * 8 + tig * 2;
                *(float2*)(g_RAG + (size_t)r0 * 32768 + col) =
                    make_float2(d[mi][nj][s][0], d[mi][nj][s][1]);
                *(float2*)(g_RAG + (size_t)r1 * 32768 + col) =
                    make_float2(d[mi][nj][s][2], d[mi][nj][s][3]);
            }
    }
}

// ----- kernel 7: reduce Z partials + softmax(dim=1) + final dot -----
__global__ __launch_bounds__(256) void k_attn2(const float* __restrict__ bfc,
                                               float* __restrict__ out) {
    __shared__ float Zs[32 * 33];
    __shared__ float As[32 * 33];
    __shared__ float Vs[32 * 33];
    __shared__ float wpart[8];
    int tid = threadIdx.x, b = blockIdx.x;
#pragma unroll
    for (int p = 0; p < 4; p++) {
        int idx = p * 256 + tid;
        int i = idx >> 5, j = idx & 31;
        float s = 0.f;
#pragma unroll
        for (int nb = 0; nb < 8; nb++)
            s += g_Zpart[((size_t)nb * 1024 + b) * 1024 + idx];
        Zs[i * 33 + j] = s;
        As[i * 33 + j] = g_RAG[(size_t)j * 32768 + b * 32 + i];
        Vs[i * 33 + j] = g_RAG[(size_t)(32 + i) * 32768 + b * 32 + j];
    }
    __syncthreads();
    int w = tid >> 5, lane = tid & 31;
    const float rscale = 0.022097086912079608f;  // 1/sqrt(2048)
    float local = 0.f;
#pragma unroll
    for (int q = 0; q < 4; q++) {
        int j = w * 4 + q;
        float lg = (Zs[lane * 33 + j] + As[lane * 33 + j] + g_c[lane * 32 + j]) * rscale;
        float mx = wredmax(lg);
        float ex = __expf(lg - mx);
        float sm = wredsum(ex);
        float contrib = (ex / sm) * (Vs[lane * 33 + j] + g_P[lane * 32 + j]);
        local += wredsum(contrib);
    }
    if (lane == 0) wpart[w] = local;
    __syncthreads();
    if (tid == 0) {
        float t = 0.f;
#pragma unroll
        for (int i = 0; i < 8; i++) t += wpart[i];
        out[b] = t + bfc[0];
    }
}

extern "C" void kernel_launch(void* const* d_in, const int* in_sizes, int n_in,
                              void* d_out, int out_size) {
    const float* x   = (const float*)d_in[0];
    const float* pe  = (const float*)d_in[1];
    const float* Wq  = (const float*)d_in[2];
    const float* bq  = (const float*)d_in[3];
    const float* Wk  = (const float*)d_in[4];
    const float* bk  = (const float*)d_in[5];
    const float* Wv  = (const float*)d_in[6];
    const float* bv  = (const float*)d_in[7];
    const float* Wfc = (const float*)d_in[8];
    const float* bfc = (const float*)d_in[9];
    float* out = (float*)d_out;

    cudaFuncSetAttribute(k_gemmM_mma, cudaFuncAttributeMaxDynamicSharedMemorySize, GSMEM);
    cudaFuncSetAttribute(k_skinny_mma, cudaFuncAttributeMaxDynamicSharedMemorySize, SKSMEM);
    cudaFuncSetAttribute(k_yz, cudaFuncAttributeMaxDynamicSharedMemorySize, YSMEM);
    cudaFuncSetAttribute(k_rag, cudaFuncAttributeMaxDynamicSharedMemorySize, RSMEM);

    k_prep<<<39744, 256>>>(x, pe, Wq, bq, Wk, bk, Wv, bv, Wfc);
    k_gemmM_mma<<<dim3(8, 8, 4), 256, GSMEM>>>();
    k_Mred<<<dim3(32, 32), dim3(32, 8)>>>();
    k_skinny_mma<<<dim3(8, 4, 3), 128, SKSMEM>>>();
    k_skred<<<384, 256>>>();
    k_small<<<dim3(32, 2), 256>>>(Wfc);
    k_yz<<<dim3(4, 256), 512, YSMEM>>>();
    k_rag<<<128, 256, RSMEM>>>();
    k_attn2<<<1024, 256>>>(bfc, out);
}

// round 11
// speedup vs baseline: 3.8728x; 1.0574x over previous
#include <cuda_runtime.h>
#include <cuda_bf16.h>
#include <cuda_fp16.h>
#include <math.h>
#include <stdint.h>

// B=1024, S=32, D=1024, D2=2048
// out[b]: Cq/Ck/Cv = pe@W2^T+b ; MhT=(Wq1^T Wk1)^T (bf16 3-split mma, split-K=4) ;
// A=Ck@Wq1 ; Bm=Cq@Wk1 ; G=Wf@Wv1 (bf16 3-split mma, split-K=4) ; c,P small ;
// k_yz: Y=X@M+Bm (fp16 mma, 128x256, K=128/stage, 1 barrier/iter) + Z partials (2-product);
// k_rag: [A;G]@Xall^T (2-product mma) ; k_attn2: reduce+softmax(dim=1)+dot.

// ----- static scratch -----
__device__ float g_Cq[65536], g_Ck[65536], g_Cv[65536];
__device__ float g_A[32768], g_Bm[32768], g_G[32768];
__device__ float g_part[393216];     // [3][4][32][1024] skinny split-K partials
__device__ float g_c[1024], g_P[1024];
__device__ float g_Zpart[8388608];   // gemmM split-K partials (4x1M), then Z partials [8][1024][32][32]
__device__ float g_RAG[2097152];     // [64][32768]
__device__ __align__(16) __half g_Xh[33554432];   // fp16 X [32768,1024]
__device__ __align__(16) __half g_Xl[33554432];   // fp16 residual
__device__ __align__(16) __half g_MhT[1048576];   // fp16 M^T [f][e]
__device__ __align__(16) __half g_AGh[65536];     // [64][1024] = [A;G] hi
__device__ __align__(16) __half g_AGl[65536];
__device__ __align__(16) __nv_bfloat16 g_WqTh[2097152];  // [e][d2]
__device__ __align__(16) __nv_bfloat16 g_WqTl[2097152];
__device__ __align__(16) __nv_bfloat16 g_WkTh[2097152];
__device__ __align__(16) __nv_bfloat16 g_WkTl[2097152];
__device__ __align__(16) __nv_bfloat16 g_WvTh[2097152];
__device__ __align__(16) __nv_bfloat16 g_WvTl[2097152];
__device__ __align__(16) __nv_bfloat16 g_CqH[65536], g_CqL[65536];  // [32,2048]
__device__ __align__(16) __nv_bfloat16 g_CkH[65536], g_CkL[65536];
__device__ __align__(16) __nv_bfloat16 g_WfH[65536], g_WfL[65536];

__device__ __forceinline__ float wredsum(float v) {
#pragma unroll
    for (int o = 16; o; o >>= 1) v += __shfl_xor_sync(0xffffffffu, v, o);
    return v;
}
__device__ __forceinline__ float wredmax(float v) {
#pragma unroll
    for (int o = 16; o; o >>= 1) v = fmaxf(v, __shfl_xor_sync(0xffffffffu, v, o));
    return v;
}
__device__ __forceinline__ uint32_t smem_u32(const void* p) {
    uint32_t a;
    asm("{ .reg .u64 t; cvta.to.shared.u64 t, %1; cvt.u32.u64 %0, t; }" : "=r"(a) : "l"(p));
    return a;
}
__device__ __forceinline__ void ldsm4(uint32_t* r, uint32_t addr) {
    asm volatile("ldmatrix.sync.aligned.m8n8.x4.shared.b16 {%0,%1,%2,%3}, [%4];"
                 : "=r"(r[0]), "=r"(r[1]), "=r"(r[2]), "=r"(r[3]) : "r"(addr));
}
__device__ __forceinline__ void mma_bf16(float* d, const uint32_t* a,
                                         uint32_t b0, uint32_t b1) {
    asm volatile(
        "mma.sync.aligned.m16n8k16.row.col.f32.bf16.bf16.f32 "
        "{%0,%1,%2,%3}, {%4,%5,%6,%7}, {%8,%9}, {%0,%1,%2,%3};"
        : "+f"(d[0]), "+f"(d[1]), "+f"(d[2]), "+f"(d[3])
        : "r"(a[0]), "r"(a[1]), "r"(a[2]), "r"(a[3]), "r"(b0), "r"(b1));
}
__device__ __forceinline__ void mma_f16(float* d, const uint32_t* a,
                                        uint32_t b0, uint32_t b1) {
    asm volatile(
        "mma.sync.aligned.m16n8k16.row.col.f32.f16.f16.f32 "
        "{%0,%1,%2,%3}, {%4,%5,%6,%7}, {%8,%9}, {%0,%1,%2,%3};"
        : "+f"(d[0]), "+f"(d[1]), "+f"(d[2]), "+f"(d[3])
        : "r"(a[0]), "r"(a[1]), "r"(a[2]), "r"(a[3]), "r"(b0), "r"(b1));
}
__device__ __forceinline__ void cpasync16(uint32_t saddr, const void* gaddr) {
    asm volatile("cp.async.cg.shared.global [%0], [%1], 16;" :: "r"(saddr), "l"(gaddr));
}
#define CP_COMMIT() asm volatile("cp.async.commit_group;" ::: "memory")
#define CP_WAIT(n)  asm volatile("cp.async.wait_group %0;" :: "n"(n) : "memory")

// ===== merged prep =====
__global__ __launch_bounds__(256) void k_prep(const float* __restrict__ x,
                                              const float* __restrict__ pe,
                                              const float* __restrict__ Wq, const float* __restrict__ bq,
                                              const float* __restrict__ Wk, const float* __restrict__ bk,
                                              const float* __restrict__ Wv, const float* __restrict__ bv,
                                              const float* __restrict__ Wfc) {
    __shared__ float sh[32 * 33];
    int blk = blockIdx.x;
    int tid = threadIdx.x;
    if (blk < 768) {
        int bz = blk >> 8, bx = blk & 255;
        const float* W; const float* bias; float* out;
        if (bz == 0)      { W = Wq; bias = bq; out = g_Cq; }
        else if (bz == 1) { W = Wk; bias = bk; out = g_Ck; }
        else              { W = Wv; bias = bv; out = g_Cv; }
        int warp = tid >> 5, lane = tid & 31;
        int d2 = bx * 8 + warp;
        float acc[32];
#pragma unroll
        for (int i = 0; i < 32; i++) acc[i] = 0.f;
        for (int e0 = 0; e0 < 1024; e0 += 32) {
            __syncthreads();
#pragma unroll
            for (int p = 0; p < 4; p++) {
                int idx = p * 256 + tid;
                sh[(idx >> 5) * 33 + (idx & 31)] = pe[(idx >> 5) * 1024 + e0 + (idx & 31)];
            }
            __syncthreads();
            float wv = W[(size_t)d2 * 2048 + 1024 + e0 + lane];
#pragma unroll
            for (int i = 0; i < 32; i++) acc[i] += sh[i * 33 + lane] * wv;
        }
        float res = 0.f;
#pragma unroll
        for (int i = 0; i < 32; i++) {
            float r = wredsum(acc[i]);
            if (lane == i) res = r;
        }
        float val = res + bias[d2];
        out[lane * 2048 + d2] = val;
        if (bz < 2) {
            __nv_bfloat16 h = __float2bfloat16(val);
            __nv_bfloat16 l = __float2bfloat16(val - __bfloat162float(h));
            __nv_bfloat16* oh = bz ? g_CkH : g_CqH;
            __nv_bfloat16* ol = bz ? g_CkL : g_CqL;
            oh[lane * 2048 + d2] = h;
            ol[lane * 2048 + d2] = l;
        }
    } else if (blk < 6912) {
        int b2 = blk - 768;
        int bx = b2 & 31, by = (b2 >> 5) & 63, bz = b2 >> 11;
        const float* W = (bz == 0) ? Wq : (bz == 1) ? Wk : Wv;
        __nv_bfloat16* oh = (bz == 0) ? g_WqTh : (bz == 1) ? g_WkTh : g_WvTh;
        __nv_bfloat16* ol = (bz == 0) ? g_WqTl : (bz == 1) ? g_WkTl : g_WvTl;
        int xx = tid & 31, yy = tid >> 5;   // 32 x 8
#pragma unroll
        for (int i = 0; i < 32; i += 8)
            sh[(yy + i) * 33 + xx] = W[(size_t)(by * 32 + yy + i) * 2048 + bx * 32 + xx];
        __syncthreads();
#pragma unroll
        for (int i = 0; i < 32; i += 8) {
            float v = sh[xx * 33 + yy + i];
            __nv_bfloat16 h = __float2bfloat16(v);
            __nv_bfloat16 l = __float2bfloat16(v - __bfloat162float(h));
            size_t o = (size_t)(bx * 32 + yy + i) * 2048 + by * 32 + xx;
            oh[o] = h;
            ol[o] = l;
        }
    } else if (blk < 6976) {
        int idx4 = (blk - 6912) * 256 + tid;
        float4 v = *(const float4*)(Wfc + (size_t)idx4 * 4);
        float vv[4] = {v.x, v.y, v.z, v.w};
#pragma unroll
        for (int q = 0; q < 4; q++) {
            __nv_bfloat16 h = __float2bfloat16(vv[q]);
            g_WfH[idx4 * 4 + q] = h;
            g_WfL[idx4 * 4 + q] = __float2bfloat16(vv[q] - __bfloat162float(h));
        }
    } else {
        size_t i = ((size_t)(blk - 6976) * 256 + tid) * 4;
        float4 v = *(const float4*)(x + i);
        __half h0 = __float2half_rn(v.x), h1 = __float2half_rn(v.y);
        __half h2 = __float2half_rn(v.z), h3 = __float2half_rn(v.w);
        *(__half2*)(g_Xh + i)     = __halves2half2(h0, h1);
        *(__half2*)(g_Xh + i + 2) = __halves2half2(h2, h3);
        *(__half2*)(g_Xl + i)     = __halves2half2(__float2half_rn(v.x - __half2float(h0)),
                                                   __float2half_rn(v.y - __half2float(h1)));
        *(__half2*)(g_Xl + i + 2) = __halves2half2(__float2half_rn(v.z - __half2float(h2)),
                                                   __float2half_rn(v.w - __half2float(h3)));
    }
}

// ----- kernel 2: M partials = Wq1^T @ Wk1, bf16 3-product mma, split-K=4 -----
#define GPAD 72
#define GBUF (128 * GPAD * 2)
#define GSTAGE (4 * GBUF)        // 73728
#define GSMEM (3 * GSTAGE)       // 221184

__device__ __forceinline__ void g_stage(uint32_t sb, int s, int m0, int n0,
                                        int k0, int tid) {
    uint32_t sa = sb + s * GSTAGE;
#pragma unroll
    for (int p = 0; p < 16; p++) {
        int idx = p * 256 + tid;
        int buf = idx >> 10;
        int t = idx & 1023;
        int row = t >> 3, c = t & 7;
        const __nv_bfloat16* src =
            (buf == 0) ? g_WqTh : (buf == 1) ? g_WqTl : (buf == 2) ? g_WkTh : g_WkTl;
        int r0 = (buf < 2) ? m0 : n0;
        cpasync16(sa + buf * GBUF + (uint32_t)(row * GPAD + c * 8) * 2,
                  src + (size_t)(r0 + row) * 2048 + k0 + c * 8);
    }
}

__global__ __launch_bounds__(256, 1) void k_gemmM_mma() {
    extern __shared__ __align__(16) char gsmem[];
    const uint32_t sb = smem_u32(gsmem);
    const int tid = threadIdx.x, lane = tid & 31, wid = tid >> 5;
    const int wm = wid >> 2, wn = wid & 3;
    const int m0 = blockIdx.y * 128, n0 = blockIdx.x * 128;
    const int kbase = blockIdx.z * 512;

    g_stage(sb, 0, m0, n0, kbase, tid);
    CP_COMMIT();
    g_stage(sb, 1, m0, n0, kbase + 64, tid);
    CP_COMMIT();

    float d[4][4][4] = {};
    const int aRow = wm * 64 + (lane & 15);
    const int aCol = (lane >> 4) * 8;
    const int bRow = wn * 32 + (lane & 7) + (lane >> 4) * 8;
    const int bCol = ((lane >> 3) & 1) * 8;

    for (int it = 0; it < 8; it++) {
        if (it < 7) CP_WAIT(1); else CP_WAIT(0);
        __syncthreads();
        if (it + 2 < 8) {
            g_stage(sb, (it + 2) % 3, m0, n0, kbase + (it + 2) * 64, tid);
            CP_COMMIT();
        }
        uint32_t st = sb + (it % 3) * GSTAGE;
#pragma unroll
        for (int ks = 0; ks < 4; ks++) {
            int kc = ks * 16;
            uint32_t arh[4][4], arl[4][4];
#pragma unroll
            for (int i = 0; i < 4; i++) {
                uint32_t ao = (uint32_t)((aRow + i * 16) * GPAD + kc + aCol) * 2;
                ldsm4(arh[i], st + ao);
                ldsm4(arl[i], st + GBUF + ao);
            }
            uint32_t brh[2][4], brl[2][4];
#pragma unroll
            for (int j = 0; j < 2; j++) {
                uint32_t bo = (uint32_t)((bRow + j * 16) * GPAD + kc + bCol) * 2;
                ldsm4(brh[j], st + 2 * GBUF + bo);
                ldsm4(brl[j], st + 3 * GBUF + bo);
            }
#pragma unroll
            for (int i = 0; i < 4; i++)
#pragma unroll
                for (int j = 0; j < 4; j++) {
                    uint32_t h0 = brh[j >> 1][(j & 1) * 2], h1 = brh[j >> 1][(j & 1) * 2 + 1];
                    uint32_t l0 = brl[j >> 1][(j & 1) * 2], l1 = brl[j >> 1][(j & 1) * 2 + 1];
                    mma_bf16(d[i][j], arh[i], h0, h1);
                    mma_bf16(d[i][j], arh[i], l0, l1);
                    mma_bf16(d[i][j], arl[i], h0, h1);
                }
        }
    }
    float* outp = g_Zpart + (size_t)blockIdx.z * 1048576;
    const int grp = lane >> 2, tig = lane & 3;
    const int mb = m0 + wm * 64, nb = n0 + wn * 32;
#pragma unroll
    for (int i = 0; i < 4; i++) {
        int r0 = mb + i * 16 + grp, r1 = r0 + 8;
#pragma unroll
        for (int j = 0; j < 4; j++) {
            int cc = nb + j * 8 + tig * 2;
            *(float2*)(outp + (size_t)r0 * 1024 + cc) = make_float2(d[i][j][0], d[i][j][1]);
            *(float2*)(outp + (size_t)r1 * 1024 + cc) = make_float2(d[i][j][2], d[i][j][3]);
        }
    }
}

// ----- k_Mred -----
__global__ void k_Mred() {
    __shared__ float t[32][33];
    int bx = blockIdx.x, by = blockIdx.y;
    int x = threadIdx.x, y = threadIdx.y;
#pragma unroll
    for (int i = 0; i < 32; i += 8) {
        size_t o = (size_t)(by * 32 + y + i) * 1024 + bx * 32 + x;
        t[y + i][x] = g_Zpart[o] + g_Zpart[1048576 + o] +
                      g_Zpart[2097152 + o] + g_Zpart[3145728 + o];
    }
    __syncthreads();
#pragma unroll
    for (int i = 0; i < 32; i += 8)
        g_MhT[(size_t)(bx * 32 + y + i) * 1024 + by * 32 + x] = __float2half_rn(t[x][y + i]);
}

// ----- kernel 3: skinny gemms via bf16 3-product mma, split-K=4 -----
#define SK_AB (32 * 72 * 2)
#define SK_BB (128 * 72 * 2)
#define SKSTAGE (2 * SK_AB + 2 * SK_BB)
#define SKSMEM (2 * SKSTAGE)

__device__ __forceinline__ void sk_stage(uint32_t sb, int s,
                                         const __nv_bfloat16* __restrict__ Ah,
                                         const __nv_bfloat16* __restrict__ Al,
                                         const __nv_bfloat16* __restrict__ Bh,
                                         const __nv_bfloat16* __restrict__ Bl,
                                         int n0, int k0, int tid) {
    uint32_t sa = sb + s * SKSTAGE;
#pragma unroll
    for (int p = 0; p < 4; p++) {
        int idx = p * 128 + tid;
        int bufl = idx >> 8;
        int t = idx & 255;
        int row = t >> 3, ch = t & 7;
        const __nv_bfloat16* src = bufl ? Al : Ah;
        cpasync16(sa + bufl * SK_AB + (uint32_t)(row * 72 + ch * 8) * 2,
                  src + (size_t)row * 2048 + k0 + ch * 8);
    }
#pragma unroll
    for (int p = 0; p < 16; p++) {
        int idx = p * 128 + tid;
        int bufl = idx >> 10;
        int t = idx & 1023;
        int row = t >> 3, ch = t & 7;
        const __nv_bfloat16* src = bufl ? Bl : Bh;
        cpasync16(sa + 2 * SK_AB + bufl * SK_BB + (uint32_t)(row * 72 + ch * 8) * 2,
                  src + (size_t)(n0 + row) * 2048 + k0 + ch * 8);
    }
}

__global__ __launch_bounds__(128, 1) void k_skinny_mma() {
    extern __shared__ __align__(16) char sksmem[];
    const uint32_t sb = smem_u32(sksmem);
    const int tid = threadIdx.x, lane = tid & 31, wn = tid >> 5;
    const int z = blockIdx.z;
    const int n0 = blockIdx.x * 128;
    const int kbase = blockIdx.y * 512;

    const __nv_bfloat16* Ah = (z == 0) ? g_CkH : (z == 1) ? g_CqH : g_WfH;
    const __nv_bfloat16* Al = (z == 0) ? g_CkL : (z == 1) ? g_CqL : g_WfL;
    const __nv_bfloat16* Bh = (z == 0) ? g_WqTh : (z == 1) ? g_WkTh : g_WvTh;
    const __nv_bfloat16* Bl = (z == 0) ? g_WqTl : (z == 1) ? g_WkTl : g_WvTl;

    sk_stage(sb, 0, Ah, Al, Bh, Bl, n0, kbase, tid);
    CP_COMMIT();

    float d[2][2][2][4] = {};
    const int aRow = lane & 15;
    const int aCol = (lane >> 4) * 8;
    const int bRow = wn * 32 + (lane & 7) + (lane >> 4) * 8;
    const int bCol = ((lane >> 3) & 1) * 8;

    for (int it = 0; it < 8; it++) {
        int nit = it + 1;
        if (nit < 8) {
            sk_stage(sb, nit & 1, Ah, Al, Bh, Bl, n0, kbase + nit * 64, tid);
            CP_COMMIT();
            CP_WAIT(1);
        } else {
            CP_WAIT(0);
        }
        __syncthreads();
        uint32_t st = sb + (it & 1) * SKSTAGE;
        uint32_t sB = st + 2 * SK_AB;
#pragma unroll
        for (int ks = 0; ks < 4; ks++) {
            int kc = ks * 16;
            uint32_t ah[2][4], al[2][4];
#pragma unroll
            for (int mi = 0; mi < 2; mi++) {
                uint32_t ao = (uint32_t)((mi * 16 + aRow) * 72 + kc + aCol) * 2;
                ldsm4(ah[mi], st + ao);
                ldsm4(al[mi], st + SK_AB + ao);
            }
            uint32_t bh[2][4], bl[2][4];
#pragma unroll
            for (int nj = 0; nj < 2; nj++) {
                uint32_t bo = (uint32_t)((bRow + nj * 16) * 72 + kc + bCol) * 2;
                ldsm4(bh[nj], sB + bo);
                ldsm4(bl[nj], sB + SK_BB + bo);
            }
#pragma unroll
            for (int mi = 0; mi < 2; mi++)
#pragma unroll
                for (int nj = 0; nj < 2; nj++)
#pragma unroll
                    for (int s = 0; s < 2; s++) {
                        mma_bf16(d[mi][nj][s], ah[mi], bh[nj][s * 2], bh[nj][s * 2 + 1]);
                        mma_bf16(d[mi][nj][s], ah[mi], bl[nj][s * 2], bl[nj][s * 2 + 1]);
                        mma_bf16(d[mi][nj][s], al[mi], bh[nj][s * 2], bh[nj][s * 2 + 1]);
                    }
        }
        __syncthreads();
    }
    float* outp = g_part + ((size_t)z * 4 + blockIdx.y) * 32768;
    const int grp = lane >> 2, tig = lane & 3;
#pragma unroll
    for (int mi = 0; mi < 2; mi++) {
        int r0 = mi * 16 + grp, r1 = r0 + 8;
#pragma unroll
        for (int nj = 0; nj < 2; nj++)
#pragma unroll
            for (int s = 0; s < 2; s++) {
                int col = n0 + wn * 32 + nj * 16 + s * 8 + tig * 2;
                *(float2*)(outp + r0 * 1024 + col) = make_float2(d[mi][nj][s][0], d[mi][nj][s][1]);
                *(float2*)(outp + r1 * 1024 + col) = make_float2(d[mi][nj][s][2], d[mi][nj][s][3]);
            }
    }
}

// ----- k_skred -----
__global__ void k_skred() {
    int idx = blockIdx.x * 256 + threadIdx.x;
    int z = idx >> 15;
    int r = idx & 32767;
    float s = 0.f;
#pragma unroll
    for (int kc = 0; kc < 4; kc++) s += g_part[((size_t)z * 4 + kc) * 32768 + r];
    float* out = (z == 0) ? g_A : (z == 1) ? g_Bm : g_G;
    out[r] = s;
    if (z != 1) {
        int agrow = (z == 0) ? (r >> 10) : 32 + (r >> 10);
        int col = r & 1023;
        __half h = __float2half_rn(s);
        g_AGh[agrow * 1024 + col] = h;
        g_AGl[agrow * 1024 + col] = __float2half_rn(s - __half2float(h));
    }
}

// ----- kernel 4: c = Cq@Ck^T, P = Wf@Cv^T -----
__global__ void k_small(const float* __restrict__ Wfc) {
    int i = blockIdx.x;
    const float* L; const float* R; float* out;
    if (blockIdx.y == 0) { L = g_Cq; R = g_Ck; out = g_c; }
    else                 { L = Wfc;  R = g_Cv; out = g_P; }
    int tid = threadIdx.x, warp = tid >> 5, lane = tid & 31;
    float acc[4] = {0.f, 0.f, 0.f, 0.f};
    for (int d = lane; d < 2048; d += 32) {
        float lv = L[i * 2048 + d];
#pragma unroll
        for (int q = 0; q < 4; q++) acc[q] += lv * R[(warp * 4 + q) * 2048 + d];
    }
#pragma unroll
    for (int q = 0; q < 4; q++) {
        float r = wredsum(acc[q]);
        if (lane == 0) out[i * 32 + warp * 4 + q] = r;
    }
}

// ====== kernel 5: fused Y=X@M+Bm (128x256, K=128/stage, 2-stage) + Z partials ======
#define YPAD2 136
#define YA_BYTES (128 * YPAD2 * 2)         // 34816
#define YB_BYTES (256 * YPAD2 * 2)         // 69632
#define YSTAGE (YA_BYTES + YB_BYTES)       // 104448
#define ZBUF (128 * 136 * 2)               // 34816
#define YSMEM (2 * YSTAGE)                 // 208896 (>= 3*ZBUF epilogue use)

__device__ __forceinline__ void y_stage(uint32_t sb, int s, int m0, int n0,
                                        int k0, int tid) {
    uint32_t sa = sb + s * YSTAGE;
#pragma unroll
    for (int p = 0; p < 12; p++) {
        int idx = p * 512 + tid;   // 0..6143
        if (idx < 2048) {          // A: 128 rows x 16 chunks
            int row = idx >> 4, c = idx & 15;
            cpasync16(sa + (uint32_t)(row * YPAD2 + c * 8) * 2,
                      g_Xh + (size_t)(m0 + row) * 1024 + k0 + c * 8);
        } else {                   // B: 256 rows x 16 chunks
            int t = idx - 2048;
            int row = t >> 4, c = t & 15;
            cpasync16(sa + YA_BYTES + (uint32_t)(row * YPAD2 + c * 8) * 2,
                      g_MhT + (size_t)(n0 + row) * 1024 + k0 + c * 8);
        }
    }
}

__global__ __launch_bounds__(512, 1) void k_yz() {
    extern __shared__ __align__(16) char ysmem[];
    const uint32_t sb = smem_u32(ysmem);
    const int tid = threadIdx.x, lane = tid & 31, wid = tid >> 5;
    const int wm = wid >> 3, wn = wid & 7;       // 2 x 8 warps
    const int m0 = blockIdx.y * 128, n0 = blockIdx.x * 256;

    y_stage(sb, 0, m0, n0, 0, tid);
    CP_COMMIT();

    float d[4][4][4] = {};
    const int aRow = wm * 64 + (lane & 15);
    const int aCol = (lane >> 4) * 8;
    const int bRow = wn * 32 + (lane & 7) + (lane >> 4) * 8;
    const int bCol = ((lane >> 3) & 1) * 8;

    for (int it = 0; it < 8; it++) {
        CP_WAIT(0);
        __syncthreads();
        if (it + 1 < 8) {
            y_stage(sb, (it + 1) & 1, m0, n0, (it + 1) * 128, tid);
            CP_COMMIT();
        }
        uint32_t abase = sb + (it & 1) * YSTAGE;
        uint32_t bbase = abase + YA_BYTES;
#pragma unroll
        for (int ks = 0; ks < 8; ks++) {
            int kc = ks * 16;
            uint32_t ar[4][4];
#pragma unroll
            for (int i = 0; i < 4; i++)
                ldsm4(ar[i], abase + (uint32_t)((aRow + i * 16) * YPAD2 + kc + aCol) * 2);
            uint32_t br[2][4];
#pragma unroll
            for (int j = 0; j < 2; j++)
                ldsm4(br[j], bbase + (uint32_t)((bRow + j * 16) * YPAD2 + kc + bCol) * 2);
#pragma unroll
            for (int i = 0; i < 4; i++)
#pragma unroll
                for (int j = 0; j < 4; j++)
                    mma_f16(d[i][j], ar[i], br[j >> 1][(j & 1) * 2],
                            br[j >> 1][(j & 1) * 2 + 1]);
        }
    }
    __syncthreads();

    // ---- epilogue: add Bm, then fused Z partials (2-product: Yh,Yl x Xh) ----
    const int grp = lane >> 2, tig = lane & 3;
#pragma unroll
    for (int i = 0; i < 4; i++) {
        int r0 = wm * 64 + i * 16 + grp;         // local row 0..127
        int p0 = r0 & 31, p1 = (r0 + 8) & 31;
#pragma unroll
        for (int j = 0; j < 4; j++) {
            int cc = n0 + wn * 32 + j * 8 + tig * 2;
            float2 b0 = *(const float2*)(g_Bm + p0 * 1024 + cc);
            float2 b1 = *(const float2*)(g_Bm + p1 * 1024 + cc);
            d[i][j][0] += b0.x; d[i][j][1] += b0.y;
            d[i][j][2] += b1.x; d[i][j][3] += b1.y;
        }
    }

    const int bb = wid >> 2;       // local batch 0..3
    const int kq = (wid >> 1) & 1; // k-half of each f-half
    const int nh = wid & 1;        // n-half of Z columns (16 each)
    const uint32_t ZYH = sb, ZYL = sb + ZBUF, ZXH = sb + 2 * ZBUF;
    float z[2][2][4] = {};

#pragma unroll 1
    for (int h = 0; h < 2; h++) {
        __syncthreads();
        // load X hi tile [128 x 128] for f-cols n0+h*128..
#pragma unroll
        for (int p = 0; p < 4; p++) {
            int idx = p * 512 + tid;       // 0..2047 = 128 rows x 16 chunks
            int row = idx >> 4, ch = idx & 15;
            cpasync16(ZXH + (uint32_t)(row * 136 + ch * 8) * 2,
                      g_Xh + (size_t)(m0 + row) * 1024 + n0 + h * 128 + ch * 8);
        }
        CP_COMMIT();
        // write Y' hi/lo for this f-half (warps whose n-range lies in half h)
        if ((wn >> 2) == h) {
#pragma unroll
            for (int i = 0; i < 4; i++) {
                int r0 = wm * 64 + i * 16 + grp;
#pragma unroll
                for (int j = 0; j < 4; j++) {
                    int cl = (wn & 3) * 32 + j * 8 + tig * 2;   // 0..127
                    float v0 = d[i][j][0], v1 = d[i][j][1];
                    float v2 = d[i][j][2], v3 = d[i][j][3];
                    __half h0 = __float2half_rn(v0), h1 = __float2half_rn(v1);
                    __half h2 = __float2half_rn(v2), h3 = __float2half_rn(v3);
                    *(__half2*)(ysmem + ((r0) * 136 + cl) * 2) = __halves2half2(h0, h1);
                    *(__half2*)(ysmem + ((r0 + 8) * 136 + cl) * 2) = __halves2half2(h2, h3);
                    *(__half2*)(ysmem + ZBUF + ((r0) * 136 + cl) * 2) =
                        __halves2half2(__float2half_rn(v0 - __half2float(h0)),
                                       __float2half_rn(v1 - __half2float(h1)));
                    *(__half2*)(ysmem + ZBUF + ((r0 + 8) * 136 + cl) * 2) =
                        __halves2half2(__float2half_rn(v2 - __half2float(h2)),
                                       __float2half_rn(v3 - __half2float(h3)));
                }
            }
        }
        CP_WAIT(0);
        __syncthreads();
        // Z mma: batch bb, n-half nh (16 cols), k-quarter kq (64 of this 128-half)
#pragma unroll
        for (int ksl = 0; ksl < 4; ksl++) {
            int kc = (kq * 4 + ksl) * 16;
            uint32_t ayh[2][4], ayl[2][4];
#pragma unroll
            for (int mi = 0; mi < 2; mi++) {
                uint32_t ao = (uint32_t)((bb * 32 + mi * 16 + (lane & 15)) * 136 +
                                         kc + (lane >> 4) * 8) * 2;
                ldsm4(ayh[mi], ZYH + ao);
                ldsm4(ayl[mi], ZYL + ao);
            }
            uint32_t bxh[4];
            uint32_t bo = (uint32_t)((bb * 32 + nh * 16 + (lane & 7) + (lane >> 4) * 8) * 136 +
                                     kc + ((lane >> 3) & 1) * 8) * 2;
            ldsm4(bxh, ZXH + bo);
#pragma unroll
            for (int mi = 0; mi < 2; mi++)
#pragma unroll
                for (int no = 0; no < 2; no++) {
                    mma_f16(z[mi][no], ayh[mi], bxh[no * 2], bxh[no * 2 + 1]);
                    mma_f16(z[mi][no], ayl[mi], bxh[no * 2], bxh[no * 2 + 1]);
                }
        }
    }
    // store Z partials: slot = blockIdx.x*2 + kq (8 slots total)
    {
        int b = blockIdx.y * 4 + bb;
        size_t base = ((size_t)(blockIdx.x * 2 + kq) * 1024 + b) * 1024;
#pragma unroll
        for (int mi = 0; mi < 2; mi++) {
            int i0 = mi * 16 + grp;
#pragma unroll
            for (int no = 0; no < 2; no++) {
                int j0 = nh * 16 + no * 8 + tig * 2;
                *(float2*)(g_Zpart + base + i0 * 32 + j0) =
                    make_float2(z[mi][no][0], z[mi][no][1]);
                *(float2*)(g_Zpart + base + (i0 + 8) * 32 + j0) =
                    make_float2(z[mi][no][2], z[mi][no][3]);
            }
        }
    }
}

// ====== kernel 6: RAG = [A;G] @ Xall^T (2-product: AGh,AGl x Xh) ======
#define RPAD 72
#define R_A_BYTES (64 * RPAD * 2)               // 9216
#define R_B_BYTES (256 * RPAD * 2)              // 36864
#define RSTAGE (2 * R_A_BYTES + R_B_BYTES)      // 55296
#define RSMEM (2 * RSTAGE)                      // 110592

__device__ __forceinline__ void r_stage(uint32_t sb, int s, int n0, int k0, int tid) {
    uint32_t sa = sb + s * RSTAGE;
#pragma unroll
    for (int p = 0; p < 4; p++) {
        int idx = p * 256 + tid;   // 0..1023
        int bufl = idx >> 9;
        int t = idx & 511;
        int row = t >> 3, ch = t & 7;
        const __half* src = bufl ? g_AGl : g_AGh;
        cpasync16(sa + bufl * R_A_BYTES + (uint32_t)(row * RPAD + ch * 8) * 2,
                  src + (size_t)row * 1024 + k0 + ch * 8);
    }
#pragma unroll
    for (int p = 0; p < 8; p++) {
        int idx = p * 256 + tid;   // 0..2047 = 256 rows x 8 chunks
        int row = idx >> 3, ch = idx & 7;
        cpasync16(sa + 2 * R_A_BYTES + (uint32_t)(row * RPAD + ch * 8) * 2,
                  g_Xh + (size_t)(n0 + row) * 1024 + k0 + ch * 8);
    }
}

__global__ __launch_bounds__(256) void k_rag() {
    extern __shared__ __align__(16) char rsmem[];
    const uint32_t sb = smem_u32(rsmem);
    const int tid = threadIdx.x, lane = tid & 31, wid = tid >> 5;
    const int wm = wid >> 2, wn = wid & 3;
    const int n0 = blockIdx.x * 256;

    r_stage(sb, 0, n0, 0, tid);
    CP_COMMIT();

    float d[2][4][2][4] = {};
    const int aRowB = wm * 32 + (lane & 15);
    const int aCol = (lane >> 4) * 8;
    const int bRowB = wn * 64 + (lane & 7) + (lane >> 4) * 8;
    const int bCol = ((lane >> 3) & 1) * 8;

    for (int it = 0; it < 16; it++) {
        int nit = it + 1;
        if (nit < 16) {
            r_stage(sb, nit & 1, n0, nit * 64, tid);
            CP_COMMIT();
            CP_WAIT(1);
        } else {
            CP_WAIT(0);
        }
        __syncthreads();
        uint32_t st = sb + (it & 1) * RSTAGE;
        uint32_t sB = st + 2 * R_A_BYTES;
#pragma unroll
        for (int ks = 0; ks < 4; ks++) {
            int kc = ks * 16;
            uint32_t ah[2][4], al[2][4];
#pragma unroll
            for (int mi = 0; mi < 2; mi++) {
                uint32_t ao = (uint32_t)((aRowB + mi * 16) * RPAD + kc + aCol) * 2;
                ldsm4(ah[mi], st + ao);
                ldsm4(al[mi], st + R_A_BYTES + ao);
            }
            uint32_t bh[4][4];
#pragma unroll
            for (int nj = 0; nj < 4; nj++) {
                uint32_t bo = (uint32_t)((bRowB + nj * 16) * RPAD + kc + bCol) * 2;
                ldsm4(bh[nj], sB + bo);
            }
#pragma unroll
            for (int mi = 0; mi < 2; mi++)
#pragma unroll
                for (int nj = 0; nj < 4; nj++)
#pragma unroll
                    for (int s = 0; s < 2; s++) {
                        mma_f16(d[mi][nj][s], ah[mi], bh[nj][s * 2], bh[nj][s * 2 + 1]);
                        mma_f16(d[mi][nj][s], al[mi], bh[nj][s * 2], bh[nj][s * 2 + 1]);
                    }
        }
        __syncthreads();
    }
    const int grp = lane >> 2, tig = lane & 3;
#pragma unroll
    for (int mi = 0; mi < 2; mi++) {
        int r0 = wm * 32 + mi * 16 + grp, r1 = r0 + 8;
#pragma unroll
        for (int nj = 0; nj < 4; nj++)
#pragma unroll
            for (int s = 0; s < 2; s++) {
                int col = n0 + wn * 64 + nj * 16 + s * 8 + tig * 2;
                *(float2*)(g_RAG + (size_t)r0 * 32768 + col) =
                    make_float2(d[mi][nj][s][0], d[mi][nj][s][1]);
                *(float2*)(g_RAG + (size_t)r1 * 32768 + col) =
                    make_float2(d[mi][nj][s][2], d[mi][nj][s][3]);
            }
    }
}

// ----- kernel 7: reduce Z partials + softmax(dim=1) + final dot -----
__global__ __launch_bounds__(256) void k_attn2(const float* __restrict__ bfc,
                                               float* __restrict__ out) {
    __shared__ float Zs[32 * 33];
    __shared__ float As[32 * 33];
    __shared__ float Vs[32 * 33];
    __shared__ float wpart[8];
    int tid = threadIdx.x, b = blockIdx.x;
#pragma unroll
    for (int p = 0; p < 4; p++) {
        int idx = p * 256 + tid;
        int i = idx >> 5, j = idx & 31;
        float s = 0.f;
#pragma unroll
        for (int nb = 0; nb < 8; nb++)
            s += g_Zpart[((size_t)nb * 1024 + b) * 1024 + idx];
        Zs[i * 33 + j] = s;
        As[i * 33 + j] = g_RAG[(size_t)j * 32768 + b * 32 + i];
        Vs[i * 33 + j] = g_RAG[(size_t)(32 + i) * 32768 + b * 32 + j];
    }
    __syncthreads();
    int w = tid >> 5, lane = tid & 31;
    const float rscale = 0.022097086912079608f;  // 1/sqrt(2048)
    float local = 0.f;
#pragma unroll
    for (int q = 0; q < 4; q++) {
        int j = w * 4 + q;
        float lg = (Zs[lane * 33 + j] + As[lane * 33 + j] + g_c[lane * 32 + j]) * rscale;
        float mx = wredmax(lg);
        float ex = __expf(lg - mx);
        float sm = wredsum(ex);
        float contrib = (ex / sm) * (Vs[lane * 33 + j] + g_P[lane * 32 + j]);
        local += wredsum(contrib);
    }
    if (lane == 0) wpart[w] = local;
    __syncthreads();
    if (tid == 0) {
        float t = 0.f;
#pragma unroll
        for (int i = 0; i < 8; i++) t += wpart[i];
        out[b] = t + bfc[0];
    }
}

extern "C" void kernel_launch(void* const* d_in, const int* in_sizes, int n_in,
                              void* d_out, int out_size) {
    const float* x   = (const float*)d_in[0];
    const float* pe  = (const float*)d_in[1];
    const float* Wq  = (const float*)d_in[2];
    const float* bq  = (const float*)d_in[3];
    const float* Wk  = (const float*)d_in[4];
    const float* bk  = (const float*)d_in[5];
    const float* Wv  = (const float*)d_in[6];
    const float* bv  = (const float*)d_in[7];
    const float* Wfc = (const float*)d_in[8];
    const float* bfc = (const float*)d_in[9];
    float* out = (float*)d_out;

    cudaFuncSetAttribute(k_gemmM_mma, cudaFuncAttributeMaxDynamicSharedMemorySize, GSMEM);
    cudaFuncSetAttribute(k_skinny_mma, cudaFuncAttributeMaxDynamicSharedMemorySize, SKSMEM);
    cudaFuncSetAttribute(k_yz, cudaFuncAttributeMaxDynamicSharedMemorySize, YSMEM);
    cudaFuncSetAttribute(k_rag, cudaFuncAttributeMaxDynamicSharedMemorySize, RSMEM);

    k_prep<<<39744, 256>>>(x, pe, Wq, bq, Wk, bk, Wv, bv, Wfc);
    k_gemmM_mma<<<dim3(8, 8, 4), 256, GSMEM>>>();
    k_Mred<<<dim3(32, 32), dim3(32, 8)>>>();
    k_skinny_mma<<<dim3(8, 4, 3), 128, SKSMEM>>>();
    k_skred<<<384, 256>>>();
    k_small<<<dim3(32, 2), 256>>>(Wfc);
    k_yz<<<dim3(4, 256), 512, YSMEM>>>();
    k_rag<<<128, 256, RSMEM>>>();
    k_attn2<<<1024, 256>>>(bfc, out);
}

// round 12
// speedup vs baseline: 3.8960x; 1.0060x over previous
#include <cuda_runtime.h>
#include <cuda_bf16.h>
#include <cuda_fp16.h>
#include <math.h>
#include <stdint.h>

// B=1024, S=32, D=1024, D2=2048
// out[b]: Cq/Ck/Cv = pe@W2^T+b ; MhT=(Wq1^T Wk1)^T (bf16 3-split mma, split-K=4) ;
// A=Ck@Wq1 ; Bm=Cq@Wk1 ; G=Wf@Wv1 (bf16 3-split mma, split-K=8) ; c,P small ;
// k_yz: Y=X@M+Bm (fp16 mma, 128x256, K=128/stage) + Z partials (2-product) ;
// k_rag: [A;G]@Xall^T (2-product mma, n-tile 128) ; k_attn2: reduce+softmax(dim=1)+dot.

// ----- static scratch -----
__device__ float g_Cq[65536], g_Ck[65536], g_Cv[65536];
__device__ float g_A[32768], g_Bm[32768], g_G[32768];
__device__ float g_part[786432];     // [3][8][32][1024] skinny split-K partials
__device__ float g_c[1024], g_P[1024];
__device__ float g_Zpart[8388608];   // gemmM split-K partials (4x1M), then Z partials [8][1024][32][32]
__device__ float g_RAG[2097152];     // [64][32768]
__device__ __align__(16) __half g_Xh[33554432];   // fp16 X [32768,1024]
__device__ __align__(16) __half g_MhT[1048576];   // fp16 M^T [f][e]
__device__ __align__(16) __half g_AGh[65536];     // [64][1024] = [A;G] hi
__device__ __align__(16) __half g_AGl[65536];
__device__ __align__(16) __nv_bfloat16 g_WqTh[2097152];  // [e][d2]
__device__ __align__(16) __nv_bfloat16 g_WqTl[2097152];
__device__ __align__(16) __nv_bfloat16 g_WkTh[2097152];
__device__ __align__(16) __nv_bfloat16 g_WkTl[2097152];
__device__ __align__(16) __nv_bfloat16 g_WvTh[2097152];
__device__ __align__(16) __nv_bfloat16 g_WvTl[2097152];
__device__ __align__(16) __nv_bfloat16 g_CqH[65536], g_CqL[65536];  // [32,2048]
__device__ __align__(16) __nv_bfloat16 g_CkH[65536], g_CkL[65536];
__device__ __align__(16) __nv_bfloat16 g_WfH[65536], g_WfL[65536];

__device__ __forceinline__ float wredsum(float v) {
#pragma unroll
    for (int o = 16; o; o >>= 1) v += __shfl_xor_sync(0xffffffffu, v, o);
    return v;
}
__device__ __forceinline__ float wredmax(float v) {
#pragma unroll
    for (int o = 16; o; o >>= 1) v = fmaxf(v, __shfl_xor_sync(0xffffffffu, v, o));
    return v;
}
__device__ __forceinline__ uint32_t smem_u32(const void* p) {
    uint32_t a;
    asm("{ .reg .u64 t; cvta.to.shared.u64 t, %1; cvt.u32.u64 %0, t; }" : "=r"(a) : "l"(p));
    return a;
}
__device__ __forceinline__ void ldsm4(uint32_t* r, uint32_t addr) {
    asm volatile("ldmatrix.sync.aligned.m8n8.x4.shared.b16 {%0,%1,%2,%3}, [%4];"
                 : "=r"(r[0]), "=r"(r[1]), "=r"(r[2]), "=r"(r[3]) : "r"(addr));
}
__device__ __forceinline__ void mma_bf16(float* d, const uint32_t* a,
                                         uint32_t b0, uint32_t b1) {
    asm volatile(
        "mma.sync.aligned.m16n8k16.row.col.f32.bf16.bf16.f32 "
        "{%0,%1,%2,%3}, {%4,%5,%6,%7}, {%8,%9}, {%0,%1,%2,%3};"
        : "+f"(d[0]), "+f"(d[1]), "+f"(d[2]), "+f"(d[3])
        : "r"(a[0]), "r"(a[1]), "r"(a[2]), "r"(a[3]), "r"(b0), "r"(b1));
}
__device__ __forceinline__ void mma_f16(float* d, const uint32_t* a,
                                        uint32_t b0, uint32_t b1) {
    asm volatile(
        "mma.sync.aligned.m16n8k16.row.col.f32.f16.f16.f32 "
        "{%0,%1,%2,%3}, {%4,%5,%6,%7}, {%8,%9}, {%0,%1,%2,%3};"
        : "+f"(d[0]), "+f"(d[1]), "+f"(d[2]), "+f"(d[3])
        : "r"(a[0]), "r"(a[1]), "r"(a[2]), "r"(a[3]), "r"(b0), "r"(b1));
}
__device__ __forceinline__ void cpasync16(uint32_t saddr, const void* gaddr) {
    asm volatile("cp.async.cg.shared.global [%0], [%1], 16;" :: "r"(saddr), "l"(gaddr));
}
#define CP_COMMIT() asm volatile("cp.async.commit_group;" ::: "memory")
#define CP_WAIT(n)  asm volatile("cp.async.wait_group %0;" :: "n"(n) : "memory")

// ===== merged prep =====
__global__ __launch_bounds__(256) void k_prep(const float* __restrict__ x,
                                              const float* __restrict__ pe,
                                              const float* __restrict__ Wq, const float* __restrict__ bq,
                                              const float* __restrict__ Wk, const float* __restrict__ bk,
                                              const float* __restrict__ Wv, const float* __restrict__ bv,
                                              const float* __restrict__ Wfc) {
    __shared__ float sh[32 * 33];
    int blk = blockIdx.x;
    int tid = threadIdx.x;
    if (blk < 768) {
        int bz = blk >> 8, bx = blk & 255;
        const float* W; const float* bias; float* out;
        if (bz == 0)      { W = Wq; bias = bq; out = g_Cq; }
        else if (bz == 1) { W = Wk; bias = bk; out = g_Ck; }
        else              { W = Wv; bias = bv; out = g_Cv; }
        int warp = tid >> 5, lane = tid & 31;
        int d2 = bx * 8 + warp;
        float acc[32];
#pragma unroll
        for (int i = 0; i < 32; i++) acc[i] = 0.f;
        for (int e0 = 0; e0 < 1024; e0 += 32) {
            __syncthreads();
#pragma unroll
            for (int p = 0; p < 4; p++) {
                int idx = p * 256 + tid;
                sh[(idx >> 5) * 33 + (idx & 31)] = pe[(idx >> 5) * 1024 + e0 + (idx & 31)];
            }
            __syncthreads();
            float wv = W[(size_t)d2 * 2048 + 1024 + e0 + lane];
#pragma unroll
            for (int i = 0; i < 32; i++) acc[i] += sh[i * 33 + lane] * wv;
        }
        float res = 0.f;
#pragma unroll
        for (int i = 0; i < 32; i++) {
            float r = wredsum(acc[i]);
            if (lane == i) res = r;
        }
        float val = res + bias[d2];
        out[lane * 2048 + d2] = val;
        if (bz < 2) {
            __nv_bfloat16 h = __float2bfloat16(val);
            __nv_bfloat16 l = __float2bfloat16(val - __bfloat162float(h));
            __nv_bfloat16* oh = bz ? g_CkH : g_CqH;
            __nv_bfloat16* ol = bz ? g_CkL : g_CqL;
            oh[lane * 2048 + d2] = h;
            ol[lane * 2048 + d2] = l;
        }
    } else if (blk < 6912) {
        int b2 = blk - 768;
        int bx = b2 & 31, by = (b2 >> 5) & 63, bz = b2 >> 11;
        const float* W = (bz == 0) ? Wq : (bz == 1) ? Wk : Wv;
        __nv_bfloat16* oh = (bz == 0) ? g_WqTh : (bz == 1) ? g_WkTh : g_WvTh;
        __nv_bfloat16* ol = (bz == 0) ? g_WqTl : (bz == 1) ? g_WkTl : g_WvTl;
        int xx = tid & 31, yy = tid >> 5;   // 32 x 8
#pragma unroll
        for (int i = 0; i < 32; i += 8)
            sh[(yy + i) * 33 + xx] = W[(size_t)(by * 32 + yy + i) * 2048 + bx * 32 + xx];
        __syncthreads();
#pragma unroll
        for (int i = 0; i < 32; i += 8) {
            float v = sh[xx * 33 + yy + i];
            __nv_bfloat16 h = __float2bfloat16(v);
            __nv_bfloat16 l = __float2bfloat16(v - __bfloat162float(h));
            size_t o = (size_t)(bx * 32 + yy + i) * 2048 + by * 32 + xx;
            oh[o] = h;
            ol[o] = l;
        }
    } else if (blk < 6976) {
        int idx4 = (blk - 6912) * 256 + tid;
        float4 v = *(const float4*)(Wfc + (size_t)idx4 * 4);
        float vv[4] = {v.x, v.y, v.z, v.w};
#pragma unroll
        for (int q = 0; q < 4; q++) {
            __nv_bfloat16 h = __float2bfloat16(vv[q]);
            g_WfH[idx4 * 4 + q] = h;
            g_WfL[idx4 * 4 + q] = __float2bfloat16(vv[q] - __bfloat162float(h));
        }
    } else {
        size_t i = ((size_t)(blk - 6976) * 256 + tid) * 4;
        float4 v = *(const float4*)(x + i);
        *(__half2*)(g_Xh + i)     = __halves2half2(__float2half_rn(v.x), __float2half_rn(v.y));
        *(__half2*)(g_Xh + i + 2) = __halves2half2(__float2half_rn(v.z), __float2half_rn(v.w));
    }
}

// ----- kernel 2: M partials = Wq1^T @ Wk1, bf16 3-product mma, split-K=4 -----
#define GPAD 72
#define GBUF (128 * GPAD * 2)
#define GSTAGE (4 * GBUF)        // 73728
#define GSMEM (3 * GSTAGE)       // 221184

__device__ __forceinline__ void g_stage(uint32_t sb, int s, int m0, int n0,
                                        int k0, int tid) {
    uint32_t sa = sb + s * GSTAGE;
#pragma unroll
    for (int p = 0; p < 16; p++) {
        int idx = p * 256 + tid;
        int buf = idx >> 10;
        int t = idx & 1023;
        int row = t >> 3, c = t & 7;
        const __nv_bfloat16* src =
            (buf == 0) ? g_WqTh : (buf == 1) ? g_WqTl : (buf == 2) ? g_WkTh : g_WkTl;
        int r0 = (buf < 2) ? m0 : n0;
        cpasync16(sa + buf * GBUF + (uint32_t)(row * GPAD + c * 8) * 2,
                  src + (size_t)(r0 + row) * 2048 + k0 + c * 8);
    }
}

__global__ __launch_bounds__(256, 1) void k_gemmM_mma() {
    extern __shared__ __align__(16) char gsmem[];
    const uint32_t sb = smem_u32(gsmem);
    const int tid = threadIdx.x, lane = tid & 31, wid = tid >> 5;
    const int wm = wid >> 2, wn = wid & 3;
    const int m0 = blockIdx.y * 128, n0 = blockIdx.x * 128;
    const int kbase = blockIdx.z * 512;

    g_stage(sb, 0, m0, n0, kbase, tid);
    CP_COMMIT();
    g_stage(sb, 1, m0, n0, kbase + 64, tid);
    CP_COMMIT();

    float d[4][4][4] = {};
    const int aRow = wm * 64 + (lane & 15);
    const int aCol = (lane >> 4) * 8;
    const int bRow = wn * 32 + (lane & 7) + (lane >> 4) * 8;
    const int bCol = ((lane >> 3) & 1) * 8;

    for (int it = 0; it < 8; it++) {
        if (it < 7) CP_WAIT(1); else CP_WAIT(0);
        __syncthreads();
        if (it + 2 < 8) {
            g_stage(sb, (it + 2) % 3, m0, n0, kbase + (it + 2) * 64, tid);
            CP_COMMIT();
        }
        uint32_t st = sb + (it % 3) * GSTAGE;
#pragma unroll
        for (int ks = 0; ks < 4; ks++) {
            int kc = ks * 16;
            uint32_t arh[4][4], arl[4][4];
#pragma unroll
            for (int i = 0; i < 4; i++) {
                uint32_t ao = (uint32_t)((aRow + i * 16) * GPAD + kc + aCol) * 2;
                ldsm4(arh[i], st + ao);
                ldsm4(arl[i], st + GBUF + ao);
            }
            uint32_t brh[2][4], brl[2][4];
#pragma unroll
            for (int j = 0; j < 2; j++) {
                uint32_t bo = (uint32_t)((bRow + j * 16) * GPAD + kc + bCol) * 2;
                ldsm4(brh[j], st + 2 * GBUF + bo);
                ldsm4(brl[j], st + 3 * GBUF + bo);
            }
#pragma unroll
            for (int i = 0; i < 4; i++)
#pragma unroll
                for (int j = 0; j < 4; j++) {
                    uint32_t h0 = brh[j >> 1][(j & 1) * 2], h1 = brh[j >> 1][(j & 1) * 2 + 1];
                    uint32_t l0 = brl[j >> 1][(j & 1) * 2], l1 = brl[j >> 1][(j & 1) * 2 + 1];
                    mma_bf16(d[i][j], arh[i], h0, h1);
                    mma_bf16(d[i][j], arh[i], l0, l1);
                    mma_bf16(d[i][j], arl[i], h0, h1);
                }
        }
    }
    float* outp = g_Zpart + (size_t)blockIdx.z * 1048576;
    const int grp = lane >> 2, tig = lane & 3;
    const int mb = m0 + wm * 64, nb = n0 + wn * 32;
#pragma unroll
    for (int i = 0; i < 4; i++) {
        int r0 = mb + i * 16 + grp, r1 = r0 + 8;
#pragma unroll
        for (int j = 0; j < 4; j++) {
            int cc = nb + j * 8 + tig * 2;
            *(float2*)(outp + (size_t)r0 * 1024 + cc) = make_float2(d[i][j][0], d[i][j][1]);
            *(float2*)(outp + (size_t)r1 * 1024 + cc) = make_float2(d[i][j][2], d[i][j][3]);
        }
    }
}

// ----- k_Mred -----
__global__ void k_Mred() {
    __shared__ float t[32][33];
    int bx = blockIdx.x, by = blockIdx.y;
    int x = threadIdx.x, y = threadIdx.y;
#pragma unroll
    for (int i = 0; i < 32; i += 8) {
        size_t o = (size_t)(by * 32 + y + i) * 1024 + bx * 32 + x;
        t[y + i][x] = g_Zpart[o] + g_Zpart[1048576 + o] +
                      g_Zpart[2097152 + o] + g_Zpart[3145728 + o];
    }
    __syncthreads();
#pragma unroll
    for (int i = 0; i < 32; i += 8)
        g_MhT[(size_t)(bx * 32 + y + i) * 1024 + by * 32 + x] = __float2half_rn(t[x][y + i]);
}

// ----- kernel 3: skinny gemms via bf16 3-product mma, split-K=8 -----
#define SK_AB (32 * 72 * 2)
#define SK_BB (128 * 72 * 2)
#define SKSTAGE (2 * SK_AB + 2 * SK_BB)
#define SKSMEM (2 * SKSTAGE)

__device__ __forceinline__ void sk_stage(uint32_t sb, int s,
                                         const __nv_bfloat16* __restrict__ Ah,
                                         const __nv_bfloat16* __restrict__ Al,
                                         const __nv_bfloat16* __restrict__ Bh,
                                         const __nv_bfloat16* __restrict__ Bl,
                                         int n0, int k0, int tid) {
    uint32_t sa = sb + s * SKSTAGE;
#pragma unroll
    for (int p = 0; p < 4; p++) {
        int idx = p * 128 + tid;
        int bufl = idx >> 8;
        int t = idx & 255;
        int row = t >> 3, ch = t & 7;
        const __nv_bfloat16* src = bufl ? Al : Ah;
        cpasync16(sa + bufl * SK_AB + (uint32_t)(row * 72 + ch * 8) * 2,
                  src + (size_t)row * 2048 + k0 + ch * 8);
    }
#pragma unroll
    for (int p = 0; p < 16; p++) {
        int idx = p * 128 + tid;
        int bufl = idx >> 10;
        int t = idx & 1023;
        int row = t >> 3, ch = t & 7;
        const __nv_bfloat16* src = bufl ? Bl : Bh;
        cpasync16(sa + 2 * SK_AB + bufl * SK_BB + (uint32_t)(row * 72 + ch * 8) * 2,
                  src + (size_t)(n0 + row) * 2048 + k0 + ch * 8);
    }
}

__global__ __launch_bounds__(128, 1) void k_skinny_mma() {
    extern __shared__ __align__(16) char sksmem[];
    const uint32_t sb = smem_u32(sksmem);
    const int tid = threadIdx.x, lane = tid & 31, wn = tid >> 5;
    const int z = blockIdx.z;
    const int n0 = blockIdx.x * 128;
    const int kbase = blockIdx.y * 256;

    const __nv_bfloat16* Ah = (z == 0) ? g_CkH : (z == 1) ? g_CqH : g_WfH;
    const __nv_bfloat16* Al = (z == 0) ? g_CkL : (z == 1) ? g_CqL : g_WfL;
    const __nv_bfloat16* Bh = (z == 0) ? g_WqTh : (z == 1) ? g_WkTh : g_WvTh;
    const __nv_bfloat16* Bl = (z == 0) ? g_WqTl : (z == 1) ? g_WkTl : g_WvTl;

    sk_stage(sb, 0, Ah, Al, Bh, Bl, n0, kbase, tid);
    CP_COMMIT();

    float d[2][2][2][4] = {};
    const int aRow = lane & 15;
    const int aCol = (lane >> 4) * 8;
    const int bRow = wn * 32 + (lane & 7) + (lane >> 4) * 8;
    const int bCol = ((lane >> 3) & 1) * 8;

    for (int it = 0; it < 4; it++) {
        int nit = it + 1;
        if (nit < 4) {
            sk_stage(sb, nit & 1, Ah, Al, Bh, Bl, n0, kbase + nit * 64, tid);
            CP_COMMIT();
            CP_WAIT(1);
        } else {
            CP_WAIT(0);
        }
        __syncthreads();
        uint32_t st = sb + (it & 1) * SKSTAGE;
        uint32_t sB = st + 2 * SK_AB;
#pragma unroll
        for (int ks = 0; ks < 4; ks++) {
            int kc = ks * 16;
            uint32_t ah[2][4], al[2][4];
#pragma unroll
            for (int mi = 0; mi < 2; mi++) {
                uint32_t ao = (uint32_t)((mi * 16 + aRow) * 72 + kc + aCol) * 2;
                ldsm4(ah[mi], st + ao);
                ldsm4(al[mi], st + SK_AB + ao);
            }
            uint32_t bh[2][4], bl[2][4];
#pragma unroll
            for (int nj = 0; nj < 2; nj++) {
                uint32_t bo = (uint32_t)((bRow + nj * 16) * 72 + kc + bCol) * 2;
                ldsm4(bh[nj], sB + bo);
                ldsm4(bl[nj], sB + SK_BB + bo);
            }
#pragma unroll
            for (int mi = 0; mi < 2; mi++)
#pragma unroll
                for (int nj = 0; nj < 2; nj++)
#pragma unroll
                    for (int s = 0; s < 2; s++) {
                        mma_bf16(d[mi][nj][s], ah[mi], bh[nj][s * 2], bh[nj][s * 2 + 1]);
                        mma_bf16(d[mi][nj][s], ah[mi], bl[nj][s * 2], bl[nj][s * 2 + 1]);
                        mma_bf16(d[mi][nj][s], al[mi], bh[nj][s * 2], bh[nj][s * 2 + 1]);
                    }
        }
        __syncthreads();
    }
    float* outp = g_part + ((size_t)z * 8 + blockIdx.y) * 32768;
    const int grp = lane >> 2, tig = lane & 3;
#pragma unroll
    for (int mi = 0; mi < 2; mi++) {
        int r0 = mi * 16 + grp, r1 = r0 + 8;
#pragma unroll
        for (int nj = 0; nj < 2; nj++)
#pragma unroll
            for (int s = 0; s < 2; s++) {
                int col = n0 + wn * 32 + nj * 16 + s * 8 + tig * 2;
                *(float2*)(outp + r0 * 1024 + col) = make_float2(d[mi][nj][s][0], d[mi][nj][s][1]);
                *(float2*)(outp + r1 * 1024 + col) = make_float2(d[mi][nj][s][2], d[mi][nj][s][3]);
            }
    }
}

// ----- k_skred (8 partials) -----
__global__ void k_skred() {
    int idx = blockIdx.x * 256 + threadIdx.x;
    int z = idx >> 15;
    int r = idx & 32767;
    float s = 0.f;
#pragma unroll
    for (int kc = 0; kc < 8; kc++) s += g_part[((size_t)z * 8 + kc) * 32768 + r];
    float* out = (z == 0) ? g_A : (z == 1) ? g_Bm : g_G;
    out[r] = s;
    if (z != 1) {
        int agrow = (z == 0) ? (r >> 10) : 32 + (r >> 10);
        int col = r & 1023;
        __half h = __float2half_rn(s);
        g_AGh[agrow * 1024 + col] = h;
        g_AGl[agrow * 1024 + col] = __float2half_rn(s - __half2float(h));
    }
}

// ----- kernel 4: c = Cq@Ck^T, P = Wf@Cv^T -----
__global__ void k_small(const float* __restrict__ Wfc) {
    int i = blockIdx.x;
    const float* L; const float* R; float* out;
    if (blockIdx.y == 0) { L = g_Cq; R = g_Ck; out = g_c; }
    else                 { L = Wfc;  R = g_Cv; out = g_P; }
    int tid = threadIdx.x, warp = tid >> 5, lane = tid & 31;
    float acc[4] = {0.f, 0.f, 0.f, 0.f};
    for (int d = lane; d < 2048; d += 32) {
        float lv = L[i * 2048 + d];
#pragma unroll
        for (int q = 0; q < 4; q++) acc[q] += lv * R[(warp * 4 + q) * 2048 + d];
    }
#pragma unroll
    for (int q = 0; q < 4; q++) {
        float r = wredsum(acc[q]);
        if (lane == 0) out[i * 32 + warp * 4 + q] = r;
    }
}

// ====== kernel 5: fused Y=X@M+Bm (128x256, K=128/stage, 2-stage) + Z partials ======
#define YPAD2 136
#define YA_BYTES (128 * YPAD2 * 2)         // 34816
#define YB_BYTES (256 * YPAD2 * 2)         // 69632
#define YSTAGE (YA_BYTES + YB_BYTES)       // 104448
#define ZBUF (128 * 136 * 2)               // 34816
#define YSMEM (2 * YSTAGE)                 // 208896

__device__ __forceinline__ void y_stage(uint32_t sb, int s, int m0, int n0,
                                        int k0, int tid) {
    uint32_t sa = sb + s * YSTAGE;
#pragma unroll
    for (int p = 0; p < 12; p++) {
        int idx = p * 512 + tid;
        if (idx < 2048) {
            int row = idx >> 4, c = idx & 15;
            cpasync16(sa + (uint32_t)(row * YPAD2 + c * 8) * 2,
                      g_Xh + (size_t)(m0 + row) * 1024 + k0 + c * 8);
        } else {
            int t = idx - 2048;
            int row = t >> 4, c = t & 15;
            cpasync16(sa + YA_BYTES + (uint32_t)(row * YPAD2 + c * 8) * 2,
                      g_MhT + (size_t)(n0 + row) * 1024 + k0 + c * 8);
        }
    }
}

__global__ __launch_bounds__(512, 1) void k_yz() {
    extern __shared__ __align__(16) char ysmem[];
    const uint32_t sb = smem_u32(ysmem);
    const int tid = threadIdx.x, lane = tid & 31, wid = tid >> 5;
    const int wm = wid >> 3, wn = wid & 7;
    const int m0 = blockIdx.y * 128, n0 = blockIdx.x * 256;

    y_stage(sb, 0, m0, n0, 0, tid);
    CP_COMMIT();

    float d[4][4][4] = {};
    const int aRow = wm * 64 + (lane & 15);
    const int aCol = (lane >> 4) * 8;
    const int bRow = wn * 32 + (lane & 7) + (lane >> 4) * 8;
    const int bCol = ((lane >> 3) & 1) * 8;

    for (int it = 0; it < 8; it++) {
        CP_WAIT(0);
        __syncthreads();
        if (it + 1 < 8) {
            y_stage(sb, (it + 1) & 1, m0, n0, (it + 1) * 128, tid);
            CP_COMMIT();
        }
        uint32_t abase = sb + (it & 1) * YSTAGE;
        uint32_t bbase = abase + YA_BYTES;
#pragma unroll
        for (int ks = 0; ks < 8; ks++) {
            int kc = ks * 16;
            uint32_t ar[4][4];
#pragma unroll
            for (int i = 0; i < 4; i++)
                ldsm4(ar[i], abase + (uint32_t)((aRow + i * 16) * YPAD2 + kc + aCol) * 2);
            uint32_t br[2][4];
#pragma unroll
            for (int j = 0; j < 2; j++)
                ldsm4(br[j], bbase + (uint32_t)((bRow + j * 16) * YPAD2 + kc + bCol) * 2);
#pragma unroll
            for (int i = 0; i < 4; i++)
#pragma unroll
                for (int j = 0; j < 4; j++)
                    mma_f16(d[i][j], ar[i], br[j >> 1][(j & 1) * 2],
                            br[j >> 1][(j & 1) * 2 + 1]);
        }
    }
    __syncthreads();

    // ---- epilogue: add Bm, then fused Z partials (2-product: Yh,Yl x Xh) ----
    const int grp = lane >> 2, tig = lane & 3;
#pragma unroll
    for (int i = 0; i < 4; i++) {
        int r0 = wm * 64 + i * 16 + grp;
        int p0 = r0 & 31, p1 = (r0 + 8) & 31;
#pragma unroll
        for (int j = 0; j < 4; j++) {
            int cc = n0 + wn * 32 + j * 8 + tig * 2;
            float2 b0 = *(const float2*)(g_Bm + p0 * 1024 + cc);
            float2 b1 = *(const float2*)(g_Bm + p1 * 1024 + cc);
            d[i][j][0] += b0.x; d[i][j][1] += b0.y;
            d[i][j][2] += b1.x; d[i][j][3] += b1.y;
        }
    }

    const int bb = wid >> 2;
    const int kq = (wid >> 1) & 1;
    const int nh = wid & 1;
    const uint32_t ZYH = sb, ZYL = sb + ZBUF, ZXH = sb + 2 * ZBUF;
    float z[2][2][4] = {};

#pragma unroll 1
    for (int h = 0; h < 2; h++) {
        __syncthreads();
#pragma unroll
        for (int p = 0; p < 4; p++) {
            int idx = p * 512 + tid;
            int row = idx >> 4, ch = idx & 15;
            cpasync16(ZXH + (uint32_t)(row * 136 + ch * 8) * 2,
                      g_Xh + (size_t)(m0 + row) * 1024 + n0 + h * 128 + ch * 8);
        }
        CP_COMMIT();
        if ((wn >> 2) == h) {
#pragma unroll
            for (int i = 0; i < 4; i++) {
                int r0 = wm * 64 + i * 16 + grp;
#pragma unroll
                for (int j = 0; j < 4; j++) {
                    int cl = (wn & 3) * 32 + j * 8 + tig * 2;
                    float v0 = d[i][j][0], v1 = d[i][j][1];
                    float v2 = d[i][j][2], v3 = d[i][j][3];
                    __half h0 = __float2half_rn(v0), h1 = __float2half_rn(v1);
                    __half h2 = __float2half_rn(v2), h3 = __float2half_rn(v3);
                    *(__half2*)(ysmem + ((r0) * 136 + cl) * 2) = __halves2half2(h0, h1);
                    *(__half2*)(ysmem + ((r0 + 8) * 136 + cl) * 2) = __halves2half2(h2, h3);
                    *(__half2*)(ysmem + ZBUF + ((r0) * 136 + cl) * 2) =
                        __halves2half2(__float2half_rn(v0 - __half2float(h0)),
                                       __float2half_rn(v1 - __half2float(h1)));
                    *(__half2*)(ysmem + ZBUF + ((r0 + 8) * 136 + cl) * 2) =
                        __halves2half2(__float2half_rn(v2 - __half2float(h2)),
                                       __float2half_rn(v3 - __half2float(h3)));
                }
            }
        }
        CP_WAIT(0);
        __syncthreads();
#pragma unroll
        for (int ksl = 0; ksl < 4; ksl++) {
            int kc = (kq * 4 + ksl) * 16;
            uint32_t ayh[2][4], ayl[2][4];
#pragma unroll
            for (int mi = 0; mi < 2; mi++) {
                uint32_t ao = (uint32_t)((bb * 32 + mi * 16 + (lane & 15)) * 136 +
                                         kc + (lane >> 4) * 8) * 2;
                ldsm4(ayh[mi], ZYH + ao);
                ldsm4(ayl[mi], ZYL + ao);
            }
            uint32_t bxh[4];
            uint32_t bo = (uint32_t)((bb * 32 + nh * 16 + (lane & 7) + (lane >> 4) * 8) * 136 +
                                     kc + ((lane >> 3) & 1) * 8) * 2;
            ldsm4(bxh, ZXH + bo);
#pragma unroll
            for (int mi = 0; mi < 2; mi++)
#pragma unroll
                for (int no = 0; no < 2; no++) {
                    mma_f16(z[mi][no], ayh[mi], bxh[no * 2], bxh[no * 2 + 1]);
                    mma_f16(z[mi][no], ayl[mi], bxh[no * 2], bxh[no * 2 + 1]);
                }
        }
    }
    {
        int b = blockIdx.y * 4 + bb;
        size_t base = ((size_t)(blockIdx.x * 2 + kq) * 1024 + b) * 1024;
#pragma unroll
        for (int mi = 0; mi < 2; mi++) {
            int i0 = mi * 16 + grp;
#pragma unroll
            for (int no = 0; no < 2; no++) {
                int j0 = nh * 16 + no * 8 + tig * 2;
                *(float2*)(g_Zpart + base + i0 * 32 + j0) =
                    make_float2(z[mi][no][0], z[mi][no][1]);
                *(float2*)(g_Zpart + base + (i0 + 8) * 32 + j0) =
                    make_float2(z[mi][no][2], z[mi][no][3]);
            }
        }
    }
}

// ====== kernel 6: RAG = [A;G] @ Xall^T (2-product, n-tile 128) ======
#define RPAD 72
#define R_A_BYTES (64 * RPAD * 2)               // 9216
#define R_B_BYTES (128 * RPAD * 2)              // 18432
#define RSTAGE (2 * R_A_BYTES + R_B_BYTES)      // 36864
#define RSMEM (2 * RSTAGE)                      // 73728

__device__ __forceinline__ void r_stage(uint32_t sb, int s, int n0, int k0, int tid) {
    uint32_t sa = sb + s * RSTAGE;
#pragma unroll
    for (int p = 0; p < 4; p++) {
        int idx = p * 256 + tid;   // 0..1023
        int bufl = idx >> 9;
        int t = idx & 511;
        int row = t >> 3, ch = t & 7;
        const __half* src = bufl ? g_AGl : g_AGh;
        cpasync16(sa + bufl * R_A_BYTES + (uint32_t)(row * RPAD + ch * 8) * 2,
                  src + (size_t)row * 1024 + k0 + ch * 8);
    }
#pragma unroll
    for (int p = 0; p < 4; p++) {
        int idx = p * 256 + tid;   // 0..1023 = 128 rows x 8 chunks
        int row = idx >> 3, ch = idx & 7;
        cpasync16(sa + 2 * R_A_BYTES + (uint32_t)(row * RPAD + ch * 8) * 2,
                  g_Xh + (size_t)(n0 + row) * 1024 + k0 + ch * 8);
    }
}

__global__ __launch_bounds__(256) void k_rag() {
    extern __shared__ __align__(16) char rsmem[];
    const uint32_t sb = smem_u32(rsmem);
    const int tid = threadIdx.x, lane = tid & 31, wid = tid >> 5;
    const int wm = wid >> 2, wn = wid & 3;   // 2 x 4 warps, warp tile 32x32
    const int n0 = blockIdx.x * 128;

    r_stage(sb, 0, n0, 0, tid);
    CP_COMMIT();

    float d[2][2][2][4] = {};
    const int aRowB = wm * 32 + (lane & 15);
    const int aCol = (lane >> 4) * 8;
    const int bRowB = wn * 32 + (lane & 7) + (lane >> 4) * 8;
    const int bCol = ((lane >> 3) & 1) * 8;

    for (int it = 0; it < 16; it++) {
        int nit = it + 1;
        if (nit < 16) {
            r_stage(sb, nit & 1, n0, nit * 64, tid);
            CP_COMMIT();
            CP_WAIT(1);
        } else {
            CP_WAIT(0);
        }
        __syncthreads();
        uint32_t st = sb + (it & 1) * RSTAGE;
        uint32_t sB = st + 2 * R_A_BYTES;
#pragma unroll
        for (int ks = 0; ks < 4; ks++) {
            int kc = ks * 16;
            uint32_t ah[2][4], al[2][4];
#pragma unroll
            for (int mi = 0; mi < 2; mi++) {
                uint32_t ao = (uint32_t)((aRowB + mi * 16) * RPAD + kc + aCol) * 2;
                ldsm4(ah[mi], st + ao);
                ldsm4(al[mi], st + R_A_BYTES + ao);
            }
            uint32_t bh[2][4];
#pragma unroll
            for (int nj = 0; nj < 2; nj++) {
                uint32_t bo = (uint32_t)((bRowB + nj * 16) * RPAD + kc + bCol) * 2;
                ldsm4(bh[nj], sB + bo);
            }
#pragma unroll
            for (int mi = 0; mi < 2; mi++)
#pragma unroll
                for (int nj = 0; nj < 2; nj++)
#pragma unroll
                    for (int s = 0; s < 2; s++) {
                        mma_f16(d[mi][nj][s], ah[mi], bh[nj][s * 2], bh[nj][s * 2 + 1]);
                        mma_f16(d[mi][nj][s], al[mi], bh[nj][s * 2], bh[nj][s * 2 + 1]);
                    }
        }
        __syncthreads();
    }
    const int grp = lane >> 2, tig = lane & 3;
#pragma unroll
    for (int mi = 0; mi < 2; mi++) {
        int r0 = wm * 32 + mi * 16 + grp, r1 = r0 + 8;
#pragma unroll
        for (int nj = 0; nj < 2; nj++)
#pragma unroll
            for (int s = 0; s < 2; s++) {
                int col = n0 + wn * 32 + nj * 16 + s * 8 + tig * 2;
                *(float2*)(g_RAG + (size_t)r0 * 32768 + col) =
                    make_float2(d[mi][nj][s][0], d[mi][nj][s][1]);
                *(float2*)(g_RAG + (size_t)r1 * 32768 + col) =
                    make_float2(d[mi][nj][s][2], d[mi][nj][s][3]);
            }
    }
}

// ----- kernel 7: reduce Z partials + softmax(dim=1) + final dot -----
__global__ __launch_bounds__(256) void k_attn2(const float* __restrict__ bfc,
                                               float* __restrict__ out) {
    __shared__ float Zs[32 * 33];
    __shared__ float As[32 * 33];
    __shared__ float Vs[32 * 33];
    __shared__ float wpart[8];
    int tid = threadIdx.x, b = blockIdx.x;
#pragma unroll
    for (int p = 0; p < 4; p++) {
        int idx = p * 256 + tid;
        int i = idx >> 5, j = idx & 31;
        float s = 0.f;
#pragma unroll
        for (int nb = 0; nb < 8; nb++)
            s += g_Zpart[((size_t)nb * 1024 + b) * 1024 + idx];
        Zs[i * 33 + j] = s;
        As[i * 33 + j] = g_RAG[(size_t)j * 32768 + b * 32 + i];
        Vs[i * 33 + j] = g_RAG[(size_t)(32 + i) * 32768 + b * 32 + j];
    }
    __syncthreads();
    int w = tid >> 5, lane = tid & 31;
    const float rscale = 0.022097086912079608f;  // 1/sqrt(2048)
    float local = 0.f;
#pragma unroll
    for (int q = 0; q < 4; q++) {
        int j = w * 4 + q;
        float lg = (Zs[lane * 33 + j] + As[lane * 33 + j] + g_c[lane * 32 + j]) * rscale;
        float mx = wredmax(lg);
        float ex = __expf(lg - mx);
        float sm = wredsum(ex);
        float contrib = (ex / sm) * (Vs[lane * 33 + j] + g_P[lane * 32 + j]);
        local += wredsum(contrib);
    }
    if (lane == 0) wpart[w] = local;
    __syncthreads();
    if (tid == 0) {
        float t = 0.f;
#pragma unroll
        for (int i = 0; i < 8; i++) t += wpart[i];
        out[b] = t + bfc[0];
    }
}

extern "C" void kernel_launch(void* const* d_in, const int* in_sizes, int n_in,
                              void* d_out, int out_size) {
    const float* x   = (const float*)d_in[0];
    const float* pe  = (const float*)d_in[1];
    const float* Wq  = (const float*)d_in[2];
    const float* bq  = (const float*)d_in[3];
    const float* Wk  = (const float*)d_in[4];
    const float* bk  = (const float*)d_in[5];
    const float* Wv  = (const float*)d_in[6];
    const float* bv  = (const float*)d_in[7];
    const float* Wfc = (const float*)d_in[8];
    const float* bfc = (const float*)d_in[9];
    float* out = (float*)d_out;

    cudaFuncSetAttribute(k_gemmM_mma, cudaFuncAttributeMaxDynamicSharedMemorySize, GSMEM);
    cudaFuncSetAttribute(k_skinny_mma, cudaFuncAttributeMaxDynamicSharedMemorySize, SKSMEM);
    cudaFuncSetAttribute(k_yz, cudaFuncAttributeMaxDynamicSharedMemorySize, YSMEM);
    cudaFuncSetAttribute(k_rag, cudaFuncAttributeMaxDynamicSharedMemorySize, RSMEM);

    k_prep<<<39744, 256>>>(x, pe, Wq, bq, Wk, bk, Wv, bv, Wfc);
    k_gemmM_mma<<<dim3(8, 8, 4), 256, GSMEM>>>();
    k_Mred<<<dim3(32, 32), dim3(32, 8)>>>();
    k_skinny_mma<<<dim3(8, 8, 3), 128, SKSMEM>>>();
    k_skred<<<384, 256>>>();
    k_small<<<dim3(32, 2), 256>>>(Wfc);
    k_yz<<<dim3(4, 256), 512, YSMEM>>>();
    k_rag<<<256, 256, RSMEM>>>();
    k_attn2<<<1024, 256>>>(bfc, out);
}

// round 13
// speedup vs baseline: 3.9591x; 1.0162x over previous
#include <cuda_runtime.h>
#include <cuda_bf16.h>
#include <cuda_fp16.h>
#include <math.h>
#include <stdint.h>

// B=1024, S=32, D=1024, D2=2048
// out[b]: Cq/Ck/Cv = pe@W2^T+b ; MhT=(Wq1^T Wk1)^T (bf16 3-split mma, split-K=4) ;
// A=Ck@Wq1 ; Bm=Cq@Wk1 ; G=Wf@Wv1 (bf16 3-split mma, split-K=8) ; c,P small ;
// k_yz: Y=X@M+Bm (fp16 mma, 128x256, warp tile 64x64) + Z partials (2-product) ;
// k_rag: [A;G]@Xall^T (2-product mma) ; k_attn2: reduce+softmax(dim=1)+dot.

// ----- static scratch -----
__device__ float g_Cq[65536], g_Ck[65536], g_Cv[65536];
__device__ float g_A[32768], g_Bm[32768], g_G[32768];
__device__ float g_part[786432];     // [3][8][32][1024] skinny split-K partials
__device__ float g_c[1024], g_P[1024];
__device__ float g_Zpart[8388608];   // gemmM split-K partials (4x1M), then Z partials [4][1024][32][32]
__device__ float g_RAG[2097152];     // [64][32768]
__device__ __align__(16) __half g_Xh[33554432];   // fp16 X [32768,1024]
__device__ __align__(16) __half g_MhT[1048576];   // fp16 M^T [f][e]
__device__ __align__(16) __half g_AGh[65536];     // [64][1024] = [A;G] hi
__device__ __align__(16) __half g_AGl[65536];
__device__ __align__(16) __nv_bfloat16 g_WqTh[2097152];  // [e][d2]
__device__ __align__(16) __nv_bfloat16 g_WqTl[2097152];
__device__ __align__(16) __nv_bfloat16 g_WkTh[2097152];
__device__ __align__(16) __nv_bfloat16 g_WkTl[2097152];
__device__ __align__(16) __nv_bfloat16 g_WvTh[2097152];
__device__ __align__(16) __nv_bfloat16 g_WvTl[2097152];
__device__ __align__(16) __nv_bfloat16 g_CqH[65536], g_CqL[65536];  // [32,2048]
__device__ __align__(16) __nv_bfloat16 g_CkH[65536], g_CkL[65536];
__device__ __align__(16) __nv_bfloat16 g_WfH[65536], g_WfL[65536];

__device__ __forceinline__ float wredsum(float v) {
#pragma unroll
    for (int o = 16; o; o >>= 1) v += __shfl_xor_sync(0xffffffffu, v, o);
    return v;
}
__device__ __forceinline__ float wredmax(float v) {
#pragma unroll
    for (int o = 16; o; o >>= 1) v = fmaxf(v, __shfl_xor_sync(0xffffffffu, v, o));
    return v;
}
__device__ __forceinline__ uint32_t smem_u32(const void* p) {
    uint32_t a;
    asm("{ .reg .u64 t; cvta.to.shared.u64 t, %1; cvt.u32.u64 %0, t; }" : "=r"(a) : "l"(p));
    return a;
}
__device__ __forceinline__ void ldsm4(uint32_t* r, uint32_t addr) {
    asm volatile("ldmatrix.sync.aligned.m8n8.x4.shared.b16 {%0,%1,%2,%3}, [%4];"
                 : "=r"(r[0]), "=r"(r[1]), "=r"(r[2]), "=r"(r[3]) : "r"(addr));
}
__device__ __forceinline__ void mma_bf16(float* d, const uint32_t* a,
                                         uint32_t b0, uint32_t b1) {
    asm volatile(
        "mma.sync.aligned.m16n8k16.row.col.f32.bf16.bf16.f32 "
        "{%0,%1,%2,%3}, {%4,%5,%6,%7}, {%8,%9}, {%0,%1,%2,%3};"
        : "+f"(d[0]), "+f"(d[1]), "+f"(d[2]), "+f"(d[3])
        : "r"(a[0]), "r"(a[1]), "r"(a[2]), "r"(a[3]), "r"(b0), "r"(b1));
}
__device__ __forceinline__ void mma_f16(float* d, const uint32_t* a,
                                        uint32_t b0, uint32_t b1) {
    asm volatile(
        "mma.sync.aligned.m16n8k16.row.col.f32.f16.f16.f32 "
        "{%0,%1,%2,%3}, {%4,%5,%6,%7}, {%8,%9}, {%0,%1,%2,%3};"
        : "+f"(d[0]), "+f"(d[1]), "+f"(d[2]), "+f"(d[3])
        : "r"(a[0]), "r"(a[1]), "r"(a[2]), "r"(a[3]), "r"(b0), "r"(b1));
}
__device__ __forceinline__ void cpasync16(uint32_t saddr, const void* gaddr) {
    asm volatile("cp.async.cg.shared.global [%0], [%1], 16;" :: "r"(saddr), "l"(gaddr));
}
#define CP_COMMIT() asm volatile("cp.async.commit_group;" ::: "memory")
#define CP_WAIT(n)  asm volatile("cp.async.wait_group %0;" :: "n"(n) : "memory")

// ===== merged prep =====
__global__ __launch_bounds__(256) void k_prep(const float* __restrict__ x,
                                              const float* __restrict__ pe,
                                              const float* __restrict__ Wq, const float* __restrict__ bq,
                                              const float* __restrict__ Wk, const float* __restrict__ bk,
                                              const float* __restrict__ Wv, const float* __restrict__ bv,
                                              const float* __restrict__ Wfc) {
    __shared__ float sh[32 * 33];
    int blk = blockIdx.x;
    int tid = threadIdx.x;
    if (blk < 768) {
        int bz = blk >> 8, bx = blk & 255;
        const float* W; const float* bias; float* out;
        if (bz == 0)      { W = Wq; bias = bq; out = g_Cq; }
        else if (bz == 1) { W = Wk; bias = bk; out = g_Ck; }
        else              { W = Wv; bias = bv; out = g_Cv; }
        int warp = tid >> 5, lane = tid & 31;
        int d2 = bx * 8 + warp;
        float acc[32];
#pragma unroll
        for (int i = 0; i < 32; i++) acc[i] = 0.f;
        for (int e0 = 0; e0 < 1024; e0 += 32) {
            __syncthreads();
#pragma unroll
            for (int p = 0; p < 4; p++) {
                int idx = p * 256 + tid;
                sh[(idx >> 5) * 33 + (idx & 31)] = pe[(idx >> 5) * 1024 + e0 + (idx & 31)];
            }
            __syncthreads();
            float wv = W[(size_t)d2 * 2048 + 1024 + e0 + lane];
#pragma unroll
            for (int i = 0; i < 32; i++) acc[i] += sh[i * 33 + lane] * wv;
        }
        float res = 0.f;
#pragma unroll
        for (int i = 0; i < 32; i++) {
            float r = wredsum(acc[i]);
            if (lane == i) res = r;
        }
        float val = res + bias[d2];
        out[lane * 2048 + d2] = val;
        if (bz < 2) {
            __nv_bfloat16 h = __float2bfloat16(val);
            __nv_bfloat16 l = __float2bfloat16(val - __bfloat162float(h));
            __nv_bfloat16* oh = bz ? g_CkH : g_CqH;
            __nv_bfloat16* ol = bz ? g_CkL : g_CqL;
            oh[lane * 2048 + d2] = h;
            ol[lane * 2048 + d2] = l;
        }
    } else if (blk < 6912) {
        int b2 = blk - 768;
        int bx = b2 & 31, by = (b2 >> 5) & 63, bz = b2 >> 11;
        const float* W = (bz == 0) ? Wq : (bz == 1) ? Wk : Wv;
        __nv_bfloat16* oh = (bz == 0) ? g_WqTh : (bz == 1) ? g_WkTh : g_WvTh;
        __nv_bfloat16* ol = (bz == 0) ? g_WqTl : (bz == 1) ? g_WkTl : g_WvTl;
        int xx = tid & 31, yy = tid >> 5;   // 32 x 8
#pragma unroll
        for (int i = 0; i < 32; i += 8)
            sh[(yy + i) * 33 + xx] = W[(size_t)(by * 32 + yy + i) * 2048 + bx * 32 + xx];
        __syncthreads();
#pragma unroll
        for (int i = 0; i < 32; i += 8) {
            float v = sh[xx * 33 + yy + i];
            __nv_bfloat16 h = __float2bfloat16(v);
            __nv_bfloat16 l = __float2bfloat16(v - __bfloat162float(h));
            size_t o = (size_t)(bx * 32 + yy + i) * 2048 + by * 32 + xx;
            oh[o] = h;
            ol[o] = l;
        }
    } else if (blk < 6976) {
        int idx4 = (blk - 6912) * 256 + tid;
        float4 v = *(const float4*)(Wfc + (size_t)idx4 * 4);
        float vv[4] = {v.x, v.y, v.z, v.w};
#pragma unroll
        for (int q = 0; q < 4; q++) {
            __nv_bfloat16 h = __float2bfloat16(vv[q]);
            g_WfH[idx4 * 4 + q] = h;
            g_WfL[idx4 * 4 + q] = __float2bfloat16(vv[q] - __bfloat162float(h));
        }
    } else {
        size_t i = ((size_t)(blk - 6976) * 256 + tid) * 4;
        float4 v = *(const float4*)(x + i);
        *(__half2*)(g_Xh + i)     = __halves2half2(__float2half_rn(v.x), __float2half_rn(v.y));
        *(__half2*)(g_Xh + i + 2) = __halves2half2(__float2half_rn(v.z), __float2half_rn(v.w));
    }
}

// ----- kernel 2: M partials = Wq1^T @ Wk1, bf16 3-product mma, split-K=4 -----
#define GPAD 72
#define GBUF (128 * GPAD * 2)
#define GSTAGE (4 * GBUF)        // 73728
#define GSMEM (3 * GSTAGE)       // 221184

__device__ __forceinline__ void g_stage(uint32_t sb, int s, int m0, int n0,
                                        int k0, int tid) {
    uint32_t sa = sb + s * GSTAGE;
#pragma unroll
    for (int p = 0; p < 16; p++) {
        int idx = p * 256 + tid;
        int buf = idx >> 10;
        int t = idx & 1023;
        int row = t >> 3, c = t & 7;
        const __nv_bfloat16* src =
            (buf == 0) ? g_WqTh : (buf == 1) ? g_WqTl : (buf == 2) ? g_WkTh : g_WkTl;
        int r0 = (buf < 2) ? m0 : n0;
        cpasync16(sa + buf * GBUF + (uint32_t)(row * GPAD + c * 8) * 2,
                  src + (size_t)(r0 + row) * 2048 + k0 + c * 8);
    }
}

__global__ __launch_bounds__(256, 1) void k_gemmM_mma() {
    extern __shared__ __align__(16) char gsmem[];
    const uint32_t sb = smem_u32(gsmem);
    const int tid = threadIdx.x, lane = tid & 31, wid = tid >> 5;
    const int wm = wid >> 2, wn = wid & 3;
    const int m0 = blockIdx.y * 128, n0 = blockIdx.x * 128;
    const int kbase = blockIdx.z * 512;

    g_stage(sb, 0, m0, n0, kbase, tid);
    CP_COMMIT();
    g_stage(sb, 1, m0, n0, kbase + 64, tid);
    CP_COMMIT();

    float d[4][4][4] = {};
    const int aRow = wm * 64 + (lane & 15);
    const int aCol = (lane >> 4) * 8;
    const int bRow = wn * 32 + (lane & 7) + (lane >> 4) * 8;
    const int bCol = ((lane >> 3) & 1) * 8;

    for (int it = 0; it < 8; it++) {
        if (it < 7) CP_WAIT(1); else CP_WAIT(0);
        __syncthreads();
        if (it + 2 < 8) {
            g_stage(sb, (it + 2) % 3, m0, n0, kbase + (it + 2) * 64, tid);
            CP_COMMIT();
        }
        uint32_t st = sb + (it % 3) * GSTAGE;
#pragma unroll
        for (int ks = 0; ks < 4; ks++) {
            int kc = ks * 16;
            uint32_t arh[4][4], arl[4][4];
#pragma unroll
            for (int i = 0; i < 4; i++) {
                uint32_t ao = (uint32_t)((aRow + i * 16) * GPAD + kc + aCol) * 2;
                ldsm4(arh[i], st + ao);
                ldsm4(arl[i], st + GBUF + ao);
            }
            uint32_t brh[2][4], brl[2][4];
#pragma unroll
            for (int j = 0; j < 2; j++) {
                uint32_t bo = (uint32_t)((bRow + j * 16) * GPAD + kc + bCol) * 2;
                ldsm4(brh[j], st + 2 * GBUF + bo);
                ldsm4(brl[j], st + 3 * GBUF + bo);
            }
#pragma unroll
            for (int i = 0; i < 4; i++)
#pragma unroll
                for (int j = 0; j < 4; j++) {
                    uint32_t h0 = brh[j >> 1][(j & 1) * 2], h1 = brh[j >> 1][(j & 1) * 2 + 1];
                    uint32_t l0 = brl[j >> 1][(j & 1) * 2], l1 = brl[j >> 1][(j & 1) * 2 + 1];
                    mma_bf16(d[i][j], arh[i], h0, h1);
                    mma_bf16(d[i][j], arh[i], l0, l1);
                    mma_bf16(d[i][j], arl[i], h0, h1);
                }
        }
    }
    float* outp = g_Zpart + (size_t)blockIdx.z * 1048576;
    const int grp = lane >> 2, tig = lane & 3;
    const int mb = m0 + wm * 64, nb = n0 + wn * 32;
#pragma unroll
    for (int i = 0; i < 4; i++) {
        int r0 = mb + i * 16 + grp, r1 = r0 + 8;
#pragma unroll
        for (int j = 0; j < 4; j++) {
            int cc = nb + j * 8 + tig * 2;
            *(float2*)(outp + (size_t)r0 * 1024 + cc) = make_float2(d[i][j][0], d[i][j][1]);
            *(float2*)(outp + (size_t)r1 * 1024 + cc) = make_float2(d[i][j][2], d[i][j][3]);
        }
    }
}

// ----- kernel 3: skinny gemms via bf16 3-product mma, split-K=8 -----
#define SK_AB (32 * 72 * 2)
#define SK_BB (128 * 72 * 2)
#define SKSTAGE (2 * SK_AB + 2 * SK_BB)
#define SKSMEM (2 * SKSTAGE)

__device__ __forceinline__ void sk_stage(uint32_t sb, int s,
                                         const __nv_bfloat16* __restrict__ Ah,
                                         const __nv_bfloat16* __restrict__ Al,
                                         const __nv_bfloat16* __restrict__ Bh,
                                         const __nv_bfloat16* __restrict__ Bl,
                                         int n0, int k0, int tid) {
    uint32_t sa = sb + s * SKSTAGE;
#pragma unroll
    for (int p = 0; p < 4; p++) {
        int idx = p * 128 + tid;
        int bufl = idx >> 8;
        int t = idx & 255;
        int row = t >> 3, ch = t & 7;
        const __nv_bfloat16* src = bufl ? Al : Ah;
        cpasync16(sa + bufl * SK_AB + (uint32_t)(row * 72 + ch * 8) * 2,
                  src + (size_t)row * 2048 + k0 + ch * 8);
    }
#pragma unroll
    for (int p = 0; p < 16; p++) {
        int idx = p * 128 + tid;
        int bufl = idx >> 10;
        int t = idx & 1023;
        int row = t >> 3, ch = t & 7;
        const __nv_bfloat16* src = bufl ? Bl : Bh;
        cpasync16(sa + 2 * SK_AB + bufl * SK_BB + (uint32_t)(row * 72 + ch * 8) * 2,
                  src + (size_t)(n0 + row) * 2048 + k0 + ch * 8);
    }
}

__global__ __launch_bounds__(128, 1) void k_skinny_mma() {
    extern __shared__ __align__(16) char sksmem[];
    const uint32_t sb = smem_u32(sksmem);
    const int tid = threadIdx.x, lane = tid & 31, wn = tid >> 5;
    const int z = blockIdx.z;
    const int n0 = blockIdx.x * 128;
    const int kbase = blockIdx.y * 256;

    const __nv_bfloat16* Ah = (z == 0) ? g_CkH : (z == 1) ? g_CqH : g_WfH;
    const __nv_bfloat16* Al = (z == 0) ? g_CkL : (z == 1) ? g_CqL : g_WfL;
    const __nv_bfloat16* Bh = (z == 0) ? g_WqTh : (z == 1) ? g_WkTh : g_WvTh;
    const __nv_bfloat16* Bl = (z == 0) ? g_WqTl : (z == 1) ? g_WkTl : g_WvTl;

    sk_stage(sb, 0, Ah, Al, Bh, Bl, n0, kbase, tid);
    CP_COMMIT();

    float d[2][2][2][4] = {};
    const int aRow = lane & 15;
    const int aCol = (lane >> 4) * 8;
    const int bRow = wn * 32 + (lane & 7) + (lane >> 4) * 8;
    const int bCol = ((lane >> 3) & 1) * 8;

    for (int it = 0; it < 4; it++) {
        CP_WAIT(0);
        __syncthreads();
        if (it + 1 < 4) {
            sk_stage(sb, (it + 1) & 1, Ah, Al, Bh, Bl, n0, kbase + (it + 1) * 64, tid);
            CP_COMMIT();
        }
        uint32_t st = sb + (it & 1) * SKSTAGE;
        uint32_t sB = st + 2 * SK_AB;
#pragma unroll
        for (int ks = 0; ks < 4; ks++) {
            int kc = ks * 16;
            uint32_t ah[2][4], al[2][4];
#pragma unroll
            for (int mi = 0; mi < 2; mi++) {
                uint32_t ao = (uint32_t)((mi * 16 + aRow) * 72 + kc + aCol) * 2;
                ldsm4(ah[mi], st + ao);
                ldsm4(al[mi], st + SK_AB + ao);
            }
            uint32_t bh[2][4], bl[2][4];
#pragma unroll
            for (int nj = 0; nj < 2; nj++) {
                uint32_t bo = (uint32_t)((bRow + nj * 16) * 72 + kc + bCol) * 2;
                ldsm4(bh[nj], sB + bo);
                ldsm4(bl[nj], sB + SK_BB + bo);
            }
#pragma unroll
            for (int mi = 0; mi < 2; mi++)
#pragma unroll
                for (int nj = 0; nj < 2; nj++)
#pragma unroll
                    for (int s = 0; s < 2; s++) {
                        mma_bf16(d[mi][nj][s], ah[mi], bh[nj][s * 2], bh[nj][s * 2 + 1]);
                        mma_bf16(d[mi][nj][s], ah[mi], bl[nj][s * 2], bl[nj][s * 2 + 1]);
                        mma_bf16(d[mi][nj][s], al[mi], bh[nj][s * 2], bh[nj][s * 2 + 1]);
                    }
        }
    }
    float* outp = g_part + ((size_t)z * 8 + blockIdx.y) * 32768;
    const int grp = lane >> 2, tig = lane & 3;
#pragma unroll
    for (int mi = 0; mi < 2; mi++) {
        int r0 = mi * 16 + grp, r1 = r0 + 8;
#pragma unroll
        for (int nj = 0; nj < 2; nj++)
#pragma unroll
            for (int s = 0; s < 2; s++) {
                int col = n0 + wn * 32 + nj * 16 + s * 8 + tig * 2;
                *(float2*)(outp + r0 * 1024 + col) = make_float2(d[mi][nj][s][0], d[mi][nj][s][1]);
                *(float2*)(outp + r1 * 1024 + col) = make_float2(d[mi][nj][s][2], d[mi][nj][s][3]);
            }
    }
}

// ----- k_mid: merged Mred | skred | small -----
__global__ __launch_bounds__(256) void k_mid(const float* __restrict__ Wfc) {
    __shared__ float t[32][33];
    __shared__ float wp[8][4];
    int blk = blockIdx.x, tid = threadIdx.x;
    if (blk < 1024) {
        // Mred: sum 4 gemmM split-K partials + transpose + fp16
        int bx = blk & 31, by = blk >> 5;
        int x = tid & 31, y = tid >> 5;   // 32 x 8
#pragma unroll
        for (int i = 0; i < 32; i += 8) {
            size_t o = (size_t)(by * 32 + y + i) * 1024 + bx * 32 + x;
            t[y + i][x] = g_Zpart[o] + g_Zpart[1048576 + o] +
                          g_Zpart[2097152 + o] + g_Zpart[3145728 + o];
        }
        __syncthreads();
#pragma unroll
        for (int i = 0; i < 32; i += 8)
            g_MhT[(size_t)(bx * 32 + y + i) * 1024 + by * 32 + x] = __float2half_rn(t[x][y + i]);
    } else if (blk < 1408) {
        // skred: reduce 8 skinny partials; emit AG fp16 hi/lo
        int idx = (blk - 1024) * 256 + tid;
        int z = idx >> 15;
        int r = idx & 32767;
        float s = 0.f;
#pragma unroll
        for (int kc = 0; kc < 8; kc++) s += g_part[((size_t)z * 8 + kc) * 32768 + r];
        float* out = (z == 0) ? g_A : (z == 1) ? g_Bm : g_G;
        out[r] = s;
        if (z != 1) {
            int agrow = (z == 0) ? (r >> 10) : 32 + (r >> 10);
            int col = r & 1023;
            __half h = __float2half_rn(s);
            g_AGh[agrow * 1024 + col] = h;
            g_AGl[agrow * 1024 + col] = __float2half_rn(s - __half2float(h));
        }
    } else {
        // small: c = Cq@Ck^T (by=0), P = Wf@Cv^T (by=1)
        int blkr = blk - 1408;   // 0..63
        int i = blkr & 31, by = blkr >> 5;
        const float* L; const float* R; float* out;
        if (by == 0) { L = g_Cq; R = g_Ck; out = g_c; }
        else         { L = Wfc;  R = g_Cv; out = g_P; }
        int warp = tid >> 5, lane = tid & 31;
        float acc[4] = {0.f, 0.f, 0.f, 0.f};
        for (int dd = lane; dd < 2048; dd += 32) {
            float lv = L[i * 2048 + dd];
#pragma unroll
            for (int q = 0; q < 4; q++) acc[q] += lv * R[(warp * 4 + q) * 2048 + dd];
        }
#pragma unroll
        for (int q = 0; q < 4; q++) {
            float r = wredsum(acc[q]);
            if (lane == 0) out[i * 32 + warp * 4 + q] = r;
        }
        (void)wp;
    }
}

// ====== kernel 5: fused Y=X@M+Bm (128x256, warp tile 64x64, 8 warps) + Z partials ======
#define YPAD2 136
#define YA_BYTES (128 * YPAD2 * 2)         // 34816
#define YB_BYTES (256 * YPAD2 * 2)         // 69632
#define YSTAGE (YA_BYTES + YB_BYTES)       // 104448
#define ZBUF (128 * 136 * 2)               // 34816
#define YSMEM (2 * YSTAGE)                 // 208896

__device__ __forceinline__ void y_stage(uint32_t sb, int s, int m0, int n0,
                                        int k0, int tid) {
    uint32_t sa = sb + s * YSTAGE;
#pragma unroll
    for (int p = 0; p < 24; p++) {
        int idx = p * 256 + tid;   // 0..6143
        if (idx < 2048) {          // A: 128 rows x 16 chunks
            int row = idx >> 4, c = idx & 15;
            cpasync16(sa + (uint32_t)(row * YPAD2 + c * 8) * 2,
                      g_Xh + (size_t)(m0 + row) * 1024 + k0 + c * 8);
        } else {                   // B: 256 rows x 16 chunks
            int t = idx - 2048;
            int row = t >> 4, c = t & 15;
            cpasync16(sa + YA_BYTES + (uint32_t)(row * YPAD2 + c * 8) * 2,
                      g_MhT + (size_t)(n0 + row) * 1024 + k0 + c * 8);
        }
    }
}

__global__ __launch_bounds__(256, 1) void k_yz() {
    extern __shared__ __align__(16) char ysmem[];
    const uint32_t sb = smem_u32(ysmem);
    const int tid = threadIdx.x, lane = tid & 31, wid = tid >> 5;
    const int wm = wid >> 2, wn = wid & 3;       // 2 x 4 warps, warp tile 64x64
    const int m0 = blockIdx.y * 128, n0 = blockIdx.x * 256;

    y_stage(sb, 0, m0, n0, 0, tid);
    CP_COMMIT();

    float d[4][8][4] = {};
    const int aRow = wm * 64 + (lane & 15);
    const int aCol = (lane >> 4) * 8;
    const int bRow = wn * 64 + (lane & 7) + (lane >> 4) * 8;
    const int bCol = ((lane >> 3) & 1) * 8;

    for (int it = 0; it < 8; it++) {
        CP_WAIT(0);
        __syncthreads();
        if (it + 1 < 8) {
            y_stage(sb, (it + 1) & 1, m0, n0, (it + 1) * 128, tid);
            CP_COMMIT();
        }
        uint32_t abase = sb + (it & 1) * YSTAGE;
        uint32_t bbase = abase + YA_BYTES;
#pragma unroll
        for (int ks = 0; ks < 8; ks++) {
            int kc = ks * 16;
            uint32_t ar[4][4];
#pragma unroll
            for (int i = 0; i < 4; i++)
                ldsm4(ar[i], abase + (uint32_t)((aRow + i * 16) * YPAD2 + kc + aCol) * 2);
            uint32_t br[4][4];
#pragma unroll
            for (int j = 0; j < 4; j++)
                ldsm4(br[j], bbase + (uint32_t)((bRow + j * 16) * YPAD2 + kc + bCol) * 2);
#pragma unroll
            for (int i = 0; i < 4; i++)
#pragma unroll
                for (int jj = 0; jj < 8; jj++)
                    mma_f16(d[i][jj], ar[i], br[jj >> 1][(jj & 1) * 2],
                            br[jj >> 1][(jj & 1) * 2 + 1]);
        }
    }
    __syncthreads();

    // ---- epilogue: add Bm, then fused Z partials (2-product: Yh,Yl x Xh) ----
    const int grp = lane >> 2, tig = lane & 3;
#pragma unroll
    for (int i = 0; i < 4; i++) {
        int r0 = wm * 64 + i * 16 + grp;
        int p0 = r0 & 31, p1 = (r0 + 8) & 31;
#pragma unroll
        for (int jj = 0; jj < 8; jj++) {
            int cc = n0 + wn * 64 + jj * 8 + tig * 2;
            float2 b0 = *(const float2*)(g_Bm + p0 * 1024 + cc);
            float2 b1 = *(const float2*)(g_Bm + p1 * 1024 + cc);
            d[i][jj][0] += b0.x; d[i][jj][1] += b0.y;
            d[i][jj][2] += b1.x; d[i][jj][3] += b1.y;
        }
    }

    const int bb = wid >> 1;   // local batch 0..3
    const int nh = wid & 1;    // n-half of Z columns (16 each)
    const uint32_t ZYH = sb, ZYL = sb + ZBUF, ZXH = sb + 2 * ZBUF;
    float z[2][2][4] = {};

#pragma unroll 1
    for (int h = 0; h < 2; h++) {
        __syncthreads();
        // load X hi tile [128 x 128] for f-cols n0+h*128..
#pragma unroll
        for (int p = 0; p < 8; p++) {
            int idx = p * 256 + tid;       // 0..2047 = 128 rows x 16 chunks
            int row = idx >> 4, ch = idx & 15;
            cpasync16(ZXH + (uint32_t)(row * 136 + ch * 8) * 2,
                      g_Xh + (size_t)(m0 + row) * 1024 + n0 + h * 128 + ch * 8);
        }
        CP_COMMIT();
        // write Y' hi/lo for this f-half (warps with n-range in half h: wn in {2h, 2h+1})
        if ((wn >> 1) == h) {
#pragma unroll
            for (int i = 0; i < 4; i++) {
                int r0 = wm * 64 + i * 16 + grp;
#pragma unroll
                for (int jj = 0; jj < 8; jj++) {
                    int cl = (wn & 1) * 64 + jj * 8 + tig * 2;   // 0..127
                    float v0 = d[i][jj][0], v1 = d[i][jj][1];
                    float v2 = d[i][jj][2], v3 = d[i][jj][3];
                    __half h0 = __float2half_rn(v0), h1 = __float2half_rn(v1);
                    __half h2 = __float2half_rn(v2), h3 = __float2half_rn(v3);
                    *(__half2*)(ysmem + ((r0) * 136 + cl) * 2) = __halves2half2(h0, h1);
                    *(__half2*)(ysmem + ((r0 + 8) * 136 + cl) * 2) = __halves2half2(h2, h3);
                    *(__half2*)(ysmem + ZBUF + ((r0) * 136 + cl) * 2) =
                        __halves2half2(__float2half_rn(v0 - __half2float(h0)),
                                       __float2half_rn(v1 - __half2float(h1)));
                    *(__half2*)(ysmem + ZBUF + ((r0 + 8) * 136 + cl) * 2) =
                        __halves2half2(__float2half_rn(v2 - __half2float(h2)),
                                       __float2half_rn(v3 - __half2float(h3)));
                }
            }
        }
        CP_WAIT(0);
        __syncthreads();
        // Z mma: batch bb, n-half nh (16 cols), full k=128 of this f-half
#pragma unroll
        for (int ksl = 0; ksl < 8; ksl++) {
            int kc = ksl * 16;
            uint32_t ayh[2][4], ayl[2][4];
#pragma unroll
            for (int mi = 0; mi < 2; mi++) {
                uint32_t ao = (uint32_t)((bb * 32 + mi * 16 + (lane & 15)) * 136 +
                                         kc + (lane >> 4) * 8) * 2;
                ldsm4(ayh[mi], ZYH + ao);
                ldsm4(ayl[mi], ZYL + ao);
            }
            uint32_t bxh[4];
            uint32_t bo = (uint32_t)((bb * 32 + nh * 16 + (lane & 7) + (lane >> 4) * 8) * 136 +
                                     kc + ((lane >> 3) & 1) * 8) * 2;
            ldsm4(bxh, ZXH + bo);
#pragma unroll
            for (int mi = 0; mi < 2; mi++)
#pragma unroll
                for (int no = 0; no < 2; no++) {
                    mma_f16(z[mi][no], ayh[mi], bxh[no * 2], bxh[no * 2 + 1]);
                    mma_f16(z[mi][no], ayl[mi], bxh[no * 2], bxh[no * 2 + 1]);
                }
        }
    }
    // store Z partials: slot = blockIdx.x (4 slots)
    {
        int b = blockIdx.y * 4 + bb;
        size_t base = ((size_t)blockIdx.x * 1024 + b) * 1024;
#pragma unroll
        for (int mi = 0; mi < 2; mi++) {
            int i0 = mi * 16 + grp;
#pragma unroll
            for (int no = 0; no < 2; no++) {
                int j0 = nh * 16 + no * 8 + tig * 2;
                *(float2*)(g_Zpart + base + i0 * 32 + j0) =
                    make_float2(z[mi][no][0], z[mi][no][1]);
                *(float2*)(g_Zpart + base + (i0 + 8) * 32 + j0) =
                    make_float2(z[mi][no][2], z[mi][no][3]);
            }
        }
    }
}

// ====== kernel 6: RAG = [A;G] @ Xall^T (2-product, n-tile 128) ======
#define RPAD 72
#define R_A_BYTES (64 * RPAD * 2)               // 9216
#define R_B_BYTES (128 * RPAD * 2)              // 18432
#define RSTAGE (2 * R_A_BYTES + R_B_BYTES)      // 36864
#define RSMEM (2 * RSTAGE)                      // 73728

__device__ __forceinline__ void r_stage(uint32_t sb, int s, int n0, int k0, int tid) {
    uint32_t sa = sb + s * RSTAGE;
#pragma unroll
    for (int p = 0; p < 4; p++) {
        int idx = p * 256 + tid;   // 0..1023
        int bufl = idx >> 9;
        int t = idx & 511;
        int row = t >> 3, ch = t & 7;
        const __half* src = bufl ? g_AGl : g_AGh;
        cpasync16(sa + bufl * R_A_BYTES + (uint32_t)(row * RPAD + ch * 8) * 2,
                  src + (size_t)row * 1024 + k0 + ch * 8);
    }
#pragma unroll
    for (int p = 0; p < 4; p++) {
        int idx = p * 256 + tid;   // 0..1023 = 128 rows x 8 chunks
        int row = idx >> 3, ch = idx & 7;
        cpasync16(sa + 2 * R_A_BYTES + (uint32_t)(row * RPAD + ch * 8) * 2,
                  g_Xh + (size_t)(n0 + row) * 1024 + k0 + ch * 8);
    }
}

__global__ __launch_bounds__(256) void k_rag() {
    extern __shared__ __align__(16) char rsmem[];
    const uint32_t sb = smem_u32(rsmem);
    const int tid = threadIdx.x, lane = tid & 31, wid = tid >> 5;
    const int wm = wid >> 2, wn = wid & 3;   // 2 x 4 warps, warp tile 32x32
    const int n0 = blockIdx.x * 128;

    r_stage(sb, 0, n0, 0, tid);
    CP_COMMIT();

    float d[2][2][2][4] = {};
    const int aRowB = wm * 32 + (lane & 15);
    const int aCol = (lane >> 4) * 8;
    const int bRowB = wn * 32 + (lane & 7) + (lane >> 4) * 8;
    const int bCol = ((lane >> 3) & 1) * 8;

    for (int it = 0; it < 16; it++) {
        CP_WAIT(0);
        __syncthreads();
        if (it + 1 < 16) {
            r_stage(sb, (it + 1) & 1, n0, (it + 1) * 64, tid);
            CP_COMMIT();
        }
        uint32_t st = sb + (it & 1) * RSTAGE;
        uint32_t sB = st + 2 * R_A_BYTES;
#pragma unroll
        for (int ks = 0; ks < 4; ks++) {
            int kc = ks * 16;
            uint32_t ah[2][4], al[2][4];
#pragma unroll
            for (int mi = 0; mi < 2; mi++) {
                uint32_t ao = (uint32_t)((aRowB + mi * 16) * RPAD + kc + aCol) * 2;
                ldsm4(ah[mi], st + ao);
                ldsm4(al[mi], st + R_A_BYTES + ao);
            }
            uint32_t bh[2][4];
#pragma unroll
            for (int nj = 0; nj < 2; nj++) {
                uint32_t bo = (uint32_t)((bRowB + nj * 16) * RPAD + kc + bCol) * 2;
                ldsm4(bh[nj], sB + bo);
            }
#pragma unroll
            for (int mi = 0; mi < 2; mi++)
#pragma unroll
                for (int nj = 0; nj < 2; nj++)
#pragma unroll
                    for (int s = 0; s < 2; s++) {
                        mma_f16(d[mi][nj][s], ah[mi], bh[nj][s * 2], bh[nj][s * 2 + 1]);
                        mma_f16(d[mi][nj][s], al[mi], bh[nj][s * 2], bh[nj][s * 2 + 1]);
                    }
        }
    }
    const int grp = lane >> 2, tig = lane & 3;
#pragma unroll
    for (int mi = 0; mi < 2; mi++) {
        int r0 = wm * 32 + mi * 16 + grp, r1 = r0 + 8;
#pragma unroll
        for (int nj = 0; nj < 2; nj++)
#pragma unroll
            for (int s = 0; s < 2; s++) {
                int col = n0 + wn * 32 + nj * 16 + s * 8 + tig * 2;
                *(float2*)(g_RAG + (size_t)r0 * 32768 + col) =
                    make_float2(d[mi][nj][s][0], d[mi][nj][s][1]);
                *(float2*)(g_RAG + (size_t)r1 * 32768 + col) =
                    make_float2(d[mi][nj][s][2], d[mi][nj][s][3]);
            }
    }
}

// ----- kernel 7: reduce Z partials + softmax(dim=1) + final dot -----
__global__ __launch_bounds__(256) void k_attn2(const float* __restrict__ bfc,
                                               float* __restrict__ out) {
    __shared__ float Zs[32 * 33];
    __shared__ float As[32 * 33];
    __shared__ float Vs[32 * 33];
    __shared__ float wpart[8];
    int tid = threadIdx.x, b = blockIdx.x;
#pragma unroll
    for (int p = 0; p < 4; p++) {
        int idx = p * 256 + tid;
        int i = idx >> 5, j = idx & 31;
        float s = 0.f;
#pragma unroll
        for (int nb = 0; nb < 4; nb++)
            s += g_Zpart[((size_t)nb * 1024 + b) * 1024 + idx];
        Zs[i * 33 + j] = s;
        As[i * 33 + j] = g_RAG[(size_t)j * 32768 + b * 32 + i];
        Vs[i * 33 + j] = g_RAG[(size_t)(32 + i) * 32768 + b * 32 + j];
    }
    __syncthreads();
    int w = tid >> 5, lane = tid & 31;
    const float rscale = 0.022097086912079608f;  // 1/sqrt(2048)
    float local = 0.f;
#pragma unroll
    for (int q = 0; q < 4; q++) {
        int j = w * 4 + q;
        float lg = (Zs[lane * 33 + j] + As[lane * 33 + j] + g_c[lane * 32 + j]) * rscale;
        float mx = wredmax(lg);
        float ex = __expf(lg - mx);
        float sm = wredsum(ex);
        float contrib = (ex / sm) * (Vs[lane * 33 + j] + g_P[lane * 32 + j]);
        local += wredsum(contrib);
    }
    if (lane == 0) wpart[w] = local;
    __syncthreads();
    if (tid == 0) {
        float t = 0.f;
#pragma unroll
        for (int i = 0; i < 8; i++) t += wpart[i];
        out[b] = t + bfc[0];
    }
}

extern "C" void kernel_launch(void* const* d_in, const int* in_sizes, int n_in,
                              void* d_out, int out_size) {
    const float* x   = (const float*)d_in[0];
    const float* pe  = (const float*)d_in[1];
    const float* Wq  = (const float*)d_in[2];
    const float* bq  = (const float*)d_in[3];
    const float* Wk  = (const float*)d_in[4];
    const float* bk  = (const float*)d_in[5];
    const float* Wv  = (const float*)d_in[6];
    const float* bv  = (const float*)d_in[7];
    const float* Wfc = (const float*)d_in[8];
    const float* bfc = (const float*)d_in[9];
    float* out = (float*)d_out;

    cudaFuncSetAttribute(k_gemmM_mma, cudaFuncAttributeMaxDynamicSharedMemorySize, GSMEM);
    cudaFuncSetAttribute(k_skinny_mma, cudaFuncAttributeMaxDynamicSharedMemorySize, SKSMEM);
    cudaFuncSetAttribute(k_yz, cudaFuncAttributeMaxDynamicSharedMemorySize, YSMEM);
    cudaFuncSetAttribute(k_rag, cudaFuncAttributeMaxDynamicSharedMemorySize, RSMEM);

    k_prep<<<39744, 256>>>(x, pe, Wq, bq, Wk, bk, Wv, bv, Wfc);
    k_gemmM_mma<<<dim3(8, 8, 4), 256, GSMEM>>>();
    k_skinny_mma<<<dim3(8, 8, 3), 128, SKSMEM>>>();
    k_mid<<<1472, 256>>>(Wfc);
    k_yz<<<dim3(4, 256), 256, YSMEM>>>();
    k_rag<<<256, 256, RSMEM>>>();
    k_attn2<<<1024, 256>>>(bfc, out);
}

// round 14
// speedup vs baseline: 3.9684x; 1.0023x over previous
#include <cuda_runtime.h>
#include <cuda_bf16.h>
#include <cuda_fp16.h>
#include <math.h>
#include <stdint.h>

// B=1024, S=32, D=1024, D2=2048
// 5-launch pipeline: k_prep -> k_gs (gemmM|skinny) -> k_mid (Mred|skred|small)
//                    -> k_yzrag (yz|rag) -> k_attn2

// ----- static scratch -----
__device__ float g_Cq[65536], g_Ck[65536], g_Cv[65536];
__device__ float g_A[32768], g_Bm[32768], g_G[32768];
__device__ float g_part[786432];     // [3][8][32][1024]
__device__ float g_c[1024], g_P[1024];
__device__ float g_Zpart[8388608];   // gemmM split-K partials (4x1M), then Z [4][1024][32][32]
__device__ float g_RAG[2097152];     // [64][32768]
__device__ __align__(16) __half g_Xh[33554432];
__device__ __align__(16) __half g_MhT[1048576];
__device__ __align__(16) __half g_AGh[65536];
__device__ __align__(16) __half g_AGl[65536];
__device__ __align__(16) __nv_bfloat16 g_WqTh[2097152];
__device__ __align__(16) __nv_bfloat16 g_WqTl[2097152];
__device__ __align__(16) __nv_bfloat16 g_WkTh[2097152];
__device__ __align__(16) __nv_bfloat16 g_WkTl[2097152];
__device__ __align__(16) __nv_bfloat16 g_WvTh[2097152];
__device__ __align__(16) __nv_bfloat16 g_WvTl[2097152];
__device__ __align__(16) __nv_bfloat16 g_CqH[65536], g_CqL[65536];
__device__ __align__(16) __nv_bfloat16 g_CkH[65536], g_CkL[65536];
__device__ __align__(16) __nv_bfloat16 g_WfH[65536], g_WfL[65536];

__device__ __forceinline__ float wredsum(float v) {
#pragma unroll
    for (int o = 16; o; o >>= 1) v += __shfl_xor_sync(0xffffffffu, v, o);
    return v;
}
__device__ __forceinline__ float wredmax(float v) {
#pragma unroll
    for (int o = 16; o; o >>= 1) v = fmaxf(v, __shfl_xor_sync(0xffffffffu, v, o));
    return v;
}
__device__ __forceinline__ uint32_t smem_u32(const void* p) {
    uint32_t a;
    asm("{ .reg .u64 t; cvta.to.shared.u64 t, %1; cvt.u32.u64 %0, t; }" : "=r"(a) : "l"(p));
    return a;
}
__device__ __forceinline__ void ldsm4(uint32_t* r, uint32_t addr) {
    asm volatile("ldmatrix.sync.aligned.m8n8.x4.shared.b16 {%0,%1,%2,%3}, [%4];"
                 : "=r"(r[0]), "=r"(r[1]), "=r"(r[2]), "=r"(r[3]) : "r"(addr));
}
__device__ __forceinline__ void mma_bf16(float* d, const uint32_t* a,
                                         uint32_t b0, uint32_t b1) {
    asm volatile(
        "mma.sync.aligned.m16n8k16.row.col.f32.bf16.bf16.f32 "
        "{%0,%1,%2,%3}, {%4,%5,%6,%7}, {%8,%9}, {%0,%1,%2,%3};"
        : "+f"(d[0]), "+f"(d[1]), "+f"(d[2]), "+f"(d[3])
        : "r"(a[0]), "r"(a[1]), "r"(a[2]), "r"(a[3]), "r"(b0), "r"(b1));
}
__device__ __forceinline__ void mma_f16(float* d, const uint32_t* a,
                                        uint32_t b0, uint32_t b1) {
    asm volatile(
        "mma.sync.aligned.m16n8k16.row.col.f32.f16.f16.f32 "
        "{%0,%1,%2,%3}, {%4,%5,%6,%7}, {%8,%9}, {%0,%1,%2,%3};"
        : "+f"(d[0]), "+f"(d[1]), "+f"(d[2]), "+f"(d[3])
        : "r"(a[0]), "r"(a[1]), "r"(a[2]), "r"(a[3]), "r"(b0), "r"(b1));
}
__device__ __forceinline__ void cpasync16(uint32_t saddr, const void* gaddr) {
    asm volatile("cp.async.cg.shared.global [%0], [%1], 16;" :: "r"(saddr), "l"(gaddr));
}
#define CP_COMMIT() asm volatile("cp.async.commit_group;" ::: "memory")
#define CP_WAIT(n)  asm volatile("cp.async.wait_group %0;" :: "n"(n) : "memory")

// ===== merged prep =====
__global__ __launch_bounds__(256) void k_prep(const float* __restrict__ x,
                                              const float* __restrict__ pe,
                                              const float* __restrict__ Wq, const float* __restrict__ bq,
                                              const float* __restrict__ Wk, const float* __restrict__ bk,
                                              const float* __restrict__ Wv, const float* __restrict__ bv,
                                              const float* __restrict__ Wfc) {
    __shared__ float sh[32 * 33];
    int blk = blockIdx.x;
    int tid = threadIdx.x;
    if (blk < 768) {
        int bz = blk >> 8, bx = blk & 255;
        const float* W; const float* bias; float* out;
        if (bz == 0)      { W = Wq; bias = bq; out = g_Cq; }
        else if (bz == 1) { W = Wk; bias = bk; out = g_Ck; }
        else              { W = Wv; bias = bv; out = g_Cv; }
        int warp = tid >> 5, lane = tid & 31;
        int d2 = bx * 8 + warp;
        float acc[32];
#pragma unroll
        for (int i = 0; i < 32; i++) acc[i] = 0.f;
        for (int e0 = 0; e0 < 1024; e0 += 32) {
            __syncthreads();
#pragma unroll
            for (int p = 0; p < 4; p++) {
                int idx = p * 256 + tid;
                sh[(idx >> 5) * 33 + (idx & 31)] = pe[(idx >> 5) * 1024 + e0 + (idx & 31)];
            }
            __syncthreads();
            float wv = W[(size_t)d2 * 2048 + 1024 + e0 + lane];
#pragma unroll
            for (int i = 0; i < 32; i++) acc[i] += sh[i * 33 + lane] * wv;
        }
        float res = 0.f;
#pragma unroll
        for (int i = 0; i < 32; i++) {
            float r = wredsum(acc[i]);
            if (lane == i) res = r;
        }
        float val = res + bias[d2];
        out[lane * 2048 + d2] = val;
        if (bz < 2) {
            __nv_bfloat16 h = __float2bfloat16(val);
            __nv_bfloat16 l = __float2bfloat16(val - __bfloat162float(h));
            __nv_bfloat16* oh = bz ? g_CkH : g_CqH;
            __nv_bfloat16* ol = bz ? g_CkL : g_CqL;
            oh[lane * 2048 + d2] = h;
            ol[lane * 2048 + d2] = l;
        }
    } else if (blk < 6912) {
        int b2 = blk - 768;
        int bx = b2 & 31, by = (b2 >> 5) & 63, bz = b2 >> 11;
        const float* W = (bz == 0) ? Wq : (bz == 1) ? Wk : Wv;
        __nv_bfloat16* oh = (bz == 0) ? g_WqTh : (bz == 1) ? g_WkTh : g_WvTh;
        __nv_bfloat16* ol = (bz == 0) ? g_WqTl : (bz == 1) ? g_WkTl : g_WvTl;
        int xx = tid & 31, yy = tid >> 5;
#pragma unroll
        for (int i = 0; i < 32; i += 8)
            sh[(yy + i) * 33 + xx] = W[(size_t)(by * 32 + yy + i) * 2048 + bx * 32 + xx];
        __syncthreads();
#pragma unroll
        for (int i = 0; i < 32; i += 8) {
            float v = sh[xx * 33 + yy + i];
            __nv_bfloat16 h = __float2bfloat16(v);
            __nv_bfloat16 l = __float2bfloat16(v - __bfloat162float(h));
            size_t o = (size_t)(bx * 32 + yy + i) * 2048 + by * 32 + xx;
            oh[o] = h;
            ol[o] = l;
        }
    } else if (blk < 6976) {
        int idx4 = (blk - 6912) * 256 + tid;
        float4 v = *(const float4*)(Wfc + (size_t)idx4 * 4);
        float vv[4] = {v.x, v.y, v.z, v.w};
#pragma unroll
        for (int q = 0; q < 4; q++) {
            __nv_bfloat16 h = __float2bfloat16(vv[q]);
            g_WfH[idx4 * 4 + q] = h;
            g_WfL[idx4 * 4 + q] = __float2bfloat16(vv[q] - __bfloat162float(h));
        }
    } else {
        size_t i = ((size_t)(blk - 6976) * 256 + tid) * 4;
        float4 v = *(const float4*)(x + i);
        *(__half2*)(g_Xh + i)     = __halves2half2(__float2half_rn(v.x), __float2half_rn(v.y));
        *(__half2*)(g_Xh + i + 2) = __halves2half2(__float2half_rn(v.z), __float2half_rn(v.w));
    }
}

// ===== k_gs: merged gemmM (blk<256) | skinny (blk 256..447) =====
#define GPAD 72
#define GBUF (128 * GPAD * 2)
#define GSTAGE (4 * GBUF)        // 73728
#define GSMEM (3 * GSTAGE)       // 221184
#define SK_AB (32 * 72 * 2)
#define SK_BB (128 * 72 * 2)
#define SKSTAGE (2 * SK_AB + 2 * SK_BB)   // 46080

__device__ __forceinline__ void g_stage(uint32_t sb, int s, int m0, int n0,
                                        int k0, int tid) {
    uint32_t sa = sb + s * GSTAGE;
#pragma unroll
    for (int p = 0; p < 16; p++) {
        int idx = p * 256 + tid;
        int buf = idx >> 10;
        int t = idx & 1023;
        int row = t >> 3, c = t & 7;
        const __nv_bfloat16* src =
            (buf == 0) ? g_WqTh : (buf == 1) ? g_WqTl : (buf == 2) ? g_WkTh : g_WkTl;
        int r0 = (buf < 2) ? m0 : n0;
        cpasync16(sa + buf * GBUF + (uint32_t)(row * GPAD + c * 8) * 2,
                  src + (size_t)(r0 + row) * 2048 + k0 + c * 8);
    }
}

__device__ __forceinline__ void sk_stage256(uint32_t sb, int s,
                                            const __nv_bfloat16* __restrict__ Ah,
                                            const __nv_bfloat16* __restrict__ Al,
                                            const __nv_bfloat16* __restrict__ Bh,
                                            const __nv_bfloat16* __restrict__ Bl,
                                            int n0, int k0, int tid) {
    uint32_t sa = sb + s * SKSTAGE;
#pragma unroll
    for (int p = 0; p < 2; p++) {
        int idx = p * 256 + tid;           // 0..511
        int bufl = idx >> 8;
        int t = idx & 255;
        int row = t >> 3, ch = t & 7;
        const __nv_bfloat16* src = bufl ? Al : Ah;
        cpasync16(sa + bufl * SK_AB + (uint32_t)(row * 72 + ch * 8) * 2,
                  src + (size_t)row * 2048 + k0 + ch * 8);
    }
#pragma unroll
    for (int p = 0; p < 8; p++) {
        int idx = p * 256 + tid;           // 0..2047
        int bufl = idx >> 10;
        int t = idx & 1023;
        int row = t >> 3, ch = t & 7;
        const __nv_bfloat16* src = bufl ? Bl : Bh;
        cpasync16(sa + 2 * SK_AB + bufl * SK_BB + (uint32_t)(row * 72 + ch * 8) * 2,
                  src + (size_t)(n0 + row) * 2048 + k0 + ch * 8);
    }
}

__global__ __launch_bounds__(256, 1) void k_gs() {
    extern __shared__ __align__(16) char gsmem[];
    const uint32_t sb = smem_u32(gsmem);
    const int tid = threadIdx.x, lane = tid & 31, wid = tid >> 5;
    int blk = blockIdx.x;
    if (blk < 256) {
        // ---- gemmM: M partials = Wq1^T @ Wk1, split-K=4 ----
        const int wm = wid >> 2, wn = wid & 3;
        const int m0 = ((blk >> 3) & 7) * 128, n0 = (blk & 7) * 128;
        const int kbase = (blk >> 6) * 512;

        g_stage(sb, 0, m0, n0, kbase, tid);
        CP_COMMIT();
        g_stage(sb, 1, m0, n0, kbase + 64, tid);
        CP_COMMIT();

        float d[4][4][4] = {};
        const int aRow = wm * 64 + (lane & 15);
        const int aCol = (lane >> 4) * 8;
        const int bRow = wn * 32 + (lane & 7) + (lane >> 4) * 8;
        const int bCol = ((lane >> 3) & 1) * 8;

        for (int it = 0; it < 8; it++) {
            if (it < 7) CP_WAIT(1); else CP_WAIT(0);
            __syncthreads();
            if (it + 2 < 8) {
                g_stage(sb, (it + 2) % 3, m0, n0, kbase + (it + 2) * 64, tid);
                CP_COMMIT();
            }
            uint32_t st = sb + (it % 3) * GSTAGE;
#pragma unroll
            for (int ks = 0; ks < 4; ks++) {
                int kc = ks * 16;
                uint32_t arh[4][4], arl[4][4];
#pragma unroll
                for (int i = 0; i < 4; i++) {
                    uint32_t ao = (uint32_t)((aRow + i * 16) * GPAD + kc + aCol) * 2;
                    ldsm4(arh[i], st + ao);
                    ldsm4(arl[i], st + GBUF + ao);
                }
                uint32_t brh[2][4], brl[2][4];
#pragma unroll
                for (int j = 0; j < 2; j++) {
                    uint32_t bo = (uint32_t)((bRow + j * 16) * GPAD + kc + bCol) * 2;
                    ldsm4(brh[j], st + 2 * GBUF + bo);
                    ldsm4(brl[j], st + 3 * GBUF + bo);
                }
#pragma unroll
                for (int i = 0; i < 4; i++)
#pragma unroll
                    for (int j = 0; j < 4; j++) {
                        uint32_t h0 = brh[j >> 1][(j & 1) * 2], h1 = brh[j >> 1][(j & 1) * 2 + 1];
                        uint32_t l0 = brl[j >> 1][(j & 1) * 2], l1 = brl[j >> 1][(j & 1) * 2 + 1];
                        mma_bf16(d[i][j], arh[i], h0, h1);
                        mma_bf16(d[i][j], arh[i], l0, l1);
                        mma_bf16(d[i][j], arl[i], h0, h1);
                    }
            }
        }
        float* outp = g_Zpart + (size_t)(blk >> 6) * 1048576;
        const int grp = lane >> 2, tig = lane & 3;
        const int mb = m0 + wm * 64, nb = n0 + wn * 32;
#pragma unroll
        for (int i = 0; i < 4; i++) {
            int r0 = mb + i * 16 + grp, r1 = r0 + 8;
#pragma unroll
            for (int j = 0; j < 4; j++) {
                int cc = nb + j * 8 + tig * 2;
                *(float2*)(outp + (size_t)r0 * 1024 + cc) = make_float2(d[i][j][0], d[i][j][1]);
                *(float2*)(outp + (size_t)r1 * 1024 + cc) = make_float2(d[i][j][2], d[i][j][3]);
            }
        }
    } else {
        // ---- skinny: split-K=8, 256 threads stage / 4 warps compute ----
        int s2 = blk - 256;
        const int z = s2 >> 6;
        const int n0 = (s2 & 7) * 128;
        const int kbase = ((s2 >> 3) & 7) * 256;

        const __nv_bfloat16* Ah = (z == 0) ? g_CkH : (z == 1) ? g_CqH : g_WfH;
        const __nv_bfloat16* Al = (z == 0) ? g_CkL : (z == 1) ? g_CqL : g_WfL;
        const __nv_bfloat16* Bh = (z == 0) ? g_WqTh : (z == 1) ? g_WkTh : g_WvTh;
        const __nv_bfloat16* Bl = (z == 0) ? g_WqTl : (z == 1) ? g_WkTl : g_WvTl;

        sk_stage256(sb, 0, Ah, Al, Bh, Bl, n0, kbase, tid);
        CP_COMMIT();

        float d[2][2][2][4] = {};
        const int wn = wid;   // only wid<4 computes
        const int aRow = lane & 15;
        const int aCol = (lane >> 4) * 8;
        const int bRow = (wn & 3) * 32 + (lane & 7) + (lane >> 4) * 8;
        const int bCol = ((lane >> 3) & 1) * 8;

        for (int it = 0; it < 4; it++) {
            CP_WAIT(0);
            __syncthreads();
            if (it + 1 < 4) {
                sk_stage256(sb, (it + 1) & 1, Ah, Al, Bh, Bl, n0, kbase + (it + 1) * 64, tid);
                CP_COMMIT();
            }
            if (wid < 4) {
                uint32_t st = sb + (it & 1) * SKSTAGE;
                uint32_t sB = st + 2 * SK_AB;
#pragma unroll
                for (int ks = 0; ks < 4; ks++) {
                    int kc = ks * 16;
                    uint32_t ah[2][4], al[2][4];
#pragma unroll
                    for (int mi = 0; mi < 2; mi++) {
                        uint32_t ao = (uint32_t)((mi * 16 + aRow) * 72 + kc + aCol) * 2;
                        ldsm4(ah[mi], st + ao);
                        ldsm4(al[mi], st + SK_AB + ao);
                    }
                    uint32_t bh[2][4], bl[2][4];
#pragma unroll
                    for (int nj = 0; nj < 2; nj++) {
                        uint32_t bo = (uint32_t)((bRow + nj * 16) * 72 + kc + bCol) * 2;
                        ldsm4(bh[nj], sB + bo);
                        ldsm4(bl[nj], sB + SK_BB + bo);
                    }
#pragma unroll
                    for (int mi = 0; mi < 2; mi++)
#pragma unroll
                        for (int nj = 0; nj < 2; nj++)
#pragma unroll
                            for (int s = 0; s < 2; s++) {
                                mma_bf16(d[mi][nj][s], ah[mi], bh[nj][s * 2], bh[nj][s * 2 + 1]);
                                mma_bf16(d[mi][nj][s], ah[mi], bl[nj][s * 2], bl[nj][s * 2 + 1]);
                                mma_bf16(d[mi][nj][s], al[mi], bh[nj][s * 2], bh[nj][s * 2 + 1]);
                            }
                }
            }
            __syncthreads();
        }
        if (wid < 4) {
            float* outp = g_part + ((size_t)z * 8 + ((s2 >> 3) & 7)) * 32768;
            const int grp = lane >> 2, tig = lane & 3;
#pragma unroll
            for (int mi = 0; mi < 2; mi++) {
                int r0 = mi * 16 + grp, r1 = r0 + 8;
#pragma unroll
                for (int nj = 0; nj < 2; nj++)
#pragma unroll
                    for (int s = 0; s < 2; s++) {
                        int col = n0 + (wn & 3) * 32 + nj * 16 + s * 8 + tig * 2;
                        *(float2*)(outp + r0 * 1024 + col) =
                            make_float2(d[mi][nj][s][0], d[mi][nj][s][1]);
                        *(float2*)(outp + r1 * 1024 + col) =
                            make_float2(d[mi][nj][s][2], d[mi][nj][s][3]);
                    }
            }
        }
    }
}

// ----- k_mid: merged Mred | skred | small -----
__global__ __launch_bounds__(256) void k_mid(const float* __restrict__ Wfc) {
    __shared__ float t[32][33];
    int blk = blockIdx.x, tid = threadIdx.x;
    if (blk < 1024) {
        int bx = blk & 31, by = blk >> 5;
        int x = tid & 31, y = tid >> 5;
#pragma unroll
        for (int i = 0; i < 32; i += 8) {
            size_t o = (size_t)(by * 32 + y + i) * 1024 + bx * 32 + x;
            t[y + i][x] = g_Zpart[o] + g_Zpart[1048576 + o] +
                          g_Zpart[2097152 + o] + g_Zpart[3145728 + o];
        }
        __syncthreads();
#pragma unroll
        for (int i = 0; i < 32; i += 8)
            g_MhT[(size_t)(bx * 32 + y + i) * 1024 + by * 32 + x] = __float2half_rn(t[x][y + i]);
    } else if (blk < 1408) {
        int idx = (blk - 1024) * 256 + tid;
        int z = idx >> 15;
        int r = idx & 32767;
        float s = 0.f;
#pragma unroll
        for (int kc = 0; kc < 8; kc++) s += g_part[((size_t)z * 8 + kc) * 32768 + r];
        float* out = (z == 0) ? g_A : (z == 1) ? g_Bm : g_G;
        out[r] = s;
        if (z != 1) {
            int agrow = (z == 0) ? (r >> 10) : 32 + (r >> 10);
            int col = r & 1023;
            __half h = __float2half_rn(s);
            g_AGh[agrow * 1024 + col] = h;
            g_AGl[agrow * 1024 + col] = __float2half_rn(s - __half2float(h));
        }
    } else {
        int blkr = blk - 1408;
        int i = blkr & 31, by = blkr >> 5;
        const float* L; const float* R; float* out;
        if (by == 0) { L = g_Cq; R = g_Ck; out = g_c; }
        else         { L = Wfc;  R = g_Cv; out = g_P; }
        int warp = tid >> 5, lane = tid & 31;
        float acc[4] = {0.f, 0.f, 0.f, 0.f};
        for (int dd = lane; dd < 2048; dd += 32) {
            float lv = L[i * 2048 + dd];
#pragma unroll
            for (int q = 0; q < 4; q++) acc[q] += lv * R[(warp * 4 + q) * 2048 + dd];
        }
#pragma unroll
        for (int q = 0; q < 4; q++) {
            float r = wredsum(acc[q]);
            if (lane == 0) out[i * 32 + warp * 4 + q] = r;
        }
    }
}

// ====== k_yzrag: merged yz (blk<1024) | rag (blk 1024..1279) ======
#define YPAD2 136
#define YA_BYTES (128 * YPAD2 * 2)         // 34816
#define YB_BYTES (256 * YPAD2 * 2)         // 69632
#define YSTAGE (YA_BYTES + YB_BYTES)       // 104448
#define ZBUF (128 * 136 * 2)               // 34816
#define YSMEM (2 * YSTAGE)                 // 208896
#define RPAD 72
#define R_A_BYTES (64 * RPAD * 2)          // 9216
#define R_B_BYTES (128 * RPAD * 2)         // 18432
#define RSTAGE (2 * R_A_BYTES + R_B_BYTES) // 36864

__device__ __forceinline__ void y_stage(uint32_t sb, int s, int m0, int n0,
                                        int k0, int tid) {
    uint32_t sa = sb + s * YSTAGE;
#pragma unroll
    for (int p = 0; p < 24; p++) {
        int idx = p * 256 + tid;
        if (idx < 2048) {
            int row = idx >> 4, c = idx & 15;
            cpasync16(sa + (uint32_t)(row * YPAD2 + c * 8) * 2,
                      g_Xh + (size_t)(m0 + row) * 1024 + k0 + c * 8);
        } else {
            int t = idx - 2048;
            int row = t >> 4, c = t & 15;
            cpasync16(sa + YA_BYTES + (uint32_t)(row * YPAD2 + c * 8) * 2,
                      g_MhT + (size_t)(n0 + row) * 1024 + k0 + c * 8);
        }
    }
}
__device__ __forceinline__ void r_stage(uint32_t sb, int s, int n0, int k0, int tid) {
    uint32_t sa = sb + s * RSTAGE;
#pragma unroll
    for (int p = 0; p < 4; p++) {
        int idx = p * 256 + tid;
        int bufl = idx >> 9;
        int t = idx & 511;
        int row = t >> 3, ch = t & 7;
        const __half* src = bufl ? g_AGl : g_AGh;
        cpasync16(sa + bufl * R_A_BYTES + (uint32_t)(row * RPAD + ch * 8) * 2,
                  src + (size_t)row * 1024 + k0 + ch * 8);
    }
#pragma unroll
    for (int p = 0; p < 4; p++) {
        int idx = p * 256 + tid;
        int row = idx >> 3, ch = idx & 7;
        cpasync16(sa + 2 * R_A_BYTES + (uint32_t)(row * RPAD + ch * 8) * 2,
                  g_Xh + (size_t)(n0 + row) * 1024 + k0 + ch * 8);
    }
}

__global__ __launch_bounds__(256, 1) void k_yzrag() {
    extern __shared__ __align__(16) char ysmem[];
    const uint32_t sb = smem_u32(ysmem);
    const int tid = threadIdx.x, lane = tid & 31, wid = tid >> 5;
    int blk = blockIdx.x;

    if (blk < 1024) {
        // ---- yz: Y=X@M+Bm + Z partials ----
        const int wm = wid >> 2, wn = wid & 3;
        const int m0 = (blk >> 2) * 128, n0 = (blk & 3) * 256;

        y_stage(sb, 0, m0, n0, 0, tid);
        CP_COMMIT();

        float d[4][8][4] = {};
        const int aRow = wm * 64 + (lane & 15);
        const int aCol = (lane >> 4) * 8;
        const int bRow = wn * 64 + (lane & 7) + (lane >> 4) * 8;
        const int bCol = ((lane >> 3) & 1) * 8;

        for (int it = 0; it < 8; it++) {
            CP_WAIT(0);
            __syncthreads();
            if (it + 1 < 8) {
                y_stage(sb, (it + 1) & 1, m0, n0, (it + 1) * 128, tid);
                CP_COMMIT();
            }
            uint32_t abase = sb + (it & 1) * YSTAGE;
            uint32_t bbase = abase + YA_BYTES;
#pragma unroll
            for (int ks = 0; ks < 8; ks++) {
                int kc = ks * 16;
                uint32_t ar[4][4];
#pragma unroll
                for (int i = 0; i < 4; i++)
                    ldsm4(ar[i], abase + (uint32_t)((aRow + i * 16) * YPAD2 + kc + aCol) * 2);
                uint32_t br[4][4];
#pragma unroll
                for (int j = 0; j < 4; j++)
                    ldsm4(br[j], bbase + (uint32_t)((bRow + j * 16) * YPAD2 + kc + bCol) * 2);
#pragma unroll
                for (int i = 0; i < 4; i++)
#pragma unroll
                    for (int jj = 0; jj < 8; jj++)
                        mma_f16(d[i][jj], ar[i], br[jj >> 1][(jj & 1) * 2],
                                br[jj >> 1][(jj & 1) * 2 + 1]);
            }
        }
        __syncthreads();

        const int grp = lane >> 2, tig = lane & 3;
#pragma unroll
        for (int i = 0; i < 4; i++) {
            int r0 = wm * 64 + i * 16 + grp;
            int p0 = r0 & 31, p1 = (r0 + 8) & 31;
#pragma unroll
            for (int jj = 0; jj < 8; jj++) {
                int cc = n0 + wn * 64 + jj * 8 + tig * 2;
                float2 b0 = *(const float2*)(g_Bm + p0 * 1024 + cc);
                float2 b1 = *(const float2*)(g_Bm + p1 * 1024 + cc);
                d[i][jj][0] += b0.x; d[i][jj][1] += b0.y;
                d[i][jj][2] += b1.x; d[i][jj][3] += b1.y;
            }
        }

        const int bb = wid >> 1;
        const int nh = wid & 1;
        const uint32_t ZYH = sb, ZYL = sb + ZBUF, ZXH = sb + 2 * ZBUF;
        float z[2][2][4] = {};

#pragma unroll 1
        for (int h = 0; h < 2; h++) {
            __syncthreads();
#pragma unroll
            for (int p = 0; p < 8; p++) {
                int idx = p * 256 + tid;
                int row = idx >> 4, ch = idx & 15;
                cpasync16(ZXH + (uint32_t)(row * 136 + ch * 8) * 2,
                          g_Xh + (size_t)(m0 + row) * 1024 + n0 + h * 128 + ch * 8);
            }
            CP_COMMIT();
            if ((wn >> 1) == h) {
#pragma unroll
                for (int i = 0; i < 4; i++) {
                    int r0 = wm * 64 + i * 16 + grp;
#pragma unroll
                    for (int jj = 0; jj < 8; jj++) {
                        int cl = (wn & 1) * 64 + jj * 8 + tig * 2;
                        float v0 = d[i][jj][0], v1 = d[i][jj][1];
                        float v2 = d[i][jj][2], v3 = d[i][jj][3];
                        __half h0 = __float2half_rn(v0), h1 = __float2half_rn(v1);
                        __half h2 = __float2half_rn(v2), h3 = __float2half_rn(v3);
                        *(__half2*)(ysmem + ((r0) * 136 + cl) * 2) = __halves2half2(h0, h1);
                        *(__half2*)(ysmem + ((r0 + 8) * 136 + cl) * 2) = __halves2half2(h2, h3);
                        *(__half2*)(ysmem + ZBUF + ((r0) * 136 + cl) * 2) =
                            __halves2half2(__float2half_rn(v0 - __half2float(h0)),
                                           __float2half_rn(v1 - __half2float(h1)));
                        *(__half2*)(ysmem + ZBUF + ((r0 + 8) * 136 + cl) * 2) =
                            __halves2half2(__float2half_rn(v2 - __half2float(h2)),
                                           __float2half_rn(v3 - __half2float(h3)));
                    }
                }
            }
            CP_WAIT(0);
            __syncthreads();
#pragma unroll
            for (int ksl = 0; ksl < 8; ksl++) {
                int kc = ksl * 16;
                uint32_t ayh[2][4], ayl[2][4];
#pragma unroll
                for (int mi = 0; mi < 2; mi++) {
                    uint32_t ao = (uint32_t)((bb * 32 + mi * 16 + (lane & 15)) * 136 +
                                             kc + (lane >> 4) * 8) * 2;
                    ldsm4(ayh[mi], ZYH + ao);
                    ldsm4(ayl[mi], ZYL + ao);
                }
                uint32_t bxh[4];
                uint32_t bo = (uint32_t)((bb * 32 + nh * 16 + (lane & 7) + (lane >> 4) * 8) * 136 +
                                         kc + ((lane >> 3) & 1) * 8) * 2;
                ldsm4(bxh, ZXH + bo);
#pragma unroll
                for (int mi = 0; mi < 2; mi++)
#pragma unroll
                    for (int no = 0; no < 2; no++) {
                        mma_f16(z[mi][no], ayh[mi], bxh[no * 2], bxh[no * 2 + 1]);
                        mma_f16(z[mi][no], ayl[mi], bxh[no * 2], bxh[no * 2 + 1]);
                    }
            }
        }
        {
            int b = (blk >> 2) * 4 + bb;
            size_t base = ((size_t)(blk & 3) * 1024 + b) * 1024;
#pragma unroll
            for (int mi = 0; mi < 2; mi++) {
                int i0 = mi * 16 + grp;
#pragma unroll
                for (int no = 0; no < 2; no++) {
                    int j0 = nh * 16 + no * 8 + tig * 2;
                    *(float2*)(g_Zpart + base + i0 * 32 + j0) =
                        make_float2(z[mi][no][0], z[mi][no][1]);
                    *(float2*)(g_Zpart + base + (i0 + 8) * 32 + j0) =
                        make_float2(z[mi][no][2], z[mi][no][3]);
                }
            }
        }
    } else {
        // ---- rag: [A;G] @ Xall^T (2-product), n-tile 128 ----
        const int wm = wid >> 2, wn = wid & 3;
        const int n0 = (blk - 1024) * 128;

        r_stage(sb, 0, n0, 0, tid);
        CP_COMMIT();

        float d[2][2][2][4] = {};
        const int aRowB = wm * 32 + (lane & 15);
        const int aCol = (lane >> 4) * 8;
        const int bRowB = wn * 32 + (lane & 7) + (lane >> 4) * 8;
        const int bCol = ((lane >> 3) & 1) * 8;

        for (int it = 0; it < 16; it++) {
            CP_WAIT(0);
            __syncthreads();
            if (it + 1 < 16) {
                r_stage(sb, (it + 1) & 1, n0, (it + 1) * 64, tid);
                CP_COMMIT();
            }
            uint32_t st = sb + (it & 1) * RSTAGE;
            uint32_t sB = st + 2 * R_A_BYTES;
#pragma unroll
            for (int ks = 0; ks < 4; ks++) {
                int kc = ks * 16;
                uint32_t ah[2][4], al[2][4];
#pragma unroll
                for (int mi = 0; mi < 2; mi++) {
                    uint32_t ao = (uint32_t)((aRowB + mi * 16) * RPAD + kc + aCol) * 2;
                    ldsm4(ah[mi], st + ao);
                    ldsm4(al[mi], st + R_A_BYTES + ao);
                }
                uint32_t bh[2][4];
#pragma unroll
                for (int nj = 0; nj < 2; nj++) {
                    uint32_t bo = (uint32_t)((bRowB + nj * 16) * RPAD + kc + bCol) * 2;
                    ldsm4(bh[nj], sB + bo);
                }
#pragma unroll
                for (int mi = 0; mi < 2; mi++)
#pragma unroll
                    for (int nj = 0; nj < 2; nj++)
#pragma unroll
                        for (int s = 0; s < 2; s++) {
                            mma_f16(d[mi][nj][s], ah[mi], bh[nj][s * 2], bh[nj][s * 2 + 1]);
                            mma_f16(d[mi][nj][s], al[mi], bh[nj][s * 2], bh[nj][s * 2 + 1]);
                        }
            }
        }
        const int grp = lane >> 2, tig = lane & 3;
#pragma unroll
        for (int mi = 0; mi < 2; mi++) {
            int r0 = wm * 32 + mi * 16 + grp, r1 = r0 + 8;
#pragma unroll
            for (int nj = 0; nj < 2; nj++)
#pragma unroll
                for (int s = 0; s < 2; s++) {
                    int col = n0 + wn * 32 + nj * 16 + s * 8 + tig * 2;
                    *(float2*)(g_RAG + (size_t)r0 * 32768 + col) =
                        make_float2(d[mi][nj][s][0], d[mi][nj][s][1]);
                    *(float2*)(g_RAG + (size_t)r1 * 32768 + col) =
                        make_float2(d[mi][nj][s][2], d[mi][nj][s][3]);
                }
        }
    }
}

// ----- kernel 7: reduce Z partials + softmax(dim=1) + final dot -----
__global__ __launch_bounds__(256) void k_attn2(const float* __restrict__ bfc,
                                               float* __restrict__ out) {
    __shared__ float Zs[32 * 33];
    __shared__ float As[32 * 33];
    __shared__ float Vs[32 * 33];
    __shared__ float wpart[8];
    int tid = threadIdx.x, b = blockIdx.x;
#pragma unroll
    for (int p = 0; p < 4; p++) {
        int idx = p * 256 + tid;
        int i = idx >> 5, j = idx & 31;
        float s = 0.f;
#pragma unroll
        for (int nb = 0; nb < 4; nb++)
            s += g_Zpart[((size_t)nb * 1024 + b) * 1024 + idx];
        Zs[i * 33 + j] = s;
        As[i * 33 + j] = g_RAG[(size_t)j * 32768 + b * 32 + i];
        Vs[i * 33 + j] = g_RAG[(size_t)(32 + i) * 32768 + b * 32 + j];
    }
    __syncthreads();
    int w = tid >> 5, lane = tid & 31;
    const float rscale = 0.022097086912079608f;  // 1/sqrt(2048)
    float local = 0.f;
#pragma unroll
    for (int q = 0; q < 4; q++) {
        int j = w * 4 + q;
        float lg = (Zs[lane * 33 + j] + As[lane * 33 + j] + g_c[lane * 32 + j]) * rscale;
        float mx = wredmax(lg);
        float ex = __expf(lg - mx);
        float sm = wredsum(ex);
        float contrib = (ex / sm) * (Vs[lane * 33 + j] + g_P[lane * 32 + j]);
        local += wredsum(contrib);
    }
    if (lane == 0) wpart[w] = local;
    __syncthreads();
    if (tid == 0) {
        float t = 0.f;
#pragma unroll
        for (int i = 0; i < 8; i++) t += wpart[i];
        out[b] = t + bfc[0];
    }
}

extern "C" void kernel_launch(void* const* d_in, const int* in_sizes, int n_in,
                              void* d_out, int out_size) {
    const float* x   = (const float*)d_in[0];
    const float* pe  = (const float*)d_in[1];
    const float* Wq  = (const float*)d_in[2];
    const float* bq  = (const float*)d_in[3];
    const float* Wk  = (const float*)d_in[4];
    const float* bk  = (const float*)d_in[5];
    const float* Wv  = (const float*)d_in[6];
    const float* bv  = (const float*)d_in[7];
    const float* Wfc = (const float*)d_in[8];
    const float* bfc = (const float*)d_in[9];
    float* out = (float*)d_out;

    cudaFuncSetAttribute(k_gs, cudaFuncAttributeMaxDynamicSharedMemorySize, GSMEM);
    cudaFuncSetAttribute(k_yzrag, cudaFuncAttributeMaxDynamicSharedMemorySize, YSMEM);

    k_prep<<<39744, 256>>>(x, pe, Wq, bq, Wk, bk, Wv, bv, Wfc);
    k_gs<<<448, 256, GSMEM>>>();
    k_mid<<<1472, 256>>>(Wfc);
    k_yzrag<<<1280, 256, YSMEM>>>();
    k_attn2<<<1024, 256>>>(bfc, out);
}

// round 15
// speedup vs baseline: 4.2304x; 1.0660x over previous
#include <cuda_runtime.h>
#include <cuda_bf16.h>
#include <cuda_fp16.h>
#include <math.h>
#include <stdint.h>

// B=1024, S=32, D=1024, D2=2048
// 5-launch pipeline: k_prep -> k_gs (gemmM|skinny) -> k_mid (Mred|skred|small)
//                    -> k_yzrag (yz 128x128 2CTA/SM | rag) -> k_attn2

// ----- static scratch -----
__device__ float g_Cq[65536], g_Ck[65536], g_Cv[65536];
__device__ float g_A[32768], g_Bm[32768], g_G[32768];
__device__ float g_part[786432];     // [3][8][32][1024]
__device__ float g_c[1024], g_P[1024];
__device__ float g_Zpart[8388608];   // gemmM split-K partials (4x1M), then Z [8][1024][32][32]
__device__ float g_RAG[2097152];     // [64][32768]
__device__ __align__(16) __half g_Xh[33554432];
__device__ __align__(16) __half g_MhT[1048576];
__device__ __align__(16) __half g_AGh[65536];
__device__ __align__(16) __half g_AGl[65536];
__device__ __align__(16) __nv_bfloat16 g_WqTh[2097152];
__device__ __align__(16) __nv_bfloat16 g_WqTl[2097152];
__device__ __align__(16) __nv_bfloat16 g_WkTh[2097152];
__device__ __align__(16) __nv_bfloat16 g_WkTl[2097152];
__device__ __align__(16) __nv_bfloat16 g_WvTh[2097152];
__device__ __align__(16) __nv_bfloat16 g_WvTl[2097152];
__device__ __align__(16) __nv_bfloat16 g_CqH[65536], g_CqL[65536];
__device__ __align__(16) __nv_bfloat16 g_CkH[65536], g_CkL[65536];
__device__ __align__(16) __nv_bfloat16 g_WfH[65536], g_WfL[65536];

__device__ __forceinline__ float wredsum(float v) {
#pragma unroll
    for (int o = 16; o; o >>= 1) v += __shfl_xor_sync(0xffffffffu, v, o);
    return v;
}
__device__ __forceinline__ float wredmax(float v) {
#pragma unroll
    for (int o = 16; o; o >>= 1) v = fmaxf(v, __shfl_xor_sync(0xffffffffu, v, o));
    return v;
}
__device__ __forceinline__ uint32_t smem_u32(const void* p) {
    uint32_t a;
    asm("{ .reg .u64 t; cvta.to.shared.u64 t, %1; cvt.u32.u64 %0, t; }" : "=r"(a) : "l"(p));
    return a;
}
__device__ __forceinline__ void ldsm4(uint32_t* r, uint32_t addr) {
    asm volatile("ldmatrix.sync.aligned.m8n8.x4.shared.b16 {%0,%1,%2,%3}, [%4];"
                 : "=r"(r[0]), "=r"(r[1]), "=r"(r[2]), "=r"(r[3]) : "r"(addr));
}
__device__ __forceinline__ void mma_bf16(float* d, const uint32_t* a,
                                         uint32_t b0, uint32_t b1) {
    asm volatile(
        "mma.sync.aligned.m16n8k16.row.col.f32.bf16.bf16.f32 "
        "{%0,%1,%2,%3}, {%4,%5,%6,%7}, {%8,%9}, {%0,%1,%2,%3};"
        : "+f"(d[0]), "+f"(d[1]), "+f"(d[2]), "+f"(d[3])
        : "r"(a[0]), "r"(a[1]), "r"(a[2]), "r"(a[3]), "r"(b0), "r"(b1));
}
__device__ __forceinline__ void mma_f16(float* d, const uint32_t* a,
                                        uint32_t b0, uint32_t b1) {
    asm volatile(
        "mma.sync.aligned.m16n8k16.row.col.f32.f16.f16.f32 "
        "{%0,%1,%2,%3}, {%4,%5,%6,%7}, {%8,%9}, {%0,%1,%2,%3};"
        : "+f"(d[0]), "+f"(d[1]), "+f"(d[2]), "+f"(d[3])
        : "r"(a[0]), "r"(a[1]), "r"(a[2]), "r"(a[3]), "r"(b0), "r"(b1));
}
__device__ __forceinline__ void cpasync16(uint32_t saddr, const void* gaddr) {
    asm volatile("cp.async.cg.shared.global [%0], [%1], 16;" :: "r"(saddr), "l"(gaddr));
}
#define CP_COMMIT() asm volatile("cp.async.commit_group;" ::: "memory")
#define CP_WAIT(n)  asm volatile("cp.async.wait_group %0;" :: "n"(n) : "memory")

// ===== merged prep =====
__global__ __launch_bounds__(256) void k_prep(const float* __restrict__ x,
                                              const float* __restrict__ pe,
                                              const float* __restrict__ Wq, const float* __restrict__ bq,
                                              const float* __restrict__ Wk, const float* __restrict__ bk,
                                              const float* __restrict__ Wv, const float* __restrict__ bv,
                                              const float* __restrict__ Wfc) {
    __shared__ float sh[32 * 33];
    int blk = blockIdx.x;
    int tid = threadIdx.x;
    if (blk < 768) {
        int bz = blk >> 8, bx = blk & 255;
        const float* W; const float* bias; float* out;
        if (bz == 0)      { W = Wq; bias = bq; out = g_Cq; }
        else if (bz == 1) { W = Wk; bias = bk; out = g_Ck; }
        else              { W = Wv; bias = bv; out = g_Cv; }
        int warp = tid >> 5, lane = tid & 31;
        int d2 = bx * 8 + warp;
        float acc[32];
#pragma unroll
        for (int i = 0; i < 32; i++) acc[i] = 0.f;
        for (int e0 = 0; e0 < 1024; e0 += 32) {
            __syncthreads();
#pragma unroll
            for (int p = 0; p < 4; p++) {
                int idx = p * 256 + tid;
                sh[(idx >> 5) * 33 + (idx & 31)] = pe[(idx >> 5) * 1024 + e0 + (idx & 31)];
            }
            __syncthreads();
            float wv = W[(size_t)d2 * 2048 + 1024 + e0 + lane];
#pragma unroll
            for (int i = 0; i < 32; i++) acc[i] += sh[i * 33 + lane] * wv;
        }
        float res = 0.f;
#pragma unroll
        for (int i = 0; i < 32; i++) {
            float r = wredsum(acc[i]);
            if (lane == i) res = r;
        }
        float val = res + bias[d2];
        out[lane * 2048 + d2] = val;
        if (bz < 2) {
            __nv_bfloat16 h = __float2bfloat16(val);
            __nv_bfloat16 l = __float2bfloat16(val - __bfloat162float(h));
            __nv_bfloat16* oh = bz ? g_CkH : g_CqH;
            __nv_bfloat16* ol = bz ? g_CkL : g_CqL;
            oh[lane * 2048 + d2] = h;
            ol[lane * 2048 + d2] = l;
        }
    } else if (blk < 6912) {
        int b2 = blk - 768;
        int bx = b2 & 31, by = (b2 >> 5) & 63, bz = b2 >> 11;
        const float* W = (bz == 0) ? Wq : (bz == 1) ? Wk : Wv;
        __nv_bfloat16* oh = (bz == 0) ? g_WqTh : (bz == 1) ? g_WkTh : g_WvTh;
        __nv_bfloat16* ol = (bz == 0) ? g_WqTl : (bz == 1) ? g_WkTl : g_WvTl;
        int xx = tid & 31, yy = tid >> 5;
#pragma unroll
        for (int i = 0; i < 32; i += 8)
            sh[(yy + i) * 33 + xx] = W[(size_t)(by * 32 + yy + i) * 2048 + bx * 32 + xx];
        __syncthreads();
#pragma unroll
        for (int i = 0; i < 32; i += 8) {
            float v = sh[xx * 33 + yy + i];
            __nv_bfloat16 h = __float2bfloat16(v);
            __nv_bfloat16 l = __float2bfloat16(v - __bfloat162float(h));
            size_t o = (size_t)(bx * 32 + yy + i) * 2048 + by * 32 + xx;
            oh[o] = h;
            ol[o] = l;
        }
    } else if (blk < 6976) {
        int idx4 = (blk - 6912) * 256 + tid;
        float4 v = *(const float4*)(Wfc + (size_t)idx4 * 4);
        float vv[4] = {v.x, v.y, v.z, v.w};
#pragma unroll
        for (int q = 0; q < 4; q++) {
            __nv_bfloat16 h = __float2bfloat16(vv[q]);
            g_WfH[idx4 * 4 + q] = h;
            g_WfL[idx4 * 4 + q] = __float2bfloat16(vv[q] - __bfloat162float(h));
        }
    } else {
        size_t i = ((size_t)(blk - 6976) * 256 + tid) * 4;
        float4 v = *(const float4*)(x + i);
        *(__half2*)(g_Xh + i)     = __halves2half2(__float2half_rn(v.x), __float2half_rn(v.y));
        *(__half2*)(g_Xh + i + 2) = __halves2half2(__float2half_rn(v.z), __float2half_rn(v.w));
    }
}

// ===== k_gs: merged gemmM (blk<256) | skinny (blk 256..447) =====
#define GPAD 72
#define GBUF (128 * GPAD * 2)
#define GSTAGE (4 * GBUF)        // 73728
#define GSMEM (3 * GSTAGE)       // 221184
#define SK_AB (32 * 72 * 2)
#define SK_BB (128 * 72 * 2)
#define SKSTAGE (2 * SK_AB + 2 * SK_BB)   // 46080

__device__ __forceinline__ void g_stage(uint32_t sb, int s, int m0, int n0,
                                        int k0, int tid) {
    uint32_t sa = sb + s * GSTAGE;
#pragma unroll
    for (int p = 0; p < 16; p++) {
        int idx = p * 256 + tid;
        int buf = idx >> 10;
        int t = idx & 1023;
        int row = t >> 3, c = t & 7;
        const __nv_bfloat16* src =
            (buf == 0) ? g_WqTh : (buf == 1) ? g_WqTl : (buf == 2) ? g_WkTh : g_WkTl;
        int r0 = (buf < 2) ? m0 : n0;
        cpasync16(sa + buf * GBUF + (uint32_t)(row * GPAD + c * 8) * 2,
                  src + (size_t)(r0 + row) * 2048 + k0 + c * 8);
    }
}

__device__ __forceinline__ void sk_stage256(uint32_t sb, int s,
                                            const __nv_bfloat16* __restrict__ Ah,
                                            const __nv_bfloat16* __restrict__ Al,
                                            const __nv_bfloat16* __restrict__ Bh,
                                            const __nv_bfloat16* __restrict__ Bl,
                                            int n0, int k0, int tid) {
    uint32_t sa = sb + s * SKSTAGE;
#pragma unroll
    for (int p = 0; p < 2; p++) {
        int idx = p * 256 + tid;
        int bufl = idx >> 8;
        int t = idx & 255;
        int row = t >> 3, ch = t & 7;
        const __nv_bfloat16* src = bufl ? Al : Ah;
        cpasync16(sa + bufl * SK_AB + (uint32_t)(row * 72 + ch * 8) * 2,
                  src + (size_t)row * 2048 + k0 + ch * 8);
    }
#pragma unroll
    for (int p = 0; p < 8; p++) {
        int idx = p * 256 + tid;
        int bufl = idx >> 10;
        int t = idx & 1023;
        int row = t >> 3, ch = t & 7;
        const __nv_bfloat16* src = bufl ? Bl : Bh;
        cpasync16(sa + 2 * SK_AB + bufl * SK_BB + (uint32_t)(row * 72 + ch * 8) * 2,
                  src + (size_t)(n0 + row) * 2048 + k0 + ch * 8);
    }
}

__global__ __launch_bounds__(256, 1) void k_gs() {
    extern __shared__ __align__(16) char gsmem[];
    const uint32_t sb = smem_u32(gsmem);
    const int tid = threadIdx.x, lane = tid & 31, wid = tid >> 5;
    int blk = blockIdx.x;
    if (blk < 256) {
        const int wm = wid >> 2, wn = wid & 3;
        const int m0 = ((blk >> 3) & 7) * 128, n0 = (blk & 7) * 128;
        const int kbase = (blk >> 6) * 512;

        g_stage(sb, 0, m0, n0, kbase, tid);
        CP_COMMIT();
        g_stage(sb, 1, m0, n0, kbase + 64, tid);
        CP_COMMIT();

        float d[4][4][4] = {};
        const int aRow = wm * 64 + (lane & 15);
        const int aCol = (lane >> 4) * 8;
        const int bRow = wn * 32 + (lane & 7) + (lane >> 4) * 8;
        const int bCol = ((lane >> 3) & 1) * 8;

        for (int it = 0; it < 8; it++) {
            if (it < 7) CP_WAIT(1); else CP_WAIT(0);
            __syncthreads();
            if (it + 2 < 8) {
                g_stage(sb, (it + 2) % 3, m0, n0, kbase + (it + 2) * 64, tid);
                CP_COMMIT();
            }
            uint32_t st = sb + (it % 3) * GSTAGE;
#pragma unroll
            for (int ks = 0; ks < 4; ks++) {
                int kc = ks * 16;
                uint32_t arh[4][4], arl[4][4];
#pragma unroll
                for (int i = 0; i < 4; i++) {
                    uint32_t ao = (uint32_t)((aRow + i * 16) * GPAD + kc + aCol) * 2;
                    ldsm4(arh[i], st + ao);
                    ldsm4(arl[i], st + GBUF + ao);
                }
                uint32_t brh[2][4], brl[2][4];
#pragma unroll
                for (int j = 0; j < 2; j++) {
                    uint32_t bo = (uint32_t)((bRow + j * 16) * GPAD + kc + bCol) * 2;
                    ldsm4(brh[j], st + 2 * GBUF + bo);
                    ldsm4(brl[j], st + 3 * GBUF + bo);
                }
#pragma unroll
                for (int i = 0; i < 4; i++)
#pragma unroll
                    for (int j = 0; j < 4; j++) {
                        uint32_t h0 = brh[j >> 1][(j & 1) * 2], h1 = brh[j >> 1][(j & 1) * 2 + 1];
                        uint32_t l0 = brl[j >> 1][(j & 1) * 2], l1 = brl[j >> 1][(j & 1) * 2 + 1];
                        mma_bf16(d[i][j], arh[i], h0, h1);
                        mma_bf16(d[i][j], arh[i], l0, l1);
                        mma_bf16(d[i][j], arl[i], h0, h1);
                    }
            }
        }
        float* outp = g_Zpart + (size_t)(blk >> 6) * 1048576;
        const int grp = lane >> 2, tig = lane & 3;
        const int mb = m0 + wm * 64, nb = n0 + wn * 32;
#pragma unroll
        for (int i = 0; i < 4; i++) {
            int r0 = mb + i * 16 + grp, r1 = r0 + 8;
#pragma unroll
            for (int j = 0; j < 4; j++) {
                int cc = nb + j * 8 + tig * 2;
                *(float2*)(outp + (size_t)r0 * 1024 + cc) = make_float2(d[i][j][0], d[i][j][1]);
                *(float2*)(outp + (size_t)r1 * 1024 + cc) = make_float2(d[i][j][2], d[i][j][3]);
            }
        }
    } else {
        int s2 = blk - 256;
        const int z = s2 >> 6;
        const int n0 = (s2 & 7) * 128;
        const int kbase = ((s2 >> 3) & 7) * 256;

        const __nv_bfloat16* Ah = (z == 0) ? g_CkH : (z == 1) ? g_CqH : g_WfH;
        const __nv_bfloat16* Al = (z == 0) ? g_CkL : (z == 1) ? g_CqL : g_WfL;
        const __nv_bfloat16* Bh = (z == 0) ? g_WqTh : (z == 1) ? g_WkTh : g_WvTh;
        const __nv_bfloat16* Bl = (z == 0) ? g_WqTl : (z == 1) ? g_WkTl : g_WvTl;

        sk_stage256(sb, 0, Ah, Al, Bh, Bl, n0, kbase, tid);
        CP_COMMIT();

        float d[2][2][2][4] = {};
        const int wn = wid;
        const int aRow = lane & 15;
        const int aCol = (lane >> 4) * 8;
        const int bRow = (wn & 3) * 32 + (lane & 7) + (lane >> 4) * 8;
        const int bCol = ((lane >> 3) & 1) * 8;

        for (int it = 0; it < 4; it++) {
            CP_WAIT(0);
            __syncthreads();
            if (it + 1 < 4) {
                sk_stage256(sb, (it + 1) & 1, Ah, Al, Bh, Bl, n0, kbase + (it + 1) * 64, tid);
                CP_COMMIT();
            }
            if (wid < 4) {
                uint32_t st = sb + (it & 1) * SKSTAGE;
                uint32_t sB = st + 2 * SK_AB;
#pragma unroll
                for (int ks = 0; ks < 4; ks++) {
                    int kc = ks * 16;
                    uint32_t ah[2][4], al[2][4];
#pragma unroll
                    for (int mi = 0; mi < 2; mi++) {
                        uint32_t ao = (uint32_t)((mi * 16 + aRow) * 72 + kc + aCol) * 2;
                        ldsm4(ah[mi], st + ao);
                        ldsm4(al[mi], st + SK_AB + ao);
                    }
                    uint32_t bh[2][4], bl[2][4];
#pragma unroll
                    for (int nj = 0; nj < 2; nj++) {
                        uint32_t bo = (uint32_t)((bRow + nj * 16) * 72 + kc + bCol) * 2;
                        ldsm4(bh[nj], sB + bo);
                        ldsm4(bl[nj], sB + SK_BB + bo);
                    }
#pragma unroll
                    for (int mi = 0; mi < 2; mi++)
#pragma unroll
                        for (int nj = 0; nj < 2; nj++)
#pragma unroll
                            for (int s = 0; s < 2; s++) {
                                mma_bf16(d[mi][nj][s], ah[mi], bh[nj][s * 2], bh[nj][s * 2 + 1]);
                                mma_bf16(d[mi][nj][s], ah[mi], bl[nj][s * 2], bl[nj][s * 2 + 1]);
                                mma_bf16(d[mi][nj][s], al[mi], bh[nj][s * 2], bh[nj][s * 2 + 1]);
                            }
                }
            }
            __syncthreads();
        }
        if (wid < 4) {
            float* outp = g_part + ((size_t)z * 8 + ((s2 >> 3) & 7)) * 32768;
            const int grp = lane >> 2, tig = lane & 3;
#pragma unroll
            for (int mi = 0; mi < 2; mi++) {
                int r0 = mi * 16 + grp, r1 = r0 + 8;
#pragma unroll
                for (int nj = 0; nj < 2; nj++)
#pragma unroll
                    for (int s = 0; s < 2; s++) {
                        int col = n0 + (wn & 3) * 32 + nj * 16 + s * 8 + tig * 2;
                        *(float2*)(outp + r0 * 1024 + col) =
                            make_float2(d[mi][nj][s][0], d[mi][nj][s][1]);
                        *(float2*)(outp + r1 * 1024 + col) =
                            make_float2(d[mi][nj][s][2], d[mi][nj][s][3]);
                    }
            }
        }
    }
}

// ----- k_mid: merged Mred | skred | small -----
__global__ __launch_bounds__(256) void k_mid(const float* __restrict__ Wfc) {
    __shared__ float t[32][33];
    int blk = blockIdx.x, tid = threadIdx.x;
    if (blk < 1024) {
        int bx = blk & 31, by = blk >> 5;
        int x = tid & 31, y = tid >> 5;
#pragma unroll
        for (int i = 0; i < 32; i += 8) {
            size_t o = (size_t)(by * 32 + y + i) * 1024 + bx * 32 + x;
            t[y + i][x] = g_Zpart[o] + g_Zpart[1048576 + o] +
                          g_Zpart[2097152 + o] + g_Zpart[3145728 + o];
        }
        __syncthreads();
#pragma unroll
        for (int i = 0; i < 32; i += 8)
            g_MhT[(size_t)(bx * 32 + y + i) * 1024 + by * 32 + x] = __float2half_rn(t[x][y + i]);
    } else if (blk < 1408) {
        int idx = (blk - 1024) * 256 + tid;
        int z = idx >> 15;
        int r = idx & 32767;
        float s = 0.f;
#pragma unroll
        for (int kc = 0; kc < 8; kc++) s += g_part[((size_t)z * 8 + kc) * 32768 + r];
        float* out = (z == 0) ? g_A : (z == 1) ? g_Bm : g_G;
        out[r] = s;
        if (z != 1) {
            int agrow = (z == 0) ? (r >> 10) : 32 + (r >> 10);
            int col = r & 1023;
            __half h = __float2half_rn(s);
            g_AGh[agrow * 1024 + col] = h;
            g_AGl[agrow * 1024 + col] = __float2half_rn(s - __half2float(h));
        }
    } else {
        int blkr = blk - 1408;
        int i = blkr & 31, by = blkr >> 5;
        const float* L; const float* R; float* out;
        if (by == 0) { L = g_Cq; R = g_Ck; out = g_c; }
        else         { L = Wfc;  R = g_Cv; out = g_P; }
        int warp = tid >> 5, lane = tid & 31;
        float acc[4] = {0.f, 0.f, 0.f, 0.f};
        for (int dd = lane; dd < 2048; dd += 32) {
            float lv = L[i * 2048 + dd];
#pragma unroll
            for (int q = 0; q < 4; q++) acc[q] += lv * R[(warp * 4 + q) * 2048 + dd];
        }
#pragma unroll
        for (int q = 0; q < 4; q++) {
            float r = wredsum(acc[q]);
            if (lane == 0) out[i * 32 + warp * 4 + q] = r;
        }
    }
}

// ====== k_yzrag: yz (blk<2048, 128x128 tile, 2 CTA/SM) | rag (blk 2048..2303) ======
#define Y3PAD 72
#define Y3BUF (128 * Y3PAD * 2)            // 18432
#define Y3STAGE (2 * Y3BUF)                // 36864 (A + B)
#define ZBUF3 (128 * 136 * 2)              // 34816
#define YSMEM3 (3 * ZBUF3)                 // 104448 (>= 2*Y3STAGE = 73728)
#define RPAD 72
#define R_A_BYTES (64 * RPAD * 2)          // 9216
#define R_B_BYTES (128 * RPAD * 2)         // 18432
#define RSTAGE (2 * R_A_BYTES + R_B_BYTES) // 36864

__device__ __forceinline__ void y_stage3(uint32_t sb, int s, int m0, int n0,
                                         int k0, int tid) {
    uint32_t sa = sb + s * Y3STAGE;
#pragma unroll
    for (int p = 0; p < 8; p++) {
        int idx = p * 256 + tid;   // 0..2047
        int buf = idx >> 10;
        int t = idx & 1023;        // 128 rows x 8 chunks
        int row = t >> 3, c = t & 7;
        const __half* src = buf ? g_MhT : g_Xh;
        int r0 = buf ? n0 : m0;
        cpasync16(sa + buf * Y3BUF + (uint32_t)(row * Y3PAD + c * 8) * 2,
                  src + (size_t)(r0 + row) * 1024 + k0 + c * 8);
    }
}
__device__ __forceinline__ void r_stage(uint32_t sb, int s, int n0, int k0, int tid) {
    uint32_t sa = sb + s * RSTAGE;
#pragma unroll
    for (int p = 0; p < 4; p++) {
        int idx = p * 256 + tid;
        int bufl = idx >> 9;
        int t = idx & 511;
        int row = t >> 3, ch = t & 7;
        const __half* src = bufl ? g_AGl : g_AGh;
        cpasync16(sa + bufl * R_A_BYTES + (uint32_t)(row * RPAD + ch * 8) * 2,
                  src + (size_t)row * 1024 + k0 + ch * 8);
    }
#pragma unroll
    for (int p = 0; p < 4; p++) {
        int idx = p * 256 + tid;
        int row = idx >> 3, ch = idx & 7;
        cpasync16(sa + 2 * R_A_BYTES + (uint32_t)(row * RPAD + ch * 8) * 2,
                  g_Xh + (size_t)(n0 + row) * 1024 + k0 + ch * 8);
    }
}

__global__ __launch_bounds__(256, 2) void k_yzrag() {
    extern __shared__ __align__(16) char ysmem[];
    const uint32_t sb = smem_u32(ysmem);
    const int tid = threadIdx.x, lane = tid & 31, wid = tid >> 5;
    int blk = blockIdx.x;

    if (blk < 2048) {
        // ---- yz: CTA 128x128, warp tile 64x32 ----
        const int wm = wid >> 2, wn = wid & 3;
        const int m0 = (blk >> 3) * 128, n0 = (blk & 7) * 128;

        y_stage3(sb, 0, m0, n0, 0, tid);
        CP_COMMIT();

        float d[4][4][4] = {};
        const int aRow = wm * 64 + (lane & 15);
        const int aCol = (lane >> 4) * 8;
        const int bRow = wn * 32 + (lane & 7) + (lane >> 4) * 8;
        const int bCol = ((lane >> 3) & 1) * 8;

        for (int it = 0; it < 16; it++) {
            CP_WAIT(0);
            __syncthreads();
            if (it + 1 < 16) {
                y_stage3(sb, (it + 1) & 1, m0, n0, (it + 1) * 64, tid);
                CP_COMMIT();
            }
            uint32_t abase = sb + (it & 1) * Y3STAGE;
            uint32_t bbase = abase + Y3BUF;
#pragma unroll
            for (int ks = 0; ks < 4; ks++) {
                int kc = ks * 16;
                uint32_t ar[4][4];
#pragma unroll
                for (int i = 0; i < 4; i++)
                    ldsm4(ar[i], abase + (uint32_t)((aRow + i * 16) * Y3PAD + kc + aCol) * 2);
                uint32_t br[2][4];
#pragma unroll
                for (int j = 0; j < 2; j++)
                    ldsm4(br[j], bbase + (uint32_t)((bRow + j * 16) * Y3PAD + kc + bCol) * 2);
#pragma unroll
                for (int i = 0; i < 4; i++)
#pragma unroll
                    for (int j = 0; j < 4; j++)
                        mma_f16(d[i][j], ar[i], br[j >> 1][(j & 1) * 2],
                                br[j >> 1][(j & 1) * 2 + 1]);
            }
        }
        __syncthreads();

        // epilogue: add Bm
        const int grp = lane >> 2, tig = lane & 3;
#pragma unroll
        for (int i = 0; i < 4; i++) {
            int r0 = wm * 64 + i * 16 + grp;
            int p0 = r0 & 31, p1 = (r0 + 8) & 31;
#pragma unroll
            for (int j = 0; j < 4; j++) {
                int cc = n0 + wn * 32 + j * 8 + tig * 2;
                float2 b0 = *(const float2*)(g_Bm + p0 * 1024 + cc);
                float2 b1 = *(const float2*)(g_Bm + p1 * 1024 + cc);
                d[i][j][0] += b0.x; d[i][j][1] += b0.y;
                d[i][j][2] += b1.x; d[i][j][3] += b1.y;
            }
        }

        // issue X tile load (128 rows x 128 f-cols at n0), into ZXH
        const uint32_t ZYH = sb, ZYL = sb + ZBUF3, ZXH = sb + 2 * ZBUF3;
#pragma unroll
        for (int p = 0; p < 8; p++) {
            int idx = p * 256 + tid;       // 0..2047 = 128 rows x 16 chunks
            int row = idx >> 4, ch = idx & 15;
            cpasync16(ZXH + (uint32_t)(row * 136 + ch * 8) * 2,
                      g_Xh + (size_t)(m0 + row) * 1024 + n0 + ch * 8);
        }
        CP_COMMIT();
        // write Y' hi/lo (full 128x128, every warp its own cols)
#pragma unroll
        for (int i = 0; i < 4; i++) {
            int r0 = wm * 64 + i * 16 + grp;
#pragma unroll
            for (int j = 0; j < 4; j++) {
                int cl = wn * 32 + j * 8 + tig * 2;
                float v0 = d[i][j][0], v1 = d[i][j][1];
                float v2 = d[i][j][2], v3 = d[i][j][3];
                __half h0 = __float2half_rn(v0), h1 = __float2half_rn(v1);
                __half h2 = __float2half_rn(v2), h3 = __float2half_rn(v3);
                *(__half2*)(ysmem + ((r0) * 136 + cl) * 2) = __halves2half2(h0, h1);
                *(__half2*)(ysmem + ((r0 + 8) * 136 + cl) * 2) = __halves2half2(h2, h3);
                *(__half2*)(ysmem + ZBUF3 + ((r0) * 136 + cl) * 2) =
                    __halves2half2(__float2half_rn(v0 - __half2float(h0)),
                                   __float2half_rn(v1 - __half2float(h1)));
                *(__half2*)(ysmem + ZBUF3 + ((r0 + 8) * 136 + cl) * 2) =
                    __halves2half2(__float2half_rn(v2 - __half2float(h2)),
                                   __float2half_rn(v3 - __half2float(h3)));
            }
        }
        CP_WAIT(0);
        __syncthreads();

        // Z mma: 8 warps = 4 batches x 2 n-halves; k = 128 (this block's f-cols)
        const int bb = wid >> 1;
        const int nh = wid & 1;
        float z[2][2][4] = {};
#pragma unroll
        for (int ksl = 0; ksl < 8; ksl++) {
            int kc = ksl * 16;
            uint32_t ayh[2][4], ayl[2][4];
#pragma unroll
            for (int mi = 0; mi < 2; mi++) {
                uint32_t ao = (uint32_t)((bb * 32 + mi * 16 + (lane & 15)) * 136 +
                                         kc + (lane >> 4) * 8) * 2;
                ldsm4(ayh[mi], ZYH + ao);
                ldsm4(ayl[mi], ZYL + ao);
            }
            uint32_t bxh[4];
            uint32_t bo = (uint32_t)((bb * 32 + nh * 16 + (lane & 7) + (lane >> 4) * 8) * 136 +
                                     kc + ((lane >> 3) & 1) * 8) * 2;
            ldsm4(bxh, ZXH + bo);
#pragma unroll
            for (int mi = 0; mi < 2; mi++)
#pragma unroll
                for (int no = 0; no < 2; no++) {
                    mma_f16(z[mi][no], ayh[mi], bxh[no * 2], bxh[no * 2 + 1]);
                    mma_f16(z[mi][no], ayl[mi], bxh[no * 2], bxh[no * 2 + 1]);
                }
        }
        // store Z partials: slot = n-block (8 slots)
        {
            int b = (blk >> 3) * 4 + bb;
            size_t base = ((size_t)(blk & 7) * 1024 + b) * 1024;
#pragma unroll
            for (int mi = 0; mi < 2; mi++) {
                int i0 = mi * 16 + grp;
#pragma unroll
                for (int no = 0; no < 2; no++) {
                    int j0 = nh * 16 + no * 8 + tig * 2;
                    *(float2*)(g_Zpart + base + i0 * 32 + j0) =
                        make_float2(z[mi][no][0], z[mi][no][1]);
                    *(float2*)(g_Zpart + base + (i0 + 8) * 32 + j0) =
                        make_float2(z[mi][no][2], z[mi][no][3]);
                }
            }
        }
    } else {
        // ---- rag: [A;G] @ Xall^T (2-product), n-tile 128 ----
        const int wm = wid >> 2, wn = wid & 3;
        const int n0 = (blk - 2048) * 128;

        r_stage(sb, 0, n0, 0, tid);
        CP_COMMIT();

        float d[2][2][2][4] = {};
        const int aRowB = wm * 32 + (lane & 15);
        const int aCol = (lane >> 4) * 8;
        const int bRowB = wn * 32 + (lane & 7) + (lane >> 4) * 8;
        const int bCol = ((lane >> 3) & 1) * 8;

        for (int it = 0; it < 16; it++) {
            CP_WAIT(0);
            __syncthreads();
            if (it + 1 < 16) {
                r_stage(sb, (it + 1) & 1, n0, (it + 1) * 64, tid);
                CP_COMMIT();
            }
            uint32_t st = sb + (it & 1) * RSTAGE;
            uint32_t sB = st + 2 * R_A_BYTES;
#pragma unroll
            for (int ks = 0; ks < 4; ks++) {
                int kc = ks * 16;
                uint32_t ah[2][4], al[2][4];
#pragma unroll
                for (int mi = 0; mi < 2; mi++) {
                    uint32_t ao = (uint32_t)((aRowB + mi * 16) * RPAD + kc + aCol) * 2;
                    ldsm4(ah[mi], st + ao);
                    ldsm4(al[mi], st + R_A_BYTES + ao);
                }
                uint32_t bh[2][4];
#pragma unroll
                for (int nj = 0; nj < 2; nj++) {
                    uint32_t bo = (uint32_t)((bRowB + nj * 16) * RPAD + kc + bCol) * 2;
                    ldsm4(bh[nj], sB + bo);
                }
#pragma unroll
                for (int mi = 0; mi < 2; mi++)
#pragma unroll
                    for (int nj = 0; nj < 2; nj++)
#pragma unroll
                        for (int s = 0; s < 2; s++) {
                            mma_f16(d[mi][nj][s], ah[mi], bh[nj][s * 2], bh[nj][s * 2 + 1]);
                            mma_f16(d[mi][nj][s], al[mi], bh[nj][s * 2], bh[nj][s * 2 + 1]);
                        }
            }
        }
        const int grp = lane >> 2, tig = lane & 3;
#pragma unroll
        for (int mi = 0; mi < 2; mi++) {
            int r0 = wm * 32 + mi * 16 + grp, r1 = r0 + 8;
#pragma unroll
            for (int nj = 0; nj < 2; nj++)
#pragma unroll
                for (int s = 0; s < 2; s++) {
                    int col = n0 + wn * 32 + nj * 16 + s * 8 + tig * 2;
                    *(float2*)(g_RAG + (size_t)r0 * 32768 + col) =
                        make_float2(d[mi][nj][s][0], d[mi][nj][s][1]);
                    *(float2*)(g_RAG + (size_t)r1 * 32768 + col) =
                        make_float2(d[mi][nj][s][2], d[mi][nj][s][3]);
                }
        }
    }
}

// ----- kernel 7: reduce Z partials (8 slots) + softmax(dim=1) + final dot -----
__global__ __launch_bounds__(256) void k_attn2(const float* __restrict__ bfc,
                                               float* __restrict__ out) {
    __shared__ float Zs[32 * 33];
    __shared__ float As[32 * 33];
    __shared__ float Vs[32 * 33];
    __shared__ float wpart[8];
    int tid = threadIdx.x, b = blockIdx.x;
#pragma unroll
    for (int p = 0; p < 4; p++) {
        int idx = p * 256 + tid;
        int i = idx >> 5, j = idx & 31;
        float s = 0.f;
#pragma unroll
        for (int nb = 0; nb < 8; nb++)
            s += g_Zpart[((size_t)nb * 1024 + b) * 1024 + idx];
        Zs[i * 33 + j] = s;
        As[i * 33 + j] = g_RAG[(size_t)j * 32768 + b * 32 + i];
        Vs[i * 33 + j] = g_RAG[(size_t)(32 + i) * 32768 + b * 32 + j];
    }
    __syncthreads();
    int w = tid >> 5, lane = tid & 31;
    const float rscale = 0.022097086912079608f;  // 1/sqrt(2048)
    float local = 0.f;
#pragma unroll
    for (int q = 0; q < 4; q++) {
        int j = w * 4 + q;
        float lg = (Zs[lane * 33 + j] + As[lane * 33 + j] + g_c[lane * 32 + j]) * rscale;
        float mx = wredmax(lg);
        float ex = __expf(lg - mx);
        float sm = wredsum(ex);
        float contrib = (ex / sm) * (Vs[lane * 33 + j] + g_P[lane * 32 + j]);
        local += wredsum(contrib);
    }
    if (lane == 0) wpart[w] = local;
    __syncthreads();
    if (tid == 0) {
        float t = 0.f;
#pragma unroll
        for (int i = 0; i < 8; i++) t += wpart[i];
        out[b] = t + bfc[0];
    }
}

extern "C" void kernel_launch(void* const* d_in, const int* in_sizes, int n_in,
                              void* d_out, int out_size) {
    const float* x   = (const float*)d_in[0];
    const float* pe  = (const float*)d_in[1];
    const float* Wq  = (const float*)d_in[2];
    const float* bq  = (const float*)d_in[3];
    const float* Wk  = (const float*)d_in[4];
    const float* bk  = (const float*)d_in[5];
    const float* Wv  = (const float*)d_in[6];
    const float* bv  = (const float*)d_in[7];
    const float* Wfc = (const float*)d_in[8];
    const float* bfc = (const float*)d_in[9];
    float* out = (float*)d_out;

    cudaFuncSetAttribute(k_gs, cudaFuncAttributeMaxDynamicSharedMemorySize, GSMEM);
    cudaFuncSetAttribute(k_yzrag, cudaFuncAttributeMaxDynamicSharedMemorySize, YSMEM3);

    k_prep<<<39744, 256>>>(x, pe, Wq, bq, Wk, bk, Wv, bv, Wfc);
    k_gs<<<448, 256, GSMEM>>>();
    k_mid<<<1472, 256>>>(Wfc);
    k_yzrag<<<2304, 256, YSMEM3>>>();
    k_attn2<<<1024, 256>>>(bfc, out);
}